// round 1
// baseline (speedup 1.0000x reference)
#include <cuda_runtime.h>

#define BATCH 32
#define WDIM  168
#define MDIM  2048
#define HIDD  128
#define NHOPS 6
#define BWCOL (BATCH * WDIM)   // 5376

// Ping-pong propagation buffers t[M, B*W] (2 x 44 MB)
__device__ float g_t[2][(size_t)MDIM * BWCOL];

// ---------------- packed f32x2 helpers ----------------
__device__ __forceinline__ unsigned long long bcast_f32x2(float a) {
    unsigned long long r;
    unsigned int u = __float_as_uint(a);
    asm("mov.b64 %0, {%1, %1};" : "=l"(r) : "r"(u));
    return r;
}
__device__ __forceinline__ void fma_f32x2(unsigned long long& d,
                                          unsigned long long a,
                                          unsigned long long b) {
    asm("fma.rn.f32x2 %0, %1, %2, %0;" : "+l"(d) : "l"(a), "l"(b));
}
__device__ __forceinline__ float2 unpack_f32x2(unsigned long long v) {
    unsigned int lo, hi;
    asm("mov.b64 {%0, %1}, %2;" : "=r"(lo), "=r"(hi) : "l"(v));
    return make_float2(__uint_as_float(lo), __uint_as_float(hi));
}

// ---------------- transpose: x[B,W,M] -> t0[M, B*W] ----------------
__global__ void transpose_kernel(const float* __restrict__ x, float* __restrict__ t) {
    __shared__ float tile[32][33];
    int m0 = blockIdx.x * 32;
    int n0 = blockIdx.y * 32;
    #pragma unroll
    for (int i = threadIdx.y; i < 32; i += 8)
        tile[i][threadIdx.x] = x[(size_t)(n0 + i) * MDIM + m0 + threadIdx.x];
    __syncthreads();
    #pragma unroll
    for (int i = threadIdx.y; i < 32; i += 8)
        t[(size_t)(m0 + i) * BWCOL + n0 + threadIdx.x] = tile[threadIdx.x][i];
}

// ---------------- SGEMM: C[2048,5376] = L[2048,2048] * B[2048,5376] ----------------
// 128x128x16 tile, 256 threads, 8x8 per thread, packed f32x2 FMA.
__global__ __launch_bounds__(256, 2) void sgemm_kernel(const float* __restrict__ A,
                                                       const float* __restrict__ B,
                                                       float* __restrict__ C) {
    const int N = BWCOL, K = MDIM;
    __shared__ __align__(16) float As[16][128];
    __shared__ __align__(16) float Bs[16][128];

    int tid = threadIdx.x;
    int m0 = blockIdx.y * 128;
    int n0 = blockIdx.x * 128;
    int tx = tid & 15, ty = tid >> 4;
    int ar = tid >> 2;           // A-load row (0..63), plus +64
    int ak = (tid & 3) << 2;     // A-load k (float4)
    int bk = tid >> 5;           // B-load k row (0..7), plus +8
    int bn = (tid & 31) << 2;    // B-load n (float4)

    unsigned long long acc[8][4];
    #pragma unroll
    for (int i = 0; i < 8; i++)
        #pragma unroll
        for (int j = 0; j < 4; j++) acc[i][j] = 0ULL;

    for (int k0 = 0; k0 < K; k0 += 16) {
        #pragma unroll
        for (int i = 0; i < 2; i++) {
            int r = ar + i * 64;
            float4 v = *(const float4*)(A + (size_t)(m0 + r) * K + k0 + ak);
            As[ak + 0][r] = v.x; As[ak + 1][r] = v.y;
            As[ak + 2][r] = v.z; As[ak + 3][r] = v.w;
        }
        #pragma unroll
        for (int i = 0; i < 2; i++) {
            int kk = bk + i * 8;
            *(float4*)(&Bs[kk][bn]) = *(const float4*)(B + (size_t)(k0 + kk) * N + n0 + bn);
        }
        __syncthreads();

        #pragma unroll
        for (int k = 0; k < 16; k++) {
            float4 a0 = *(const float4*)(&As[k][ty * 4]);
            float4 a1 = *(const float4*)(&As[k][ty * 4 + 64]);
            ulonglong2 b0 = *(const ulonglong2*)(&Bs[k][tx * 4]);
            ulonglong2 b1 = *(const ulonglong2*)(&Bs[k][tx * 4 + 64]);
            unsigned long long bb0 = b0.x, bb1 = b0.y, bb2 = b1.x, bb3 = b1.y;
            float av[8] = {a0.x, a0.y, a0.z, a0.w, a1.x, a1.y, a1.z, a1.w};
            #pragma unroll
            for (int i = 0; i < 8; i++) {
                unsigned long long aa = bcast_f32x2(av[i]);
                fma_f32x2(acc[i][0], aa, bb0);
                fma_f32x2(acc[i][1], aa, bb1);
                fma_f32x2(acc[i][2], aa, bb2);
                fma_f32x2(acc[i][3], aa, bb3);
            }
        }
        __syncthreads();
    }

    #pragma unroll
    for (int i = 0; i < 8; i++) {
        int r = m0 + ((i < 4) ? (ty * 4 + i) : (64 + ty * 4 + (i - 4)));
        float* Crow = C + (size_t)r * N + n0;
        float2 c0 = unpack_f32x2(acc[i][0]);
        float2 c1 = unpack_f32x2(acc[i][1]);
        float2 c2 = unpack_f32x2(acc[i][2]);
        float2 c3 = unpack_f32x2(acc[i][3]);
        *(float4*)(Crow + tx * 4)      = make_float4(c0.x, c0.y, c1.x, c1.y);
        *(float4*)(Crow + tx * 4 + 64) = make_float4(c2.x, c2.y, c3.x, c3.y);
    }
}

// ---------------- fused hop MLP: s[b,m] (+)= W2 . relu(W1 . t[b,m,:] + b1) + b2 ----------------
// 256 threads / block, 32 (b,m) rows per block. Each warp handles 4 rows;
// lane owns h = lane + 32*j (j=0..3); warp-shuffle reduce over the 128 hidden units.
__global__ __launch_bounds__(256) void mlp_kernel(const float* __restrict__ t,
                                                  const float* __restrict__ W1,
                                                  const float* __restrict__ b1,
                                                  const float* __restrict__ W2,
                                                  const float* __restrict__ b2,
                                                  int hop, int accum,
                                                  float* __restrict__ out) {
    const float* W1h = W1 + hop * HIDD * WDIM;
    const float* b1h = b1 + hop * HIDD;
    const float* W2h = W2 + hop * HIDD;
    float b2h = b2[hop];

    __shared__ __align__(16) float Ts[56][36];     // [k][row], padded
    __shared__ float W1s[HIDD][57];                // [h][k], pad 57 => conflict-free strided reads

    int tid  = threadIdx.x;
    int lane = tid & 31;
    int warp = tid >> 5;          // 8 warps, 4 rows each
    int r0 = blockIdx.x * 32;     // rows r0..r0+31 share the same batch b (M % 32 == 0)
    int b  = r0 >> 11;            // / 2048
    int m0 = r0 & 2047;
    const float* trow0 = t + (size_t)m0 * BWCOL + b * WDIM;

    float b1r[4], w2r[4];
    #pragma unroll
    for (int j = 0; j < 4; j++) {
        b1r[j] = b1h[lane + 32 * j];
        w2r[j] = W2h[lane + 32 * j];
    }

    float acc[4][4] = {};
    for (int w0 = 0; w0 < WDIM; w0 += 56) {
        for (int idx = tid; idx < 32 * 56; idx += 256) {
            int row = idx / 56, w = idx - row * 56;
            Ts[w][row] = trow0[(size_t)row * BWCOL + w0 + w];
        }
        for (int idx = tid; idx < HIDD * 56; idx += 256) {
            int h = idx / 56, w = idx - h * 56;
            W1s[h][w] = W1h[h * WDIM + w0 + w];
        }
        __syncthreads();

        #pragma unroll 8
        for (int k = 0; k < 56; k++) {
            float4 tv = *(const float4*)(&Ts[k][warp * 4]);
            float tvv[4] = {tv.x, tv.y, tv.z, tv.w};
            #pragma unroll
            for (int j = 0; j < 4; j++) {
                float wv = W1s[lane + 32 * j][k];
                #pragma unroll
                for (int i = 0; i < 4; i++) acc[i][j] += tvv[i] * wv;
            }
        }
        __syncthreads();
    }

    float part[4];
    #pragma unroll
    for (int i = 0; i < 4; i++) {
        float s = 0.f;
        #pragma unroll
        for (int j = 0; j < 4; j++) {
            float h = fmaxf(acc[i][j] + b1r[j], 0.f);
            s += h * w2r[j];
        }
        #pragma unroll
        for (int off = 16; off > 0; off >>= 1)
            s += __shfl_xor_sync(0xffffffffu, s, off);
        part[i] = s;
    }
    if (lane < 4) {
        int r = r0 + warp * 4 + lane;
        float v = part[lane] + b2h;
        if (accum) v += out[r];
        out[r] = v;
    }
}

extern "C" void kernel_launch(void* const* d_in, const int* in_sizes, int n_in,
                              void* d_out, int out_size) {
    const float* x  = (const float*)d_in[0];
    const float* L  = (const float*)d_in[1];
    const float* W1 = (const float*)d_in[2];
    const float* b1 = (const float*)d_in[3];
    const float* W2 = (const float*)d_in[4];
    const float* b2 = (const float*)d_in[5];
    float* out = (float*)d_out;

    float* tbuf = nullptr;
    cudaGetSymbolAddress((void**)&tbuf, g_t);
    float* t0 = tbuf;
    float* t1 = tbuf + (size_t)MDIM * BWCOL;

    // 1) xt = transpose(x)  -> t0[M, B*W]
    dim3 tgrid(MDIM / 32, BWCOL / 32), tblk(32, 8);
    transpose_kernel<<<tgrid, tblk>>>(x, t0);

    // 2) hop 0 MLP writes s
    mlp_kernel<<<(BATCH * MDIM) / 32, 256>>>(t0, W1, b1, W2, b2, 0, 0, out);

    // 3) hops 1..6: t <- L @ t ; s += MLP_i(t)
    dim3 ggrid(BWCOL / 128, MDIM / 128);
    float* src = t0;
    float* dst = t1;
    for (int hop = 1; hop <= NHOPS; hop++) {
        sgemm_kernel<<<ggrid, 256>>>(L, src, dst);
        mlp_kernel<<<(BATCH * MDIM) / 32, 256>>>(dst, W1, b1, W2, b2, hop, 1, out);
        float* tmp = src; src = dst; dst = tmp;
    }
}

// round 3
// speedup vs baseline: 4.3784x; 4.3784x over previous
#include <cuda_runtime.h>
#include <cuda_bf16.h>
#include <cuda.h>
#include <cstdint>

#define BATCH 32
#define WDIM  168
#define MDIM  2048
#define HIDD  128
#define NHOPS 6
#define BWCOL (BATCH * WDIM)   // 5376

#if defined(__CUDA_ARCH__) && defined(__CUDA_ARCH_FEAT_SM103_ALL)
#define HAS_TC 1
#else
#define HAS_TC 0
#endif

// t stored TRANSPOSED: T[n][m], n in [0,5376), m contiguous. Split bf16 hi/lo.
__device__ __align__(1024) __nv_bfloat16 g_hi[2][(size_t)BWCOL * MDIM];
__device__ __align__(1024) __nv_bfloat16 g_lo[2][(size_t)BWCOL * MDIM];
__device__ __align__(1024) __nv_bfloat16 g_Lhi[(size_t)MDIM * MDIM];
__device__ __align__(1024) __nv_bfloat16 g_Llo[(size_t)MDIM * MDIM];

// ======================= common helpers =======================
__device__ __forceinline__ uint32_t smem_u32(const void* p) {
    uint32_t a;
    asm("{ .reg .u64 t; cvta.to.shared.u64 t, %1; cvt.u32.u64 %0, t; }" : "=r"(a) : "l"(p));
    return a;
}
__device__ __forceinline__ uint32_t sw128(uint32_t o) { return o ^ ((o >> 3) & 0x70); }

// packed f32x2
__device__ __forceinline__ unsigned long long bcast2(float a) {
    unsigned long long r; unsigned int u = __float_as_uint(a);
    asm("mov.b64 %0, {%1, %1};" : "=l"(r) : "r"(u));
    return r;
}
__device__ __forceinline__ void fma2(unsigned long long& d, unsigned long long a, unsigned long long b) {
    asm("fma.rn.f32x2 %0, %1, %2, %0;" : "+l"(d) : "l"(a), "l"(b));
}
__device__ __forceinline__ float2 unpack2(unsigned long long v) {
    unsigned int lo, hi;
    asm("mov.b64 {%0, %1}, %2;" : "=r"(lo), "=r"(hi) : "l"(v));
    return make_float2(__uint_as_float(lo), __uint_as_float(hi));
}

// ---- base-target ops (sm_80+) ----
__device__ __forceinline__ void cp16(uint32_t dst, const void* src) {
    asm volatile("cp.async.cg.shared.global [%0], [%1], 16;" :: "r"(dst), "l"(src));
}
#define CP_COMMIT() asm volatile("cp.async.commit_group;" ::: "memory")
#define CP_WAIT(n)  asm volatile("cp.async.wait_group %0;" :: "n"(n) : "memory")

__device__ __forceinline__ void ldsm4(uint32_t& r0, uint32_t& r1, uint32_t& r2, uint32_t& r3, uint32_t a) {
    asm volatile("ldmatrix.sync.aligned.m8n8.x4.shared.b16 {%0,%1,%2,%3}, [%4];"
                 : "=r"(r0), "=r"(r1), "=r"(r2), "=r"(r3) : "r"(a));
}
__device__ __forceinline__ void mma16816(float* c, const uint32_t* a, const uint32_t* b) {
    asm volatile("mma.sync.aligned.m16n8k16.row.col.f32.bf16.bf16.f32 "
                 "{%0,%1,%2,%3}, {%4,%5,%6,%7}, {%8,%9}, {%0,%1,%2,%3};"
                 : "+f"(c[0]), "+f"(c[1]), "+f"(c[2]), "+f"(c[3])
                 : "r"(a[0]), "r"(a[1]), "r"(a[2]), "r"(a[3]), "r"(b[0]), "r"(b[1]));
}

// ======================= fp32 -> bf16 hi/lo split =======================
__global__ void split_kernel(const float* __restrict__ in, __nv_bfloat16* __restrict__ hi,
                             __nv_bfloat16* __restrict__ lo, int n4) {
    int i = blockIdx.x * blockDim.x + threadIdx.x;
    if (i >= n4) return;
    float4 v = ((const float4*)in)[i];
    __nv_bfloat16 h[4], l[4];
    float vv[4] = {v.x, v.y, v.z, v.w};
    #pragma unroll
    for (int j = 0; j < 4; j++) {
        h[j] = __float2bfloat16(vv[j]);
        l[j] = __float2bfloat16(vv[j] - __bfloat162float(h[j]));
    }
    ((ushort4*)hi)[i] = make_ushort4(*(unsigned short*)&h[0], *(unsigned short*)&h[1],
                                     *(unsigned short*)&h[2], *(unsigned short*)&h[3]);
    ((ushort4*)lo)[i] = make_ushort4(*(unsigned short*)&l[0], *(unsigned short*)&l[1],
                                     *(unsigned short*)&l[2], *(unsigned short*)&l[3]);
}

// ======================= tcgen05 path ('a' targets only) =======================
#if HAS_TC
__device__ __forceinline__ uint32_t elect_one() {
    uint32_t p;
    asm volatile("{ .reg .pred p; elect.sync _|p, 0xFFFFFFFF; selp.b32 %0, 1, 0, p; }" : "=r"(p));
    return p;
}
#define MBAR_INIT(a, c) asm volatile("mbarrier.init.shared.b64 [%0], %1;" :: "r"(a), "r"(c) : "memory")
#define MBAR_EXPECT_TX(a, b) asm volatile("mbarrier.arrive.expect_tx.shared.b64 _, [%0], %1;" :: "r"(a), "r"(b) : "memory")
#define MBAR_WAIT(a, ph) do { \
    uint32_t _m = (a), _p = (ph), _d; \
    asm volatile("{ .reg .pred p; mbarrier.try_wait.parity.acquire.cta.shared::cta.b64 p, [%1], %2; selp.b32 %0,1,0,p; }" \
        : "=r"(_d) : "r"(_m), "r"(_p) : "memory"); \
    if (!_d) { asm volatile("{ .reg .pred P1; WL%=: mbarrier.try_wait.parity.acquire.cta.shared::cta.b64 P1, [%0], %1, 0x989680; @P1 bra.uni WD%=; bra.uni WL%=; WD%=: }" \
        :: "r"(_m), "r"(_p) : "memory"); } \
} while (0)
#define TMA_LOAD_2D(sm, map, cx, cy, mb) \
    asm volatile("cp.async.bulk.tensor.2d.shared::cta.global.tile.mbarrier::complete_tx::bytes [%0], [%1, {%2, %3}], [%4];" \
        :: "r"(sm), "l"(map), "r"(cx), "r"(cy), "r"(mb) : "memory")
#define TC_ALLOC(smaddr, n)   asm volatile("tcgen05.alloc.cta_group::1.sync.aligned.shared::cta.b32 [%0], %1;" :: "r"(smaddr), "r"(n) : "memory")
#define TC_RELINQ()           asm volatile("tcgen05.relinquish_alloc_permit.cta_group::1.sync.aligned;")
#define TC_DEALLOC(t, n)      asm volatile("tcgen05.dealloc.cta_group::1.sync.aligned.b32 %0, %1;" :: "r"(t), "r"(n))
#define TC_COMMIT(mb)         asm volatile("tcgen05.commit.cta_group::1.mbarrier::arrive::one.shared::cluster.b64 [%0];" :: "r"(mb) : "memory")
#define TC_FENCE_AFTER()      asm volatile("tcgen05.fence::after_thread_sync;" ::: "memory")
#define TC_FENCE_BEFORE()     asm volatile("tcgen05.fence::before_thread_sync;" ::: "memory")
#define TC_WAIT_LD()          asm volatile("tcgen05.wait::ld.sync.aligned;" ::: "memory")
#define TC_LD_X32(r, addr) \
    asm volatile("tcgen05.ld.sync.aligned.32x32b.x32.b32 " \
        "{%0,%1,%2,%3,%4,%5,%6,%7,%8,%9,%10,%11,%12,%13,%14,%15," \
        "%16,%17,%18,%19,%20,%21,%22,%23,%24,%25,%26,%27,%28,%29,%30,%31}, [%32];" \
        : "=r"((r)[0]),"=r"((r)[1]),"=r"((r)[2]),"=r"((r)[3]),"=r"((r)[4]),"=r"((r)[5]),"=r"((r)[6]),"=r"((r)[7]), \
          "=r"((r)[8]),"=r"((r)[9]),"=r"((r)[10]),"=r"((r)[11]),"=r"((r)[12]),"=r"((r)[13]),"=r"((r)[14]),"=r"((r)[15]), \
          "=r"((r)[16]),"=r"((r)[17]),"=r"((r)[18]),"=r"((r)[19]),"=r"((r)[20]),"=r"((r)[21]),"=r"((r)[22]),"=r"((r)[23]), \
          "=r"((r)[24]),"=r"((r)[25]),"=r"((r)[26]),"=r"((r)[27]),"=r"((r)[28]),"=r"((r)[29]),"=r"((r)[30]),"=r"((r)[31]) \
        : "r"(addr))

static constexpr uint64_t DESC_SW128 =
    (uint64_t(2) << 61) | (uint64_t(1) << 46) | (uint64_t(64) << 32) | (uint64_t(1) << 16);
__device__ __forceinline__ uint64_t mk_desc(uint32_t sm) {
    return DESC_SW128 | ((uint64_t)(sm >> 4) & 0x3FFF);
}
#define IDESC 0x8400490u  // kind::f16, D=F32, A=BF16, B=BF16, M=128, N=256
__device__ __forceinline__ void mma_ss(uint32_t d, uint64_t a, uint64_t b, uint32_t en) {
    asm volatile("{ .reg .pred p; setp.ne.u32 p, %5, 0;\n\t"
        "tcgen05.mma.cta_group::1.kind::f16 [%0], %1, %2, %3, {%4,%4,%4,%4}, p; }"
        :: "r"(d), "l"(a), "l"(b), "r"(IDESC), "r"(0u), "r"(en) : "memory");
}
#endif // HAS_TC

#define KCHUNK 64
#define NCHUNK (MDIM / KCHUNK)
#define SM_TMEMPTR 0
#define SM_FULL(s)  (16 + (s) * 8)
#define SM_EMPTY(s) (32 + (s) * 8)
#define STAGE_BYTES 98304
#define SM_STAGE(s) (1024 + (s) * STAGE_BYTES)
#define A_HI(s) (SM_STAGE(s))
#define A_LO(s) (SM_STAGE(s) + 16384)
#define B_HI(s) (SM_STAGE(s) + 32768)
#define B_LO(s) (SM_STAGE(s) + 65536)
#define SM_OUT_HI 1024
#define SM_OUT_LO (1024 + 65536)
#define TC_SMEM (1024 + 2 * STAGE_BYTES)   // 197632

__global__ __launch_bounds__(256, 1) void gemm_tc(
    const __grid_constant__ CUtensorMap mapAhi,
    const __grid_constant__ CUtensorMap mapAlo,
    const __grid_constant__ CUtensorMap mapBhi,
    const __grid_constant__ CUtensorMap mapBlo,
    __nv_bfloat16* __restrict__ dst_hi,
    __nv_bfloat16* __restrict__ dst_lo)
{
#if HAS_TC
    extern __shared__ char smem[];
    uint32_t smb = smem_u32(smem);
    int tid = threadIdx.x, wid = tid >> 5, lane = tid & 31;
    int n0 = blockIdx.x * 256;
    int m0 = blockIdx.y * 128;

    if (wid == 4) { TC_ALLOC(smb + SM_TMEMPTR, 512); TC_RELINQ(); }
    if (tid == 0) {
        MBAR_INIT(smb + SM_FULL(0), 1);
        MBAR_INIT(smb + SM_FULL(1), 1);
        MBAR_INIT(smb + SM_EMPTY(0), 1);
        MBAR_INIT(smb + SM_EMPTY(1), 1);
    }
    __syncthreads();
    uint32_t tmem;
    asm volatile("ld.shared.b32 %0, [%1];" : "=r"(tmem) : "r"(smb + SM_TMEMPTR));

    if (wid == 4) {
        uint32_t e1 = elect_one();
        int pf[2] = {0, 0}, pe[2] = {0, 0};
        if (e1) {
            #pragma unroll
            for (int s = 0; s < 2; s++) {
                MBAR_EXPECT_TX(smb + SM_FULL(s), STAGE_BYTES);
                int k0 = s * KCHUNK;
                TMA_LOAD_2D(smb + A_HI(s), &mapAhi, k0, m0, smb + SM_FULL(s));
                TMA_LOAD_2D(smb + A_LO(s), &mapAlo, k0, m0, smb + SM_FULL(s));
                TMA_LOAD_2D(smb + B_HI(s), &mapBhi, k0, n0, smb + SM_FULL(s));
                TMA_LOAD_2D(smb + B_LO(s), &mapBlo, k0, n0, smb + SM_FULL(s));
            }
        }
        for (int c = 0; c < NCHUNK; c++) {
            int s = c & 1;
            MBAR_WAIT(smb + SM_FULL(s), pf[s]); pf[s] ^= 1;
            if (e1) {
                uint64_t ah = mk_desc(smb + A_HI(s));
                uint64_t al = mk_desc(smb + A_LO(s));
                uint64_t bh = mk_desc(smb + B_HI(s));
                uint64_t bl = mk_desc(smb + B_LO(s));
                #pragma unroll
                for (int ks = 0; ks < 4; ks++)
                    mma_ss(tmem, ah + ks * 2, bh + ks * 2, (c == 0 && ks == 0) ? 0u : 1u);
                #pragma unroll
                for (int ks = 0; ks < 4; ks++)
                    mma_ss(tmem, ah + ks * 2, bl + ks * 2, 1u);
                #pragma unroll
                for (int ks = 0; ks < 4; ks++)
                    mma_ss(tmem, al + ks * 2, bh + ks * 2, 1u);
                TC_COMMIT(smb + SM_EMPTY(s));
            }
            if (c + 2 < NCHUNK) {
                MBAR_WAIT(smb + SM_EMPTY(s), pe[s]); pe[s] ^= 1;
                if (e1) {
                    MBAR_EXPECT_TX(smb + SM_FULL(s), STAGE_BYTES);
                    int k0 = (c + 2) * KCHUNK;
                    TMA_LOAD_2D(smb + A_HI(s), &mapAhi, k0, m0, smb + SM_FULL(s));
                    TMA_LOAD_2D(smb + A_LO(s), &mapAlo, k0, m0, smb + SM_FULL(s));
                    TMA_LOAD_2D(smb + B_HI(s), &mapBhi, k0, n0, smb + SM_FULL(s));
                    TMA_LOAD_2D(smb + B_LO(s), &mapBlo, k0, n0, smb + SM_FULL(s));
                }
            }
        }
        MBAR_WAIT(smb + SM_EMPTY(1), pe[1]);
    }
    __syncthreads();

    __nv_bfloat16* shi = (__nv_bfloat16*)(smem + SM_OUT_HI);
    __nv_bfloat16* slo = (__nv_bfloat16*)(smem + SM_OUT_LO);
    if (wid < 4) {
        TC_FENCE_AFTER();
        int mloc = wid * 32 + lane;
        #pragma unroll
        for (int blk = 0; blk < 8; blk++) {
            uint32_t r[32];
            TC_LD_X32(r, tmem + blk * 32);
            TC_WAIT_LD();
            #pragma unroll
            for (int j = 0; j < 32; j++) {
                float v = __uint_as_float(r[j]);
                __nv_bfloat16 h = __float2bfloat16(v);
                __nv_bfloat16 l = __float2bfloat16(v - __bfloat162float(h));
                int nloc = blk * 32 + j;
                shi[nloc * 128 + mloc] = h;
                slo[nloc * 128 + mloc] = l;
            }
        }
        TC_FENCE_BEFORE();
    }
    __syncthreads();
    for (int idx = tid; idx < 256 * 128 / 8; idx += 256) {
        int nloc = idx >> 4;
        int m8 = (idx & 15) * 8;
        size_t g = (size_t)(n0 + nloc) * MDIM + m0 + m8;
        *(uint4*)(dst_hi + g) = *(uint4*)(shi + nloc * 128 + m8);
        *(uint4*)(dst_lo + g) = *(uint4*)(slo + nloc * 128 + m8);
    }
    __syncthreads();
    if (wid == 4) TC_DEALLOC(tmem, 512);
#endif
}

// ======================= mma.sync fallback (base target) =======================
// 128x128x64 tile, 256 threads (8 warps: 4m x 2n), warp tile 32x64, split-bf16 x3.
#define FB_STAGE(s) (1024 + (s) * 65536)
#define FB_AHI(s) (FB_STAGE(s))
#define FB_ALO(s) (FB_STAGE(s) + 16384)
#define FB_BHI(s) (FB_STAGE(s) + 32768)
#define FB_BLO(s) (FB_STAGE(s) + 49152)
#define FB_OUT_HI 1024
#define FB_OUT_LO (1024 + 32768)
#define FB_SMEM (1024 + 2 * 65536)   // 132096

#if !HAS_TC
__device__ __forceinline__ void fb_load_stage(uint32_t smb, int s, int k0, int m0, int n0,
                                              const __nv_bfloat16* Ah, const __nv_bfloat16* Al,
                                              const __nv_bfloat16* Bh, const __nv_bfloat16* Bl,
                                              int tid) {
    const __nv_bfloat16* src[4] = {Ah, Al, Bh, Bl};
    int rowbase[4] = {m0, m0, n0, n0};
    #pragma unroll
    for (int t = 0; t < 4; t++) {
        uint32_t sb = smb + FB_STAGE(s) + t * 16384;
        #pragma unroll
        for (int i = 0; i < 4; i++) {
            int c = tid + i * 256;
            int row = c >> 3, col = c & 7;
            const void* g = src[t] + (size_t)(rowbase[t] + row) * MDIM + k0 + col * 8;
            cp16(sb + sw128(row * 128 + col * 16), g);
        }
    }
}
#endif

__global__ __launch_bounds__(256, 1) void gemm_mma(
    const __nv_bfloat16* __restrict__ Ahi_g, const __nv_bfloat16* __restrict__ Alo_g,
    const __nv_bfloat16* __restrict__ Bhi_g, const __nv_bfloat16* __restrict__ Blo_g,
    __nv_bfloat16* __restrict__ dst_hi, __nv_bfloat16* __restrict__ dst_lo)
{
#if !HAS_TC
    extern __shared__ char smem[];
    uint32_t smb = smem_u32(smem);
    int tid = threadIdx.x, wid = tid >> 5, lane = tid & 31;
    int n0 = blockIdx.x * 128;
    int m0 = blockIdx.y * 128;
    int wm = wid & 3, wn = wid >> 2;

    float acc[2][8][4];
    #pragma unroll
    for (int i = 0; i < 2; i++)
        #pragma unroll
        for (int j = 0; j < 8; j++)
            #pragma unroll
            for (int r = 0; r < 4; r++) acc[i][j][r] = 0.f;

    fb_load_stage(smb, 0, 0, m0, n0, Ahi_g, Alo_g, Bhi_g, Blo_g, tid); CP_COMMIT();
    fb_load_stage(smb, 1, KCHUNK, m0, n0, Ahi_g, Alo_g, Bhi_g, Blo_g, tid); CP_COMMIT();

    int g = lane >> 3;       // ldmatrix lane group 0..3
    int lr = lane & 7;

    for (int kt = 0; kt < NCHUNK; kt++) {
        int s = kt & 1;
        if (kt == NCHUNK - 1) { CP_WAIT(0); } else { CP_WAIT(1); }
        __syncthreads();

        uint32_t abh = smb + FB_AHI(s), abl = smb + FB_ALO(s);
        uint32_t bbh = smb + FB_BHI(s), bbl = smb + FB_BLO(s);
        #pragma unroll
        for (int kk = 0; kk < 64; kk += 16) {
            uint32_t Ah[2][4], Al[2][4], Bh[8][2], Bl[8][2];
            #pragma unroll
            for (int mf = 0; mf < 2; mf++) {
                uint32_t off = sw128((uint32_t)((wm * 32 + mf * 16 + (g & 1) * 8 + lr) * 128 + kk * 2 + (g >> 1) * 16));
                ldsm4(Ah[mf][0], Ah[mf][1], Ah[mf][2], Ah[mf][3], abh + off);
                ldsm4(Al[mf][0], Al[mf][1], Al[mf][2], Al[mf][3], abl + off);
            }
            #pragma unroll
            for (int bg = 0; bg < 4; bg++) {
                uint32_t off = sw128((uint32_t)((wn * 64 + bg * 16 + (g & 1) * 8 + lr) * 128 + kk * 2 + (g >> 1) * 16));
                uint32_t t0, t1, t2, t3;
                ldsm4(t0, t1, t2, t3, bbh + off);
                Bh[2 * bg][0] = t0; Bh[2 * bg + 1][0] = t1;
                Bh[2 * bg][1] = t2; Bh[2 * bg + 1][1] = t3;
                ldsm4(t0, t1, t2, t3, bbl + off);
                Bl[2 * bg][0] = t0; Bl[2 * bg + 1][0] = t1;
                Bl[2 * bg][1] = t2; Bl[2 * bg + 1][1] = t3;
            }
            #pragma unroll
            for (int mf = 0; mf < 2; mf++)
                #pragma unroll
                for (int nf = 0; nf < 8; nf++) {
                    mma16816(acc[mf][nf], Ah[mf], Bh[nf]);
                    mma16816(acc[mf][nf], Ah[mf], Bl[nf]);
                    mma16816(acc[mf][nf], Al[mf], Bh[nf]);
                }
        }
        __syncthreads();
        if (kt + 2 < NCHUNK) {
            fb_load_stage(smb, s, (kt + 2) * KCHUNK, m0, n0, Ahi_g, Alo_g, Bhi_g, Blo_g, tid);
            CP_COMMIT();
        }
    }

    // epilogue: regs -> smem transpose [n][m] -> coalesced STG
    __nv_bfloat16* shi = (__nv_bfloat16*)(smem + FB_OUT_HI);
    __nv_bfloat16* slo = (__nv_bfloat16*)(smem + FB_OUT_LO);
    int rr = lane >> 2, cc = (lane & 3) * 2;
    #pragma unroll
    for (int mf = 0; mf < 2; mf++)
        #pragma unroll
        for (int nf = 0; nf < 8; nf++) {
            int mb = wm * 32 + mf * 16 + rr;
            int nb = wn * 64 + nf * 8 + cc;
            #pragma unroll
            for (int r = 0; r < 4; r++) {
                int m = mb + (r >> 1) * 8;
                int n = nb + (r & 1);
                float v = acc[mf][nf][r];
                __nv_bfloat16 h = __float2bfloat16(v);
                __nv_bfloat16 l = __float2bfloat16(v - __bfloat162float(h));
                shi[n * 128 + m] = h;
                slo[n * 128 + m] = l;
            }
        }
    __syncthreads();
    for (int idx = tid; idx < 128 * 128 / 8; idx += 256) {
        int nloc = idx >> 4;
        int m8 = (idx & 15) * 8;
        size_t gg = (size_t)(n0 + nloc) * MDIM + m0 + m8;
        *(uint4*)(dst_hi + gg) = *(uint4*)(shi + nloc * 128 + m8);
        *(uint4*)(dst_lo + gg) = *(uint4*)(slo + nloc * 128 + m8);
    }
#endif
}

// ======================= fused hop MLP (packed f32x2) =======================
__global__ __launch_bounds__(256) void mlp_kernel(const __nv_bfloat16* __restrict__ thi,
                                                  const __nv_bfloat16* __restrict__ tlo,
                                                  const float* __restrict__ W1,
                                                  const float* __restrict__ b1,
                                                  const float* __restrict__ W2,
                                                  const float* __restrict__ b2,
                                                  int hop, int accum,
                                                  float* __restrict__ out) {
    const float* W1h = W1 + hop * HIDD * WDIM;
    const float* b1h = b1 + hop * HIDD;
    const float* W2h = W2 + hop * HIDD;
    float b2h = b2[hop];

    __shared__ __align__(16) float Ts[56][36];
    __shared__ float W1s[HIDD][57];

    int tid = threadIdx.x, lane = tid & 31, warp = tid >> 5;
    int r0 = blockIdx.x * 32;
    int b = r0 >> 11;
    int m0 = r0 & (MDIM - 1);
    size_t nbase = (size_t)b * WDIM;

    float b1r[4], w2r[4];
    #pragma unroll
    for (int j = 0; j < 4; j++) {
        b1r[j] = b1h[lane + 32 * j];
        w2r[j] = W2h[lane + 32 * j];
    }

    unsigned long long acc2[2][4] = {};
    for (int w0 = 0; w0 < WDIM; w0 += 56) {
        for (int idx = tid; idx < 56 * 16; idx += 256) {
            int w = idx >> 4, r2 = (idx & 15) << 1;
            size_t g = (nbase + w0 + w) * MDIM + m0 + r2;
            __nv_bfloat162 h2 = *(const __nv_bfloat162*)(thi + g);
            __nv_bfloat162 l2 = *(const __nv_bfloat162*)(tlo + g);
            Ts[w][r2]     = __bfloat162float(h2.x) + __bfloat162float(l2.x);
            Ts[w][r2 + 1] = __bfloat162float(h2.y) + __bfloat162float(l2.y);
        }
        for (int idx = tid; idx < HIDD * 56; idx += 256) {
            int h = idx / 56, w = idx - h * 56;
            W1s[h][w] = W1h[h * WDIM + w0 + w];
        }
        __syncthreads();

        #pragma unroll 4
        for (int k = 0; k < 56; k++) {
            ulonglong2 tv = *(const ulonglong2*)(&Ts[k][warp * 4]);
            #pragma unroll
            for (int j = 0; j < 4; j++) {
                unsigned long long wv = bcast2(W1s[lane + 32 * j][k]);
                fma2(acc2[0][j], tv.x, wv);
                fma2(acc2[1][j], tv.y, wv);
            }
        }
        __syncthreads();
    }

    float c[4][4];
    #pragma unroll
    for (int p = 0; p < 2; p++)
        #pragma unroll
        for (int j = 0; j < 4; j++) {
            float2 u = unpack2(acc2[p][j]);
            c[2 * p][j] = u.x;
            c[2 * p + 1][j] = u.y;
        }
    float part[4];
    #pragma unroll
    for (int i = 0; i < 4; i++) {
        float s = 0.f;
        #pragma unroll
        for (int j = 0; j < 4; j++)
            s += fmaxf(c[i][j] + b1r[j], 0.f) * w2r[j];
        #pragma unroll
        for (int off = 16; off > 0; off >>= 1)
            s += __shfl_xor_sync(0xffffffffu, s, off);
        part[i] = s;
    }
    if (lane < 4) {
        int r = r0 + warp * 4 + lane;
        float v = part[lane] + b2h;
        if (accum) v += out[r];
        out[r] = v;
    }
}

// ======================= host =======================
typedef CUresult (*PFN_tmEncode)(CUtensorMap*, CUtensorMapDataType, cuuint32_t, void*,
                                 const cuuint64_t*, const cuuint64_t*, const cuuint32_t*,
                                 const cuuint32_t*, CUtensorMapInterleave, CUtensorMapSwizzle,
                                 CUtensorMapL2promotion, CUtensorMapFloatOOBfill);

static void make_map(PFN_tmEncode enc, CUtensorMap* m, void* ptr,
                     unsigned long long d0, unsigned long long d1,
                     unsigned box0, unsigned box1) {
    cuuint64_t dims[2] = {d0, d1};
    cuuint64_t strides[1] = {d0 * 2};
    cuuint32_t box[2] = {box0, box1};
    cuuint32_t es[2] = {1, 1};
    enc(m, CU_TENSOR_MAP_DATA_TYPE_BFLOAT16, 2, ptr, dims, strides, box, es,
        CU_TENSOR_MAP_INTERLEAVE_NONE, CU_TENSOR_MAP_SWIZZLE_128B,
        CU_TENSOR_MAP_L2_PROMOTION_L2_128B, CU_TENSOR_MAP_FLOAT_OOB_FILL_NONE);
}

extern "C" void kernel_launch(void* const* d_in, const int* in_sizes, int n_in,
                              void* d_out, int out_size) {
    const float* x  = (const float*)d_in[0];
    const float* L  = (const float*)d_in[1];
    const float* W1 = (const float*)d_in[2];
    const float* b1 = (const float*)d_in[3];
    const float* W2 = (const float*)d_in[4];
    const float* b2 = (const float*)d_in[5];
    float* out = (float*)d_out;

    __nv_bfloat16 *hi0, *hi1, *lo0, *lo1, *Lhi, *Llo;
    cudaGetSymbolAddress((void**)&hi0, g_hi);
    hi1 = hi0 + (size_t)BWCOL * MDIM;
    cudaGetSymbolAddress((void**)&lo0, g_lo);
    lo1 = lo0 + (size_t)BWCOL * MDIM;
    cudaGetSymbolAddress((void**)&Lhi, g_Lhi);
    cudaGetSymbolAddress((void**)&Llo, g_Llo);

    PFN_tmEncode enc = nullptr;
    cudaDriverEntryPointQueryResult qr;
    cudaGetDriverEntryPointByVersion("cuTensorMapEncodeTiled", (void**)&enc, 12000,
                                     cudaEnableDefault, &qr);

    CUtensorMap mAhi, mAlo, mBhi[2], mBlo[2];
    make_map(enc, &mAhi, Lhi, MDIM, MDIM, 64, 128);
    make_map(enc, &mAlo, Llo, MDIM, MDIM, 64, 128);
    make_map(enc, &mBhi[0], hi0, MDIM, BWCOL, 64, 256);
    make_map(enc, &mBhi[1], hi1, MDIM, BWCOL, 64, 256);
    make_map(enc, &mBlo[0], lo0, MDIM, BWCOL, 64, 256);
    make_map(enc, &mBlo[1], lo1, MDIM, BWCOL, 64, 256);

    cudaFuncSetAttribute(gemm_tc, cudaFuncAttributeMaxDynamicSharedMemorySize, TC_SMEM);
    cudaFuncSetAttribute(gemm_mma, cudaFuncAttributeMaxDynamicSharedMemorySize, FB_SMEM);

    {
        int n4 = (BWCOL * MDIM) / 4;
        split_kernel<<<(n4 + 255) / 256, 256>>>(x, hi0, lo0, n4);
        n4 = (MDIM * MDIM) / 4;
        split_kernel<<<(n4 + 255) / 256, 256>>>(L, Lhi, Llo, n4);
    }

    mlp_kernel<<<(BATCH * MDIM) / 32, 256>>>(hi0, lo0, W1, b1, W2, b2, 0, 0, out);

    dim3 tcgrid(BWCOL / 256, MDIM / 128);
    dim3 mmagrid(BWCOL / 128, MDIM / 128);
    __nv_bfloat16* bufs_hi[2] = {hi0, hi1};
    __nv_bfloat16* bufs_lo[2] = {lo0, lo1};
    for (int hop = 1; hop <= NHOPS; hop++) {
        int src = (hop + 1) & 1;
        int dst = hop & 1;
        gemm_tc<<<tcgrid, 256, TC_SMEM>>>(mAhi, mAlo, mBhi[src], mBlo[src],
                                          bufs_hi[dst], bufs_lo[dst]);
        gemm_mma<<<mmagrid, 256, FB_SMEM>>>(Lhi, Llo, bufs_hi[src], bufs_lo[src],
                                            bufs_hi[dst], bufs_lo[dst]);
        mlp_kernel<<<(BATCH * MDIM) / 32, 256>>>(bufs_hi[dst], bufs_lo[dst],
                                                 W1, b1, W2, b2, hop, 1, out);
    }
}

// round 4
// speedup vs baseline: 4.7053x; 1.0747x over previous
#include <cuda_runtime.h>
#include <cuda_bf16.h>
#include <cuda.h>
#include <cstdint>

#define BATCH 32
#define WDIM  168
#define MDIM  2048
#define HIDD  128
#define NHOPS 6
#define BWCOL (BATCH * WDIM)   // 5376

#if defined(__CUDA_ARCH__) && defined(__CUDA_ARCH_FEAT_SM103_ALL)
#define HAS_TC 1
#else
#define HAS_TC 0
#endif

// t stored TRANSPOSED: T[n][m], n in [0,5376), m contiguous. Split bf16 hi/lo.
__device__ __align__(1024) __nv_bfloat16 g_hi[2][(size_t)BWCOL * MDIM];
__device__ __align__(1024) __nv_bfloat16 g_lo[2][(size_t)BWCOL * MDIM];
__device__ __align__(1024) __nv_bfloat16 g_Lhi[(size_t)MDIM * MDIM];
__device__ __align__(1024) __nv_bfloat16 g_Llo[(size_t)MDIM * MDIM];

// ======================= common helpers =======================
__device__ __forceinline__ uint32_t smem_u32(const void* p) {
    uint32_t a;
    asm("{ .reg .u64 t; cvta.to.shared.u64 t, %1; cvt.u32.u64 %0, t; }" : "=r"(a) : "l"(p));
    return a;
}
// packed f32x2
__device__ __forceinline__ unsigned long long bcast2(float a) {
    unsigned long long r; unsigned int u = __float_as_uint(a);
    asm("mov.b64 %0, {%1, %1};" : "=l"(r) : "r"(u));
    return r;
}
__device__ __forceinline__ void fma2(unsigned long long& d, unsigned long long a, unsigned long long b) {
    asm("fma.rn.f32x2 %0, %1, %2, %0;" : "+l"(d) : "l"(a), "l"(b));
}
__device__ __forceinline__ float2 unpack2(unsigned long long v) {
    unsigned int lo, hi;
    asm("mov.b64 {%0, %1}, %2;" : "=r"(lo), "=r"(hi) : "l"(v));
    return make_float2(__uint_as_float(lo), __uint_as_float(hi));
}

// ======================= fp32 -> bf16 hi/lo split =======================
__global__ void split_kernel(const float* __restrict__ in, __nv_bfloat16* __restrict__ hi,
                             __nv_bfloat16* __restrict__ lo, int n4) {
    int i = blockIdx.x * blockDim.x + threadIdx.x;
    if (i >= n4) return;
    float4 v = ((const float4*)in)[i];
    __nv_bfloat16 h[4], l[4];
    float vv[4] = {v.x, v.y, v.z, v.w};
    #pragma unroll
    for (int j = 0; j < 4; j++) {
        h[j] = __float2bfloat16(vv[j]);
        l[j] = __float2bfloat16(vv[j] - __bfloat162float(h[j]));
    }
    ((ushort4*)hi)[i] = make_ushort4(*(unsigned short*)&h[0], *(unsigned short*)&h[1],
                                     *(unsigned short*)&h[2], *(unsigned short*)&h[3]);
    ((ushort4*)lo)[i] = make_ushort4(*(unsigned short*)&l[0], *(unsigned short*)&l[1],
                                     *(unsigned short*)&l[2], *(unsigned short*)&l[3]);
}

// ======================= tcgen05 cg2 GEMM ('a' targets only) =======================
#if HAS_TC
__device__ __forceinline__ uint32_t elect_one() {
    uint32_t p;
    asm volatile("{ .reg .pred p; elect.sync _|p, 0xFFFFFFFF; selp.b32 %0, 1, 0, p; }" : "=r"(p));
    return p;
}
#define MBAR_INIT(a, c) asm volatile("mbarrier.init.shared.b64 [%0], %1;" :: "r"(a), "r"(c) : "memory")
#define MBAR_EXPECT_TX(a, b) asm volatile("mbarrier.arrive.expect_tx.shared.b64 _, [%0], %1;" :: "r"(a), "r"(b) : "memory")
#define MBAR_WAIT(a, ph) do { \
    uint32_t _m = (a), _p = (ph), _d; \
    asm volatile("{ .reg .pred p; mbarrier.try_wait.parity.acquire.cta.shared::cta.b64 p, [%1], %2; selp.b32 %0,1,0,p; }" \
        : "=r"(_d) : "r"(_m), "r"(_p) : "memory"); \
    if (!_d) { asm volatile("{ .reg .pred P1; WL%=: mbarrier.try_wait.parity.acquire.cta.shared::cta.b64 P1, [%0], %1, 0x989680; @P1 bra.uni WD%=; bra.uni WL%=; WD%=: }" \
        :: "r"(_m), "r"(_p) : "memory"); } \
} while (0)
// cg2 TMA: complete_tx lands on the LEADER CTA's barrier (bit 24 cleared)
#define TMA_2D_CG2(sm, map, cx, cy, mb) \
    asm volatile("{ .reg .b32 lb; and.b32 lb, %4, 0xFEFFFFFF;\n\t" \
        "cp.async.bulk.tensor.2d.cta_group::2.shared::cluster.global.tile.mbarrier::complete_tx::bytes " \
        "[%0], [%1, {%2, %3}], [lb]; }" \
        :: "r"(sm), "l"(map), "r"(cx), "r"(cy), "r"(mb) : "memory")
#define TC_ALLOC_CG2(smaddr, n)  asm volatile("tcgen05.alloc.cta_group::2.sync.aligned.shared::cta.b32 [%0], %1;" :: "r"(smaddr), "r"(n) : "memory")
#define TC_RELINQ_CG2()          asm volatile("tcgen05.relinquish_alloc_permit.cta_group::2.sync.aligned;")
#define TC_DEALLOC_CG2(t, n)     asm volatile("tcgen05.dealloc.cta_group::2.sync.aligned.b32 %0, %1;" :: "r"(t), "r"(n))
#define TC_COMMIT_MC2(mb) \
    asm volatile("tcgen05.commit.cta_group::2.mbarrier::arrive::one.shared::cluster.multicast::cluster.b64 [%0], %1;" \
        :: "r"(mb), "h"((unsigned short)0x3) : "memory")
#define TC_FENCE_AFTER()      asm volatile("tcgen05.fence::after_thread_sync;" ::: "memory")
#define TC_FENCE_BEFORE()     asm volatile("tcgen05.fence::before_thread_sync;" ::: "memory")
#define TC_WAIT_LD()          asm volatile("tcgen05.wait::ld.sync.aligned;" ::: "memory")
#define TC_LD_X32(r, addr) \
    asm volatile("tcgen05.ld.sync.aligned.32x32b.x32.b32 " \
        "{%0,%1,%2,%3,%4,%5,%6,%7,%8,%9,%10,%11,%12,%13,%14,%15," \
        "%16,%17,%18,%19,%20,%21,%22,%23,%24,%25,%26,%27,%28,%29,%30,%31}, [%32];" \
        : "=r"((r)[0]),"=r"((r)[1]),"=r"((r)[2]),"=r"((r)[3]),"=r"((r)[4]),"=r"((r)[5]),"=r"((r)[6]),"=r"((r)[7]), \
          "=r"((r)[8]),"=r"((r)[9]),"=r"((r)[10]),"=r"((r)[11]),"=r"((r)[12]),"=r"((r)[13]),"=r"((r)[14]),"=r"((r)[15]), \
          "=r"((r)[16]),"=r"((r)[17]),"=r"((r)[18]),"=r"((r)[19]),"=r"((r)[20]),"=r"((r)[21]),"=r"((r)[22]),"=r"((r)[23]), \
          "=r"((r)[24]),"=r"((r)[25]),"=r"((r)[26]),"=r"((r)[27]),"=r"((r)[28]),"=r"((r)[29]),"=r"((r)[30]),"=r"((r)[31]) \
        : "r"(addr))
#define CLUSTER_SYNC() do { \
    asm volatile("barrier.cluster.arrive.aligned;" ::: "memory"); \
    asm volatile("barrier.cluster.wait.aligned;" ::: "memory"); \
} while (0)

static constexpr uint64_t DESC_SW128 =
    (uint64_t(2) << 61) | (uint64_t(1) << 46) | (uint64_t(64) << 32) | (uint64_t(1) << 16);
__device__ __forceinline__ uint64_t mk_desc(uint32_t sm) {
    return DESC_SW128 | ((uint64_t)(sm >> 4) & 0x3FFF);
}
// kind::f16, D=F32, A=BF16, B=BF16, M=256 (cg2), N=256
#define IDESC_CG2 0x10400490u
__device__ __forceinline__ void mma_cg2(uint32_t d, uint64_t a, uint64_t b, uint32_t en) {
    asm volatile("{ .reg .pred p; setp.ne.u32 p, %5, 0;\n\t"
        "tcgen05.mma.cta_group::2.kind::f16 [%0], %1, %2, %3, {%4,%4,%4,%4,%4,%4,%4,%4}, p; }"
        :: "r"(d), "l"(a), "l"(b), "r"(IDESC_CG2), "r"(0u), "r"(en) : "memory");
}
#endif // HAS_TC

#define KCHUNK 64
#define NCHUNK (MDIM / KCHUNK)   // 32
#define NSTAGE 3
#define SM_TMEMPTR 0
#define SM_FULL(s)  (16 + (s) * 8)
#define SM_EMPTY(s) (64 + (s) * 8)
#define STAGE_CTA 65536
#define TX_BYTES (2 * STAGE_CTA)      // both CTAs' loads land on leader barrier
#define SM_STAGE(s) (1024 + (s) * STAGE_CTA)
#define A_HI(s) (SM_STAGE(s))
#define A_LO(s) (SM_STAGE(s) + 16384)
#define B_HI(s) (SM_STAGE(s) + 32768)
#define B_LO(s) (SM_STAGE(s) + 49152)
#define SM_OUT_HI 1024
#define SM_OUT_LO (1024 + 65536)
#define TC_SMEM (1024 + NSTAGE * STAGE_CTA)   // 197632

__global__ __launch_bounds__(256, 1) __cluster_dims__(2, 1, 1) void gemm_tc(
    const __grid_constant__ CUtensorMap mapAhi,
    const __grid_constant__ CUtensorMap mapAlo,
    const __grid_constant__ CUtensorMap mapBhi,
    const __grid_constant__ CUtensorMap mapBlo,
    __nv_bfloat16* __restrict__ dst_hi,
    __nv_bfloat16* __restrict__ dst_lo)
{
#if HAS_TC
    extern __shared__ char smem[];
    uint32_t smb = smem_u32(smem);
    int tid = threadIdx.x, wid = tid >> 5, lane = tid & 31;
    uint32_t rank;
    asm("mov.u32 %0, %%cluster_ctarank;" : "=r"(rank));
    int mbase = blockIdx.x * 128;                 // this CTA's 128 M rows
    int n0 = blockIdx.y * 256;                    // tile N base
    int brow = n0 + (int)rank * 128;              // this CTA's 128 B rows

    if (wid == 4) { TC_ALLOC_CG2(smb + SM_TMEMPTR, 512); TC_RELINQ_CG2(); }
    if (tid == 0) {
        #pragma unroll
        for (int s = 0; s < NSTAGE; s++) {
            MBAR_INIT(smb + SM_FULL(s), 1);
            MBAR_INIT(smb + SM_EMPTY(s), 1);
        }
    }
    __syncthreads();
    CLUSTER_SYNC();   // barriers visible cluster-wide before cg2 TMA / multicast commit

    uint32_t tmem;
    asm volatile("ld.shared.b32 %0, [%1];" : "=r"(tmem) : "r"(smb + SM_TMEMPTR));

    if (wid == 4) {
        uint32_t e1 = elect_one();
        uint32_t pf[NSTAGE] = {0, 0, 0}, pe[NSTAGE] = {0, 0, 0};
        if (e1) {
            #pragma unroll
            for (int s = 0; s < NSTAGE; s++) {
                if (rank == 0) MBAR_EXPECT_TX(smb + SM_FULL(s), TX_BYTES);
                int k0 = s * KCHUNK;
                TMA_2D_CG2(smb + A_HI(s), &mapAhi, k0, mbase, smb + SM_FULL(s));
                TMA_2D_CG2(smb + A_LO(s), &mapAlo, k0, mbase, smb + SM_FULL(s));
                TMA_2D_CG2(smb + B_HI(s), &mapBhi, k0, brow, smb + SM_FULL(s));
                TMA_2D_CG2(smb + B_LO(s), &mapBlo, k0, brow, smb + SM_FULL(s));
            }
        }
        int s = 0;
        for (int c = 0; c < NCHUNK; c++) {
            if (rank == 0) {
                MBAR_WAIT(smb + SM_FULL(s), pf[s]); pf[s] ^= 1;
                if (e1) {
                    uint64_t ah = mk_desc(smb + A_HI(s));
                    uint64_t al = mk_desc(smb + A_LO(s));
                    uint64_t bh = mk_desc(smb + B_HI(s));
                    uint64_t bl = mk_desc(smb + B_LO(s));
                    #pragma unroll
                    for (int ks = 0; ks < 4; ks++)
                        mma_cg2(tmem, ah + ks * 2, bh + ks * 2, (c == 0 && ks == 0) ? 0u : 1u);
                    #pragma unroll
                    for (int ks = 0; ks < 4; ks++)
                        mma_cg2(tmem, ah + ks * 2, bl + ks * 2, 1u);
                    #pragma unroll
                    for (int ks = 0; ks < 4; ks++)
                        mma_cg2(tmem, al + ks * 2, bh + ks * 2, 1u);
                    TC_COMMIT_MC2(smb + SM_EMPTY(s));
                }
            }
            if (c + NSTAGE < NCHUNK) {
                MBAR_WAIT(smb + SM_EMPTY(s), pe[s]); pe[s] ^= 1;
                if (e1) {
                    if (rank == 0) MBAR_EXPECT_TX(smb + SM_FULL(s), TX_BYTES);
                    int k0 = (c + NSTAGE) * KCHUNK;
                    TMA_2D_CG2(smb + A_HI(s), &mapAhi, k0, mbase, smb + SM_FULL(s));
                    TMA_2D_CG2(smb + A_LO(s), &mapAlo, k0, mbase, smb + SM_FULL(s));
                    TMA_2D_CG2(smb + B_HI(s), &mapBhi, k0, brow, smb + SM_FULL(s));
                    TMA_2D_CG2(smb + B_LO(s), &mapBlo, k0, brow, smb + SM_FULL(s));
                }
            }
            if (++s == NSTAGE) s = 0;
        }
        // wait for final chunk's commit (covers all prior MMAs), on both CTAs
        int fs = (NCHUNK - 1) % NSTAGE;
        MBAR_WAIT(smb + SM_EMPTY(fs), pe[fs]);
    }
    __syncthreads();

    // ---- epilogue: this CTA's 128 M rows x 256 N cols from local TMEM ----
    __nv_bfloat16* shi = (__nv_bfloat16*)(smem + SM_OUT_HI);
    __nv_bfloat16* slo = (__nv_bfloat16*)(smem + SM_OUT_LO);
    if (wid < 4) {
        TC_FENCE_AFTER();
        int mloc = wid * 32 + lane;
        #pragma unroll
        for (int blk = 0; blk < 8; blk++) {
            uint32_t r[32];
            TC_LD_X32(r, tmem + blk * 32);
            TC_WAIT_LD();
            #pragma unroll
            for (int j = 0; j < 32; j++) {
                float v = __uint_as_float(r[j]);
                __nv_bfloat16 h = __float2bfloat16(v);
                __nv_bfloat16 l = __float2bfloat16(v - __bfloat162float(h));
                int nloc = blk * 32 + j;
                shi[nloc * 128 + mloc] = h;
                slo[nloc * 128 + mloc] = l;
            }
        }
        TC_FENCE_BEFORE();
    }
    __syncthreads();
    for (int idx = tid; idx < 256 * 128 / 8; idx += 256) {
        int nloc = idx >> 4;
        int m8 = (idx & 15) * 8;
        size_t g = (size_t)(n0 + nloc) * MDIM + mbase + m8;
        *(uint4*)(dst_hi + g) = *(uint4*)(shi + nloc * 128 + m8);
        *(uint4*)(dst_lo + g) = *(uint4*)(slo + nloc * 128 + m8);
    }
    __syncthreads();
    if (wid == 4) TC_DEALLOC_CG2(tmem, 512);
    CLUSTER_SYNC();   // peer SMEM must stay alive until both CTAs are done
#endif
}

// ======================= fused hop MLP (packed f32x2, 64 rows/block) =======================
__global__ __launch_bounds__(256) void mlp_kernel(const __nv_bfloat16* __restrict__ thi,
                                                  const __nv_bfloat16* __restrict__ tlo,
                                                  const float* __restrict__ W1,
                                                  const float* __restrict__ b1,
                                                  const float* __restrict__ W2,
                                                  const float* __restrict__ b2,
                                                  int hop, int accum,
                                                  float* __restrict__ out) {
    const float* W1h = W1 + hop * HIDD * WDIM;
    const float* b1h = b1 + hop * HIDD;
    const float* W2h = W2 + hop * HIDD;
    float b2h = b2[hop];

    __shared__ __align__(16) float Ts[56][72];   // [k][row], 64 rows + pad
    __shared__ float W1s[HIDD][57];              // [h][k], conflict-free strided reads

    int tid = threadIdx.x, lane = tid & 31, warp = tid >> 5;   // 8 warps x 8 rows
    int r0 = blockIdx.x * 64;
    int b = r0 >> 11;
    int m0 = r0 & (MDIM - 1);
    size_t nbase = (size_t)b * WDIM;

    float b1r[4], w2r[4];
    #pragma unroll
    for (int j = 0; j < 4; j++) {
        b1r[j] = b1h[lane + 32 * j];
        w2r[j] = W2h[lane + 32 * j];
    }

    unsigned long long acc2[4][4] = {};
    for (int w0 = 0; w0 < WDIM; w0 += 56) {
        for (int idx = tid; idx < 56 * 32; idx += 256) {
            int w = idx >> 5, r2 = (idx & 31) << 1;
            size_t g = (nbase + w0 + w) * MDIM + m0 + r2;
            __nv_bfloat162 h2 = *(const __nv_bfloat162*)(thi + g);
            __nv_bfloat162 l2 = *(const __nv_bfloat162*)(tlo + g);
            Ts[w][r2]     = __bfloat162float(h2.x) + __bfloat162float(l2.x);
            Ts[w][r2 + 1] = __bfloat162float(h2.y) + __bfloat162float(l2.y);
        }
        for (int idx = tid; idx < HIDD * 56; idx += 256) {
            int h = idx / 56, w = idx - h * 56;
            W1s[h][w] = W1h[h * WDIM + w0 + w];
        }
        __syncthreads();

        #pragma unroll 4
        for (int k = 0; k < 56; k++) {
            ulonglong2 t01 = *(const ulonglong2*)(&Ts[k][warp * 8]);
            ulonglong2 t23 = *(const ulonglong2*)(&Ts[k][warp * 8 + 4]);
            #pragma unroll
            for (int j = 0; j < 4; j++) {
                unsigned long long wv = bcast2(W1s[lane + 32 * j][k]);
                fma2(acc2[0][j], t01.x, wv);
                fma2(acc2[1][j], t01.y, wv);
                fma2(acc2[2][j], t23.x, wv);
                fma2(acc2[3][j], t23.y, wv);
            }
        }
        __syncthreads();
    }

    float c[8][4];
    #pragma unroll
    for (int p = 0; p < 4; p++)
        #pragma unroll
        for (int j = 0; j < 4; j++) {
            float2 u = unpack2(acc2[p][j]);
            c[2 * p][j] = u.x;
            c[2 * p + 1][j] = u.y;
        }
    float part[8];
    #pragma unroll
    for (int i = 0; i < 8; i++) {
        float s = 0.f;
        #pragma unroll
        for (int j = 0; j < 4; j++)
            s += fmaxf(c[i][j] + b1r[j], 0.f) * w2r[j];
        #pragma unroll
        for (int off = 16; off > 0; off >>= 1)
            s += __shfl_xor_sync(0xffffffffu, s, off);
        part[i] = s;
    }
    if (lane < 8) {
        int r = r0 + warp * 8 + lane;
        float v = part[lane] + b2h;
        if (accum) v += out[r];
        out[r] = v;
    }
}

// ======================= host =======================
typedef CUresult (*PFN_tmEncode)(CUtensorMap*, CUtensorMapDataType, cuuint32_t, void*,
                                 const cuuint64_t*, const cuuint64_t*, const cuuint32_t*,
                                 const cuuint32_t*, CUtensorMapInterleave, CUtensorMapSwizzle,
                                 CUtensorMapL2promotion, CUtensorMapFloatOOBfill);

static void make_map(PFN_tmEncode enc, CUtensorMap* m, void* ptr,
                     unsigned long long d0, unsigned long long d1,
                     unsigned box0, unsigned box1) {
    cuuint64_t dims[2] = {d0, d1};
    cuuint64_t strides[1] = {d0 * 2};
    cuuint32_t box[2] = {box0, box1};
    cuuint32_t es[2] = {1, 1};
    enc(m, CU_TENSOR_MAP_DATA_TYPE_BFLOAT16, 2, ptr, dims, strides, box, es,
        CU_TENSOR_MAP_INTERLEAVE_NONE, CU_TENSOR_MAP_SWIZZLE_128B,
        CU_TENSOR_MAP_L2_PROMOTION_L2_128B, CU_TENSOR_MAP_FLOAT_OOB_FILL_NONE);
}

extern "C" void kernel_launch(void* const* d_in, const int* in_sizes, int n_in,
                              void* d_out, int out_size) {
    const float* x  = (const float*)d_in[0];
    const float* L  = (const float*)d_in[1];
    const float* W1 = (const float*)d_in[2];
    const float* b1 = (const float*)d_in[3];
    const float* W2 = (const float*)d_in[4];
    const float* b2 = (const float*)d_in[5];
    float* out = (float*)d_out;

    __nv_bfloat16 *hi0, *hi1, *lo0, *lo1, *Lhi, *Llo;
    cudaGetSymbolAddress((void**)&hi0, g_hi);
    hi1 = hi0 + (size_t)BWCOL * MDIM;
    cudaGetSymbolAddress((void**)&lo0, g_lo);
    lo1 = lo0 + (size_t)BWCOL * MDIM;
    cudaGetSymbolAddress((void**)&Lhi, g_Lhi);
    cudaGetSymbolAddress((void**)&Llo, g_Llo);

    PFN_tmEncode enc = nullptr;
    cudaDriverEntryPointQueryResult qr;
    cudaGetDriverEntryPointByVersion("cuTensorMapEncodeTiled", (void**)&enc, 12000,
                                     cudaEnableDefault, &qr);

    CUtensorMap mAhi, mAlo, mBhi[2], mBlo[2];
    make_map(enc, &mAhi, Lhi, MDIM, MDIM, 64, 128);
    make_map(enc, &mAlo, Llo, MDIM, MDIM, 64, 128);
    make_map(enc, &mBhi[0], hi0, MDIM, BWCOL, 64, 128);
    make_map(enc, &mBhi[1], hi1, MDIM, BWCOL, 64, 128);
    make_map(enc, &mBlo[0], lo0, MDIM, BWCOL, 64, 128);
    make_map(enc, &mBlo[1], lo1, MDIM, BWCOL, 64, 128);

    cudaFuncSetAttribute(gemm_tc, cudaFuncAttributeMaxDynamicSharedMemorySize, TC_SMEM);

    {
        int n4 = (BWCOL * MDIM) / 4;
        split_kernel<<<(n4 + 255) / 256, 256>>>(x, hi0, lo0, n4);
        n4 = (MDIM * MDIM) / 4;
        split_kernel<<<(n4 + 255) / 256, 256>>>(L, Lhi, Llo, n4);
    }

    mlp_kernel<<<(BATCH * MDIM) / 64, 256>>>(hi0, lo0, W1, b1, W2, b2, 0, 0, out);

    // grid.x = 16 CTAs (8 m-tiles x 2 cluster ranks), grid.y = 21 n-tiles
    dim3 tcgrid(2 * (MDIM / 256), BWCOL / 256);
    __nv_bfloat16* bufs_hi[2] = {hi0, hi1};
    __nv_bfloat16* bufs_lo[2] = {lo0, lo1};
    for (int hop = 1; hop <= NHOPS; hop++) {
        int src = (hop + 1) & 1;
        int dst = hop & 1;
        gemm_tc<<<tcgrid, 256, TC_SMEM>>>(mAhi, mAlo, mBhi[src], mBlo[src],
                                          bufs_hi[dst], bufs_lo[dst]);
        mlp_kernel<<<(BATCH * MDIM) / 64, 256>>>(bufs_hi[dst], bufs_lo[dst],
                                                 W1, b1, W2, b2, hop, 1, out);
    }
}

// round 5
// speedup vs baseline: 4.8418x; 1.0290x over previous
#include <cuda_runtime.h>
#include <cuda_bf16.h>
#include <cuda.h>
#include <cstdint>

#define BATCH 32
#define WDIM  168
#define MDIM  2048
#define HIDD  128
#define NHOPS 6
#define BWCOL (BATCH * WDIM)   // 5376

#if defined(__CUDA_ARCH__) && defined(__CUDA_ARCH_FEAT_SM103_ALL)
#define HAS_TC 1
#else
#define HAS_TC 0
#endif

// t stored TRANSPOSED: T[n][m], n in [0,5376), m contiguous. Split bf16 hi/lo.
__device__ __align__(1024) __nv_bfloat16 g_hi[2][(size_t)BWCOL * MDIM];
__device__ __align__(1024) __nv_bfloat16 g_lo[2][(size_t)BWCOL * MDIM];
__device__ __align__(1024) __nv_bfloat16 g_Lhi[(size_t)MDIM * MDIM];
__device__ __align__(1024) __nv_bfloat16 g_Llo[(size_t)MDIM * MDIM];

// ======================= common helpers =======================
__device__ __forceinline__ uint32_t smem_u32(const void* p) {
    uint32_t a;
    asm("{ .reg .u64 t; cvta.to.shared.u64 t, %1; cvt.u32.u64 %0, t; }" : "=r"(a) : "l"(p));
    return a;
}
// packed f32x2
__device__ __forceinline__ unsigned long long bcast2(float a) {
    unsigned long long r; unsigned int u = __float_as_uint(a);
    asm("mov.b64 %0, {%1, %1};" : "=l"(r) : "r"(u));
    return r;
}
__device__ __forceinline__ void fma2(unsigned long long& d, unsigned long long a, unsigned long long b) {
    asm("fma.rn.f32x2 %0, %1, %2, %0;" : "+l"(d) : "l"(a), "l"(b));
}
__device__ __forceinline__ float2 unpack2(unsigned long long v) {
    unsigned int lo, hi;
    asm("mov.b64 {%0, %1}, %2;" : "=r"(lo), "=r"(hi) : "l"(v));
    return make_float2(__uint_as_float(lo), __uint_as_float(hi));
}

// ======================= fp32 -> bf16 hi/lo split =======================
__global__ void split_kernel(const float* __restrict__ in, __nv_bfloat16* __restrict__ hi,
                             __nv_bfloat16* __restrict__ lo, int n4) {
    int i = blockIdx.x * blockDim.x + threadIdx.x;
    if (i >= n4) return;
    float4 v = ((const float4*)in)[i];
    __nv_bfloat16 h[4], l[4];
    float vv[4] = {v.x, v.y, v.z, v.w};
    #pragma unroll
    for (int j = 0; j < 4; j++) {
        h[j] = __float2bfloat16(vv[j]);
        l[j] = __float2bfloat16(vv[j] - __bfloat162float(h[j]));
    }
    ((ushort4*)hi)[i] = make_ushort4(*(unsigned short*)&h[0], *(unsigned short*)&h[1],
                                     *(unsigned short*)&h[2], *(unsigned short*)&h[3]);
    ((ushort4*)lo)[i] = make_ushort4(*(unsigned short*)&l[0], *(unsigned short*)&l[1],
                                     *(unsigned short*)&l[2], *(unsigned short*)&l[3]);
}

// ======================= tcgen05 persistent cg2 GEMM ('a' targets only) =======================
#if HAS_TC
__device__ __forceinline__ uint32_t elect_one() {
    uint32_t p;
    asm volatile("{ .reg .pred p; elect.sync _|p, 0xFFFFFFFF; selp.b32 %0, 1, 0, p; }" : "=r"(p));
    return p;
}
#define MBAR_INIT(a, c) asm volatile("mbarrier.init.shared.b64 [%0], %1;" :: "r"(a), "r"(c) : "memory")
#define MBAR_EXPECT_TX(a, b) asm volatile("mbarrier.arrive.expect_tx.shared.b64 _, [%0], %1;" :: "r"(a), "r"(b) : "memory")
#define MBAR_WAIT(a, ph) do { \
    uint32_t _m = (a), _p = (ph), _d; \
    asm volatile("{ .reg .pred p; mbarrier.try_wait.parity.acquire.cta.shared::cta.b64 p, [%1], %2; selp.b32 %0,1,0,p; }" \
        : "=r"(_d) : "r"(_m), "r"(_p) : "memory"); \
    if (!_d) { asm volatile("{ .reg .pred P1; WL%=: mbarrier.try_wait.parity.acquire.cta.shared::cta.b64 P1, [%0], %1, 0x989680; @P1 bra.uni WD%=; bra.uni WL%=; WD%=: }" \
        :: "r"(_m), "r"(_p) : "memory"); } \
} while (0)
#define MBAR_ARRIVE_RANK0(a) \
    asm volatile("{ .reg .b32 ra; mapa.shared::cluster.u32 ra, %0, 0; mbarrier.arrive.shared::cluster.b64 _, [ra]; }" \
        :: "r"(a) : "memory")
// cg2 TMA: complete_tx lands on the LEADER CTA's barrier (bit 24 cleared)
#define TMA_2D_CG2(sm, map, cx, cy, mb) \
    asm volatile("{ .reg .b32 lb; and.b32 lb, %4, 0xFEFFFFFF;\n\t" \
        "cp.async.bulk.tensor.2d.cta_group::2.shared::cluster.global.tile.mbarrier::complete_tx::bytes " \
        "[%0], [%1, {%2, %3}], [lb]; }" \
        :: "r"(sm), "l"(map), "r"(cx), "r"(cy), "r"(mb) : "memory")
#define TC_ALLOC_CG2(smaddr, n)  asm volatile("tcgen05.alloc.cta_group::2.sync.aligned.shared::cta.b32 [%0], %1;" :: "r"(smaddr), "r"(n) : "memory")
#define TC_RELINQ_CG2()          asm volatile("tcgen05.relinquish_alloc_permit.cta_group::2.sync.aligned;")
#define TC_DEALLOC_CG2(t, n)     asm volatile("tcgen05.dealloc.cta_group::2.sync.aligned.b32 %0, %1;" :: "r"(t), "r"(n))
#define TC_COMMIT_MC2(mb) \
    asm volatile("tcgen05.commit.cta_group::2.mbarrier::arrive::one.shared::cluster.multicast::cluster.b64 [%0], %1;" \
        :: "r"(mb), "h"((unsigned short)0x3) : "memory")
#define TC_FENCE_AFTER()      asm volatile("tcgen05.fence::after_thread_sync;" ::: "memory")
#define TC_FENCE_BEFORE()     asm volatile("tcgen05.fence::before_thread_sync;" ::: "memory")
#define TC_WAIT_LD()          asm volatile("tcgen05.wait::ld.sync.aligned;" ::: "memory")
#define TC_LD_X32(r, addr) \
    asm volatile("tcgen05.ld.sync.aligned.32x32b.x32.b32 " \
        "{%0,%1,%2,%3,%4,%5,%6,%7,%8,%9,%10,%11,%12,%13,%14,%15," \
        "%16,%17,%18,%19,%20,%21,%22,%23,%24,%25,%26,%27,%28,%29,%30,%31}, [%32];" \
        : "=r"((r)[0]),"=r"((r)[1]),"=r"((r)[2]),"=r"((r)[3]),"=r"((r)[4]),"=r"((r)[5]),"=r"((r)[6]),"=r"((r)[7]), \
          "=r"((r)[8]),"=r"((r)[9]),"=r"((r)[10]),"=r"((r)[11]),"=r"((r)[12]),"=r"((r)[13]),"=r"((r)[14]),"=r"((r)[15]), \
          "=r"((r)[16]),"=r"((r)[17]),"=r"((r)[18]),"=r"((r)[19]),"=r"((r)[20]),"=r"((r)[21]),"=r"((r)[22]),"=r"((r)[23]), \
          "=r"((r)[24]),"=r"((r)[25]),"=r"((r)[26]),"=r"((r)[27]),"=r"((r)[28]),"=r"((r)[29]),"=r"((r)[30]),"=r"((r)[31]) \
        : "r"(addr))
#define CLUSTER_SYNC() do { \
    asm volatile("barrier.cluster.arrive.aligned;" ::: "memory"); \
    asm volatile("barrier.cluster.wait.aligned;" ::: "memory"); \
} while (0)

static constexpr uint64_t DESC_SW128 =
    (uint64_t(2) << 61) | (uint64_t(1) << 46) | (uint64_t(64) << 32) | (uint64_t(1) << 16);
__device__ __forceinline__ uint64_t mk_desc(uint32_t sm) {
    return DESC_SW128 | ((uint64_t)(sm >> 4) & 0x3FFF);
}
// kind::f16, D=F32, A=BF16, B=BF16, M=256 (cg2), N=256
#define IDESC_CG2 0x10400490u
__device__ __forceinline__ void mma_cg2(uint32_t d, uint64_t a, uint64_t b, uint32_t en) {
    asm volatile("{ .reg .pred p; setp.ne.u32 p, %5, 0;\n\t"
        "tcgen05.mma.cta_group::2.kind::f16 [%0], %1, %2, %3, {%4,%4,%4,%4,%4,%4,%4,%4}, p; }"
        :: "r"(d), "l"(a), "l"(b), "r"(IDESC_CG2), "r"(0u), "r"(en) : "memory");
}
#endif // HAS_TC

#define KCHUNK 64
#define NCHUNK (MDIM / KCHUNK)     // 32 chunks per tile
#define NSTAGE 3
#define NPAIRS 74
#define NTILES_TOTAL 168           // 8 m-tiles x 21 n-tiles
#define SM_TMEMPTR 0
#define SM_FULL(s)  (16 + (s) * 8)
#define SM_EMPTY(s) (48 + (s) * 8)
#define SM_MDONE(t) (80 + (t) * 8)
#define SM_EPID(t)  (96 + (t) * 8)
#define STAGE_CTA 65536
#define TX_BYTES (2 * STAGE_CTA)   // both CTAs' loads land on leader barrier
#define SM_STAGE(s) (1024 + (s) * STAGE_CTA)
#define A_HI(s) (SM_STAGE(s))
#define A_LO(s) (SM_STAGE(s) + 16384)
#define B_HI(s) (SM_STAGE(s) + 32768)
#define B_LO(s) (SM_STAGE(s) + 49152)
#define EPI_HI (1024 + NSTAGE * STAGE_CTA)     // 197632
#define EPI_LO (EPI_HI + 8192)
#define TC_SMEM (EPI_LO + 8192)                // 214016

__global__ __launch_bounds__(160, 1) __cluster_dims__(2, 1, 1) void gemm_tc(
    const __grid_constant__ CUtensorMap mapAhi,
    const __grid_constant__ CUtensorMap mapAlo,
    const __grid_constant__ CUtensorMap mapBhi,
    const __grid_constant__ CUtensorMap mapBlo,
    __nv_bfloat16* __restrict__ dst_hi,
    __nv_bfloat16* __restrict__ dst_lo)
{
#if HAS_TC
    extern __shared__ char smem[];
    uint32_t smb = smem_u32(smem);
    int tid = threadIdx.x, wid = tid >> 5, lane = tid & 31;
    uint32_t rank;
    asm("mov.u32 %0, %%cluster_ctarank;" : "=r"(rank));
    int pair = blockIdx.x >> 1;
    int my_ntiles = (NTILES_TOTAL - pair + NPAIRS - 1) / NPAIRS;   // 3 for pair<20 else 2

    if (wid == 4) { TC_ALLOC_CG2(smb + SM_TMEMPTR, 512); TC_RELINQ_CG2(); }
    if (tid == 0) {
        #pragma unroll
        for (int s = 0; s < NSTAGE; s++) {
            MBAR_INIT(smb + SM_FULL(s), 1);
            MBAR_INIT(smb + SM_EMPTY(s), 1);
        }
        MBAR_INIT(smb + SM_MDONE(0), 1);
        MBAR_INIT(smb + SM_MDONE(1), 1);
        MBAR_INIT(smb + SM_EPID(0), 2);   // one arrival per CTA
        MBAR_INIT(smb + SM_EPID(1), 2);
    }
    __syncthreads();
    CLUSTER_SYNC();   // barriers visible cluster-wide before cg2 TMA / multicast commit

    uint32_t tmem;
    asm volatile("ld.shared.b32 %0, [%1];" : "=r"(tmem) : "r"(smb + SM_TMEMPTR));

    if (wid == 4) {
        // ---------------- control warp: TMA producer (both ranks) + MMA (rank 0) ----------------
        uint32_t e1 = elect_one();
        uint32_t pf[NSTAGE] = {0, 0, 0}, pe[NSTAGE] = {0, 0, 0}, ped[2] = {0, 0};
        int total = my_ntiles * NCHUNK;

        if (e1) {
            #pragma unroll
            for (int g = 0; g < NSTAGE; g++) {          // total >= 64 > NSTAGE always
                int t = pair + NPAIRS * (g >> 5);
                int mt = t & 7, nt = t >> 3;
                int k0 = (g & 31) * KCHUNK;
                int ma = mt * 256 + (int)rank * 128;
                int nb = nt * 256 + (int)rank * 128;
                if (rank == 0) MBAR_EXPECT_TX(smb + SM_FULL(g), TX_BYTES);
                TMA_2D_CG2(smb + A_HI(g), &mapAhi, k0, ma, smb + SM_FULL(g));
                TMA_2D_CG2(smb + A_LO(g), &mapAlo, k0, ma, smb + SM_FULL(g));
                TMA_2D_CG2(smb + B_HI(g), &mapBhi, k0, nb, smb + SM_FULL(g));
                TMA_2D_CG2(smb + B_LO(g), &mapBlo, k0, nb, smb + SM_FULL(g));
            }
        }
        int s = 0;
        for (int g = 0; g < total; g++) {
            int c = g & 31, ti = g >> 5, slot = ti & 1;
            if (rank == 0) {
                if (c == 0 && ti >= 2) {            // D-slot reuse: wait both CTAs' epilogues
                    MBAR_WAIT(smb + SM_EPID(slot), ped[slot]); ped[slot] ^= 1;
                }
                MBAR_WAIT(smb + SM_FULL(s), pf[s]); pf[s] ^= 1;
                if (e1) {
                    uint64_t ah = mk_desc(smb + A_HI(s));
                    uint64_t al = mk_desc(smb + A_LO(s));
                    uint64_t bh = mk_desc(smb + B_HI(s));
                    uint64_t bl = mk_desc(smb + B_LO(s));
                    uint32_t dt = tmem + slot * 256;
                    #pragma unroll
                    for (int ks = 0; ks < 4; ks++)
                        mma_cg2(dt, ah + ks * 2, bh + ks * 2, (c == 0 && ks == 0) ? 0u : 1u);
                    #pragma unroll
                    for (int ks = 0; ks < 4; ks++)
                        mma_cg2(dt, ah + ks * 2, bl + ks * 2, 1u);
                    #pragma unroll
                    for (int ks = 0; ks < 4; ks++)
                        mma_cg2(dt, al + ks * 2, bh + ks * 2, 1u);
                    TC_COMMIT_MC2(smb + SM_EMPTY(s));
                    if (c == NCHUNK - 1) TC_COMMIT_MC2(smb + SM_MDONE(slot));
                }
            }
            int gn = g + NSTAGE;
            if (gn < total) {
                MBAR_WAIT(smb + SM_EMPTY(s), pe[s]); pe[s] ^= 1;
                if (e1) {
                    int t = pair + NPAIRS * (gn >> 5);
                    int mt = t & 7, nt = t >> 3;
                    int k0 = (gn & 31) * KCHUNK;
                    int ma = mt * 256 + (int)rank * 128;
                    int nb = nt * 256 + (int)rank * 128;
                    if (rank == 0) MBAR_EXPECT_TX(smb + SM_FULL(s), TX_BYTES);
                    TMA_2D_CG2(smb + A_HI(s), &mapAhi, k0, ma, smb + SM_FULL(s));
                    TMA_2D_CG2(smb + A_LO(s), &mapAlo, k0, ma, smb + SM_FULL(s));
                    TMA_2D_CG2(smb + B_HI(s), &mapBhi, k0, nb, smb + SM_FULL(s));
                    TMA_2D_CG2(smb + B_LO(s), &mapBlo, k0, nb, smb + SM_FULL(s));
                }
            }
            if (++s == NSTAGE) s = 0;
        }
    } else {
        // ---------------- epilogue warps 0..3 (128 threads) ----------------
        uint32_t pm[2] = {0, 0};
        __nv_bfloat16* shi = (__nv_bfloat16*)(smem + EPI_HI);
        __nv_bfloat16* slo = (__nv_bfloat16*)(smem + EPI_LO);
        int mloc = wid * 32 + lane;
        for (int ti = 0; ti < my_ntiles; ti++) {
            int slot = ti & 1;
            int t = pair + NPAIRS * ti;
            int mt = t & 7, nt = t >> 3;
            int mg = mt * 256 + (int)rank * 128;   // this CTA's 128 M rows
            int ng = nt * 256;
            MBAR_WAIT(smb + SM_MDONE(slot), pm[slot]); pm[slot] ^= 1;
            TC_FENCE_AFTER();
            #pragma unroll 1
            for (int blk = 0; blk < 8; blk++) {
                uint32_t r[32];
                TC_LD_X32(r, tmem + slot * 256 + blk * 32);
                TC_WAIT_LD();
                #pragma unroll
                for (int j = 0; j < 32; j++) {
                    float v = __uint_as_float(r[j]);
                    __nv_bfloat16 h = __float2bfloat16(v);
                    __nv_bfloat16 l = __float2bfloat16(v - __bfloat162float(h));
                    shi[j * 128 + mloc] = h;
                    slo[j * 128 + mloc] = l;
                }
                asm volatile("bar.sync 1, 128;" ::: "memory");
                #pragma unroll
                for (int idx = tid; idx < 512; idx += 128) {
                    int nl = idx >> 4;
                    int m8 = (idx & 15) * 8;
                    size_t ga = (size_t)(ng + blk * 32 + nl) * MDIM + mg + m8;
                    *(uint4*)(dst_hi + ga) = *(uint4*)(shi + nl * 128 + m8);
                    *(uint4*)(dst_lo + ga) = *(uint4*)(slo + nl * 128 + m8);
                }
                asm volatile("bar.sync 1, 128;" ::: "memory");
            }
            TC_FENCE_BEFORE();
            if (tid == 0) MBAR_ARRIVE_RANK0(smb + SM_EPID(slot));   // free D slot (cluster arrive)
        }
    }
    __syncthreads();
    if (wid == 4) TC_DEALLOC_CG2(tmem, 512);
    CLUSTER_SYNC();   // peer SMEM/TMEM must stay alive until both CTAs are done
#endif
}

// ======================= fused hop MLP (packed f32x2, 64 rows/block) =======================
__global__ __launch_bounds__(256) void mlp_kernel(const __nv_bfloat16* __restrict__ thi,
                                                  const __nv_bfloat16* __restrict__ tlo,
                                                  const float* __restrict__ W1,
                                                  const float* __restrict__ b1,
                                                  const float* __restrict__ W2,
                                                  const float* __restrict__ b2,
                                                  int hop, int accum,
                                                  float* __restrict__ out) {
    const float* W1h = W1 + hop * HIDD * WDIM;
    const float* b1h = b1 + hop * HIDD;
    const float* W2h = W2 + hop * HIDD;
    float b2h = b2[hop];

    __shared__ __align__(16) float Ts[56][72];   // [k][row], 64 rows + pad
    __shared__ float W1s[HIDD][57];              // [h][k], conflict-free strided reads

    int tid = threadIdx.x, lane = tid & 31, warp = tid >> 5;   // 8 warps x 8 rows
    int r0 = blockIdx.x * 64;
    int b = r0 >> 11;
    int m0 = r0 & (MDIM - 1);
    size_t nbase = (size_t)b * WDIM;

    float b1r[4], w2r[4];
    #pragma unroll
    for (int j = 0; j < 4; j++) {
        b1r[j] = b1h[lane + 32 * j];
        w2r[j] = W2h[lane + 32 * j];
    }

    unsigned long long acc2[4][4] = {};
    for (int w0 = 0; w0 < WDIM; w0 += 56) {
        for (int idx = tid; idx < 56 * 32; idx += 256) {
            int w = idx >> 5, r2 = (idx & 31) << 1;
            size_t g = (nbase + w0 + w) * MDIM + m0 + r2;
            __nv_bfloat162 h2 = *(const __nv_bfloat162*)(thi + g);
            __nv_bfloat162 l2 = *(const __nv_bfloat162*)(tlo + g);
            Ts[w][r2]     = __bfloat162float(h2.x) + __bfloat162float(l2.x);
            Ts[w][r2 + 1] = __bfloat162float(h2.y) + __bfloat162float(l2.y);
        }
        for (int idx = tid; idx < HIDD * 56; idx += 256) {
            int h = idx / 56, w = idx - h * 56;
            W1s[h][w] = W1h[h * WDIM + w0 + w];
        }
        __syncthreads();

        #pragma unroll 4
        for (int k = 0; k < 56; k++) {
            ulonglong2 t01 = *(const ulonglong2*)(&Ts[k][warp * 8]);
            ulonglong2 t23 = *(const ulonglong2*)(&Ts[k][warp * 8 + 4]);
            #pragma unroll
            for (int j = 0; j < 4; j++) {
                unsigned long long wv = bcast2(W1s[lane + 32 * j][k]);
                fma2(acc2[0][j], t01.x, wv);
                fma2(acc2[1][j], t01.y, wv);
                fma2(acc2[2][j], t23.x, wv);
                fma2(acc2[3][j], t23.y, wv);
            }
        }
        __syncthreads();
    }

    float c[8][4];
    #pragma unroll
    for (int p = 0; p < 4; p++)
        #pragma unroll
        for (int j = 0; j < 4; j++) {
            float2 u = unpack2(acc2[p][j]);
            c[2 * p][j] = u.x;
            c[2 * p + 1][j] = u.y;
        }
    float part[8];
    #pragma unroll
    for (int i = 0; i < 8; i++) {
        float s = 0.f;
        #pragma unroll
        for (int j = 0; j < 4; j++)
            s += fmaxf(c[i][j] + b1r[j], 0.f) * w2r[j];
        #pragma unroll
        for (int off = 16; off > 0; off >>= 1)
            s += __shfl_xor_sync(0xffffffffu, s, off);
        part[i] = s;
    }
    if (lane < 8) {
        int r = r0 + warp * 8 + lane;
        float v = part[lane] + b2h;
        if (accum) v += out[r];
        out[r] = v;
    }
}

// ======================= host =======================
typedef CUresult (*PFN_tmEncode)(CUtensorMap*, CUtensorMapDataType, cuuint32_t, void*,
                                 const cuuint64_t*, const cuuint64_t*, const cuuint32_t*,
                                 const cuuint32_t*, CUtensorMapInterleave, CUtensorMapSwizzle,
                                 CUtensorMapL2promotion, CUtensorMapFloatOOBfill);

static void make_map(PFN_tmEncode enc, CUtensorMap* m, void* ptr,
                     unsigned long long d0, unsigned long long d1,
                     unsigned box0, unsigned box1) {
    cuuint64_t dims[2] = {d0, d1};
    cuuint64_t strides[1] = {d0 * 2};
    cuuint32_t box[2] = {box0, box1};
    cuuint32_t es[2] = {1, 1};
    enc(m, CU_TENSOR_MAP_DATA_TYPE_BFLOAT16, 2, ptr, dims, strides, box, es,
        CU_TENSOR_MAP_INTERLEAVE_NONE, CU_TENSOR_MAP_SWIZZLE_128B,
        CU_TENSOR_MAP_L2_PROMOTION_L2_128B, CU_TENSOR_MAP_FLOAT_OOB_FILL_NONE);
}

extern "C" void kernel_launch(void* const* d_in, const int* in_sizes, int n_in,
                              void* d_out, int out_size) {
    const float* x  = (const float*)d_in[0];
    const float* L  = (const float*)d_in[1];
    const float* W1 = (const float*)d_in[2];
    const float* b1 = (const float*)d_in[3];
    const float* W2 = (const float*)d_in[4];
    const float* b2 = (const float*)d_in[5];
    float* out = (float*)d_out;

    __nv_bfloat16 *hi0, *hi1, *lo0, *lo1, *Lhi, *Llo;
    cudaGetSymbolAddress((void**)&hi0, g_hi);
    hi1 = hi0 + (size_t)BWCOL * MDIM;
    cudaGetSymbolAddress((void**)&lo0, g_lo);
    lo1 = lo0 + (size_t)BWCOL * MDIM;
    cudaGetSymbolAddress((void**)&Lhi, g_Lhi);
    cudaGetSymbolAddress((void**)&Llo, g_Llo);

    PFN_tmEncode enc = nullptr;
    cudaDriverEntryPointQueryResult qr;
    cudaGetDriverEntryPointByVersion("cuTensorMapEncodeTiled", (void**)&enc, 12000,
                                     cudaEnableDefault, &qr);

    CUtensorMap mAhi, mAlo, mBhi[2], mBlo[2];
    make_map(enc, &mAhi, Lhi, MDIM, MDIM, 64, 128);
    make_map(enc, &mAlo, Llo, MDIM, MDIM, 64, 128);
    make_map(enc, &mBhi[0], hi0, MDIM, BWCOL, 64, 128);
    make_map(enc, &mBhi[1], hi1, MDIM, BWCOL, 64, 128);
    make_map(enc, &mBlo[0], lo0, MDIM, BWCOL, 64, 128);
    make_map(enc, &mBlo[1], lo1, MDIM, BWCOL, 64, 128);

    cudaFuncSetAttribute(gemm_tc, cudaFuncAttributeMaxDynamicSharedMemorySize, TC_SMEM);

    {
        int n4 = (BWCOL * MDIM) / 4;
        split_kernel<<<(n4 + 255) / 256, 256>>>(x, hi0, lo0, n4);
        n4 = (MDIM * MDIM) / 4;
        split_kernel<<<(n4 + 255) / 256, 256>>>(L, Lhi, Llo, n4);
    }

    mlp_kernel<<<(BATCH * MDIM) / 64, 256>>>(hi0, lo0, W1, b1, W2, b2, 0, 0, out);

    __nv_bfloat16* bufs_hi[2] = {hi0, hi1};
    __nv_bfloat16* bufs_lo[2] = {lo0, lo1};
    for (int hop = 1; hop <= NHOPS; hop++) {
        int src = (hop + 1) & 1;
        int dst = hop & 1;
        gemm_tc<<<2 * NPAIRS, 160, TC_SMEM>>>(mAhi, mAlo, mBhi[src], mBlo[src],
                                              bufs_hi[dst], bufs_lo[dst]);
        mlp_kernel<<<(BATCH * MDIM) / 64, 256>>>(bufs_hi[dst], bufs_lo[dst],
                                                 W1, b1, W2, b2, hop, 1, out);
    }
}

// round 7
// speedup vs baseline: 6.1217x; 1.2644x over previous
#include <cuda_runtime.h>
#include <cuda_bf16.h>
#include <cuda.h>
#include <cstdint>

#define BATCH 32
#define WDIM  168
#define MDIM  2048
#define HIDD  128
#define NHOPS 6
#define BWCOL (BATCH * WDIM)   // 5376
#define KWPAD 192

#if defined(__CUDA_ARCH__) && defined(__CUDA_ARCH_FEAT_SM103_ALL)
#define HAS_TC 1
#else
#define HAS_TC 0
#endif

// t stored TRANSPOSED: T[n][m], m contiguous (GEMM B operand). Split bf16 hi/lo.
__device__ __align__(1024) __nv_bfloat16 g_hi[2][(size_t)BWCOL * MDIM];
__device__ __align__(1024) __nv_bfloat16 g_lo[2][(size_t)BWCOL * MDIM];
__device__ __align__(1024) __nv_bfloat16 g_Lhi[(size_t)MDIM * MDIM];
__device__ __align__(1024) __nv_bfloat16 g_Llo[(size_t)MDIM * MDIM];
// m-major copy for MLP A operand: tmT[b][m][wpad], w contiguous, zero-padded to 192
__device__ __align__(1024) __nv_bfloat16 g_tmThi[(size_t)BATCH * MDIM * KWPAD];
__device__ __align__(1024) __nv_bfloat16 g_tmTlo[(size_t)BATCH * MDIM * KWPAD];
// W1 split, zero-padded K: [hop][128][192]
__device__ __align__(1024) __nv_bfloat16 g_W1hi[(NHOPS + 1) * HIDD * KWPAD];
__device__ __align__(1024) __nv_bfloat16 g_W1lo[(NHOPS + 1) * HIDD * KWPAD];

// ======================= common helpers =======================
__device__ __forceinline__ uint32_t smem_u32(const void* p) {
    uint32_t a;
    asm("{ .reg .u64 t; cvta.to.shared.u64 t, %1; cvt.u32.u64 %0, t; }" : "=r"(a) : "l"(p));
    return a;
}

// ======================= splits =======================
__global__ void split_kernel(const float* __restrict__ in, __nv_bfloat16* __restrict__ hi,
                             __nv_bfloat16* __restrict__ lo, int n4) {
    int i = blockIdx.x * blockDim.x + threadIdx.x;
    if (i >= n4) return;
    float4 v = ((const float4*)in)[i];
    __nv_bfloat16 h[4], l[4];
    float vv[4] = {v.x, v.y, v.z, v.w};
    #pragma unroll
    for (int j = 0; j < 4; j++) {
        h[j] = __float2bfloat16(vv[j]);
        l[j] = __float2bfloat16(vv[j] - __bfloat162float(h[j]));
    }
    ((ushort4*)hi)[i] = make_ushort4(*(unsigned short*)&h[0], *(unsigned short*)&h[1],
                                     *(unsigned short*)&h[2], *(unsigned short*)&h[3]);
    ((ushort4*)lo)[i] = make_ushort4(*(unsigned short*)&l[0], *(unsigned short*)&l[1],
                                     *(unsigned short*)&l[2], *(unsigned short*)&l[3]);
}

__global__ void splitW1_kernel(const float* __restrict__ W1, __nv_bfloat16* __restrict__ hi,
                               __nv_bfloat16* __restrict__ lo) {
    int i = blockIdx.x * blockDim.x + threadIdx.x;
    if (i >= (NHOPS + 1) * HIDD * KWPAD) return;
    int w = i % KWPAD;
    int hh = i / KWPAD;
    float v = (w < WDIM) ? W1[hh * WDIM + w] : 0.f;
    __nv_bfloat16 h = __float2bfloat16(v);
    hi[i] = h;
    lo[i] = __float2bfloat16(v - __bfloat162float(h));
}

// x[b][w][m] -> tmT[b][m][wpad] split hi/lo, zero pad w>=168
__global__ void xsplitT_kernel(const float* __restrict__ x,
                               __nv_bfloat16* __restrict__ thi,
                               __nv_bfloat16* __restrict__ tlo) {
    __shared__ float tile[32][33];
    int m0 = blockIdx.x * 32, w0 = blockIdx.y * 32, b = blockIdx.z;
    int tx = threadIdx.x, ty = threadIdx.y;
    #pragma unroll
    for (int i = ty; i < 32; i += 8) {
        int w = w0 + i;
        tile[i][tx] = (w < WDIM) ? x[((size_t)b * WDIM + w) * MDIM + m0 + tx] : 0.f;
    }
    __syncthreads();
    #pragma unroll
    for (int i = ty; i < 32; i += 8) {
        float v = tile[tx][i];
        __nv_bfloat16 h = __float2bfloat16(v);
        __nv_bfloat16 l = __float2bfloat16(v - __bfloat162float(h));
        size_t idx = ((size_t)b * MDIM + m0 + i) * KWPAD + w0 + tx;
        thi[idx] = h;
        tlo[idx] = l;
    }
}

// ======================= tcgen05 macros ('a' targets only) =======================
#if HAS_TC
__device__ __forceinline__ uint32_t elect_one() {
    uint32_t p;
    asm volatile("{ .reg .pred p; elect.sync _|p, 0xFFFFFFFF; selp.b32 %0, 1, 0, p; }" : "=r"(p));
    return p;
}
#define MBAR_INIT(a, c) asm volatile("mbarrier.init.shared.b64 [%0], %1;" :: "r"(a), "r"(c) : "memory")
#define MBAR_EXPECT_TX(a, b) asm volatile("mbarrier.arrive.expect_tx.shared.b64 _, [%0], %1;" :: "r"(a), "r"(b) : "memory")
#define MBAR_WAIT(a, ph) do { \
    uint32_t _m = (a), _p = (ph), _d; \
    asm volatile("{ .reg .pred p; mbarrier.try_wait.parity.acquire.cta.shared::cta.b64 p, [%1], %2; selp.b32 %0,1,0,p; }" \
        : "=r"(_d) : "r"(_m), "r"(_p) : "memory"); \
    if (!_d) { asm volatile("{ .reg .pred P1; WL%=: mbarrier.try_wait.parity.acquire.cta.shared::cta.b64 P1, [%0], %1, 0x989680; @P1 bra.uni WD%=; bra.uni WL%=; WD%=: }" \
        :: "r"(_m), "r"(_p) : "memory"); } \
} while (0)
#define MBAR_ARRIVE_RANK0(a) \
    asm volatile("{ .reg .b32 ra; mapa.shared::cluster.u32 ra, %0, 0; mbarrier.arrive.shared::cluster.b64 _, [ra]; }" \
        :: "r"(a) : "memory")
#define TMA_2D(sm, map, cx, cy, mb) \
    asm volatile("cp.async.bulk.tensor.2d.shared::cta.global.tile.mbarrier::complete_tx::bytes [%0], [%1, {%2, %3}], [%4];" \
        :: "r"(sm), "l"(map), "r"(cx), "r"(cy), "r"(mb) : "memory")
#define TMA_2D_CG2(sm, map, cx, cy, mb) \
    asm volatile("{ .reg .b32 lb; and.b32 lb, %4, 0xFEFFFFFF;\n\t" \
        "cp.async.bulk.tensor.2d.cta_group::2.shared::cluster.global.tile.mbarrier::complete_tx::bytes " \
        "[%0], [%1, {%2, %3}], [lb]; }" \
        :: "r"(sm), "l"(map), "r"(cx), "r"(cy), "r"(mb) : "memory")
#define TC_ALLOC(smaddr, n)      asm volatile("tcgen05.alloc.cta_group::1.sync.aligned.shared::cta.b32 [%0], %1;" :: "r"(smaddr), "r"(n) : "memory")
#define TC_RELINQ()              asm volatile("tcgen05.relinquish_alloc_permit.cta_group::1.sync.aligned;")
#define TC_DEALLOC(t, n)         asm volatile("tcgen05.dealloc.cta_group::1.sync.aligned.b32 %0, %1;" :: "r"(t), "r"(n))
#define TC_COMMIT(mb)            asm volatile("tcgen05.commit.cta_group::1.mbarrier::arrive::one.shared::cluster.b64 [%0];" :: "r"(mb) : "memory")
#define TC_ALLOC_CG2(smaddr, n)  asm volatile("tcgen05.alloc.cta_group::2.sync.aligned.shared::cta.b32 [%0], %1;" :: "r"(smaddr), "r"(n) : "memory")
#define TC_RELINQ_CG2()          asm volatile("tcgen05.relinquish_alloc_permit.cta_group::2.sync.aligned;")
#define TC_DEALLOC_CG2(t, n)     asm volatile("tcgen05.dealloc.cta_group::2.sync.aligned.b32 %0, %1;" :: "r"(t), "r"(n))
#define TC_COMMIT_MC2(mb) \
    asm volatile("tcgen05.commit.cta_group::2.mbarrier::arrive::one.shared::cluster.multicast::cluster.b64 [%0], %1;" \
        :: "r"(mb), "h"((unsigned short)0x3) : "memory")
#define TC_FENCE_AFTER()      asm volatile("tcgen05.fence::after_thread_sync;" ::: "memory")
#define TC_FENCE_BEFORE()     asm volatile("tcgen05.fence::before_thread_sync;" ::: "memory")
#define TC_WAIT_LD()          asm volatile("tcgen05.wait::ld.sync.aligned;" ::: "memory")
#define TC_LD_X32(r, addr) \
    asm volatile("tcgen05.ld.sync.aligned.32x32b.x32.b32 " \
        "{%0,%1,%2,%3,%4,%5,%6,%7,%8,%9,%10,%11,%12,%13,%14,%15," \
        "%16,%17,%18,%19,%20,%21,%22,%23,%24,%25,%26,%27,%28,%29,%30,%31}, [%32];" \
        : "=r"((r)[0]),"=r"((r)[1]),"=r"((r)[2]),"=r"((r)[3]),"=r"((r)[4]),"=r"((r)[5]),"=r"((r)[6]),"=r"((r)[7]), \
          "=r"((r)[8]),"=r"((r)[9]),"=r"((r)[10]),"=r"((r)[11]),"=r"((r)[12]),"=r"((r)[13]),"=r"((r)[14]),"=r"((r)[15]), \
          "=r"((r)[16]),"=r"((r)[17]),"=r"((r)[18]),"=r"((r)[19]),"=r"((r)[20]),"=r"((r)[21]),"=r"((r)[22]),"=r"((r)[23]), \
          "=r"((r)[24]),"=r"((r)[25]),"=r"((r)[26]),"=r"((r)[27]),"=r"((r)[28]),"=r"((r)[29]),"=r"((r)[30]),"=r"((r)[31]) \
        : "r"(addr))
#define CLUSTER_SYNC() do { \
    asm volatile("barrier.cluster.arrive.aligned;" ::: "memory"); \
    asm volatile("barrier.cluster.wait.aligned;" ::: "memory"); \
} while (0)

static constexpr uint64_t DESC_SW128 =
    (uint64_t(2) << 61) | (uint64_t(1) << 46) | (uint64_t(64) << 32) | (uint64_t(1) << 16);
__device__ __forceinline__ uint64_t mk_desc(uint32_t sm) {
    return DESC_SW128 | ((uint64_t)(sm >> 4) & 0x3FFF);
}
// kind::f16, D=F32, A=BF16, B=BF16, M=256 (cg2), N=256
#define IDESC_CG2 0x10400490u
__device__ __forceinline__ void mma_cg2(uint32_t d, uint64_t a, uint64_t b, uint32_t en) {
    asm volatile("{ .reg .pred p; setp.ne.u32 p, %5, 0;\n\t"
        "tcgen05.mma.cta_group::2.kind::f16 [%0], %1, %2, %3, {%4,%4,%4,%4,%4,%4,%4,%4}, p; }"
        :: "r"(d), "l"(a), "l"(b), "r"(IDESC_CG2), "r"(0u), "r"(en) : "memory");
}
// kind::f16, D=F32, A=BF16 K-major, B=BF16 K-major, M=128, N=128 (cg1)
#define IDESC_M128N128 0x8200490u
__device__ __forceinline__ void mma_128(uint32_t d, uint64_t a, uint64_t b, uint32_t en) {
    asm volatile("{ .reg .pred p; setp.ne.u32 p, %5, 0;\n\t"
        "tcgen05.mma.cta_group::1.kind::f16 [%0], %1, %2, %3, {%4,%4,%4,%4}, p; }"
        :: "r"(d), "l"(a), "l"(b), "r"(IDESC_M128N128), "r"(0u), "r"(en) : "memory");
}
#endif // HAS_TC

// ======================= persistent cg2 propagation GEMM =======================
#define KCHUNK 64
#define NCHUNK (MDIM / KCHUNK)     // 32 chunks per tile
#define NSTAGE 3
#define NPAIRS 74
#define NTILES_TOTAL 168           // 8 m-tiles x 21 n-tiles
#define SM_TMEMPTR 0
#define SM_FULL(s)  (16 + (s) * 8)
#define SM_EMPTY(s) (48 + (s) * 8)
#define SM_MDONE(t) (80 + (t) * 8)
#define SM_EPID(t)  (96 + (t) * 8)
#define STAGE_CTA 65536
#define TX_BYTES (2 * STAGE_CTA)
#define SM_STAGE(s) (1024 + (s) * STAGE_CTA)
#define A_HI(s) (SM_STAGE(s))
#define A_LO(s) (SM_STAGE(s) + 16384)
#define B_HI(s) (SM_STAGE(s) + 32768)
#define B_LO(s) (SM_STAGE(s) + 49152)
#define EPI_PITCH 136
#define EPI_BYTES (32 * EPI_PITCH * 2)          // 8704
#define EPI_HI (1024 + NSTAGE * STAGE_CTA)
#define EPI_LO (EPI_HI + EPI_BYTES)
#define TC_SMEM (EPI_LO + EPI_BYTES)            // 215040

__global__ __launch_bounds__(160, 1) __cluster_dims__(2, 1, 1) void gemm_tc(
    const __grid_constant__ CUtensorMap mapAhi,
    const __grid_constant__ CUtensorMap mapAlo,
    const __grid_constant__ CUtensorMap mapBhi,
    const __grid_constant__ CUtensorMap mapBlo,
    __nv_bfloat16* __restrict__ dst_hi,
    __nv_bfloat16* __restrict__ dst_lo,
    __nv_bfloat16* __restrict__ tmT_hi,
    __nv_bfloat16* __restrict__ tmT_lo,
    int write_nm)
{
#if HAS_TC
    extern __shared__ char smem[];
    uint32_t smb = smem_u32(smem);
    int tid = threadIdx.x, wid = tid >> 5, lane = tid & 31;
    uint32_t rank;
    asm("mov.u32 %0, %%cluster_ctarank;" : "=r"(rank));
    int pair = blockIdx.x >> 1;
    int my_ntiles = (NTILES_TOTAL - pair + NPAIRS - 1) / NPAIRS;

    if (wid == 4) { TC_ALLOC_CG2(smb + SM_TMEMPTR, 512); TC_RELINQ_CG2(); }
    if (tid == 0) {
        #pragma unroll
        for (int s = 0; s < NSTAGE; s++) {
            MBAR_INIT(smb + SM_FULL(s), 1);
            MBAR_INIT(smb + SM_EMPTY(s), 1);
        }
        MBAR_INIT(smb + SM_MDONE(0), 1);
        MBAR_INIT(smb + SM_MDONE(1), 1);
        MBAR_INIT(smb + SM_EPID(0), 2);
        MBAR_INIT(smb + SM_EPID(1), 2);
    }
    __syncthreads();
    CLUSTER_SYNC();

    uint32_t tmem;
    asm volatile("ld.shared.b32 %0, [%1];" : "=r"(tmem) : "r"(smb + SM_TMEMPTR));

    if (wid == 4) {
        uint32_t e1 = elect_one();
        uint32_t pf[NSTAGE] = {0, 0, 0}, pe[NSTAGE] = {0, 0, 0}, ped[2] = {0, 0};
        int total = my_ntiles * NCHUNK;

        if (e1) {
            #pragma unroll
            for (int g = 0; g < NSTAGE; g++) {
                int t = pair + NPAIRS * (g >> 5);
                int mt = t & 7, nt = t >> 3;
                int k0 = (g & 31) * KCHUNK;
                int ma = mt * 256 + (int)rank * 128;
                int nb = nt * 256 + (int)rank * 128;
                if (rank == 0) MBAR_EXPECT_TX(smb + SM_FULL(g), TX_BYTES);
                TMA_2D_CG2(smb + A_HI(g), &mapAhi, k0, ma, smb + SM_FULL(g));
                TMA_2D_CG2(smb + A_LO(g), &mapAlo, k0, ma, smb + SM_FULL(g));
                TMA_2D_CG2(smb + B_HI(g), &mapBhi, k0, nb, smb + SM_FULL(g));
                TMA_2D_CG2(smb + B_LO(g), &mapBlo, k0, nb, smb + SM_FULL(g));
            }
        }
        int s = 0;
        for (int g = 0; g < total; g++) {
            int c = g & 31, ti = g >> 5, slot = ti & 1;
            if (rank == 0) {
                if (c == 0 && ti >= 2) {
                    MBAR_WAIT(smb + SM_EPID(slot), ped[slot]); ped[slot] ^= 1;
                }
                MBAR_WAIT(smb + SM_FULL(s), pf[s]); pf[s] ^= 1;
                if (e1) {
                    uint64_t ah = mk_desc(smb + A_HI(s));
                    uint64_t al = mk_desc(smb + A_LO(s));
                    uint64_t bh = mk_desc(smb + B_HI(s));
                    uint64_t bl = mk_desc(smb + B_LO(s));
                    uint32_t dt = tmem + slot * 256;
                    #pragma unroll
                    for (int ks = 0; ks < 4; ks++)
                        mma_cg2(dt, ah + ks * 2, bh + ks * 2, (c == 0 && ks == 0) ? 0u : 1u);
                    #pragma unroll
                    for (int ks = 0; ks < 4; ks++)
                        mma_cg2(dt, ah + ks * 2, bl + ks * 2, 1u);
                    #pragma unroll
                    for (int ks = 0; ks < 4; ks++)
                        mma_cg2(dt, al + ks * 2, bh + ks * 2, 1u);
                    TC_COMMIT_MC2(smb + SM_EMPTY(s));
                    if (c == NCHUNK - 1) TC_COMMIT_MC2(smb + SM_MDONE(slot));
                }
            }
            int gn = g + NSTAGE;
            if (gn < total) {
                MBAR_WAIT(smb + SM_EMPTY(s), pe[s]); pe[s] ^= 1;
                if (e1) {
                    int t = pair + NPAIRS * (gn >> 5);
                    int mt = t & 7, nt = t >> 3;
                    int k0 = (gn & 31) * KCHUNK;
                    int ma = mt * 256 + (int)rank * 128;
                    int nb = nt * 256 + (int)rank * 128;
                    if (rank == 0) MBAR_EXPECT_TX(smb + SM_FULL(s), TX_BYTES);
                    TMA_2D_CG2(smb + A_HI(s), &mapAhi, k0, ma, smb + SM_FULL(s));
                    TMA_2D_CG2(smb + A_LO(s), &mapAlo, k0, ma, smb + SM_FULL(s));
                    TMA_2D_CG2(smb + B_HI(s), &mapBhi, k0, nb, smb + SM_FULL(s));
                    TMA_2D_CG2(smb + B_LO(s), &mapBlo, k0, nb, smb + SM_FULL(s));
                }
            }
            if (++s == NSTAGE) s = 0;
        }
    } else {
        uint32_t pm[2] = {0, 0};
        __nv_bfloat16* shi = (__nv_bfloat16*)(smem + EPI_HI);
        __nv_bfloat16* slo = (__nv_bfloat16*)(smem + EPI_LO);
        int mloc = wid * 32 + lane;
        for (int ti = 0; ti < my_ntiles; ti++) {
            int slot = ti & 1;
            int t = pair + NPAIRS * ti;
            int mt = t & 7, nt = t >> 3;
            int mg = mt * 256 + (int)rank * 128;
            int ng = nt * 256;
            MBAR_WAIT(smb + SM_MDONE(slot), pm[slot]); pm[slot] ^= 1;
            TC_FENCE_AFTER();
            #pragma unroll 1
            for (int blk = 0; blk < 8; blk++) {
                uint32_t r[32];
                TC_LD_X32(r, tmem + slot * 256 + blk * 32);
                TC_WAIT_LD();
                #pragma unroll
                for (int j = 0; j < 32; j++) {
                    float v = __uint_as_float(r[j]);
                    __nv_bfloat16 h = __float2bfloat16(v);
                    __nv_bfloat16 l = __float2bfloat16(v - __bfloat162float(h));
                    shi[j * EPI_PITCH + mloc] = h;
                    slo[j * EPI_PITCH + mloc] = l;
                }
                asm volatile("bar.sync 1, 128;" ::: "memory");
                // pass 1: [n][m] orientation for next hop's GEMM B
                if (write_nm) {
                    #pragma unroll
                    for (int idx = tid; idx < 512; idx += 128) {
                        int nl = idx >> 4;
                        int m8 = (idx & 15) * 8;
                        size_t ga = (size_t)(ng + blk * 32 + nl) * MDIM + mg + m8;
                        *(uint4*)(dst_hi + ga) = *(uint4*)(shi + nl * EPI_PITCH + m8);
                        *(uint4*)(dst_lo + ga) = *(uint4*)(slo + nl * EPI_PITCH + m8);
                    }
                }
                // pass 2: m-major tmT[b][m][w] for the MLP A operand.
                // 8-n groups never cross batch boundary (168 % 8 == 0).
                {
                    int mrow = mg + tid;
                    #pragma unroll
                    for (int j8 = 0; j8 < 32; j8 += 8) {
                        int n0 = ng + blk * 32 + j8;
                        int bb = n0 / WDIM;
                        int w = n0 - bb * WDIM;
                        uint4 uh, ul;
                        unsigned short* ph = (unsigned short*)&uh;
                        unsigned short* pl = (unsigned short*)&ul;
                        #pragma unroll
                        for (int q = 0; q < 8; q++) {
                            ph[q] = *(unsigned short*)&shi[(j8 + q) * EPI_PITCH + tid];
                            pl[q] = *(unsigned short*)&slo[(j8 + q) * EPI_PITCH + tid];
                        }
                        size_t base = ((size_t)bb * MDIM + mrow) * KWPAD + w;
                        *(uint4*)(tmT_hi + base) = uh;
                        *(uint4*)(tmT_lo + base) = ul;
                    }
                }
                asm volatile("bar.sync 1, 128;" ::: "memory");
            }
            TC_FENCE_BEFORE();
            if (tid == 0) MBAR_ARRIVE_RANK0(smb + SM_EPID(slot));
        }
    }
    __syncthreads();
    if (wid == 4) TC_DEALLOC_CG2(tmem, 512);
    CLUSTER_SYNC();
#endif
}

// ======================= tensor-core fused MLP (all K-major SS) =======================
// Per CTA: D[m=128 lanes][h=128 cols] = tmT_b[mtile] . W1^T ; then per-lane
// s = sum_h W2[h]*relu(D+b1[h]) + b2 -> out.
#define MLF(s)    (16 + (s) * 8)
#define MLDONE    48
#define MLST(s)   (1024 + (s) * 65536)
#define MLA_HI(s) (MLST(s))
#define MLA_LO(s) (MLST(s) + 16384)
#define MLB_HI(s) (MLST(s) + 32768)
#define MLB_LO(s) (MLST(s) + 49152)
#define MLP_SMEM (1024 + 3 * 65536)   // 197632

__global__ __launch_bounds__(160, 1) void mlp_tc(
    const __grid_constant__ CUtensorMap mapAhi,   // tmT hi: [32*2048 rows][192]
    const __grid_constant__ CUtensorMap mapAlo,
    const __grid_constant__ CUtensorMap mapBhi,   // W1 hi: [(NHOPS+1)*128 rows][192]
    const __grid_constant__ CUtensorMap mapBlo,
    const float* __restrict__ b1,
    const float* __restrict__ W2,
    const float* __restrict__ b2,
    int hop, int accum,
    float* __restrict__ out)
{
#if HAS_TC
    extern __shared__ char smem[];
    uint32_t smb = smem_u32(smem);
    int tid = threadIdx.x, wid = tid >> 5, lane = tid & 31;
    int b = blockIdx.x >> 4;
    int mt = blockIdx.x & 15;
    int arow = b * MDIM + mt * 128;   // A tile rows in tmT
    int brow = hop * HIDD;            // W1 tile rows

    if (wid == 4) { TC_ALLOC(smb + SM_TMEMPTR, 128); TC_RELINQ(); }
    if (tid == 0) {
        MBAR_INIT(smb + MLF(0), 1);
        MBAR_INIT(smb + MLF(1), 1);
        MBAR_INIT(smb + MLF(2), 1);
        MBAR_INIT(smb + MLDONE, 1);
    }
    __syncthreads();
    uint32_t tmem;
    asm volatile("ld.shared.b32 %0, [%1];" : "=r"(tmem) : "r"(smb + SM_TMEMPTR));

    if (wid == 4) {
        uint32_t e1 = elect_one();
        if (e1) {
            #pragma unroll
            for (int s = 0; s < 3; s++) {     // all 3 K chunks in flight
                MBAR_EXPECT_TX(smb + MLF(s), 65536);
                int k0 = s * 64;
                TMA_2D(smb + MLA_HI(s), &mapAhi, k0, arow, smb + MLF(s));
                TMA_2D(smb + MLA_LO(s), &mapAlo, k0, arow, smb + MLF(s));
                TMA_2D(smb + MLB_HI(s), &mapBhi, k0, brow, smb + MLF(s));
                TMA_2D(smb + MLB_LO(s), &mapBlo, k0, brow, smb + MLF(s));
            }
        }
        #pragma unroll 1
        for (int s = 0; s < 3; s++) {
            MBAR_WAIT(smb + MLF(s), 0);
            if (e1) {
                uint64_t ad[2] = {mk_desc(smb + MLA_HI(s)), mk_desc(smb + MLA_LO(s))};
                uint64_t bd[2] = {mk_desc(smb + MLB_HI(s)), mk_desc(smb + MLB_LO(s))};
                int ta[3] = {0, 0, 1}, tb[3] = {0, 1, 0};
                #pragma unroll
                for (int t = 0; t < 3; t++)
                    #pragma unroll
                    for (int ks = 0; ks < 4; ks++)
                        mma_128(tmem, ad[ta[t]] + ks * 2, bd[tb[t]] + ks * 2,
                                (s == 0 && t == 0 && ks == 0) ? 0u : 1u);
            }
        }
        if (e1) TC_COMMIT(smb + MLDONE);
    } else {
        // lanes = m; thread-local reduce over 128 h columns
        MBAR_WAIT(smb + MLDONE, 0);
        TC_FENCE_AFTER();
        const float* b1h = b1 + hop * HIDD;
        const float* W2h = W2 + hop * HIDD;
        float s = 0.f;
        #pragma unroll 1
        for (int cb = 0; cb < 4; cb++) {
            uint32_t r[32];
            TC_LD_X32(r, tmem + cb * 32);
            TC_WAIT_LD();
            #pragma unroll
            for (int j = 0; j < 32; j++) {
                int h = cb * 32 + j;
                s += W2h[h] * fmaxf(__uint_as_float(r[j]) + b1h[h], 0.f);
            }
        }
        TC_FENCE_BEFORE();
        s += b2[hop];
        int gi = b * MDIM + mt * 128 + wid * 32 + lane;
        if (accum) s += out[gi];
        out[gi] = s;
    }
    __syncthreads();
    if (wid == 4) TC_DEALLOC(tmem, 128);
#endif
}

// ======================= host =======================
typedef CUresult (*PFN_tmEncode)(CUtensorMap*, CUtensorMapDataType, cuuint32_t, void*,
                                 const cuuint64_t*, const cuuint64_t*, const cuuint32_t*,
                                 const cuuint32_t*, CUtensorMapInterleave, CUtensorMapSwizzle,
                                 CUtensorMapL2promotion, CUtensorMapFloatOOBfill);

static void make_map(PFN_tmEncode enc, CUtensorMap* m, void* ptr,
                     unsigned long long d0, unsigned long long d1,
                     unsigned box0, unsigned box1) {
    cuuint64_t dims[2] = {d0, d1};
    cuuint64_t strides[1] = {d0 * 2};
    cuuint32_t box[2] = {box0, box1};
    cuuint32_t es[2] = {1, 1};
    enc(m, CU_TENSOR_MAP_DATA_TYPE_BFLOAT16, 2, ptr, dims, strides, box, es,
        CU_TENSOR_MAP_INTERLEAVE_NONE, CU_TENSOR_MAP_SWIZZLE_128B,
        CU_TENSOR_MAP_L2_PROMOTION_L2_128B, CU_TENSOR_MAP_FLOAT_OOB_FILL_NONE);
}

extern "C" void kernel_launch(void* const* d_in, const int* in_sizes, int n_in,
                              void* d_out, int out_size) {
    const float* x  = (const float*)d_in[0];
    const float* L  = (const float*)d_in[1];
    const float* W1 = (const float*)d_in[2];
    const float* b1 = (const float*)d_in[3];
    const float* W2 = (const float*)d_in[4];
    const float* b2 = (const float*)d_in[5];
    float* out = (float*)d_out;

    __nv_bfloat16 *hi0, *hi1, *lo0, *lo1, *Lhi, *Llo, *W1hi, *W1lo, *tmThi, *tmTlo;
    cudaGetSymbolAddress((void**)&hi0, g_hi);
    hi1 = hi0 + (size_t)BWCOL * MDIM;
    cudaGetSymbolAddress((void**)&lo0, g_lo);
    lo1 = lo0 + (size_t)BWCOL * MDIM;
    cudaGetSymbolAddress((void**)&Lhi, g_Lhi);
    cudaGetSymbolAddress((void**)&Llo, g_Llo);
    cudaGetSymbolAddress((void**)&W1hi, g_W1hi);
    cudaGetSymbolAddress((void**)&W1lo, g_W1lo);
    cudaGetSymbolAddress((void**)&tmThi, g_tmThi);
    cudaGetSymbolAddress((void**)&tmTlo, g_tmTlo);

    PFN_tmEncode enc = nullptr;
    cudaDriverEntryPointQueryResult qr;
    cudaGetDriverEntryPointByVersion("cuTensorMapEncodeTiled", (void**)&enc, 12000,
                                     cudaEnableDefault, &qr);

    CUtensorMap mAhi, mAlo, mBhi[2], mBlo[2], mW1hi, mW1lo, mTmhi, mTmlo;
    make_map(enc, &mAhi, Lhi, MDIM, MDIM, 64, 128);
    make_map(enc, &mAlo, Llo, MDIM, MDIM, 64, 128);
    make_map(enc, &mBhi[0], hi0, MDIM, BWCOL, 64, 128);
    make_map(enc, &mBhi[1], hi1, MDIM, BWCOL, 64, 128);
    make_map(enc, &mBlo[0], lo0, MDIM, BWCOL, 64, 128);
    make_map(enc, &mBlo[1], lo1, MDIM, BWCOL, 64, 128);
    make_map(enc, &mW1hi, W1hi, KWPAD, (NHOPS + 1) * HIDD, 64, 128);
    make_map(enc, &mW1lo, W1lo, KWPAD, (NHOPS + 1) * HIDD, 64, 128);
    make_map(enc, &mTmhi, tmThi, KWPAD, (unsigned long long)BATCH * MDIM, 64, 128);
    make_map(enc, &mTmlo, tmTlo, KWPAD, (unsigned long long)BATCH * MDIM, 64, 128);

    cudaFuncSetAttribute(gemm_tc, cudaFuncAttributeMaxDynamicSharedMemorySize, TC_SMEM);
    cudaFuncSetAttribute(mlp_tc, cudaFuncAttributeMaxDynamicSharedMemorySize, MLP_SMEM);

    {
        int n4 = (BWCOL * MDIM) / 4;
        split_kernel<<<(n4 + 255) / 256, 256>>>(x, hi0, lo0, n4);
        n4 = (MDIM * MDIM) / 4;
        split_kernel<<<(n4 + 255) / 256, 256>>>(L, Lhi, Llo, n4);
        int nw = (NHOPS + 1) * HIDD * KWPAD;
        splitW1_kernel<<<(nw + 255) / 256, 256>>>(W1, W1hi, W1lo);
        dim3 tg(MDIM / 32, KWPAD / 32, BATCH), tb(32, 8);
        xsplitT_kernel<<<tg, tb>>>(x, tmThi, tmTlo);
    }

    mlp_tc<<<BATCH * 16, 160, MLP_SMEM>>>(mTmhi, mTmlo, mW1hi, mW1lo,
                                          b1, W2, b2, 0, 0, out);

    for (int hop = 1; hop <= NHOPS; hop++) {
        int src = (hop + 1) & 1;
        int dst = hop & 1;
        gemm_tc<<<2 * NPAIRS, 160, TC_SMEM>>>(mAhi, mAlo, mBhi[src], mBlo[src],
                                              dst ? hi1 : hi0, dst ? lo1 : lo0,
                                              tmThi, tmTlo, hop < NHOPS ? 1 : 0);
        mlp_tc<<<BATCH * 16, 160, MLP_SMEM>>>(mTmhi, mTmlo, mW1hi, mW1lo,
                                              b1, W2, b2, hop, 1, out);
    }
}

// round 8
// speedup vs baseline: 7.7885x; 1.2723x over previous
#include <cuda_runtime.h>
#include <cuda_bf16.h>
#include <cuda.h>
#include <cstdint>

#define BATCH 32
#define WDIM  168
#define MDIM  2048
#define HIDD  128
#define NHOPS 6
#define BWCOL (BATCH * WDIM)   // 5376
#define KWPAD 192

#if defined(__CUDA_ARCH__) && defined(__CUDA_ARCH_FEAT_SM103_ALL)
#define HAS_TC 1
#else
#define HAS_TC 0
#endif

// t stored TRANSPOSED: T[n][m], m contiguous (GEMM B operand). Split bf16 hi/lo.
__device__ __align__(1024) __nv_bfloat16 g_hi[2][(size_t)BWCOL * MDIM];
__device__ __align__(1024) __nv_bfloat16 g_lo[2][(size_t)BWCOL * MDIM];
__device__ __align__(1024) __nv_bfloat16 g_Lhi[(size_t)MDIM * MDIM];
__device__ __align__(1024) __nv_bfloat16 g_Llo[(size_t)MDIM * MDIM];
// m-major copy for MLP A operand: tmT[b][m][wpad], w contiguous, zero-padded to 192
__device__ __align__(1024) __nv_bfloat16 g_tmThi[(size_t)BATCH * MDIM * KWPAD];
__device__ __align__(1024) __nv_bfloat16 g_tmTlo[(size_t)BATCH * MDIM * KWPAD];
// W1 split, zero-padded K: [hop][128][192]
__device__ __align__(1024) __nv_bfloat16 g_W1hi[(NHOPS + 1) * HIDD * KWPAD];
__device__ __align__(1024) __nv_bfloat16 g_W1lo[(NHOPS + 1) * HIDD * KWPAD];

// ======================= common helpers =======================
__device__ __forceinline__ uint32_t smem_u32(const void* p) {
    uint32_t a;
    asm("{ .reg .u64 t; cvta.to.shared.u64 t, %1; cvt.u32.u64 %0, t; }" : "=r"(a) : "l"(p));
    return a;
}

// ======================= splits =======================
__global__ void split_kernel(const float* __restrict__ in, __nv_bfloat16* __restrict__ hi,
                             __nv_bfloat16* __restrict__ lo, int n4) {
    int i = blockIdx.x * blockDim.x + threadIdx.x;
    if (i >= n4) return;
    float4 v = ((const float4*)in)[i];
    __nv_bfloat16 h[4], l[4];
    float vv[4] = {v.x, v.y, v.z, v.w};
    #pragma unroll
    for (int j = 0; j < 4; j++) {
        h[j] = __float2bfloat16(vv[j]);
        l[j] = __float2bfloat16(vv[j] - __bfloat162float(h[j]));
    }
    ((ushort4*)hi)[i] = make_ushort4(*(unsigned short*)&h[0], *(unsigned short*)&h[1],
                                     *(unsigned short*)&h[2], *(unsigned short*)&h[3]);
    ((ushort4*)lo)[i] = make_ushort4(*(unsigned short*)&l[0], *(unsigned short*)&l[1],
                                     *(unsigned short*)&l[2], *(unsigned short*)&l[3]);
}

__global__ void splitW1_kernel(const float* __restrict__ W1, __nv_bfloat16* __restrict__ hi,
                               __nv_bfloat16* __restrict__ lo) {
    int i = blockIdx.x * blockDim.x + threadIdx.x;
    if (i >= (NHOPS + 1) * HIDD * KWPAD) return;
    int w = i % KWPAD;
    int hh = i / KWPAD;
    float v = (w < WDIM) ? W1[hh * WDIM + w] : 0.f;
    __nv_bfloat16 h = __float2bfloat16(v);
    hi[i] = h;
    lo[i] = __float2bfloat16(v - __bfloat162float(h));
}

// x[b][w][m] -> tmT[b][m][wpad] split hi/lo, zero pad w>=168
__global__ void xsplitT_kernel(const float* __restrict__ x,
                               __nv_bfloat16* __restrict__ thi,
                               __nv_bfloat16* __restrict__ tlo) {
    __shared__ float tile[32][33];
    int m0 = blockIdx.x * 32, w0 = blockIdx.y * 32, b = blockIdx.z;
    int tx = threadIdx.x, ty = threadIdx.y;
    #pragma unroll
    for (int i = ty; i < 32; i += 8) {
        int w = w0 + i;
        tile[i][tx] = (w < WDIM) ? x[((size_t)b * WDIM + w) * MDIM + m0 + tx] : 0.f;
    }
    __syncthreads();
    #pragma unroll
    for (int i = ty; i < 32; i += 8) {
        float v = tile[tx][i];
        __nv_bfloat16 h = __float2bfloat16(v);
        __nv_bfloat16 l = __float2bfloat16(v - __bfloat162float(h));
        size_t idx = ((size_t)b * MDIM + m0 + i) * KWPAD + w0 + tx;
        thi[idx] = h;
        tlo[idx] = l;
    }
}

// ======================= tcgen05 macros ('a' targets only) =======================
#if HAS_TC
__device__ __forceinline__ uint32_t elect_one() {
    uint32_t p;
    asm volatile("{ .reg .pred p; elect.sync _|p, 0xFFFFFFFF; selp.b32 %0, 1, 0, p; }" : "=r"(p));
    return p;
}
#define MBAR_INIT(a, c) asm volatile("mbarrier.init.shared.b64 [%0], %1;" :: "r"(a), "r"(c) : "memory")
#define MBAR_EXPECT_TX(a, b) asm volatile("mbarrier.arrive.expect_tx.shared.b64 _, [%0], %1;" :: "r"(a), "r"(b) : "memory")
#define MBAR_WAIT(a, ph) do { \
    uint32_t _m = (a), _p = (ph), _d; \
    asm volatile("{ .reg .pred p; mbarrier.try_wait.parity.acquire.cta.shared::cta.b64 p, [%1], %2; selp.b32 %0,1,0,p; }" \
        : "=r"(_d) : "r"(_m), "r"(_p) : "memory"); \
    if (!_d) { asm volatile("{ .reg .pred P1; WL%=: mbarrier.try_wait.parity.acquire.cta.shared::cta.b64 P1, [%0], %1, 0x989680; @P1 bra.uni WD%=; bra.uni WL%=; WD%=: }" \
        :: "r"(_m), "r"(_p) : "memory"); } \
} while (0)
#define MBAR_ARRIVE_RANK0(a) \
    asm volatile("{ .reg .b32 ra; mapa.shared::cluster.u32 ra, %0, 0; mbarrier.arrive.shared::cluster.b64 _, [ra]; }" \
        :: "r"(a) : "memory")
#define TMA_2D(sm, map, cx, cy, mb) \
    asm volatile("cp.async.bulk.tensor.2d.shared::cta.global.tile.mbarrier::complete_tx::bytes [%0], [%1, {%2, %3}], [%4];" \
        :: "r"(sm), "l"(map), "r"(cx), "r"(cy), "r"(mb) : "memory")
#define TMA_2D_CG2(sm, map, cx, cy, mb) \
    asm volatile("{ .reg .b32 lb; and.b32 lb, %4, 0xFEFFFFFF;\n\t" \
        "cp.async.bulk.tensor.2d.cta_group::2.shared::cluster.global.tile.mbarrier::complete_tx::bytes " \
        "[%0], [%1, {%2, %3}], [lb]; }" \
        :: "r"(sm), "l"(map), "r"(cx), "r"(cy), "r"(mb) : "memory")
#define TC_ALLOC(smaddr, n)      asm volatile("tcgen05.alloc.cta_group::1.sync.aligned.shared::cta.b32 [%0], %1;" :: "r"(smaddr), "r"(n) : "memory")
#define TC_RELINQ()              asm volatile("tcgen05.relinquish_alloc_permit.cta_group::1.sync.aligned;")
#define TC_DEALLOC(t, n)         asm volatile("tcgen05.dealloc.cta_group::1.sync.aligned.b32 %0, %1;" :: "r"(t), "r"(n))
#define TC_COMMIT(mb)            asm volatile("tcgen05.commit.cta_group::1.mbarrier::arrive::one.shared::cluster.b64 [%0];" :: "r"(mb) : "memory")
#define TC_ALLOC_CG2(smaddr, n)  asm volatile("tcgen05.alloc.cta_group::2.sync.aligned.shared::cta.b32 [%0], %1;" :: "r"(smaddr), "r"(n) : "memory")
#define TC_RELINQ_CG2()          asm volatile("tcgen05.relinquish_alloc_permit.cta_group::2.sync.aligned;")
#define TC_DEALLOC_CG2(t, n)     asm volatile("tcgen05.dealloc.cta_group::2.sync.aligned.b32 %0, %1;" :: "r"(t), "r"(n))
#define TC_COMMIT_MC2(mb) \
    asm volatile("tcgen05.commit.cta_group::2.mbarrier::arrive::one.shared::cluster.multicast::cluster.b64 [%0], %1;" \
        :: "r"(mb), "h"((unsigned short)0x3) : "memory")
#define TC_FENCE_AFTER()      asm volatile("tcgen05.fence::after_thread_sync;" ::: "memory")
#define TC_FENCE_BEFORE()     asm volatile("tcgen05.fence::before_thread_sync;" ::: "memory")
#define TC_WAIT_LD()          asm volatile("tcgen05.wait::ld.sync.aligned;" ::: "memory")
#define TC_LD_X32(r, addr) \
    asm volatile("tcgen05.ld.sync.aligned.32x32b.x32.b32 " \
        "{%0,%1,%2,%3,%4,%5,%6,%7,%8,%9,%10,%11,%12,%13,%14,%15," \
        "%16,%17,%18,%19,%20,%21,%22,%23,%24,%25,%26,%27,%28,%29,%30,%31}, [%32];" \
        : "=r"((r)[0]),"=r"((r)[1]),"=r"((r)[2]),"=r"((r)[3]),"=r"((r)[4]),"=r"((r)[5]),"=r"((r)[6]),"=r"((r)[7]), \
          "=r"((r)[8]),"=r"((r)[9]),"=r"((r)[10]),"=r"((r)[11]),"=r"((r)[12]),"=r"((r)[13]),"=r"((r)[14]),"=r"((r)[15]), \
          "=r"((r)[16]),"=r"((r)[17]),"=r"((r)[18]),"=r"((r)[19]),"=r"((r)[20]),"=r"((r)[21]),"=r"((r)[22]),"=r"((r)[23]), \
          "=r"((r)[24]),"=r"((r)[25]),"=r"((r)[26]),"=r"((r)[27]),"=r"((r)[28]),"=r"((r)[29]),"=r"((r)[30]),"=r"((r)[31]) \
        : "r"(addr))
#define CLUSTER_SYNC() do { \
    asm volatile("barrier.cluster.arrive.aligned;" ::: "memory"); \
    asm volatile("barrier.cluster.wait.aligned;" ::: "memory"); \
} while (0)

static constexpr uint64_t DESC_SW128 =
    (uint64_t(2) << 61) | (uint64_t(1) << 46) | (uint64_t(64) << 32) | (uint64_t(1) << 16);
__device__ __forceinline__ uint64_t mk_desc(uint32_t sm) {
    return DESC_SW128 | ((uint64_t)(sm >> 4) & 0x3FFF);
}
// kind::f16, D=F32, A=BF16, B=BF16, M=256 (cg2), N=256
#define IDESC_CG2 0x10400490u
__device__ __forceinline__ void mma_cg2(uint32_t d, uint64_t a, uint64_t b, uint32_t en) {
    asm volatile("{ .reg .pred p; setp.ne.u32 p, %5, 0;\n\t"
        "tcgen05.mma.cta_group::2.kind::f16 [%0], %1, %2, %3, {%4,%4,%4,%4,%4,%4,%4,%4}, p; }"
        :: "r"(d), "l"(a), "l"(b), "r"(IDESC_CG2), "r"(0u), "r"(en) : "memory");
}
// kind::f16, D=F32, A=BF16 K-major, B=BF16 K-major, M=128, N=128 (cg1)
#define IDESC_M128N128 0x8200490u
__device__ __forceinline__ void mma_128(uint32_t d, uint64_t a, uint64_t b, uint32_t en) {
    asm volatile("{ .reg .pred p; setp.ne.u32 p, %5, 0;\n\t"
        "tcgen05.mma.cta_group::1.kind::f16 [%0], %1, %2, %3, {%4,%4,%4,%4}, p; }"
        :: "r"(d), "l"(a), "l"(b), "r"(IDESC_M128N128), "r"(0u), "r"(en) : "memory");
}
#endif // HAS_TC

// ======================= persistent cg2 propagation GEMM =======================
#define KCHUNK 64
#define NCHUNK (MDIM / KCHUNK)     // 32 chunks per tile
#define NSTAGE 3
#define NPAIRS 74
#define NTILES_TOTAL 168           // 8 m-tiles x 21 n-tiles
#define SM_TMEMPTR 0
#define SM_FULL(s)  (16 + (s) * 8)
#define SM_EMPTY(s) (48 + (s) * 8)
#define SM_MDONE(t) (80 + (t) * 8)
#define SM_EPID(t)  (96 + (t) * 8)
#define STAGE_CTA 65536
#define TX_BYTES (2 * STAGE_CTA)
#define SM_STAGE(s) (1024 + (s) * STAGE_CTA)
#define A_HI(s) (SM_STAGE(s))
#define A_LO(s) (SM_STAGE(s) + 16384)
#define B_HI(s) (SM_STAGE(s) + 32768)
#define B_LO(s) (SM_STAGE(s) + 49152)
#define EPI_PITCH 136
#define EPI_BYTES (32 * EPI_PITCH * 2)          // 8704
#define EPI_HI (1024 + NSTAGE * STAGE_CTA)
#define EPI_LO (EPI_HI + EPI_BYTES)
#define TC_SMEM (EPI_LO + EPI_BYTES)            // 215040

__global__ __launch_bounds__(192, 1) __cluster_dims__(2, 1, 1) void gemm_tc(
    const __grid_constant__ CUtensorMap mapAhi,
    const __grid_constant__ CUtensorMap mapAlo,
    const __grid_constant__ CUtensorMap mapBhi,
    const __grid_constant__ CUtensorMap mapBlo,
    __nv_bfloat16* __restrict__ dst_hi,
    __nv_bfloat16* __restrict__ dst_lo,
    __nv_bfloat16* __restrict__ tmT_hi,
    __nv_bfloat16* __restrict__ tmT_lo,
    int write_nm)
{
#if HAS_TC
    extern __shared__ char smem[];
    uint32_t smb = smem_u32(smem);
    int tid = threadIdx.x, wid = tid >> 5, lane = tid & 31;
    uint32_t rank;
    asm("mov.u32 %0, %%cluster_ctarank;" : "=r"(rank));
    int pair = blockIdx.x >> 1;
    int my_ntiles = (NTILES_TOTAL - pair + NPAIRS - 1) / NPAIRS;
    int total = my_ntiles * NCHUNK;

    if (wid == 4) { TC_ALLOC_CG2(smb + SM_TMEMPTR, 512); TC_RELINQ_CG2(); }
    if (tid == 0) {
        #pragma unroll
        for (int s = 0; s < NSTAGE; s++) {
            MBAR_INIT(smb + SM_FULL(s), 1);
            MBAR_INIT(smb + SM_EMPTY(s), 1);
        }
        MBAR_INIT(smb + SM_MDONE(0), 1);
        MBAR_INIT(smb + SM_MDONE(1), 1);
        MBAR_INIT(smb + SM_EPID(0), 2);
        MBAR_INIT(smb + SM_EPID(1), 2);
    }
    __syncthreads();
    CLUSTER_SYNC();

    uint32_t tmem;
    asm volatile("ld.shared.b32 %0, [%1];" : "=r"(tmem) : "r"(smb + SM_TMEMPTR));

    if (wid == 4) {
        // ---------------- TMA producer warp (both ranks) ----------------
        uint32_t e1 = elect_one();
        uint32_t pe[NSTAGE] = {0, 0, 0};
        if (e1) {
            #pragma unroll
            for (int g = 0; g < NSTAGE; g++) {
                int t = pair + NPAIRS * (g >> 5);
                int mt = t & 7, nt = t >> 3;
                int k0 = (g & 31) * KCHUNK;
                int ma = mt * 256 + (int)rank * 128;
                int nb = nt * 256 + (int)rank * 128;
                if (rank == 0) MBAR_EXPECT_TX(smb + SM_FULL(g), TX_BYTES);
                TMA_2D_CG2(smb + A_HI(g), &mapAhi, k0, ma, smb + SM_FULL(g));
                TMA_2D_CG2(smb + A_LO(g), &mapAlo, k0, ma, smb + SM_FULL(g));
                TMA_2D_CG2(smb + B_HI(g), &mapBhi, k0, nb, smb + SM_FULL(g));
                TMA_2D_CG2(smb + B_LO(g), &mapBlo, k0, nb, smb + SM_FULL(g));
            }
            int s = 0;
            for (int g = NSTAGE; g < total; g++) {
                // stage s frees when chunk g-NSTAGE's MMAs complete (multicast commit)
                MBAR_WAIT(smb + SM_EMPTY(s), pe[s]); pe[s] ^= 1;
                int t = pair + NPAIRS * (g >> 5);
                int mt = t & 7, nt = t >> 3;
                int k0 = (g & 31) * KCHUNK;
                int ma = mt * 256 + (int)rank * 128;
                int nb = nt * 256 + (int)rank * 128;
                if (rank == 0) MBAR_EXPECT_TX(smb + SM_FULL(s), TX_BYTES);
                TMA_2D_CG2(smb + A_HI(s), &mapAhi, k0, ma, smb + SM_FULL(s));
                TMA_2D_CG2(smb + A_LO(s), &mapAlo, k0, ma, smb + SM_FULL(s));
                TMA_2D_CG2(smb + B_HI(s), &mapBhi, k0, nb, smb + SM_FULL(s));
                TMA_2D_CG2(smb + B_LO(s), &mapBlo, k0, nb, smb + SM_FULL(s));
                if (++s == NSTAGE) s = 0;
            }
        }
    } else if (wid == 5) {
        // ---------------- MMA consumer warp (rank 0 only) ----------------
        if (rank == 0) {
            uint32_t e1 = elect_one();
            uint32_t pf[NSTAGE] = {0, 0, 0}, ped[2] = {0, 0};
            int s = 0;
            for (int g = 0; g < total; g++) {
                int c = g & 31, ti = g >> 5, slot = ti & 1;
                if (c == 0 && ti >= 2) {      // D-slot reuse gated on both epilogues
                    MBAR_WAIT(smb + SM_EPID(slot), ped[slot]); ped[slot] ^= 1;
                }
                MBAR_WAIT(smb + SM_FULL(s), pf[s]); pf[s] ^= 1;
                if (e1) {
                    uint64_t ah = mk_desc(smb + A_HI(s));
                    uint64_t al = mk_desc(smb + A_LO(s));
                    uint64_t bh = mk_desc(smb + B_HI(s));
                    uint64_t bl = mk_desc(smb + B_LO(s));
                    uint32_t dt = tmem + slot * 256;
                    #pragma unroll
                    for (int ks = 0; ks < 4; ks++)
                        mma_cg2(dt, ah + ks * 2, bh + ks * 2, (c == 0 && ks == 0) ? 0u : 1u);
                    #pragma unroll
                    for (int ks = 0; ks < 4; ks++)
                        mma_cg2(dt, ah + ks * 2, bl + ks * 2, 1u);
                    #pragma unroll
                    for (int ks = 0; ks < 4; ks++)
                        mma_cg2(dt, al + ks * 2, bh + ks * 2, 1u);
                    TC_COMMIT_MC2(smb + SM_EMPTY(s));
                    if (c == NCHUNK - 1) TC_COMMIT_MC2(smb + SM_MDONE(slot));
                }
                if (++s == NSTAGE) s = 0;
            }
        }
    } else {
        // ---------------- epilogue warps 0..3 (128 threads) ----------------
        uint32_t pm[2] = {0, 0};
        __nv_bfloat16* shi = (__nv_bfloat16*)(smem + EPI_HI);
        __nv_bfloat16* slo = (__nv_bfloat16*)(smem + EPI_LO);
        int mloc = wid * 32 + lane;
        for (int ti = 0; ti < my_ntiles; ti++) {
            int slot = ti & 1;
            int t = pair + NPAIRS * ti;
            int mt = t & 7, nt = t >> 3;
            int mg = mt * 256 + (int)rank * 128;
            int ng = nt * 256;
            MBAR_WAIT(smb + SM_MDONE(slot), pm[slot]); pm[slot] ^= 1;
            TC_FENCE_AFTER();
            #pragma unroll 1
            for (int blk = 0; blk < 8; blk++) {
                uint32_t r[32];
                TC_LD_X32(r, tmem + slot * 256 + blk * 32);
                TC_WAIT_LD();
                #pragma unroll
                for (int j = 0; j < 32; j++) {
                    float v = __uint_as_float(r[j]);
                    __nv_bfloat16 h = __float2bfloat16(v);
                    __nv_bfloat16 l = __float2bfloat16(v - __bfloat162float(h));
                    shi[j * EPI_PITCH + mloc] = h;
                    slo[j * EPI_PITCH + mloc] = l;
                }
                asm volatile("bar.sync 1, 128;" ::: "memory");
                // pass 1: [n][m] orientation for next hop's GEMM B
                if (write_nm) {
                    #pragma unroll
                    for (int idx = tid; idx < 512; idx += 128) {
                        int nl = idx >> 4;
                        int m8 = (idx & 15) * 8;
                        size_t ga = (size_t)(ng + blk * 32 + nl) * MDIM + mg + m8;
                        *(uint4*)(dst_hi + ga) = *(uint4*)(shi + nl * EPI_PITCH + m8);
                        *(uint4*)(dst_lo + ga) = *(uint4*)(slo + nl * EPI_PITCH + m8);
                    }
                }
                // pass 2: m-major tmT[b][m][w] for the MLP A operand.
                {
                    int mrow = mg + tid;
                    #pragma unroll
                    for (int j8 = 0; j8 < 32; j8 += 8) {
                        int n0 = ng + blk * 32 + j8;
                        int bb = n0 / WDIM;
                        int w = n0 - bb * WDIM;
                        uint4 uh, ul;
                        unsigned short* ph = (unsigned short*)&uh;
                        unsigned short* pl = (unsigned short*)&ul;
                        #pragma unroll
                        for (int q = 0; q < 8; q++) {
                            ph[q] = *(unsigned short*)&shi[(j8 + q) * EPI_PITCH + tid];
                            pl[q] = *(unsigned short*)&slo[(j8 + q) * EPI_PITCH + tid];
                        }
                        size_t base = ((size_t)bb * MDIM + mrow) * KWPAD + w;
                        *(uint4*)(tmT_hi + base) = uh;
                        *(uint4*)(tmT_lo + base) = ul;
                    }
                }
                asm volatile("bar.sync 1, 128;" ::: "memory");
            }
            TC_FENCE_BEFORE();
            if (tid == 0) MBAR_ARRIVE_RANK0(smb + SM_EPID(slot));
        }
    }
    __syncthreads();
    if (wid == 4) TC_DEALLOC_CG2(tmem, 512);
    CLUSTER_SYNC();
#endif
}

// ======================= tensor-core fused MLP (all K-major SS) =======================
#define MLF(s)    (16 + (s) * 8)
#define MLDONE    48
#define MLST(s)   (1024 + (s) * 65536)
#define MLA_HI(s) (MLST(s))
#define MLA_LO(s) (MLST(s) + 16384)
#define MLB_HI(s) (MLST(s) + 32768)
#define MLB_LO(s) (MLST(s) + 49152)
#define MLP_SMEM (1024 + 3 * 65536)   // 197632

__global__ __launch_bounds__(160, 1) void mlp_tc(
    const __grid_constant__ CUtensorMap mapAhi,   // tmT hi: [32*2048 rows][192]
    const __grid_constant__ CUtensorMap mapAlo,
    const __grid_constant__ CUtensorMap mapBhi,   // W1 hi: [(NHOPS+1)*128 rows][192]
    const __grid_constant__ CUtensorMap mapBlo,
    const float* __restrict__ b1,
    const float* __restrict__ W2,
    const float* __restrict__ b2,
    int hop, int accum,
    float* __restrict__ out)
{
#if HAS_TC
    extern __shared__ char smem[];
    uint32_t smb = smem_u32(smem);
    int tid = threadIdx.x, wid = tid >> 5, lane = tid & 31;
    int b = blockIdx.x >> 4;
    int mt = blockIdx.x & 15;
    int arow = b * MDIM + mt * 128;
    int brow = hop * HIDD;

    if (wid == 4) { TC_ALLOC(smb + SM_TMEMPTR, 128); TC_RELINQ(); }
    if (tid == 0) {
        MBAR_INIT(smb + MLF(0), 1);
        MBAR_INIT(smb + MLF(1), 1);
        MBAR_INIT(smb + MLF(2), 1);
        MBAR_INIT(smb + MLDONE, 1);
    }
    __syncthreads();
    uint32_t tmem;
    asm volatile("ld.shared.b32 %0, [%1];" : "=r"(tmem) : "r"(smb + SM_TMEMPTR));

    if (wid == 4) {
        uint32_t e1 = elect_one();
        if (e1) {
            #pragma unroll
            for (int s = 0; s < 3; s++) {
                MBAR_EXPECT_TX(smb + MLF(s), 65536);
                int k0 = s * 64;
                TMA_2D(smb + MLA_HI(s), &mapAhi, k0, arow, smb + MLF(s));
                TMA_2D(smb + MLA_LO(s), &mapAlo, k0, arow, smb + MLF(s));
                TMA_2D(smb + MLB_HI(s), &mapBhi, k0, brow, smb + MLF(s));
                TMA_2D(smb + MLB_LO(s), &mapBlo, k0, brow, smb + MLF(s));
            }
        }
        #pragma unroll 1
        for (int s = 0; s < 3; s++) {
            MBAR_WAIT(smb + MLF(s), 0);
            if (e1) {
                uint64_t ad[2] = {mk_desc(smb + MLA_HI(s)), mk_desc(smb + MLA_LO(s))};
                uint64_t bd[2] = {mk_desc(smb + MLB_HI(s)), mk_desc(smb + MLB_LO(s))};
                int ta[3] = {0, 0, 1}, tb[3] = {0, 1, 0};
                #pragma unroll
                for (int t = 0; t < 3; t++)
                    #pragma unroll
                    for (int ks = 0; ks < 4; ks++)
                        mma_128(tmem, ad[ta[t]] + ks * 2, bd[tb[t]] + ks * 2,
                                (s == 0 && t == 0 && ks == 0) ? 0u : 1u);
            }
        }
        if (e1) TC_COMMIT(smb + MLDONE);
    } else {
        MBAR_WAIT(smb + MLDONE, 0);
        TC_FENCE_AFTER();
        const float* b1h = b1 + hop * HIDD;
        const float* W2h = W2 + hop * HIDD;
        float s = 0.f;
        #pragma unroll 1
        for (int cb = 0; cb < 4; cb++) {
            uint32_t r[32];
            TC_LD_X32(r, tmem + cb * 32);
            TC_WAIT_LD();
            #pragma unroll
            for (int j = 0; j < 32; j++) {
                int h = cb * 32 + j;
                s += W2h[h] * fmaxf(__uint_as_float(r[j]) + b1h[h], 0.f);
            }
        }
        TC_FENCE_BEFORE();
        s += b2[hop];
        int gi = b * MDIM + mt * 128 + wid * 32 + lane;
        if (accum) s += out[gi];
        out[gi] = s;
    }
    __syncthreads();
    if (wid == 4) TC_DEALLOC(tmem, 128);
#endif
}

// ======================= host =======================
typedef CUresult (*PFN_tmEncode)(CUtensorMap*, CUtensorMapDataType, cuuint32_t, void*,
                                 const cuuint64_t*, const cuuint64_t*, const cuuint32_t*,
                                 const cuuint32_t*, CUtensorMapInterleave, CUtensorMapSwizzle,
                                 CUtensorMapL2promotion, CUtensorMapFloatOOBfill);

static void make_map(PFN_tmEncode enc, CUtensorMap* m, void* ptr,
                     unsigned long long d0, unsigned long long d1,
                     unsigned box0, unsigned box1) {
    cuuint64_t dims[2] = {d0, d1};
    cuuint64_t strides[1] = {d0 * 2};
    cuuint32_t box[2] = {box0, box1};
    cuuint32_t es[2] = {1, 1};
    enc(m, CU_TENSOR_MAP_DATA_TYPE_BFLOAT16, 2, ptr, dims, strides, box, es,
        CU_TENSOR_MAP_INTERLEAVE_NONE, CU_TENSOR_MAP_SWIZZLE_128B,
        CU_TENSOR_MAP_L2_PROMOTION_L2_128B, CU_TENSOR_MAP_FLOAT_OOB_FILL_NONE);
}

extern "C" void kernel_launch(void* const* d_in, const int* in_sizes, int n_in,
                              void* d_out, int out_size) {
    const float* x  = (const float*)d_in[0];
    const float* L  = (const float*)d_in[1];
    const float* W1 = (const float*)d_in[2];
    const float* b1 = (const float*)d_in[3];
    const float* W2 = (const float*)d_in[4];
    const float* b2 = (const float*)d_in[5];
    float* out = (float*)d_out;

    __nv_bfloat16 *hi0, *hi1, *lo0, *lo1, *Lhi, *Llo, *W1hi, *W1lo, *tmThi, *tmTlo;
    cudaGetSymbolAddress((void**)&hi0, g_hi);
    hi1 = hi0 + (size_t)BWCOL * MDIM;
    cudaGetSymbolAddress((void**)&lo0, g_lo);
    lo1 = lo0 + (size_t)BWCOL * MDIM;
    cudaGetSymbolAddress((void**)&Lhi, g_Lhi);
    cudaGetSymbolAddress((void**)&Llo, g_Llo);
    cudaGetSymbolAddress((void**)&W1hi, g_W1hi);
    cudaGetSymbolAddress((void**)&W1lo, g_W1lo);
    cudaGetSymbolAddress((void**)&tmThi, g_tmThi);
    cudaGetSymbolAddress((void**)&tmTlo, g_tmTlo);

    PFN_tmEncode enc = nullptr;
    cudaDriverEntryPointQueryResult qr;
    cudaGetDriverEntryPointByVersion("cuTensorMapEncodeTiled", (void**)&enc, 12000,
                                     cudaEnableDefault, &qr);

    CUtensorMap mAhi, mAlo, mBhi[2], mBlo[2], mW1hi, mW1lo, mTmhi, mTmlo;
    make_map(enc, &mAhi, Lhi, MDIM, MDIM, 64, 128);
    make_map(enc, &mAlo, Llo, MDIM, MDIM, 64, 128);
    make_map(enc, &mBhi[0], hi0, MDIM, BWCOL, 64, 128);
    make_map(enc, &mBhi[1], hi1, MDIM, BWCOL, 64, 128);
    make_map(enc, &mBlo[0], lo0, MDIM, BWCOL, 64, 128);
    make_map(enc, &mBlo[1], lo1, MDIM, BWCOL, 64, 128);
    make_map(enc, &mW1hi, W1hi, KWPAD, (NHOPS + 1) * HIDD, 64, 128);
    make_map(enc, &mW1lo, W1lo, KWPAD, (NHOPS + 1) * HIDD, 64, 128);
    make_map(enc, &mTmhi, tmThi, KWPAD, (unsigned long long)BATCH * MDIM, 64, 128);
    make_map(enc, &mTmlo, tmTlo, KWPAD, (unsigned long long)BATCH * MDIM, 64, 128);

    cudaFuncSetAttribute(gemm_tc, cudaFuncAttributeMaxDynamicSharedMemorySize, TC_SMEM);
    cudaFuncSetAttribute(mlp_tc, cudaFuncAttributeMaxDynamicSharedMemorySize, MLP_SMEM);

    {
        int n4 = (BWCOL * MDIM) / 4;
        split_kernel<<<(n4 + 255) / 256, 256>>>(x, hi0, lo0, n4);
        n4 = (MDIM * MDIM) / 4;
        split_kernel<<<(n4 + 255) / 256, 256>>>(L, Lhi, Llo, n4);
        int nw = (NHOPS + 1) * HIDD * KWPAD;
        splitW1_kernel<<<(nw + 255) / 256, 256>>>(W1, W1hi, W1lo);
        dim3 tg(MDIM / 32, KWPAD / 32, BATCH), tb(32, 8);
        xsplitT_kernel<<<tg, tb>>>(x, tmThi, tmTlo);
    }

    mlp_tc<<<BATCH * 16, 160, MLP_SMEM>>>(mTmhi, mTmlo, mW1hi, mW1lo,
                                          b1, W2, b2, 0, 0, out);

    for (int hop = 1; hop <= NHOPS; hop++) {
        int src = (hop + 1) & 1;
        int dst = hop & 1;
        gemm_tc<<<2 * NPAIRS, 192, TC_SMEM>>>(mAhi, mAlo, mBhi[src], mBlo[src],
                                              dst ? hi1 : hi0, dst ? lo1 : lo0,
                                              tmThi, tmTlo, hop < NHOPS ? 1 : 0);
        mlp_tc<<<BATCH * 16, 160, MLP_SMEM>>>(mTmhi, mTmlo, mW1hi, mW1lo,
                                              b1, W2, b2, hop, 1, out);
    }
}

// round 10
// speedup vs baseline: 8.4872x; 1.0897x over previous
#include <cuda_runtime.h>
#include <cuda_bf16.h>
#include <cuda.h>
#include <cstdint>

#define BATCH 32
#define WDIM  168
#define MDIM  2048
#define HIDD  128
#define NHOPS 6
#define BWCOL (BATCH * WDIM)   // 5376
#define KWPAD 192

#if defined(__CUDA_ARCH__) && defined(__CUDA_ARCH_FEAT_SM103_ALL)
#define HAS_TC 1
#else
#define HAS_TC 0
#endif

// t stored TRANSPOSED: T[n][m], m contiguous (GEMM B operand). Split bf16 hi/lo.
__device__ __align__(1024) __nv_bfloat16 g_hi[2][(size_t)BWCOL * MDIM];
__device__ __align__(1024) __nv_bfloat16 g_lo[2][(size_t)BWCOL * MDIM];
__device__ __align__(1024) __nv_bfloat16 g_Lhi[(size_t)MDIM * MDIM];
__device__ __align__(1024) __nv_bfloat16 g_Llo[(size_t)MDIM * MDIM];
// m-major copy for MLP A operand: tmT[b][m][wpad], w contiguous, zero-padded to 192
__device__ __align__(1024) __nv_bfloat16 g_tmThi[(size_t)BATCH * MDIM * KWPAD];
__device__ __align__(1024) __nv_bfloat16 g_tmTlo[(size_t)BATCH * MDIM * KWPAD];
// W1 split, zero-padded K: [hop][128][192]
__device__ __align__(1024) __nv_bfloat16 g_W1hi[(NHOPS + 1) * HIDD * KWPAD];
__device__ __align__(1024) __nv_bfloat16 g_W1lo[(NHOPS + 1) * HIDD * KWPAD];

// ======================= common helpers =======================
__device__ __forceinline__ uint32_t smem_u32(const void* p) {
    uint32_t a;
    asm("{ .reg .u64 t; cvta.to.shared.u64 t, %1; cvt.u32.u64 %0, t; }" : "=r"(a) : "l"(p));
    return a;
}

// ======================= splits =======================
__global__ void split_kernel(const float* __restrict__ in, __nv_bfloat16* __restrict__ hi,
                             __nv_bfloat16* __restrict__ lo, int n4) {
    int i = blockIdx.x * blockDim.x + threadIdx.x;
    if (i >= n4) return;
    float4 v = ((const float4*)in)[i];
    __nv_bfloat16 h[4], l[4];
    float vv[4] = {v.x, v.y, v.z, v.w};
    #pragma unroll
    for (int j = 0; j < 4; j++) {
        h[j] = __float2bfloat16(vv[j]);
        l[j] = __float2bfloat16(vv[j] - __bfloat162float(h[j]));
    }
    ((ushort4*)hi)[i] = make_ushort4(*(unsigned short*)&h[0], *(unsigned short*)&h[1],
                                     *(unsigned short*)&h[2], *(unsigned short*)&h[3]);
    ((ushort4*)lo)[i] = make_ushort4(*(unsigned short*)&l[0], *(unsigned short*)&l[1],
                                     *(unsigned short*)&l[2], *(unsigned short*)&l[3]);
}

__global__ void splitW1_kernel(const float* __restrict__ W1, __nv_bfloat16* __restrict__ hi,
                               __nv_bfloat16* __restrict__ lo) {
    int i = blockIdx.x * blockDim.x + threadIdx.x;
    if (i >= (NHOPS + 1) * HIDD * KWPAD) return;
    int w = i % KWPAD;
    int hh = i / KWPAD;
    float v = (w < WDIM) ? W1[hh * WDIM + w] : 0.f;
    __nv_bfloat16 h = __float2bfloat16(v);
    hi[i] = h;
    lo[i] = __float2bfloat16(v - __bfloat162float(h));
}

// fused prologue: x[b][w][m] -> hi0/lo0 [n=b*W+w][m] AND tmT[b][m][wpad] (w>=168 zero)
__global__ void prep_kernel(const float* __restrict__ x,
                            __nv_bfloat16* __restrict__ hi0,
                            __nv_bfloat16* __restrict__ lo0,
                            __nv_bfloat16* __restrict__ thi,
                            __nv_bfloat16* __restrict__ tlo) {
    __shared__ __nv_bfloat16 th[32][33], tl[32][33];
    int m0 = blockIdx.x * 32, w0 = blockIdx.y * 32, b = blockIdx.z;
    int tx = threadIdx.x, ty = threadIdx.y;
    #pragma unroll
    for (int i = ty; i < 32; i += 8) {
        int w = w0 + i;
        float v = (w < WDIM) ? x[((size_t)b * WDIM + w) * MDIM + m0 + tx] : 0.f;
        __nv_bfloat16 h = __float2bfloat16(v);
        __nv_bfloat16 l = __float2bfloat16(v - __bfloat162float(h));
        th[i][tx] = h;
        tl[i][tx] = l;
        if (w < WDIM) {
            size_t gi = ((size_t)b * WDIM + w) * MDIM + m0 + tx;
            hi0[gi] = h;
            lo0[gi] = l;
        }
    }
    __syncthreads();
    #pragma unroll
    for (int i = ty; i < 32; i += 8) {
        size_t idx = ((size_t)b * MDIM + m0 + i) * KWPAD + w0 + tx;
        thi[idx] = th[tx][i];
        tlo[idx] = tl[tx][i];
    }
}

// ======================= tcgen05 macros ('a' targets only) =======================
#if HAS_TC
__device__ __forceinline__ uint32_t elect_one() {
    uint32_t p;
    asm volatile("{ .reg .pred p; elect.sync _|p, 0xFFFFFFFF; selp.b32 %0, 1, 0, p; }" : "=r"(p));
    return p;
}
#define MBAR_INIT(a, c) asm volatile("mbarrier.init.shared.b64 [%0], %1;" :: "r"(a), "r"(c) : "memory")
#define MBAR_EXPECT_TX(a, b) asm volatile("mbarrier.arrive.expect_tx.shared.b64 _, [%0], %1;" :: "r"(a), "r"(b) : "memory")
#define MBAR_WAIT(a, ph) do { \
    uint32_t _m = (a), _p = (ph), _d; \
    asm volatile("{ .reg .pred p; mbarrier.try_wait.parity.acquire.cta.shared::cta.b64 p, [%1], %2; selp.b32 %0,1,0,p; }" \
        : "=r"(_d) : "r"(_m), "r"(_p) : "memory"); \
    if (!_d) { asm volatile("{ .reg .pred P1; WL%=: mbarrier.try_wait.parity.acquire.cta.shared::cta.b64 P1, [%0], %1, 0x989680; @P1 bra.uni WD%=; bra.uni WL%=; WD%=: }" \
        :: "r"(_m), "r"(_p) : "memory"); } \
} while (0)
#define MBAR_ARRIVE_RANK0(a) \
    asm volatile("{ .reg .b32 ra; mapa.shared::cluster.u32 ra, %0, 0; mbarrier.arrive.shared::cluster.b64 _, [ra]; }" \
        :: "r"(a) : "memory")
#define TMA_2D(sm, map, cx, cy, mb) \
    asm volatile("cp.async.bulk.tensor.2d.shared::cta.global.tile.mbarrier::complete_tx::bytes [%0], [%1, {%2, %3}], [%4];" \
        :: "r"(sm), "l"(map), "r"(cx), "r"(cy), "r"(mb) : "memory")
#define TMA_2D_CG2(sm, map, cx, cy, mb) \
    asm volatile("{ .reg .b32 lb; and.b32 lb, %4, 0xFEFFFFFF;\n\t" \
        "cp.async.bulk.tensor.2d.cta_group::2.shared::cluster.global.tile.mbarrier::complete_tx::bytes " \
        "[%0], [%1, {%2, %3}], [lb]; }" \
        :: "r"(sm), "l"(map), "r"(cx), "r"(cy), "r"(mb) : "memory")
#define TC_ALLOC(smaddr, n)      asm volatile("tcgen05.alloc.cta_group::1.sync.aligned.shared::cta.b32 [%0], %1;" :: "r"(smaddr), "r"(n) : "memory")
#define TC_RELINQ()              asm volatile("tcgen05.relinquish_alloc_permit.cta_group::1.sync.aligned;")
#define TC_DEALLOC(t, n)         asm volatile("tcgen05.dealloc.cta_group::1.sync.aligned.b32 %0, %1;" :: "r"(t), "r"(n))
#define TC_COMMIT(mb)            asm volatile("tcgen05.commit.cta_group::1.mbarrier::arrive::one.shared::cluster.b64 [%0];" :: "r"(mb) : "memory")
#define TC_ALLOC_CG2(smaddr, n)  asm volatile("tcgen05.alloc.cta_group::2.sync.aligned.shared::cta.b32 [%0], %1;" :: "r"(smaddr), "r"(n) : "memory")
#define TC_RELINQ_CG2()          asm volatile("tcgen05.relinquish_alloc_permit.cta_group::2.sync.aligned;")
#define TC_DEALLOC_CG2(t, n)     asm volatile("tcgen05.dealloc.cta_group::2.sync.aligned.b32 %0, %1;" :: "r"(t), "r"(n))
#define TC_COMMIT_MC2(mb) \
    asm volatile("tcgen05.commit.cta_group::2.mbarrier::arrive::one.shared::cluster.multicast::cluster.b64 [%0], %1;" \
        :: "r"(mb), "h"((unsigned short)0x3) : "memory")
#define TC_FENCE_AFTER()      asm volatile("tcgen05.fence::after_thread_sync;" ::: "memory")
#define TC_FENCE_BEFORE()     asm volatile("tcgen05.fence::before_thread_sync;" ::: "memory")
#define TC_WAIT_LD()          asm volatile("tcgen05.wait::ld.sync.aligned;" ::: "memory")
#define TC_LD_X32(r, addr) \
    asm volatile("tcgen05.ld.sync.aligned.32x32b.x32.b32 " \
        "{%0,%1,%2,%3,%4,%5,%6,%7,%8,%9,%10,%11,%12,%13,%14,%15," \
        "%16,%17,%18,%19,%20,%21,%22,%23,%24,%25,%26,%27,%28,%29,%30,%31}, [%32];" \
        : "=r"((r)[0]),"=r"((r)[1]),"=r"((r)[2]),"=r"((r)[3]),"=r"((r)[4]),"=r"((r)[5]),"=r"((r)[6]),"=r"((r)[7]), \
          "=r"((r)[8]),"=r"((r)[9]),"=r"((r)[10]),"=r"((r)[11]),"=r"((r)[12]),"=r"((r)[13]),"=r"((r)[14]),"=r"((r)[15]), \
          "=r"((r)[16]),"=r"((r)[17]),"=r"((r)[18]),"=r"((r)[19]),"=r"((r)[20]),"=r"((r)[21]),"=r"((r)[22]),"=r"((r)[23]), \
          "=r"((r)[24]),"=r"((r)[25]),"=r"((r)[26]),"=r"((r)[27]),"=r"((r)[28]),"=r"((r)[29]),"=r"((r)[30]),"=r"((r)[31]) \
        : "r"(addr))
#define CLUSTER_SYNC() do { \
    asm volatile("barrier.cluster.arrive.aligned;" ::: "memory"); \
    asm volatile("barrier.cluster.wait.aligned;" ::: "memory"); \
} while (0)

static constexpr uint64_t DESC_SW128 =
    (uint64_t(2) << 61) | (uint64_t(1) << 46) | (uint64_t(64) << 32) | (uint64_t(1) << 16);
__device__ __forceinline__ uint64_t mk_desc(uint32_t sm) {
    return DESC_SW128 | ((uint64_t)(sm >> 4) & 0x3FFF);
}
// kind::f16, D=F32, A=BF16, B=BF16, M=256 (cg2): N=256 / N=128 variants
#define IDESC_CG2_N256 0x10400490u
#define IDESC_CG2_N128 0x10200490u
__device__ __forceinline__ void mma_cg2(uint32_t d, uint64_t a, uint64_t b,
                                        uint32_t idesc, uint32_t en) {
    asm volatile("{ .reg .pred p; setp.ne.u32 p, %5, 0;\n\t"
        "tcgen05.mma.cta_group::2.kind::f16 [%0], %1, %2, %3, {%4,%4,%4,%4,%4,%4,%4,%4}, p; }"
        :: "r"(d), "l"(a), "l"(b), "r"(idesc), "r"(0u), "r"(en) : "memory");
}
// kind::f16, D=F32, A=BF16 K-major, B=BF16 K-major, M=128, N=128 (cg1)
#define IDESC_M128N128 0x8200490u
__device__ __forceinline__ void mma_128(uint32_t d, uint64_t a, uint64_t b, uint32_t en) {
    asm volatile("{ .reg .pred p; setp.ne.u32 p, %5, 0;\n\t"
        "tcgen05.mma.cta_group::1.kind::f16 [%0], %1, %2, %3, {%4,%4,%4,%4}, p; }"
        :: "r"(d), "l"(a), "l"(b), "r"(IDESC_M128N128), "r"(0u), "r"(en) : "memory");
}
#endif // HAS_TC

// ======================= persistent cg2 propagation GEMM =======================
#define KCHUNK 64
#define NCHUNK 32                  // K chunks per unit (K = 2048)
#define NSTAGE 3
#define NPAIRS 74
#define SM_TMEMPTR 0
#define SM_FULL(s)  (16 + (s) * 8)
#define SM_EMPTY(s) (48 + (s) * 8)
#define SM_MDONE(t) (80 + (t) * 8)
#define SM_EPID(t)  (96 + (t) * 8)
#define STAGE_CTA 65536
#define SM_STAGE(s) (1024 + (s) * STAGE_CTA)
#define A_HI(s) (SM_STAGE(s))
#define A_LO(s) (SM_STAGE(s) + 16384)
#define B_HI(s) (SM_STAGE(s) + 32768)
#define B_LO(s) (SM_STAGE(s) + 49152)
#define EPI_PITCH 136
#define EPI_BYTES (32 * EPI_PITCH * 2)          // 8704
#define EPI_HI (1024 + NSTAGE * STAGE_CTA)
#define EPI_LO (EPI_HI + EPI_BYTES)
#define TC_SMEM (EPI_LO + EPI_BYTES)            // 215040

// balanced schedule: units 0,1 = full tiles (pair, pair+74); unit 2 (pairs<40)
// = half tile: tile 148+(pair>>1), n-offset (pair&1)*128, N=128.
#if HAS_TC
__device__ __forceinline__ void unit_params(int pair, int u, int& mt, int& nt,
                                            int& noff, int& nlen) {
    int t = (u == 0) ? pair : ((u == 1) ? pair + NPAIRS : 148 + (pair >> 1));
    mt = t & 7;
    nt = t >> 3;
    noff = (u < 2) ? 0 : ((pair & 1) * 128);
    nlen = (u < 2) ? 256 : 128;
}
#endif

__global__ __launch_bounds__(192, 1) __cluster_dims__(2, 1, 1) void gemm_tc(
    const __grid_constant__ CUtensorMap mapAhi,
    const __grid_constant__ CUtensorMap mapAlo,
    const __grid_constant__ CUtensorMap mapBhi,     // box 64 x 128 rows
    const __grid_constant__ CUtensorMap mapBlo,
    const __grid_constant__ CUtensorMap mapBhi64,   // box 64 x 64 rows
    const __grid_constant__ CUtensorMap mapBlo64,
    __nv_bfloat16* __restrict__ dst_hi,
    __nv_bfloat16* __restrict__ dst_lo,
    __nv_bfloat16* __restrict__ tmT_hi,
    __nv_bfloat16* __restrict__ tmT_lo,
    int write_nm)
{
#if HAS_TC
    extern __shared__ char smem[];
    uint32_t smb = smem_u32(smem);
    int tid = threadIdx.x, wid = tid >> 5, lane = tid & 31;
    uint32_t rank;
    asm("mov.u32 %0, %%cluster_ctarank;" : "=r"(rank));
    int pair = blockIdx.x >> 1;
    int my_units = 2 + (pair < 40 ? 1 : 0);
    int total = my_units * NCHUNK;

    if (wid == 4) { TC_ALLOC_CG2(smb + SM_TMEMPTR, 512); TC_RELINQ_CG2(); }
    if (tid == 0) {
        #pragma unroll
        for (int s = 0; s < NSTAGE; s++) {
            MBAR_INIT(smb + SM_FULL(s), 1);
            MBAR_INIT(smb + SM_EMPTY(s), 1);
        }
        MBAR_INIT(smb + SM_MDONE(0), 1);
        MBAR_INIT(smb + SM_MDONE(1), 1);
        MBAR_INIT(smb + SM_EPID(0), 2);
        MBAR_INIT(smb + SM_EPID(1), 2);
    }
    __syncthreads();
    CLUSTER_SYNC();

    uint32_t tmem;
    asm volatile("ld.shared.b32 %0, [%1];" : "=r"(tmem) : "r"(smb + SM_TMEMPTR));

    if (wid == 4) {
        // ---------------- TMA producer warp (both ranks) ----------------
        uint32_t e1 = elect_one();
        uint32_t pe[NSTAGE] = {0, 0, 0};
        if (e1) {
            int s = 0;
            for (int g = 0; g < total; g++) {
                if (g >= NSTAGE) { MBAR_WAIT(smb + SM_EMPTY(s), pe[s]); pe[s] ^= 1; }
                int u = g >> 5, c = g & 31;
                int mt, nt, noff, nlen;
                unit_params(pair, u, mt, nt, noff, nlen);
                int k0 = c * KCHUNK;
                int ma = mt * 256 + (int)rank * 128;
                int nb = nt * 256 + noff + (int)rank * (nlen >> 1);
                if (rank == 0) {
                    uint32_t tx = 65536u + (uint32_t)nlen * 256u;
                    MBAR_EXPECT_TX(smb + SM_FULL(s), tx);
                }
                TMA_2D_CG2(smb + A_HI(s), &mapAhi, k0, ma, smb + SM_FULL(s));
                TMA_2D_CG2(smb + A_LO(s), &mapAlo, k0, ma, smb + SM_FULL(s));
                if (nlen == 256) {
                    TMA_2D_CG2(smb + B_HI(s), &mapBhi, k0, nb, smb + SM_FULL(s));
                    TMA_2D_CG2(smb + B_LO(s), &mapBlo, k0, nb, smb + SM_FULL(s));
                } else {
                    TMA_2D_CG2(smb + B_HI(s), &mapBhi64, k0, nb, smb + SM_FULL(s));
                    TMA_2D_CG2(smb + B_LO(s), &mapBlo64, k0, nb, smb + SM_FULL(s));
                }
                if (++s == NSTAGE) s = 0;
            }
        }
    } else if (wid == 5) {
        // ---------------- MMA consumer warp (rank 0 only) ----------------
        if (rank == 0) {
            uint32_t e1 = elect_one();
            uint32_t pf[NSTAGE] = {0, 0, 0}, ped[2] = {0, 0};
            int s = 0;
            for (int g = 0; g < total; g++) {
                int c = g & 31, u = g >> 5, slot = u & 1;
                int mt, nt, noff, nlen;
                unit_params(pair, u, mt, nt, noff, nlen);
                uint32_t idesc = (nlen == 256) ? IDESC_CG2_N256 : IDESC_CG2_N128;
                if (c == 0 && u >= 2) {      // D-slot reuse gated on both epilogues
                    MBAR_WAIT(smb + SM_EPID(slot), ped[slot]); ped[slot] ^= 1;
                }
                MBAR_WAIT(smb + SM_FULL(s), pf[s]); pf[s] ^= 1;
                if (e1) {
                    uint64_t ah = mk_desc(smb + A_HI(s));
                    uint64_t al = mk_desc(smb + A_LO(s));
                    uint64_t bh = mk_desc(smb + B_HI(s));
                    uint64_t bl = mk_desc(smb + B_LO(s));
                    uint32_t dt = tmem + slot * 256;
                    #pragma unroll
                    for (int ks = 0; ks < 4; ks++)
                        mma_cg2(dt, ah + ks * 2, bh + ks * 2, idesc, (c == 0 && ks == 0) ? 0u : 1u);
                    #pragma unroll
                    for (int ks = 0; ks < 4; ks++)
                        mma_cg2(dt, ah + ks * 2, bl + ks * 2, idesc, 1u);
                    #pragma unroll
                    for (int ks = 0; ks < 4; ks++)
                        mma_cg2(dt, al + ks * 2, bh + ks * 2, idesc, 1u);
                    TC_COMMIT_MC2(smb + SM_EMPTY(s));
                    if (c == NCHUNK - 1) TC_COMMIT_MC2(smb + SM_MDONE(slot));
                }
                if (++s == NSTAGE) s = 0;
            }
        }
    } else {
        // ---------------- epilogue warps 0..3 (128 threads) ----------------
        uint32_t pm[2] = {0, 0};
        __nv_bfloat16* shi = (__nv_bfloat16*)(smem + EPI_HI);
        __nv_bfloat16* slo = (__nv_bfloat16*)(smem + EPI_LO);
        int mloc = wid * 32 + lane;
        for (int u = 0; u < my_units; u++) {
            int slot = u & 1;
            int mt, nt, noff, nlen;
            unit_params(pair, u, mt, nt, noff, nlen);
            int mg = mt * 256 + (int)rank * 128;
            int ng = nt * 256 + noff;
            int blkcnt = nlen >> 5;
            MBAR_WAIT(smb + SM_MDONE(slot), pm[slot]); pm[slot] ^= 1;
            TC_FENCE_AFTER();
            #pragma unroll 1
            for (int blk = 0; blk < blkcnt; blk++) {
                uint32_t r[32];
                TC_LD_X32(r, tmem + slot * 256 + blk * 32);
                TC_WAIT_LD();
                #pragma unroll
                for (int j = 0; j < 32; j++) {
                    float v = __uint_as_float(r[j]);
                    __nv_bfloat16 h = __float2bfloat16(v);
                    __nv_bfloat16 l = __float2bfloat16(v - __bfloat162float(h));
                    shi[j * EPI_PITCH + mloc] = h;
                    slo[j * EPI_PITCH + mloc] = l;
                }
                asm volatile("bar.sync 1, 128;" ::: "memory");
                // pass 1: [n][m] orientation for next hop's GEMM B
                if (write_nm) {
                    #pragma unroll
                    for (int idx = tid; idx < 512; idx += 128) {
                        int nl = idx >> 4;
                        int m8 = (idx & 15) * 8;
                        size_t ga = (size_t)(ng + blk * 32 + nl) * MDIM + mg + m8;
                        *(uint4*)(dst_hi + ga) = *(uint4*)(shi + nl * EPI_PITCH + m8);
                        *(uint4*)(dst_lo + ga) = *(uint4*)(slo + nl * EPI_PITCH + m8);
                    }
                }
                // pass 2: m-major tmT[b][m][w] for the MLP A operand (168 % 8 == 0)
                {
                    int mrow = mg + tid;
                    #pragma unroll
                    for (int j8 = 0; j8 < 32; j8 += 8) {
                        int n0 = ng + blk * 32 + j8;
                        int bb = n0 / WDIM;
                        int w = n0 - bb * WDIM;
                        uint4 uh, ul;
                        unsigned short* ph = (unsigned short*)&uh;
                        unsigned short* pl = (unsigned short*)&ul;
                        #pragma unroll
                        for (int q = 0; q < 8; q++) {
                            ph[q] = *(unsigned short*)&shi[(j8 + q) * EPI_PITCH + tid];
                            pl[q] = *(unsigned short*)&slo[(j8 + q) * EPI_PITCH + tid];
                        }
                        size_t base = ((size_t)bb * MDIM + mrow) * KWPAD + w;
                        *(uint4*)(tmT_hi + base) = uh;
                        *(uint4*)(tmT_lo + base) = ul;
                    }
                }
                asm volatile("bar.sync 1, 128;" ::: "memory");
            }
            TC_FENCE_BEFORE();
            if (tid == 0) MBAR_ARRIVE_RANK0(smb + SM_EPID(slot));
        }
    }
    __syncthreads();
    if (wid == 4) TC_DEALLOC_CG2(tmem, 512);
    CLUSTER_SYNC();
#endif
}

// ======================= tensor-core fused MLP (all K-major SS) =======================
#define MLF(s)    (16 + (s) * 8)
#define MLDONE    48
#define MLST(s)   (1024 + (s) * 65536)
#define MLA_HI(s) (MLST(s))
#define MLA_LO(s) (MLST(s) + 16384)
#define MLB_HI(s) (MLST(s) + 32768)
#define MLB_LO(s) (MLST(s) + 49152)
#define MLP_SMEM (1024 + 3 * 65536)   // 197632

__global__ __launch_bounds__(160, 1) void mlp_tc(
    const __grid_constant__ CUtensorMap mapAhi,   // tmT hi: [32*2048 rows][192]
    const __grid_constant__ CUtensorMap mapAlo,
    const __grid_constant__ CUtensorMap mapBhi,   // W1 hi: [(NHOPS+1)*128 rows][192]
    const __grid_constant__ CUtensorMap mapBlo,
    const float* __restrict__ b1,
    const float* __restrict__ W2,
    const float* __restrict__ b2,
    int hop, int accum,
    float* __restrict__ out)
{
#if HAS_TC
    extern __shared__ char smem[];
    uint32_t smb = smem_u32(smem);
    int tid = threadIdx.x, wid = tid >> 5, lane = tid & 31;
    int b = blockIdx.x >> 4;
    int mt = blockIdx.x & 15;
    int arow = b * MDIM + mt * 128;
    int brow = hop * HIDD;

    if (wid == 4) { TC_ALLOC(smb + SM_TMEMPTR, 128); TC_RELINQ(); }
    if (tid == 0) {
        MBAR_INIT(smb + MLF(0), 1);
        MBAR_INIT(smb + MLF(1), 1);
        MBAR_INIT(smb + MLF(2), 1);
        MBAR_INIT(smb + MLDONE, 1);
    }
    __syncthreads();
    uint32_t tmem;
    asm volatile("ld.shared.b32 %0, [%1];" : "=r"(tmem) : "r"(smb + SM_TMEMPTR));

    if (wid == 4) {
        uint32_t e1 = elect_one();
        if (e1) {
            #pragma unroll
            for (int s = 0; s < 3; s++) {
                MBAR_EXPECT_TX(smb + MLF(s), 65536);
                int k0 = s * 64;
                TMA_2D(smb + MLA_HI(s), &mapAhi, k0, arow, smb + MLF(s));
                TMA_2D(smb + MLA_LO(s), &mapAlo, k0, arow, smb + MLF(s));
                TMA_2D(smb + MLB_HI(s), &mapBhi, k0, brow, smb + MLF(s));
                TMA_2D(smb + MLB_LO(s), &mapBlo, k0, brow, smb + MLF(s));
            }
        }
        #pragma unroll 1
        for (int s = 0; s < 3; s++) {
            MBAR_WAIT(smb + MLF(s), 0);
            if (e1) {
                uint64_t ad[2] = {mk_desc(smb + MLA_HI(s)), mk_desc(smb + MLA_LO(s))};
                uint64_t bd[2] = {mk_desc(smb + MLB_HI(s)), mk_desc(smb + MLB_LO(s))};
                int ta[3] = {0, 0, 1}, tb[3] = {0, 1, 0};
                #pragma unroll
                for (int t = 0; t < 3; t++)
                    #pragma unroll
                    for (int ks = 0; ks < 4; ks++)
                        mma_128(tmem, ad[ta[t]] + ks * 2, bd[tb[t]] + ks * 2,
                                (s == 0 && t == 0 && ks == 0) ? 0u : 1u);
            }
        }
        if (e1) TC_COMMIT(smb + MLDONE);
    } else {
        MBAR_WAIT(smb + MLDONE, 0);
        TC_FENCE_AFTER();
        const float* b1h = b1 + hop * HIDD;
        const float* W2h = W2 + hop * HIDD;
        float s = 0.f;
        #pragma unroll 1
        for (int cb = 0; cb < 4; cb++) {
            uint32_t r[32];
            TC_LD_X32(r, tmem + cb * 32);
            TC_WAIT_LD();
            #pragma unroll
            for (int j = 0; j < 32; j++) {
                int h = cb * 32 + j;
                s += W2h[h] * fmaxf(__uint_as_float(r[j]) + b1h[h], 0.f);
            }
        }
        TC_FENCE_BEFORE();
        s += b2[hop];
        int gi = b * MDIM + mt * 128 + wid * 32 + lane;
        if (accum) s += out[gi];
        out[gi] = s;
    }
    __syncthreads();
    if (wid == 4) TC_DEALLOC(tmem, 128);
#endif
}

// ======================= host =======================
typedef CUresult (*PFN_tmEncode)(CUtensorMap*, CUtensorMapDataType, cuuint32_t, void*,
                                 const cuuint64_t*, const cuuint64_t*, const cuuint32_t*,
                                 const cuuint32_t*, CUtensorMapInterleave, CUtensorMapSwizzle,
                                 CUtensorMapL2promotion, CUtensorMapFloatOOBfill);

static void make_map(PFN_tmEncode enc, CUtensorMap* m, void* ptr,
                     unsigned long long d0, unsigned long long d1,
                     unsigned box0, unsigned box1) {
    cuuint64_t dims[2] = {d0, d1};
    cuuint64_t strides[1] = {d0 * 2};
    cuuint32_t box[2] = {box0, box1};
    cuuint32_t es[2] = {1, 1};
    enc(m, CU_TENSOR_MAP_DATA_TYPE_BFLOAT16, 2, ptr, dims, strides, box, es,
        CU_TENSOR_MAP_INTERLEAVE_NONE, CU_TENSOR_MAP_SWIZZLE_128B,
        CU_TENSOR_MAP_L2_PROMOTION_L2_128B, CU_TENSOR_MAP_FLOAT_OOB_FILL_NONE);
}

extern "C" void kernel_launch(void* const* d_in, const int* in_sizes, int n_in,
                              void* d_out, int out_size) {
    const float* x  = (const float*)d_in[0];
    const float* L  = (const float*)d_in[1];
    const float* W1 = (const float*)d_in[2];
    const float* b1 = (const float*)d_in[3];
    const float* W2 = (const float*)d_in[4];
    const float* b2 = (const float*)d_in[5];
    float* out = (float*)d_out;

    __nv_bfloat16 *hi0, *hi1, *lo0, *lo1, *Lhi, *Llo, *W1hi, *W1lo, *tmThi, *tmTlo;
    cudaGetSymbolAddress((void**)&hi0, g_hi);
    hi1 = hi0 + (size_t)BWCOL * MDIM;
    cudaGetSymbolAddress((void**)&lo0, g_lo);
    lo1 = lo0 + (size_t)BWCOL * MDIM;
    cudaGetSymbolAddress((void**)&Lhi, g_Lhi);
    cudaGetSymbolAddress((void**)&Llo, g_Llo);
    cudaGetSymbolAddress((void**)&W1hi, g_W1hi);
    cudaGetSymbolAddress((void**)&W1lo, g_W1lo);
    cudaGetSymbolAddress((void**)&tmThi, g_tmThi);
    cudaGetSymbolAddress((void**)&tmTlo, g_tmTlo);

    PFN_tmEncode enc = nullptr;
    cudaDriverEntryPointQueryResult qr;
    cudaGetDriverEntryPointByVersion("cuTensorMapEncodeTiled", (void**)&enc, 12000,
                                     cudaEnableDefault, &qr);

    CUtensorMap mAhi, mAlo, mBhi[2], mBlo[2], mBhi64[2], mBlo64[2];
    CUtensorMap mW1hi, mW1lo, mTmhi, mTmlo;
    make_map(enc, &mAhi, Lhi, MDIM, MDIM, 64, 128);
    make_map(enc, &mAlo, Llo, MDIM, MDIM, 64, 128);
    make_map(enc, &mBhi[0], hi0, MDIM, BWCOL, 64, 128);
    make_map(enc, &mBhi[1], hi1, MDIM, BWCOL, 64, 128);
    make_map(enc, &mBlo[0], lo0, MDIM, BWCOL, 64, 128);
    make_map(enc, &mBlo[1], lo1, MDIM, BWCOL, 64, 128);
    make_map(enc, &mBhi64[0], hi0, MDIM, BWCOL, 64, 64);
    make_map(enc, &mBhi64[1], hi1, MDIM, BWCOL, 64, 64);
    make_map(enc, &mBlo64[0], lo0, MDIM, BWCOL, 64, 64);
    make_map(enc, &mBlo64[1], lo1, MDIM, BWCOL, 64, 64);
    make_map(enc, &mW1hi, W1hi, KWPAD, (NHOPS + 1) * HIDD, 64, 128);
    make_map(enc, &mW1lo, W1lo, KWPAD, (NHOPS + 1) * HIDD, 64, 128);
    make_map(enc, &mTmhi, tmThi, KWPAD, (unsigned long long)BATCH * MDIM, 64, 128);
    make_map(enc, &mTmlo, tmTlo, KWPAD, (unsigned long long)BATCH * MDIM, 64, 128);

    cudaFuncSetAttribute(gemm_tc, cudaFuncAttributeMaxDynamicSharedMemorySize, TC_SMEM);
    cudaFuncSetAttribute(mlp_tc, cudaFuncAttributeMaxDynamicSharedMemorySize, MLP_SMEM);

    {
        dim3 tg(MDIM / 32, KWPAD / 32, BATCH), tb(32, 8);
        prep_kernel<<<tg, tb>>>(x, hi0, lo0, tmThi, tmTlo);
        int n4 = (MDIM * MDIM) / 4;
        split_kernel<<<(n4 + 255) / 256, 256>>>(L, Lhi, Llo, n4);
        int nw = (NHOPS + 1) * HIDD * KWPAD;
        splitW1_kernel<<<(nw + 255) / 256, 256>>>(W1, W1hi, W1lo);
    }

    mlp_tc<<<BATCH * 16, 160, MLP_SMEM>>>(mTmhi, mTmlo, mW1hi, mW1lo,
                                          b1, W2, b2, 0, 0, out);

    for (int hop = 1; hop <= NHOPS; hop++) {
        int src = (hop + 1) & 1;
        int dst = hop & 1;
        gemm_tc<<<2 * NPAIRS, 192, TC_SMEM>>>(mAhi, mAlo, mBhi[src], mBlo[src],
                                              mBhi64[src], mBlo64[src],
                                              dst ? hi1 : hi0, dst ? lo1 : lo0,
                                              tmThi, tmTlo, hop < NHOPS ? 1 : 0);
        mlp_tc<<<BATCH * 16, 160, MLP_SMEM>>>(mTmhi, mTmlo, mW1hi, mW1lo,
                                              b1, W2, b2, hop, 1, out);
    }
}

// round 11
// speedup vs baseline: 8.9896x; 1.0592x over previous
#include <cuda_runtime.h>
#include <cuda_bf16.h>
#include <cuda.h>
#include <cstdint>

#define BATCH 32
#define WDIM  168
#define MDIM  2048
#define HIDD  128
#define NHOPS 6
#define BWCOL (BATCH * WDIM)   // 5376
#define KWPAD 192

#if defined(__CUDA_ARCH__) && defined(__CUDA_ARCH_FEAT_SM103_ALL)
#define HAS_TC 1
#else
#define HAS_TC 0
#endif

// t stored TRANSPOSED: T[n][m], m contiguous (GEMM B operand). Split bf16 hi/lo.
__device__ __align__(1024) __nv_bfloat16 g_hi[2][(size_t)BWCOL * MDIM];
__device__ __align__(1024) __nv_bfloat16 g_lo[2][(size_t)BWCOL * MDIM];
__device__ __align__(1024) __nv_bfloat16 g_Lhi[(size_t)MDIM * MDIM];
__device__ __align__(1024) __nv_bfloat16 g_Llo[(size_t)MDIM * MDIM];
// m-major copy for MLP A operand: tmT[b][m][wpad], w contiguous, zero-padded to 192
__device__ __align__(1024) __nv_bfloat16 g_tmThi[(size_t)BATCH * MDIM * KWPAD];
__device__ __align__(1024) __nv_bfloat16 g_tmTlo[(size_t)BATCH * MDIM * KWPAD];
// W1 split, zero-padded K: [hop][128][192]
__device__ __align__(1024) __nv_bfloat16 g_W1hi[(NHOPS + 1) * HIDD * KWPAD];
__device__ __align__(1024) __nv_bfloat16 g_W1lo[(NHOPS + 1) * HIDD * KWPAD];

// ======================= common helpers =======================
__device__ __forceinline__ uint32_t smem_u32(const void* p) {
    uint32_t a;
    asm("{ .reg .u64 t; cvta.to.shared.u64 t, %1; cvt.u32.u64 %0, t; }" : "=r"(a) : "l"(p));
    return a;
}

// ======================= splits =======================
__global__ void split_kernel(const float* __restrict__ in, __nv_bfloat16* __restrict__ hi,
                             __nv_bfloat16* __restrict__ lo, int n4) {
    int i = blockIdx.x * blockDim.x + threadIdx.x;
    if (i >= n4) return;
    float4 v = ((const float4*)in)[i];
    __nv_bfloat16 h[4], l[4];
    float vv[4] = {v.x, v.y, v.z, v.w};
    #pragma unroll
    for (int j = 0; j < 4; j++) {
        h[j] = __float2bfloat16(vv[j]);
        l[j] = __float2bfloat16(vv[j] - __bfloat162float(h[j]));
    }
    ((ushort4*)hi)[i] = make_ushort4(*(unsigned short*)&h[0], *(unsigned short*)&h[1],
                                     *(unsigned short*)&h[2], *(unsigned short*)&h[3]);
    ((ushort4*)lo)[i] = make_ushort4(*(unsigned short*)&l[0], *(unsigned short*)&l[1],
                                     *(unsigned short*)&l[2], *(unsigned short*)&l[3]);
}

__global__ void splitW1_kernel(const float* __restrict__ W1, __nv_bfloat16* __restrict__ hi,
                               __nv_bfloat16* __restrict__ lo) {
    int i = blockIdx.x * blockDim.x + threadIdx.x;
    if (i >= (NHOPS + 1) * HIDD * KWPAD) return;
    int w = i % KWPAD;
    int hh = i / KWPAD;
    float v = (w < WDIM) ? W1[hh * WDIM + w] : 0.f;
    __nv_bfloat16 h = __float2bfloat16(v);
    hi[i] = h;
    lo[i] = __float2bfloat16(v - __bfloat162float(h));
}

// fused prologue: x[b][w][m] -> hi0/lo0 [n=b*W+w][m] AND tmT[b][m][wpad] (w>=168 zero)
__global__ void prep_kernel(const float* __restrict__ x,
                            __nv_bfloat16* __restrict__ hi0,
                            __nv_bfloat16* __restrict__ lo0,
                            __nv_bfloat16* __restrict__ thi,
                            __nv_bfloat16* __restrict__ tlo) {
    __shared__ __nv_bfloat16 th[32][33], tl[32][33];
    int m0 = blockIdx.x * 32, w0 = blockIdx.y * 32, b = blockIdx.z;
    int tx = threadIdx.x, ty = threadIdx.y;
    #pragma unroll
    for (int i = ty; i < 32; i += 8) {
        int w = w0 + i;
        float v = (w < WDIM) ? x[((size_t)b * WDIM + w) * MDIM + m0 + tx] : 0.f;
        __nv_bfloat16 h = __float2bfloat16(v);
        __nv_bfloat16 l = __float2bfloat16(v - __bfloat162float(h));
        th[i][tx] = h;
        tl[i][tx] = l;
        if (w < WDIM) {
            size_t gi = ((size_t)b * WDIM + w) * MDIM + m0 + tx;
            hi0[gi] = h;
            lo0[gi] = l;
        }
    }
    __syncthreads();
    #pragma unroll
    for (int i = ty; i < 32; i += 8) {
        size_t idx = ((size_t)b * MDIM + m0 + i) * KWPAD + w0 + tx;
        thi[idx] = th[tx][i];
        tlo[idx] = tl[tx][i];
    }
}

// ======================= tcgen05 macros ('a' targets only) =======================
#if HAS_TC
__device__ __forceinline__ uint32_t elect_one() {
    uint32_t p;
    asm volatile("{ .reg .pred p; elect.sync _|p, 0xFFFFFFFF; selp.b32 %0, 1, 0, p; }" : "=r"(p));
    return p;
}
#define MBAR_INIT(a, c) asm volatile("mbarrier.init.shared.b64 [%0], %1;" :: "r"(a), "r"(c) : "memory")
#define MBAR_EXPECT_TX(a, b) asm volatile("mbarrier.arrive.expect_tx.shared.b64 _, [%0], %1;" :: "r"(a), "r"(b) : "memory")
#define MBAR_ARRIVE(a) asm volatile("mbarrier.arrive.shared.b64 _, [%0];" :: "r"(a) : "memory")
#define MBAR_WAIT(a, ph) do { \
    uint32_t _m = (a), _p = (ph), _d; \
    asm volatile("{ .reg .pred p; mbarrier.try_wait.parity.acquire.cta.shared::cta.b64 p, [%1], %2; selp.b32 %0,1,0,p; }" \
        : "=r"(_d) : "r"(_m), "r"(_p) : "memory"); \
    if (!_d) { asm volatile("{ .reg .pred P1; WL%=: mbarrier.try_wait.parity.acquire.cta.shared::cta.b64 P1, [%0], %1, 0x989680; @P1 bra.uni WD%=; bra.uni WL%=; WD%=: }" \
        :: "r"(_m), "r"(_p) : "memory"); } \
} while (0)
#define MBAR_ARRIVE_RANK0(a) \
    asm volatile("{ .reg .b32 ra; mapa.shared::cluster.u32 ra, %0, 0; mbarrier.arrive.shared::cluster.b64 _, [ra]; }" \
        :: "r"(a) : "memory")
#define TMA_2D(sm, map, cx, cy, mb) \
    asm volatile("cp.async.bulk.tensor.2d.shared::cta.global.tile.mbarrier::complete_tx::bytes [%0], [%1, {%2, %3}], [%4];" \
        :: "r"(sm), "l"(map), "r"(cx), "r"(cy), "r"(mb) : "memory")
#define TMA_2D_CG2(sm, map, cx, cy, mb) \
    asm volatile("{ .reg .b32 lb; and.b32 lb, %4, 0xFEFFFFFF;\n\t" \
        "cp.async.bulk.tensor.2d.cta_group::2.shared::cluster.global.tile.mbarrier::complete_tx::bytes " \
        "[%0], [%1, {%2, %3}], [lb]; }" \
        :: "r"(sm), "l"(map), "r"(cx), "r"(cy), "r"(mb) : "memory")
#define TC_ALLOC(smaddr, n)      asm volatile("tcgen05.alloc.cta_group::1.sync.aligned.shared::cta.b32 [%0], %1;" :: "r"(smaddr), "r"(n) : "memory")
#define TC_RELINQ()              asm volatile("tcgen05.relinquish_alloc_permit.cta_group::1.sync.aligned;")
#define TC_DEALLOC(t, n)         asm volatile("tcgen05.dealloc.cta_group::1.sync.aligned.b32 %0, %1;" :: "r"(t), "r"(n))
#define TC_COMMIT(mb)            asm volatile("tcgen05.commit.cta_group::1.mbarrier::arrive::one.shared::cluster.b64 [%0];" :: "r"(mb) : "memory")
#define TC_ALLOC_CG2(smaddr, n)  asm volatile("tcgen05.alloc.cta_group::2.sync.aligned.shared::cta.b32 [%0], %1;" :: "r"(smaddr), "r"(n) : "memory")
#define TC_RELINQ_CG2()          asm volatile("tcgen05.relinquish_alloc_permit.cta_group::2.sync.aligned;")
#define TC_DEALLOC_CG2(t, n)     asm volatile("tcgen05.dealloc.cta_group::2.sync.aligned.b32 %0, %1;" :: "r"(t), "r"(n))
#define TC_COMMIT_MC2(mb) \
    asm volatile("tcgen05.commit.cta_group::2.mbarrier::arrive::one.shared::cluster.multicast::cluster.b64 [%0], %1;" \
        :: "r"(mb), "h"((unsigned short)0x3) : "memory")
#define TC_FENCE_AFTER()      asm volatile("tcgen05.fence::after_thread_sync;" ::: "memory")
#define TC_FENCE_BEFORE()     asm volatile("tcgen05.fence::before_thread_sync;" ::: "memory")
#define TC_WAIT_LD()          asm volatile("tcgen05.wait::ld.sync.aligned;" ::: "memory")
#define TC_LD_X32(r, addr) \
    asm volatile("tcgen05.ld.sync.aligned.32x32b.x32.b32 " \
        "{%0,%1,%2,%3,%4,%5,%6,%7,%8,%9,%10,%11,%12,%13,%14,%15," \
        "%16,%17,%18,%19,%20,%21,%22,%23,%24,%25,%26,%27,%28,%29,%30,%31}, [%32];" \
        : "=r"((r)[0]),"=r"((r)[1]),"=r"((r)[2]),"=r"((r)[3]),"=r"((r)[4]),"=r"((r)[5]),"=r"((r)[6]),"=r"((r)[7]), \
          "=r"((r)[8]),"=r"((r)[9]),"=r"((r)[10]),"=r"((r)[11]),"=r"((r)[12]),"=r"((r)[13]),"=r"((r)[14]),"=r"((r)[15]), \
          "=r"((r)[16]),"=r"((r)[17]),"=r"((r)[18]),"=r"((r)[19]),"=r"((r)[20]),"=r"((r)[21]),"=r"((r)[22]),"=r"((r)[23]), \
          "=r"((r)[24]),"=r"((r)[25]),"=r"((r)[26]),"=r"((r)[27]),"=r"((r)[28]),"=r"((r)[29]),"=r"((r)[30]),"=r"((r)[31]) \
        : "r"(addr))
#define CLUSTER_SYNC() do { \
    asm volatile("barrier.cluster.arrive.aligned;" ::: "memory"); \
    asm volatile("barrier.cluster.wait.aligned;" ::: "memory"); \
} while (0)

static constexpr uint64_t DESC_SW128 =
    (uint64_t(2) << 61) | (uint64_t(1) << 46) | (uint64_t(64) << 32) | (uint64_t(1) << 16);
__device__ __forceinline__ uint64_t mk_desc(uint32_t sm) {
    return DESC_SW128 | ((uint64_t)(sm >> 4) & 0x3FFF);
}
// kind::f16, D=F32, A=BF16, B=BF16, M=256 (cg2): N=256 / N=128 variants
#define IDESC_CG2_N256 0x10400490u
#define IDESC_CG2_N128 0x10200490u
__device__ __forceinline__ void mma_cg2(uint32_t d, uint64_t a, uint64_t b,
                                        uint32_t idesc, uint32_t en) {
    asm volatile("{ .reg .pred p; setp.ne.u32 p, %5, 0;\n\t"
        "tcgen05.mma.cta_group::2.kind::f16 [%0], %1, %2, %3, {%4,%4,%4,%4,%4,%4,%4,%4}, p; }"
        :: "r"(d), "l"(a), "l"(b), "r"(idesc), "r"(0u), "r"(en) : "memory");
}
// kind::f16, D=F32, A=BF16 K-major, B=BF16 K-major, M=128, N=128 (cg1)
#define IDESC_M128N128 0x8200490u
__device__ __forceinline__ void mma_128(uint32_t d, uint64_t a, uint64_t b, uint32_t en) {
    asm volatile("{ .reg .pred p; setp.ne.u32 p, %5, 0;\n\t"
        "tcgen05.mma.cta_group::1.kind::f16 [%0], %1, %2, %3, {%4,%4,%4,%4}, p; }"
        :: "r"(d), "l"(a), "l"(b), "r"(IDESC_M128N128), "r"(0u), "r"(en) : "memory");
}
#endif // HAS_TC

// ======================= persistent cg2 propagation GEMM =======================
#define KCHUNK 64
#define NCHUNK 32                  // K chunks per unit (K = 2048)
#define NSTAGE 3
#define NPAIRS 74
#define SM_TMEMPTR 0
#define SM_FULL(s)  (16 + (s) * 8)
#define SM_EMPTY(s) (48 + (s) * 8)
#define SM_MDONE(t) (80 + (t) * 8)
#define SM_EPID(t)  (96 + (t) * 8)
#define STAGE_CTA 65536
#define SM_STAGE(s) (1024 + (s) * STAGE_CTA)
#define A_HI(s) (SM_STAGE(s))
#define A_LO(s) (SM_STAGE(s) + 16384)
#define B_HI(s) (SM_STAGE(s) + 32768)
#define B_LO(s) (SM_STAGE(s) + 49152)
#define EPI_PITCH 136
#define EPI_BYTES (32 * EPI_PITCH * 2)          // 8704
#define EPI_HI (1024 + NSTAGE * STAGE_CTA)
#define EPI_LO (EPI_HI + EPI_BYTES)
#define TC_SMEM (EPI_LO + EPI_BYTES)            // 215040

// balanced schedule: units 0,1 = full tiles (pair, pair+74); unit 2 (pairs<40)
// = half tile: tile 148+(pair>>1), n-offset (pair&1)*128, N=128.
#if HAS_TC
__device__ __forceinline__ void unit_params(int pair, int u, int& mt, int& nt,
                                            int& noff, int& nlen) {
    int t = (u == 0) ? pair : ((u == 1) ? pair + NPAIRS : 148 + (pair >> 1));
    mt = t & 7;
    nt = t >> 3;
    noff = (u < 2) ? 0 : ((pair & 1) * 128);
    nlen = (u < 2) ? 256 : 128;
}
#endif

__global__ __launch_bounds__(192, 1) __cluster_dims__(2, 1, 1) void gemm_tc(
    const __grid_constant__ CUtensorMap mapAhi,
    const __grid_constant__ CUtensorMap mapAlo,
    const __grid_constant__ CUtensorMap mapBhi,     // box 64 x 128 rows
    const __grid_constant__ CUtensorMap mapBlo,
    const __grid_constant__ CUtensorMap mapBhi64,   // box 64 x 64 rows
    const __grid_constant__ CUtensorMap mapBlo64,
    __nv_bfloat16* __restrict__ dst_hi,
    __nv_bfloat16* __restrict__ dst_lo,
    __nv_bfloat16* __restrict__ tmT_hi,
    __nv_bfloat16* __restrict__ tmT_lo,
    int write_nm)
{
#if HAS_TC
    extern __shared__ char smem[];
    uint32_t smb = smem_u32(smem);
    int tid = threadIdx.x, wid = tid >> 5, lane = tid & 31;
    uint32_t rank;
    asm("mov.u32 %0, %%cluster_ctarank;" : "=r"(rank));
    int pair = blockIdx.x >> 1;
    int my_units = 2 + (pair < 40 ? 1 : 0);
    int total = my_units * NCHUNK;

    if (wid == 4) { TC_ALLOC_CG2(smb + SM_TMEMPTR, 512); TC_RELINQ_CG2(); }
    if (tid == 0) {
        #pragma unroll
        for (int s = 0; s < NSTAGE; s++) {
            MBAR_INIT(smb + SM_FULL(s), 1);
            MBAR_INIT(smb + SM_EMPTY(s), 1);
        }
        MBAR_INIT(smb + SM_MDONE(0), 1);
        MBAR_INIT(smb + SM_MDONE(1), 1);
        MBAR_INIT(smb + SM_EPID(0), 2);
        MBAR_INIT(smb + SM_EPID(1), 2);
    }
    __syncthreads();
    CLUSTER_SYNC();

    uint32_t tmem;
    asm volatile("ld.shared.b32 %0, [%1];" : "=r"(tmem) : "r"(smb + SM_TMEMPTR));

    if (wid == 4) {
        // ---------------- TMA producer warp (both ranks) ----------------
        uint32_t e1 = elect_one();
        uint32_t pe[NSTAGE] = {0, 0, 0};
        if (e1) {
            int s = 0;
            for (int g = 0; g < total; g++) {
                if (g >= NSTAGE) { MBAR_WAIT(smb + SM_EMPTY(s), pe[s]); pe[s] ^= 1; }
                int u = g >> 5, c = g & 31;
                int mt, nt, noff, nlen;
                unit_params(pair, u, mt, nt, noff, nlen);
                int k0 = c * KCHUNK;
                int ma = mt * 256 + (int)rank * 128;
                int nb = nt * 256 + noff + (int)rank * (nlen >> 1);
                if (rank == 0) {
                    uint32_t tx = 65536u + (uint32_t)nlen * 256u;
                    MBAR_EXPECT_TX(smb + SM_FULL(s), tx);
                }
                TMA_2D_CG2(smb + A_HI(s), &mapAhi, k0, ma, smb + SM_FULL(s));
                TMA_2D_CG2(smb + A_LO(s), &mapAlo, k0, ma, smb + SM_FULL(s));
                if (nlen == 256) {
                    TMA_2D_CG2(smb + B_HI(s), &mapBhi, k0, nb, smb + SM_FULL(s));
                    TMA_2D_CG2(smb + B_LO(s), &mapBlo, k0, nb, smb + SM_FULL(s));
                } else {
                    TMA_2D_CG2(smb + B_HI(s), &mapBhi64, k0, nb, smb + SM_FULL(s));
                    TMA_2D_CG2(smb + B_LO(s), &mapBlo64, k0, nb, smb + SM_FULL(s));
                }
                if (++s == NSTAGE) s = 0;
            }
        }
    } else if (wid == 5) {
        // ---------------- MMA consumer warp (rank 0 only) ----------------
        if (rank == 0) {
            uint32_t e1 = elect_one();
            uint32_t pf[NSTAGE] = {0, 0, 0}, ped[2] = {0, 0};
            int s = 0;
            for (int g = 0; g < total; g++) {
                int c = g & 31, u = g >> 5, slot = u & 1;
                int mt, nt, noff, nlen;
                unit_params(pair, u, mt, nt, noff, nlen);
                uint32_t idesc = (nlen == 256) ? IDESC_CG2_N256 : IDESC_CG2_N128;
                if (c == 0 && u >= 2) {      // D-slot reuse gated on both epilogues
                    MBAR_WAIT(smb + SM_EPID(slot), ped[slot]); ped[slot] ^= 1;
                }
                MBAR_WAIT(smb + SM_FULL(s), pf[s]); pf[s] ^= 1;
                if (e1) {
                    uint64_t ah = mk_desc(smb + A_HI(s));
                    uint64_t al = mk_desc(smb + A_LO(s));
                    uint64_t bh = mk_desc(smb + B_HI(s));
                    uint64_t bl = mk_desc(smb + B_LO(s));
                    uint32_t dt = tmem + slot * 256;
                    #pragma unroll
                    for (int ks = 0; ks < 4; ks++)
                        mma_cg2(dt, ah + ks * 2, bh + ks * 2, idesc, (c == 0 && ks == 0) ? 0u : 1u);
                    #pragma unroll
                    for (int ks = 0; ks < 4; ks++)
                        mma_cg2(dt, ah + ks * 2, bl + ks * 2, idesc, 1u);
                    #pragma unroll
                    for (int ks = 0; ks < 4; ks++)
                        mma_cg2(dt, al + ks * 2, bh + ks * 2, idesc, 1u);
                    TC_COMMIT_MC2(smb + SM_EMPTY(s));
                    if (c == NCHUNK - 1) TC_COMMIT_MC2(smb + SM_MDONE(slot));
                }
                if (++s == NSTAGE) s = 0;
            }
        }
    } else {
        // ---------------- epilogue warps 0..3 (128 threads) ----------------
        uint32_t pm[2] = {0, 0};
        __nv_bfloat16* shi = (__nv_bfloat16*)(smem + EPI_HI);
        __nv_bfloat16* slo = (__nv_bfloat16*)(smem + EPI_LO);
        int mloc = wid * 32 + lane;
        for (int u = 0; u < my_units; u++) {
            int slot = u & 1;
            int mt, nt, noff, nlen;
            unit_params(pair, u, mt, nt, noff, nlen);
            int mg = mt * 256 + (int)rank * 128;
            int ng = nt * 256 + noff;
            int blkcnt = nlen >> 5;
            MBAR_WAIT(smb + SM_MDONE(slot), pm[slot]); pm[slot] ^= 1;
            TC_FENCE_AFTER();
            #pragma unroll 1
            for (int blk = 0; blk < blkcnt; blk++) {
                uint32_t r[32];
                TC_LD_X32(r, tmem + slot * 256 + blk * 32);
                TC_WAIT_LD();
                #pragma unroll
                for (int j = 0; j < 32; j++) {
                    float v = __uint_as_float(r[j]);
                    __nv_bfloat16 h = __float2bfloat16(v);
                    __nv_bfloat16 l = __float2bfloat16(v - __bfloat162float(h));
                    shi[j * EPI_PITCH + mloc] = h;
                    slo[j * EPI_PITCH + mloc] = l;
                }
                asm volatile("bar.sync 1, 128;" ::: "memory");
                // pass 1: [n][m] orientation for next hop's GEMM B
                if (write_nm) {
                    #pragma unroll
                    for (int idx = tid; idx < 512; idx += 128) {
                        int nl = idx >> 4;
                        int m8 = (idx & 15) * 8;
                        size_t ga = (size_t)(ng + blk * 32 + nl) * MDIM + mg + m8;
                        *(uint4*)(dst_hi + ga) = *(uint4*)(shi + nl * EPI_PITCH + m8);
                        *(uint4*)(dst_lo + ga) = *(uint4*)(slo + nl * EPI_PITCH + m8);
                    }
                }
                // pass 2: m-major tmT[b][m][w] for the MLP A operand (168 % 8 == 0)
                {
                    int mrow = mg + tid;
                    #pragma unroll
                    for (int j8 = 0; j8 < 32; j8 += 8) {
                        int n0 = ng + blk * 32 + j8;
                        int bb = n0 / WDIM;
                        int w = n0 - bb * WDIM;
                        uint4 uh, ul;
                        unsigned short* ph = (unsigned short*)&uh;
                        unsigned short* pl = (unsigned short*)&ul;
                        #pragma unroll
                        for (int q = 0; q < 8; q++) {
                            ph[q] = *(unsigned short*)&shi[(j8 + q) * EPI_PITCH + tid];
                            pl[q] = *(unsigned short*)&slo[(j8 + q) * EPI_PITCH + tid];
                        }
                        size_t base = ((size_t)bb * MDIM + mrow) * KWPAD + w;
                        *(uint4*)(tmT_hi + base) = uh;
                        *(uint4*)(tmT_lo + base) = ul;
                    }
                }
                asm volatile("bar.sync 1, 128;" ::: "memory");
            }
            TC_FENCE_BEFORE();
            if (tid == 0) MBAR_ARRIVE_RANK0(smb + SM_EPID(slot));
        }
    }
    __syncthreads();
    if (wid == 4) TC_DEALLOC_CG2(tmem, 512);
    CLUSTER_SYNC();
#endif
}

// ======================= persistent tensor-core fused MLP =======================
// 128 CTAs x 4 tiles. W1 chunks resident in SMEM; A (tmT) streamed, 3-stage ring.
// Producer warp 4, MMA warp 5, epilogue warps 0..3. TMEM 2x128 D slots.
#define MLTILES 4
#define MLCHUNKS (MLTILES * 3)
#define MLF(s)    (16 + (s) * 8)
#define MLE(s)    (48 + (s) * 8)
#define MLW1F     80
#define MLMD(t)   (88 + (t) * 8)
#define MLEP(t)   (104 + (t) * 8)
#define MLA_HI(s) (1024 + (s) * 32768)
#define MLA_LO(s) (MLA_HI(s) + 16384)
#define MLW1H(c)  (1024 + 98304 + (c) * 16384)
#define MLW1L(c)  (1024 + 98304 + 49152 + (c) * 16384)
#define MLP_SMEM  (1024 + 98304 + 98304)   // 197632

__global__ __launch_bounds__(192, 1) void mlp_tc(
    const __grid_constant__ CUtensorMap mapAhi,   // tmT hi: [32*2048 rows][192]
    const __grid_constant__ CUtensorMap mapAlo,
    const __grid_constant__ CUtensorMap mapBhi,   // W1 hi: [(NHOPS+1)*128 rows][192]
    const __grid_constant__ CUtensorMap mapBlo,
    const float* __restrict__ b1,
    const float* __restrict__ W2,
    const float* __restrict__ b2,
    int hop, int accum,
    float* __restrict__ out)
{
#if HAS_TC
    extern __shared__ char smem[];
    uint32_t smb = smem_u32(smem);
    int tid = threadIdx.x, wid = tid >> 5;
    int cta = blockIdx.x;   // 0..127

    if (wid == 4) { TC_ALLOC(smb + SM_TMEMPTR, 256); TC_RELINQ(); }
    if (tid == 0) {
        #pragma unroll
        for (int s = 0; s < 3; s++) {
            MBAR_INIT(smb + MLF(s), 1);
            MBAR_INIT(smb + MLE(s), 1);
        }
        MBAR_INIT(smb + MLW1F, 1);
        MBAR_INIT(smb + MLMD(0), 1);
        MBAR_INIT(smb + MLMD(1), 1);
        MBAR_INIT(smb + MLEP(0), 1);
        MBAR_INIT(smb + MLEP(1), 1);
    }
    __syncthreads();
    uint32_t tmem;
    asm volatile("ld.shared.b32 %0, [%1];" : "=r"(tmem) : "r"(smb + SM_TMEMPTR));

    if (wid == 4) {
        // ---------------- TMA producer warp ----------------
        uint32_t e1 = elect_one();
        uint32_t pe[3] = {0, 0, 0};
        if (e1) {
            // W1 chunks resident, once
            MBAR_EXPECT_TX(smb + MLW1F, 98304);
            #pragma unroll
            for (int c = 0; c < 3; c++) {
                TMA_2D(smb + MLW1H(c), &mapBhi, c * 64, hop * HIDD, smb + MLW1F);
                TMA_2D(smb + MLW1L(c), &mapBlo, c * 64, hop * HIDD, smb + MLW1F);
            }
            int s = 0;
            for (int g = 0; g < MLCHUNKS; g++) {
                if (g >= 3) { MBAR_WAIT(smb + MLE(s), pe[s]); pe[s] ^= 1; }
                int u = g / 3, c = g - u * 3;
                int t = cta + 128 * u;
                int arow = (t >> 4) * MDIM + (t & 15) * 128;
                MBAR_EXPECT_TX(smb + MLF(s), 32768);
                TMA_2D(smb + MLA_HI(s), &mapAhi, c * 64, arow, smb + MLF(s));
                TMA_2D(smb + MLA_LO(s), &mapAlo, c * 64, arow, smb + MLF(s));
                if (++s == 3) s = 0;
            }
        }
    } else if (wid == 5) {
        // ---------------- MMA consumer warp ----------------
        uint32_t e1 = elect_one();
        uint32_t pf[3] = {0, 0, 0}, ped[2] = {0, 0};
        MBAR_WAIT(smb + MLW1F, 0);
        int s = 0;
        for (int g = 0; g < MLCHUNKS; g++) {
            int u = g / 3, c = g - u * 3, slot = u & 1;
            if (c == 0 && u >= 2) {
                MBAR_WAIT(smb + MLEP(slot), ped[slot]); ped[slot] ^= 1;
            }
            MBAR_WAIT(smb + MLF(s), pf[s]); pf[s] ^= 1;
            if (e1) {
                uint64_t ah = mk_desc(smb + MLA_HI(s));
                uint64_t al = mk_desc(smb + MLA_LO(s));
                uint64_t bh = mk_desc(smb + MLW1H(c));
                uint64_t bl = mk_desc(smb + MLW1L(c));
                uint32_t dt = tmem + slot * 128;
                #pragma unroll
                for (int ks = 0; ks < 4; ks++)
                    mma_128(dt, ah + ks * 2, bh + ks * 2, (c == 0 && ks == 0) ? 0u : 1u);
                #pragma unroll
                for (int ks = 0; ks < 4; ks++)
                    mma_128(dt, ah + ks * 2, bl + ks * 2, 1u);
                #pragma unroll
                for (int ks = 0; ks < 4; ks++)
                    mma_128(dt, al + ks * 2, bh + ks * 2, 1u);
                TC_COMMIT(smb + MLE(s));
                if (c == 2) TC_COMMIT(smb + MLMD(slot));
            }
            if (++s == 3) s = 0;
        }
    } else {
        // ---------------- epilogue warps 0..3 (128 threads), lane = m ----------------
        uint32_t pm[2] = {0, 0};
        const float* b1h = b1 + hop * HIDD;
        const float* W2h = W2 + hop * HIDD;
        float b2v = b2[hop];
        for (int u = 0; u < MLTILES; u++) {
            int slot = u & 1;
            int t = cta + 128 * u;
            int gi = (t >> 4) * MDIM + (t & 15) * 128 + tid;
            MBAR_WAIT(smb + MLMD(slot), pm[slot]); pm[slot] ^= 1;
            TC_FENCE_AFTER();
            float s = 0.f;
            #pragma unroll 1
            for (int cb = 0; cb < 4; cb++) {
                uint32_t r[32];
                TC_LD_X32(r, tmem + slot * 128 + cb * 32);
                TC_WAIT_LD();
                #pragma unroll
                for (int j = 0; j < 32; j++) {
                    int h = cb * 32 + j;
                    s += W2h[h] * fmaxf(__uint_as_float(r[j]) + b1h[h], 0.f);
                }
            }
            TC_FENCE_BEFORE();
            s += b2v;
            if (accum) s += out[gi];
            out[gi] = s;
            asm volatile("bar.sync 1, 128;" ::: "memory");
            if (tid == 0) MBAR_ARRIVE(smb + MLEP(slot));
        }
    }
    __syncthreads();
    if (wid == 4) TC_DEALLOC(tmem, 256);
#endif
}

// ======================= host =======================
typedef CUresult (*PFN_tmEncode)(CUtensorMap*, CUtensorMapDataType, cuuint32_t, void*,
                                 const cuuint64_t*, const cuuint64_t*, const cuuint32_t*,
                                 const cuuint32_t*, CUtensorMapInterleave, CUtensorMapSwizzle,
                                 CUtensorMapL2promotion, CUtensorMapFloatOOBfill);

static void make_map(PFN_tmEncode enc, CUtensorMap* m, void* ptr,
                     unsigned long long d0, unsigned long long d1,
                     unsigned box0, unsigned box1) {
    cuuint64_t dims[2] = {d0, d1};
    cuuint64_t strides[1] = {d0 * 2};
    cuuint32_t box[2] = {box0, box1};
    cuuint32_t es[2] = {1, 1};
    enc(m, CU_TENSOR_MAP_DATA_TYPE_BFLOAT16, 2, ptr, dims, strides, box, es,
        CU_TENSOR_MAP_INTERLEAVE_NONE, CU_TENSOR_MAP_SWIZZLE_128B,
        CU_TENSOR_MAP_L2_PROMOTION_L2_128B, CU_TENSOR_MAP_FLOAT_OOB_FILL_NONE);
}

extern "C" void kernel_launch(void* const* d_in, const int* in_sizes, int n_in,
                              void* d_out, int out_size) {
    const float* x  = (const float*)d_in[0];
    const float* L  = (const float*)d_in[1];
    const float* W1 = (const float*)d_in[2];
    const float* b1 = (const float*)d_in[3];
    const float* W2 = (const float*)d_in[4];
    const float* b2 = (const float*)d_in[5];
    float* out = (float*)d_out;

    __nv_bfloat16 *hi0, *hi1, *lo0, *lo1, *Lhi, *Llo, *W1hi, *W1lo, *tmThi, *tmTlo;
    cudaGetSymbolAddress((void**)&hi0, g_hi);
    hi1 = hi0 + (size_t)BWCOL * MDIM;
    cudaGetSymbolAddress((void**)&lo0, g_lo);
    lo1 = lo0 + (size_t)BWCOL * MDIM;
    cudaGetSymbolAddress((void**)&Lhi, g_Lhi);
    cudaGetSymbolAddress((void**)&Llo, g_Llo);
    cudaGetSymbolAddress((void**)&W1hi, g_W1hi);
    cudaGetSymbolAddress((void**)&W1lo, g_W1lo);
    cudaGetSymbolAddress((void**)&tmThi, g_tmThi);
    cudaGetSymbolAddress((void**)&tmTlo, g_tmTlo);

    PFN_tmEncode enc = nullptr;
    cudaDriverEntryPointQueryResult qr;
    cudaGetDriverEntryPointByVersion("cuTensorMapEncodeTiled", (void**)&enc, 12000,
                                     cudaEnableDefault, &qr);

    CUtensorMap mAhi, mAlo, mBhi[2], mBlo[2], mBhi64[2], mBlo64[2];
    CUtensorMap mW1hi, mW1lo, mTmhi, mTmlo;
    make_map(enc, &mAhi, Lhi, MDIM, MDIM, 64, 128);
    make_map(enc, &mAlo, Llo, MDIM, MDIM, 64, 128);
    make_map(enc, &mBhi[0], hi0, MDIM, BWCOL, 64, 128);
    make_map(enc, &mBhi[1], hi1, MDIM, BWCOL, 64, 128);
    make_map(enc, &mBlo[0], lo0, MDIM, BWCOL, 64, 128);
    make_map(enc, &mBlo[1], lo1, MDIM, BWCOL, 64, 128);
    make_map(enc, &mBhi64[0], hi0, MDIM, BWCOL, 64, 64);
    make_map(enc, &mBhi64[1], hi1, MDIM, BWCOL, 64, 64);
    make_map(enc, &mBlo64[0], lo0, MDIM, BWCOL, 64, 64);
    make_map(enc, &mBlo64[1], lo1, MDIM, BWCOL, 64, 64);
    make_map(enc, &mW1hi, W1hi, KWPAD, (NHOPS + 1) * HIDD, 64, 128);
    make_map(enc, &mW1lo, W1lo, KWPAD, (NHOPS + 1) * HIDD, 64, 128);
    make_map(enc, &mTmhi, tmThi, KWPAD, (unsigned long long)BATCH * MDIM, 64, 128);
    make_map(enc, &mTmlo, tmTlo, KWPAD, (unsigned long long)BATCH * MDIM, 64, 128);

    cudaFuncSetAttribute(gemm_tc, cudaFuncAttributeMaxDynamicSharedMemorySize, TC_SMEM);
    cudaFuncSetAttribute(mlp_tc, cudaFuncAttributeMaxDynamicSharedMemorySize, MLP_SMEM);

    {
        dim3 tg(MDIM / 32, KWPAD / 32, BATCH), tb(32, 8);
        prep_kernel<<<tg, tb>>>(x, hi0, lo0, tmThi, tmTlo);
        int n4 = (MDIM * MDIM) / 4;
        split_kernel<<<(n4 + 255) / 256, 256>>>(L, Lhi, Llo, n4);
        int nw = (NHOPS + 1) * HIDD * KWPAD;
        splitW1_kernel<<<(nw + 255) / 256, 256>>>(W1, W1hi, W1lo);
    }

    mlp_tc<<<128, 192, MLP_SMEM>>>(mTmhi, mTmlo, mW1hi, mW1lo,
                                   b1, W2, b2, 0, 0, out);

    for (int hop = 1; hop <= NHOPS; hop++) {
        int src = (hop + 1) & 1;
        int dst = hop & 1;
        gemm_tc<<<2 * NPAIRS, 192, TC_SMEM>>>(mAhi, mAlo, mBhi[src], mBlo[src],
                                              mBhi64[src], mBlo64[src],
                                              dst ? hi1 : hi0, dst ? lo1 : lo0,
                                              tmThi, tmTlo, hop < NHOPS ? 1 : 0);
        mlp_tc<<<128, 192, MLP_SMEM>>>(mTmhi, mTmlo, mW1hi, mW1lo,
                                       b1, W2, b2, hop, 1, out);
    }
}

// round 12
// speedup vs baseline: 9.4624x; 1.0526x over previous
#include <cuda_runtime.h>
#include <cuda_bf16.h>
#include <cuda.h>
#include <cstdint>

#define BATCH 32
#define WDIM  168
#define MDIM  2048
#define HIDD  128
#define NHOPS 6
#define BWCOL (BATCH * WDIM)   // 5376
#define KWPAD 192

#if defined(__CUDA_ARCH__) && defined(__CUDA_ARCH_FEAT_SM103_ALL)
#define HAS_TC 1
#else
#define HAS_TC 0
#endif

// t stored TRANSPOSED: T[n][m], m contiguous (GEMM B operand). Split bf16 hi/lo.
__device__ __align__(1024) __nv_bfloat16 g_hi[2][(size_t)BWCOL * MDIM];
__device__ __align__(1024) __nv_bfloat16 g_lo[2][(size_t)BWCOL * MDIM];
__device__ __align__(1024) __nv_bfloat16 g_Lhi[(size_t)MDIM * MDIM];
__device__ __align__(1024) __nv_bfloat16 g_Llo[(size_t)MDIM * MDIM];
// m-major copy for MLP A operand: tmT[slot][b][m][wpad], double-buffered for hop overlap
__device__ __align__(1024) __nv_bfloat16 g_tmThi[2][(size_t)BATCH * MDIM * KWPAD];
__device__ __align__(1024) __nv_bfloat16 g_tmTlo[2][(size_t)BATCH * MDIM * KWPAD];
// W1 split, zero-padded K: [hop][128][192]
__device__ __align__(1024) __nv_bfloat16 g_W1hi[(NHOPS + 1) * HIDD * KWPAD];
__device__ __align__(1024) __nv_bfloat16 g_W1lo[(NHOPS + 1) * HIDD * KWPAD];

// ======================= common helpers =======================
__device__ __forceinline__ uint32_t smem_u32(const void* p) {
    uint32_t a;
    asm("{ .reg .u64 t; cvta.to.shared.u64 t, %1; cvt.u32.u64 %0, t; }" : "=r"(a) : "l"(p));
    return a;
}

// ======================= splits =======================
__global__ void split_kernel(const float* __restrict__ in, __nv_bfloat16* __restrict__ hi,
                             __nv_bfloat16* __restrict__ lo, int n4) {
    int i = blockIdx.x * blockDim.x + threadIdx.x;
    if (i >= n4) return;
    float4 v = ((const float4*)in)[i];
    __nv_bfloat16 h[4], l[4];
    float vv[4] = {v.x, v.y, v.z, v.w};
    #pragma unroll
    for (int j = 0; j < 4; j++) {
        h[j] = __float2bfloat16(vv[j]);
        l[j] = __float2bfloat16(vv[j] - __bfloat162float(h[j]));
    }
    ((ushort4*)hi)[i] = make_ushort4(*(unsigned short*)&h[0], *(unsigned short*)&h[1],
                                     *(unsigned short*)&h[2], *(unsigned short*)&h[3]);
    ((ushort4*)lo)[i] = make_ushort4(*(unsigned short*)&l[0], *(unsigned short*)&l[1],
                                     *(unsigned short*)&l[2], *(unsigned short*)&l[3]);
}

__global__ void splitW1_kernel(const float* __restrict__ W1, __nv_bfloat16* __restrict__ hi,
                               __nv_bfloat16* __restrict__ lo) {
    int i = blockIdx.x * blockDim.x + threadIdx.x;
    if (i >= (NHOPS + 1) * HIDD * KWPAD) return;
    int w = i % KWPAD;
    int hh = i / KWPAD;
    float v = (w < WDIM) ? W1[hh * WDIM + w] : 0.f;
    __nv_bfloat16 h = __float2bfloat16(v);
    hi[i] = h;
    lo[i] = __float2bfloat16(v - __bfloat162float(h));
}

// fused prologue: x[b][w][m] -> hi0/lo0 [n=b*W+w][m] AND tmT[b][m][wpad] (w>=168 zero)
__global__ void prep_kernel(const float* __restrict__ x,
                            __nv_bfloat16* __restrict__ hi0,
                            __nv_bfloat16* __restrict__ lo0,
                            __nv_bfloat16* __restrict__ thi,
                            __nv_bfloat16* __restrict__ tlo) {
    __shared__ __nv_bfloat16 th[32][33], tl[32][33];
    int m0 = blockIdx.x * 32, w0 = blockIdx.y * 32, b = blockIdx.z;
    int tx = threadIdx.x, ty = threadIdx.y;
    #pragma unroll
    for (int i = ty; i < 32; i += 8) {
        int w = w0 + i;
        float v = (w < WDIM) ? x[((size_t)b * WDIM + w) * MDIM + m0 + tx] : 0.f;
        __nv_bfloat16 h = __float2bfloat16(v);
        __nv_bfloat16 l = __float2bfloat16(v - __bfloat162float(h));
        th[i][tx] = h;
        tl[i][tx] = l;
        if (w < WDIM) {
            size_t gi = ((size_t)b * WDIM + w) * MDIM + m0 + tx;
            hi0[gi] = h;
            lo0[gi] = l;
        }
    }
    __syncthreads();
    #pragma unroll
    for (int i = ty; i < 32; i += 8) {
        size_t idx = ((size_t)b * MDIM + m0 + i) * KWPAD + w0 + tx;
        thi[idx] = th[tx][i];
        tlo[idx] = tl[tx][i];
    }
}

// ======================= tcgen05 macros ('a' targets only) =======================
#if HAS_TC
__device__ __forceinline__ uint32_t elect_one() {
    uint32_t p;
    asm volatile("{ .reg .pred p; elect.sync _|p, 0xFFFFFFFF; selp.b32 %0, 1, 0, p; }" : "=r"(p));
    return p;
}
#define MBAR_INIT(a, c) asm volatile("mbarrier.init.shared.b64 [%0], %1;" :: "r"(a), "r"(c) : "memory")
#define MBAR_EXPECT_TX(a, b) asm volatile("mbarrier.arrive.expect_tx.shared.b64 _, [%0], %1;" :: "r"(a), "r"(b) : "memory")
#define MBAR_ARRIVE(a) asm volatile("mbarrier.arrive.shared.b64 _, [%0];" :: "r"(a) : "memory")
#define MBAR_WAIT(a, ph) do { \
    uint32_t _m = (a), _p = (ph), _d; \
    asm volatile("{ .reg .pred p; mbarrier.try_wait.parity.acquire.cta.shared::cta.b64 p, [%1], %2; selp.b32 %0,1,0,p; }" \
        : "=r"(_d) : "r"(_m), "r"(_p) : "memory"); \
    if (!_d) { asm volatile("{ .reg .pred P1; WL%=: mbarrier.try_wait.parity.acquire.cta.shared::cta.b64 P1, [%0], %1, 0x989680; @P1 bra.uni WD%=; bra.uni WL%=; WD%=: }" \
        :: "r"(_m), "r"(_p) : "memory"); } \
} while (0)
#define MBAR_ARRIVE_RANK0(a) \
    asm volatile("{ .reg .b32 ra; mapa.shared::cluster.u32 ra, %0, 0; mbarrier.arrive.shared::cluster.b64 _, [ra]; }" \
        :: "r"(a) : "memory")
#define TMA_2D(sm, map, cx, cy, mb) \
    asm volatile("cp.async.bulk.tensor.2d.shared::cta.global.tile.mbarrier::complete_tx::bytes [%0], [%1, {%2, %3}], [%4];" \
        :: "r"(sm), "l"(map), "r"(cx), "r"(cy), "r"(mb) : "memory")
#define TMA_2D_CG2(sm, map, cx, cy, mb) \
    asm volatile("{ .reg .b32 lb; and.b32 lb, %4, 0xFEFFFFFF;\n\t" \
        "cp.async.bulk.tensor.2d.cta_group::2.shared::cluster.global.tile.mbarrier::complete_tx::bytes " \
        "[%0], [%1, {%2, %3}], [lb]; }" \
        :: "r"(sm), "l"(map), "r"(cx), "r"(cy), "r"(mb) : "memory")
#define TC_ALLOC(smaddr, n)      asm volatile("tcgen05.alloc.cta_group::1.sync.aligned.shared::cta.b32 [%0], %1;" :: "r"(smaddr), "r"(n) : "memory")
#define TC_RELINQ()              asm volatile("tcgen05.relinquish_alloc_permit.cta_group::1.sync.aligned;")
#define TC_DEALLOC(t, n)         asm volatile("tcgen05.dealloc.cta_group::1.sync.aligned.b32 %0, %1;" :: "r"(t), "r"(n))
#define TC_COMMIT(mb)            asm volatile("tcgen05.commit.cta_group::1.mbarrier::arrive::one.shared::cluster.b64 [%0];" :: "r"(mb) : "memory")
#define TC_ALLOC_CG2(smaddr, n)  asm volatile("tcgen05.alloc.cta_group::2.sync.aligned.shared::cta.b32 [%0], %1;" :: "r"(smaddr), "r"(n) : "memory")
#define TC_RELINQ_CG2()          asm volatile("tcgen05.relinquish_alloc_permit.cta_group::2.sync.aligned;")
#define TC_DEALLOC_CG2(t, n)     asm volatile("tcgen05.dealloc.cta_group::2.sync.aligned.b32 %0, %1;" :: "r"(t), "r"(n))
#define TC_COMMIT_MC2(mb) \
    asm volatile("tcgen05.commit.cta_group::2.mbarrier::arrive::one.shared::cluster.multicast::cluster.b64 [%0], %1;" \
        :: "r"(mb), "h"((unsigned short)0x3) : "memory")
#define TC_FENCE_AFTER()      asm volatile("tcgen05.fence::after_thread_sync;" ::: "memory")
#define TC_FENCE_BEFORE()     asm volatile("tcgen05.fence::before_thread_sync;" ::: "memory")
#define TC_WAIT_LD()          asm volatile("tcgen05.wait::ld.sync.aligned;" ::: "memory")
#define TC_LD_X32(r, addr) \
    asm volatile("tcgen05.ld.sync.aligned.32x32b.x32.b32 " \
        "{%0,%1,%2,%3,%4,%5,%6,%7,%8,%9,%10,%11,%12,%13,%14,%15," \
        "%16,%17,%18,%19,%20,%21,%22,%23,%24,%25,%26,%27,%28,%29,%30,%31}, [%32];" \
        : "=r"((r)[0]),"=r"((r)[1]),"=r"((r)[2]),"=r"((r)[3]),"=r"((r)[4]),"=r"((r)[5]),"=r"((r)[6]),"=r"((r)[7]), \
          "=r"((r)[8]),"=r"((r)[9]),"=r"((r)[10]),"=r"((r)[11]),"=r"((r)[12]),"=r"((r)[13]),"=r"((r)[14]),"=r"((r)[15]), \
          "=r"((r)[16]),"=r"((r)[17]),"=r"((r)[18]),"=r"((r)[19]),"=r"((r)[20]),"=r"((r)[21]),"=r"((r)[22]),"=r"((r)[23]), \
          "=r"((r)[24]),"=r"((r)[25]),"=r"((r)[26]),"=r"((r)[27]),"=r"((r)[28]),"=r"((r)[29]),"=r"((r)[30]),"=r"((r)[31]) \
        : "r"(addr))
#define CLUSTER_SYNC() do { \
    asm volatile("barrier.cluster.arrive.aligned;" ::: "memory"); \
    asm volatile("barrier.cluster.wait.aligned;" ::: "memory"); \
} while (0)

static constexpr uint64_t DESC_SW128 =
    (uint64_t(2) << 61) | (uint64_t(1) << 46) | (uint64_t(64) << 32) | (uint64_t(1) << 16);
__device__ __forceinline__ uint64_t mk_desc(uint32_t sm) {
    return DESC_SW128 | ((uint64_t)(sm >> 4) & 0x3FFF);
}
// kind::f16, D=F32, A=BF16, B=BF16, M=256 (cg2): N=256 / N=128 variants
#define IDESC_CG2_N256 0x10400490u
#define IDESC_CG2_N128 0x10200490u
__device__ __forceinline__ void mma_cg2(uint32_t d, uint64_t a, uint64_t b,
                                        uint32_t idesc, uint32_t en) {
    asm volatile("{ .reg .pred p; setp.ne.u32 p, %5, 0;\n\t"
        "tcgen05.mma.cta_group::2.kind::f16 [%0], %1, %2, %3, {%4,%4,%4,%4,%4,%4,%4,%4}, p; }"
        :: "r"(d), "l"(a), "l"(b), "r"(idesc), "r"(0u), "r"(en) : "memory");
}
// kind::f16, D=F32, A=BF16 K-major, B=BF16 K-major, M=128, N=128 (cg1)
#define IDESC_M128N128 0x8200490u
__device__ __forceinline__ void mma_128(uint32_t d, uint64_t a, uint64_t b, uint32_t en) {
    asm volatile("{ .reg .pred p; setp.ne.u32 p, %5, 0;\n\t"
        "tcgen05.mma.cta_group::1.kind::f16 [%0], %1, %2, %3, {%4,%4,%4,%4}, p; }"
        :: "r"(d), "l"(a), "l"(b), "r"(IDESC_M128N128), "r"(0u), "r"(en) : "memory");
}
#endif // HAS_TC

// ======================= persistent cg2 propagation GEMM =======================
#define KCHUNK 64
#define NCHUNK 32                  // K chunks per unit (K = 2048)
#define NSTAGE 3
#define NPAIRS 74
#define SM_TMEMPTR 0
#define SM_FULL(s)  (16 + (s) * 8)
#define SM_EMPTY(s) (48 + (s) * 8)
#define SM_MDONE(t) (80 + (t) * 8)
#define SM_EPID(t)  (96 + (t) * 8)
#define STAGE_CTA 65536
#define SM_STAGE(s) (1024 + (s) * STAGE_CTA)
#define A_HI(s) (SM_STAGE(s))
#define A_LO(s) (SM_STAGE(s) + 16384)
#define B_HI(s) (SM_STAGE(s) + 32768)
#define B_LO(s) (SM_STAGE(s) + 49152)
#define EPI_PITCH 136
#define EPI_BYTES (32 * EPI_PITCH * 2)          // 8704
#define EPI_HI (1024 + NSTAGE * STAGE_CTA)
#define EPI_LO (EPI_HI + EPI_BYTES)
#define TC_SMEM (EPI_LO + EPI_BYTES)            // 215040

// balanced schedule: units 0,1 = full tiles (pair, pair+74); unit 2 (pairs<40)
// = half tile: tile 148+(pair>>1), n-offset (pair&1)*128, N=128.
#if HAS_TC
__device__ __forceinline__ void unit_params(int pair, int u, int& mt, int& nt,
                                            int& noff, int& nlen) {
    int t = (u == 0) ? pair : ((u == 1) ? pair + NPAIRS : 148 + (pair >> 1));
    mt = t & 7;
    nt = t >> 3;
    noff = (u < 2) ? 0 : ((pair & 1) * 128);
    nlen = (u < 2) ? 256 : 128;
}
#endif

__global__ __launch_bounds__(192, 1) __cluster_dims__(2, 1, 1) void gemm_tc(
    const __grid_constant__ CUtensorMap mapAhi,
    const __grid_constant__ CUtensorMap mapAlo,
    const __grid_constant__ CUtensorMap mapBhi,     // box 64 x 128 rows
    const __grid_constant__ CUtensorMap mapBlo,
    const __grid_constant__ CUtensorMap mapBhi64,   // box 64 x 64 rows
    const __grid_constant__ CUtensorMap mapBlo64,
    __nv_bfloat16* __restrict__ dst_hi,
    __nv_bfloat16* __restrict__ dst_lo,
    __nv_bfloat16* __restrict__ tmT_hi,
    __nv_bfloat16* __restrict__ tmT_lo,
    int write_nm)
{
#if HAS_TC
    extern __shared__ char smem[];
    uint32_t smb = smem_u32(smem);
    int tid = threadIdx.x, wid = tid >> 5, lane = tid & 31;
    uint32_t rank;
    asm("mov.u32 %0, %%cluster_ctarank;" : "=r"(rank));
    int pair = blockIdx.x >> 1;
    int my_units = 2 + (pair < 40 ? 1 : 0);
    int total = my_units * NCHUNK;

    if (wid == 4) { TC_ALLOC_CG2(smb + SM_TMEMPTR, 512); TC_RELINQ_CG2(); }
    if (tid == 0) {
        #pragma unroll
        for (int s = 0; s < NSTAGE; s++) {
            MBAR_INIT(smb + SM_FULL(s), 1);
            MBAR_INIT(smb + SM_EMPTY(s), 1);
        }
        MBAR_INIT(smb + SM_MDONE(0), 1);
        MBAR_INIT(smb + SM_MDONE(1), 1);
        MBAR_INIT(smb + SM_EPID(0), 2);
        MBAR_INIT(smb + SM_EPID(1), 2);
    }
    __syncthreads();
    CLUSTER_SYNC();

    uint32_t tmem;
    asm volatile("ld.shared.b32 %0, [%1];" : "=r"(tmem) : "r"(smb + SM_TMEMPTR));

    if (wid == 4) {
        // ---------------- TMA producer warp (both ranks) ----------------
        uint32_t e1 = elect_one();
        uint32_t pe[NSTAGE] = {0, 0, 0};
        if (e1) {
            int s = 0;
            for (int g = 0; g < total; g++) {
                if (g >= NSTAGE) { MBAR_WAIT(smb + SM_EMPTY(s), pe[s]); pe[s] ^= 1; }
                int u = g >> 5, c = g & 31;
                int mt, nt, noff, nlen;
                unit_params(pair, u, mt, nt, noff, nlen);
                int k0 = c * KCHUNK;
                int ma = mt * 256 + (int)rank * 128;
                int nb = nt * 256 + noff + (int)rank * (nlen >> 1);
                if (rank == 0) {
                    uint32_t tx = 65536u + (uint32_t)nlen * 256u;
                    MBAR_EXPECT_TX(smb + SM_FULL(s), tx);
                }
                TMA_2D_CG2(smb + A_HI(s), &mapAhi, k0, ma, smb + SM_FULL(s));
                TMA_2D_CG2(smb + A_LO(s), &mapAlo, k0, ma, smb + SM_FULL(s));
                if (nlen == 256) {
                    TMA_2D_CG2(smb + B_HI(s), &mapBhi, k0, nb, smb + SM_FULL(s));
                    TMA_2D_CG2(smb + B_LO(s), &mapBlo, k0, nb, smb + SM_FULL(s));
                } else {
                    TMA_2D_CG2(smb + B_HI(s), &mapBhi64, k0, nb, smb + SM_FULL(s));
                    TMA_2D_CG2(smb + B_LO(s), &mapBlo64, k0, nb, smb + SM_FULL(s));
                }
                if (++s == NSTAGE) s = 0;
            }
        }
    } else if (wid == 5) {
        // ---------------- MMA consumer warp (rank 0 only) ----------------
        if (rank == 0) {
            uint32_t e1 = elect_one();
            uint32_t pf[NSTAGE] = {0, 0, 0}, ped[2] = {0, 0};
            int s = 0;
            for (int g = 0; g < total; g++) {
                int c = g & 31, u = g >> 5, slot = u & 1;
                int mt, nt, noff, nlen;
                unit_params(pair, u, mt, nt, noff, nlen);
                uint32_t idesc = (nlen == 256) ? IDESC_CG2_N256 : IDESC_CG2_N128;
                if (c == 0 && u >= 2) {      // D-slot reuse gated on both epilogues
                    MBAR_WAIT(smb + SM_EPID(slot), ped[slot]); ped[slot] ^= 1;
                }
                MBAR_WAIT(smb + SM_FULL(s), pf[s]); pf[s] ^= 1;
                if (e1) {
                    uint64_t ah = mk_desc(smb + A_HI(s));
                    uint64_t al = mk_desc(smb + A_LO(s));
                    uint64_t bh = mk_desc(smb + B_HI(s));
                    uint64_t bl = mk_desc(smb + B_LO(s));
                    uint32_t dt = tmem + slot * 256;
                    #pragma unroll
                    for (int ks = 0; ks < 4; ks++)
                        mma_cg2(dt, ah + ks * 2, bh + ks * 2, idesc, (c == 0 && ks == 0) ? 0u : 1u);
                    #pragma unroll
                    for (int ks = 0; ks < 4; ks++)
                        mma_cg2(dt, ah + ks * 2, bl + ks * 2, idesc, 1u);
                    #pragma unroll
                    for (int ks = 0; ks < 4; ks++)
                        mma_cg2(dt, al + ks * 2, bh + ks * 2, idesc, 1u);
                    TC_COMMIT_MC2(smb + SM_EMPTY(s));
                    if (c == NCHUNK - 1) TC_COMMIT_MC2(smb + SM_MDONE(slot));
                }
                if (++s == NSTAGE) s = 0;
            }
        }
    } else {
        // ---------------- epilogue warps 0..3 (128 threads) ----------------
        uint32_t pm[2] = {0, 0};
        __nv_bfloat16* shi = (__nv_bfloat16*)(smem + EPI_HI);
        __nv_bfloat16* slo = (__nv_bfloat16*)(smem + EPI_LO);
        int mloc = wid * 32 + lane;
        for (int u = 0; u < my_units; u++) {
            int slot = u & 1;
            int mt, nt, noff, nlen;
            unit_params(pair, u, mt, nt, noff, nlen);
            int mg = mt * 256 + (int)rank * 128;
            int ng = nt * 256 + noff;
            int blkcnt = nlen >> 5;
            MBAR_WAIT(smb + SM_MDONE(slot), pm[slot]); pm[slot] ^= 1;
            TC_FENCE_AFTER();
            #pragma unroll 1
            for (int blk = 0; blk < blkcnt; blk++) {
                uint32_t r[32];
                TC_LD_X32(r, tmem + slot * 256 + blk * 32);
                TC_WAIT_LD();
                #pragma unroll
                for (int j = 0; j < 32; j++) {
                    float v = __uint_as_float(r[j]);
                    __nv_bfloat16 h = __float2bfloat16(v);
                    __nv_bfloat16 l = __float2bfloat16(v - __bfloat162float(h));
                    shi[j * EPI_PITCH + mloc] = h;
                    slo[j * EPI_PITCH + mloc] = l;
                }
                asm volatile("bar.sync 1, 128;" ::: "memory");
                // pass 1: [n][m] orientation for next hop's GEMM B
                if (write_nm) {
                    #pragma unroll
                    for (int idx = tid; idx < 512; idx += 128) {
                        int nl = idx >> 4;
                        int m8 = (idx & 15) * 8;
                        size_t ga = (size_t)(ng + blk * 32 + nl) * MDIM + mg + m8;
                        *(uint4*)(dst_hi + ga) = *(uint4*)(shi + nl * EPI_PITCH + m8);
                        *(uint4*)(dst_lo + ga) = *(uint4*)(slo + nl * EPI_PITCH + m8);
                    }
                }
                // pass 2: m-major tmT[b][m][w] for the MLP A operand (168 % 8 == 0)
                {
                    int mrow = mg + tid;
                    #pragma unroll
                    for (int j8 = 0; j8 < 32; j8 += 8) {
                        int n0 = ng + blk * 32 + j8;
                        int bb = n0 / WDIM;
                        int w = n0 - bb * WDIM;
                        uint4 uh, ul;
                        unsigned short* ph = (unsigned short*)&uh;
                        unsigned short* pl = (unsigned short*)&ul;
                        #pragma unroll
                        for (int q = 0; q < 8; q++) {
                            ph[q] = *(unsigned short*)&shi[(j8 + q) * EPI_PITCH + tid];
                            pl[q] = *(unsigned short*)&slo[(j8 + q) * EPI_PITCH + tid];
                        }
                        size_t base = ((size_t)bb * MDIM + mrow) * KWPAD + w;
                        *(uint4*)(tmT_hi + base) = uh;
                        *(uint4*)(tmT_lo + base) = ul;
                    }
                }
                asm volatile("bar.sync 1, 128;" ::: "memory");
            }
            TC_FENCE_BEFORE();
            if (tid == 0) MBAR_ARRIVE_RANK0(smb + SM_EPID(slot));
        }
    }
    __syncthreads();
    if (wid == 4) TC_DEALLOC_CG2(tmem, 512);
    CLUSTER_SYNC();
#endif
}

// ======================= persistent tensor-core fused MLP =======================
#define MLTILES 4
#define MLCHUNKS (MLTILES * 3)
#define MLF(s)    (16 + (s) * 8)
#define MLE(s)    (48 + (s) * 8)
#define MLW1F     80
#define MLMD(t)   (88 + (t) * 8)
#define MLEP(t)   (104 + (t) * 8)
#define MLA_HI(s) (1024 + (s) * 32768)
#define MLA_LO(s) (MLA_HI(s) + 16384)
#define MLW1H(c)  (1024 + 98304 + (c) * 16384)
#define MLW1L(c)  (1024 + 98304 + 49152 + (c) * 16384)
#define MLP_SMEM  (1024 + 98304 + 98304)   // 197632

__global__ __launch_bounds__(192, 1) void mlp_tc(
    const __grid_constant__ CUtensorMap mapAhi,   // tmT hi: [32*2048 rows][192]
    const __grid_constant__ CUtensorMap mapAlo,
    const __grid_constant__ CUtensorMap mapBhi,   // W1 hi: [(NHOPS+1)*128 rows][192]
    const __grid_constant__ CUtensorMap mapBlo,
    const float* __restrict__ b1,
    const float* __restrict__ W2,
    const float* __restrict__ b2,
    int hop, int accum,
    float* __restrict__ out)
{
#if HAS_TC
    extern __shared__ char smem[];
    uint32_t smb = smem_u32(smem);
    int tid = threadIdx.x, wid = tid >> 5;
    int cta = blockIdx.x;   // 0..127

    if (wid == 4) { TC_ALLOC(smb + SM_TMEMPTR, 256); TC_RELINQ(); }
    if (tid == 0) {
        #pragma unroll
        for (int s = 0; s < 3; s++) {
            MBAR_INIT(smb + MLF(s), 1);
            MBAR_INIT(smb + MLE(s), 1);
        }
        MBAR_INIT(smb + MLW1F, 1);
        MBAR_INIT(smb + MLMD(0), 1);
        MBAR_INIT(smb + MLMD(1), 1);
        MBAR_INIT(smb + MLEP(0), 1);
        MBAR_INIT(smb + MLEP(1), 1);
    }
    __syncthreads();
    uint32_t tmem;
    asm volatile("ld.shared.b32 %0, [%1];" : "=r"(tmem) : "r"(smb + SM_TMEMPTR));

    if (wid == 4) {
        // ---------------- TMA producer warp ----------------
        uint32_t e1 = elect_one();
        uint32_t pe[3] = {0, 0, 0};
        if (e1) {
            MBAR_EXPECT_TX(smb + MLW1F, 98304);
            #pragma unroll
            for (int c = 0; c < 3; c++) {
                TMA_2D(smb + MLW1H(c), &mapBhi, c * 64, hop * HIDD, smb + MLW1F);
                TMA_2D(smb + MLW1L(c), &mapBlo, c * 64, hop * HIDD, smb + MLW1F);
            }
            int s = 0;
            for (int g = 0; g < MLCHUNKS; g++) {
                if (g >= 3) { MBAR_WAIT(smb + MLE(s), pe[s]); pe[s] ^= 1; }
                int u = g / 3, c = g - u * 3;
                int t = cta + 128 * u;
                int arow = (t >> 4) * MDIM + (t & 15) * 128;
                MBAR_EXPECT_TX(smb + MLF(s), 32768);
                TMA_2D(smb + MLA_HI(s), &mapAhi, c * 64, arow, smb + MLF(s));
                TMA_2D(smb + MLA_LO(s), &mapAlo, c * 64, arow, smb + MLF(s));
                if (++s == 3) s = 0;
            }
        }
    } else if (wid == 5) {
        // ---------------- MMA consumer warp ----------------
        uint32_t e1 = elect_one();
        uint32_t pf[3] = {0, 0, 0}, ped[2] = {0, 0};
        MBAR_WAIT(smb + MLW1F, 0);
        int s = 0;
        for (int g = 0; g < MLCHUNKS; g++) {
            int u = g / 3, c = g - u * 3, slot = u & 1;
            if (c == 0 && u >= 2) {
                MBAR_WAIT(smb + MLEP(slot), ped[slot]); ped[slot] ^= 1;
            }
            MBAR_WAIT(smb + MLF(s), pf[s]); pf[s] ^= 1;
            if (e1) {
                uint64_t ah = mk_desc(smb + MLA_HI(s));
                uint64_t al = mk_desc(smb + MLA_LO(s));
                uint64_t bh = mk_desc(smb + MLW1H(c));
                uint64_t bl = mk_desc(smb + MLW1L(c));
                uint32_t dt = tmem + slot * 128;
                #pragma unroll
                for (int ks = 0; ks < 4; ks++)
                    mma_128(dt, ah + ks * 2, bh + ks * 2, (c == 0 && ks == 0) ? 0u : 1u);
                #pragma unroll
                for (int ks = 0; ks < 4; ks++)
                    mma_128(dt, ah + ks * 2, bl + ks * 2, 1u);
                #pragma unroll
                for (int ks = 0; ks < 4; ks++)
                    mma_128(dt, al + ks * 2, bh + ks * 2, 1u);
                TC_COMMIT(smb + MLE(s));
                if (c == 2) TC_COMMIT(smb + MLMD(slot));
            }
            if (++s == 3) s = 0;
        }
    } else {
        // ---------------- epilogue warps 0..3 (128 threads), lane = m ----------------
        uint32_t pm[2] = {0, 0};
        const float* b1h = b1 + hop * HIDD;
        const float* W2h = W2 + hop * HIDD;
        float b2v = b2[hop];
        for (int u = 0; u < MLTILES; u++) {
            int slot = u & 1;
            int t = cta + 128 * u;
            int gi = (t >> 4) * MDIM + (t & 15) * 128 + tid;
            MBAR_WAIT(smb + MLMD(slot), pm[slot]); pm[slot] ^= 1;
            TC_FENCE_AFTER();
            float s = 0.f;
            #pragma unroll 1
            for (int cb = 0; cb < 4; cb++) {
                uint32_t r[32];
                TC_LD_X32(r, tmem + slot * 128 + cb * 32);
                TC_WAIT_LD();
                #pragma unroll
                for (int j = 0; j < 32; j++) {
                    int h = cb * 32 + j;
                    s += W2h[h] * fmaxf(__uint_as_float(r[j]) + b1h[h], 0.f);
                }
            }
            TC_FENCE_BEFORE();
            s += b2v;
            if (accum) s += out[gi];
            out[gi] = s;
            asm volatile("bar.sync 1, 128;" ::: "memory");
            if (tid == 0) MBAR_ARRIVE(smb + MLEP(slot));
        }
    }
    __syncthreads();
    if (wid == 4) TC_DEALLOC(tmem, 256);
#endif
}

// ======================= host =======================
typedef CUresult (*PFN_tmEncode)(CUtensorMap*, CUtensorMapDataType, cuuint32_t, void*,
                                 const cuuint64_t*, const cuuint64_t*, const cuuint32_t*,
                                 const cuuint32_t*, CUtensorMapInterleave, CUtensorMapSwizzle,
                                 CUtensorMapL2promotion, CUtensorMapFloatOOBfill);

static void make_map(PFN_tmEncode enc, CUtensorMap* m, void* ptr,
                     unsigned long long d0, unsigned long long d1,
                     unsigned box0, unsigned box1) {
    cuuint64_t dims[2] = {d0, d1};
    cuuint64_t strides[1] = {d0 * 2};
    cuuint32_t box[2] = {box0, box1};
    cuuint32_t es[2] = {1, 1};
    enc(m, CU_TENSOR_MAP_DATA_TYPE_BFLOAT16, 2, ptr, dims, strides, box, es,
        CU_TENSOR_MAP_INTERLEAVE_NONE, CU_TENSOR_MAP_SWIZZLE_128B,
        CU_TENSOR_MAP_L2_PROMOTION_L2_128B, CU_TENSOR_MAP_FLOAT_OOB_FILL_NONE);
}

extern "C" void kernel_launch(void* const* d_in, const int* in_sizes, int n_in,
                              void* d_out, int out_size) {
    const float* x  = (const float*)d_in[0];
    const float* L  = (const float*)d_in[1];
    const float* W1 = (const float*)d_in[2];
    const float* b1 = (const float*)d_in[3];
    const float* W2 = (const float*)d_in[4];
    const float* b2 = (const float*)d_in[5];
    float* out = (float*)d_out;

    __nv_bfloat16 *hi0, *hi1, *lo0, *lo1, *Lhi, *Llo, *W1hi, *W1lo;
    __nv_bfloat16 *tmThi0, *tmTlo0, *tmThi1, *tmTlo1;
    cudaGetSymbolAddress((void**)&hi0, g_hi);
    hi1 = hi0 + (size_t)BWCOL * MDIM;
    cudaGetSymbolAddress((void**)&lo0, g_lo);
    lo1 = lo0 + (size_t)BWCOL * MDIM;
    cudaGetSymbolAddress((void**)&Lhi, g_Lhi);
    cudaGetSymbolAddress((void**)&Llo, g_Llo);
    cudaGetSymbolAddress((void**)&W1hi, g_W1hi);
    cudaGetSymbolAddress((void**)&W1lo, g_W1lo);
    cudaGetSymbolAddress((void**)&tmThi0, g_tmThi);
    tmThi1 = tmThi0 + (size_t)BATCH * MDIM * KWPAD;
    cudaGetSymbolAddress((void**)&tmTlo0, g_tmTlo);
    tmTlo1 = tmTlo0 + (size_t)BATCH * MDIM * KWPAD;

    PFN_tmEncode enc = nullptr;
    cudaDriverEntryPointQueryResult qr;
    cudaGetDriverEntryPointByVersion("cuTensorMapEncodeTiled", (void**)&enc, 12000,
                                     cudaEnableDefault, &qr);

    CUtensorMap mAhi, mAlo, mBhi[2], mBlo[2], mBhi64[2], mBlo64[2];
    CUtensorMap mW1hi, mW1lo, mTmhi[2], mTmlo[2];
    make_map(enc, &mAhi, Lhi, MDIM, MDIM, 64, 128);
    make_map(enc, &mAlo, Llo, MDIM, MDIM, 64, 128);
    make_map(enc, &mBhi[0], hi0, MDIM, BWCOL, 64, 128);
    make_map(enc, &mBhi[1], hi1, MDIM, BWCOL, 64, 128);
    make_map(enc, &mBlo[0], lo0, MDIM, BWCOL, 64, 128);
    make_map(enc, &mBlo[1], lo1, MDIM, BWCOL, 64, 128);
    make_map(enc, &mBhi64[0], hi0, MDIM, BWCOL, 64, 64);
    make_map(enc, &mBhi64[1], hi1, MDIM, BWCOL, 64, 64);
    make_map(enc, &mBlo64[0], lo0, MDIM, BWCOL, 64, 64);
    make_map(enc, &mBlo64[1], lo1, MDIM, BWCOL, 64, 64);
    make_map(enc, &mW1hi, W1hi, KWPAD, (NHOPS + 1) * HIDD, 64, 128);
    make_map(enc, &mW1lo, W1lo, KWPAD, (NHOPS + 1) * HIDD, 64, 128);
    make_map(enc, &mTmhi[0], tmThi0, KWPAD, (unsigned long long)BATCH * MDIM, 64, 128);
    make_map(enc, &mTmhi[1], tmThi1, KWPAD, (unsigned long long)BATCH * MDIM, 64, 128);
    make_map(enc, &mTmlo[0], tmTlo0, KWPAD, (unsigned long long)BATCH * MDIM, 64, 128);
    make_map(enc, &mTmlo[1], tmTlo1, KWPAD, (unsigned long long)BATCH * MDIM, 64, 128);

    cudaFuncSetAttribute(gemm_tc, cudaFuncAttributeMaxDynamicSharedMemorySize, TC_SMEM);
    cudaFuncSetAttribute(mlp_tc, cudaFuncAttributeMaxDynamicSharedMemorySize, MLP_SMEM);

    __nv_bfloat16* tmThiS[2] = {tmThi0, tmThi1};
    __nv_bfloat16* tmTloS[2] = {tmTlo0, tmTlo1};

    // side stream + fork/join events (created at capture time; replay cost = 0)
    cudaStream_t s1;
    cudaStreamCreateWithFlags(&s1, cudaStreamNonBlocking);
    cudaEvent_t eG[NHOPS + 1], eM[NHOPS + 1];
    for (int i = 0; i <= NHOPS; i++) {
        cudaEventCreateWithFlags(&eG[i], cudaEventDisableTiming);
        cudaEventCreateWithFlags(&eM[i], cudaEventDisableTiming);
    }

    {
        dim3 tg(MDIM / 32, KWPAD / 32, BATCH), tb(32, 8);
        prep_kernel<<<tg, tb>>>(x, hi0, lo0, tmThi0, tmTlo0);   // tmT slot 0
        int n4 = (MDIM * MDIM) / 4;
        split_kernel<<<(n4 + 255) / 256, 256>>>(L, Lhi, Llo, n4);
        int nw = (NHOPS + 1) * HIDD * KWPAD;
        splitW1_kernel<<<(nw + 255) / 256, 256>>>(W1, W1hi, W1lo);
    }

    // hop 0 MLP on side stream (reads tmT slot 0)
    cudaEventRecord(eG[0], 0);
    cudaStreamWaitEvent(s1, eG[0], 0);
    mlp_tc<<<128, 192, MLP_SMEM, s1>>>(mTmhi[0], mTmlo[0], mW1hi, mW1lo,
                                       b1, W2, b2, 0, 0, out);
    cudaEventRecord(eM[0], s1);

    for (int hop = 1; hop <= NHOPS; hop++) {
        int src = (hop + 1) & 1;
        int dst = hop & 1;
        int slot = hop & 1;           // tmT slot written by this gemm
        // gemm(hop) overwrites tmT slot used by mlp(hop-2)  (slot 0 also by mlp(0))
        if (hop >= 2) cudaStreamWaitEvent(0, eM[hop - 2], 0);
        else if (slot == 0) cudaStreamWaitEvent(0, eM[0], 0);   // unreachable (slot=1 at hop1) but safe
        gemm_tc<<<2 * NPAIRS, 192, TC_SMEM>>>(mAhi, mAlo, mBhi[src], mBlo[src],
                                              mBhi64[src], mBlo64[src],
                                              dst ? hi1 : hi0, dst ? lo1 : lo0,
                                              tmThiS[slot], tmTloS[slot],
                                              hop < NHOPS ? 1 : 0);
        cudaEventRecord(eG[hop], 0);
        cudaStreamWaitEvent(s1, eG[hop], 0);
        mlp_tc<<<128, 192, MLP_SMEM, s1>>>(mTmhi[slot], mTmlo[slot], mW1hi, mW1lo,
                                           b1, W2, b2, hop, 1, out);
        cudaEventRecord(eM[hop], s1);
    }
    // join: main stream completes only after the last MLP accumulation
    cudaStreamWaitEvent(0, eM[NHOPS], 0);
}

// round 13
// speedup vs baseline: 9.9595x; 1.0525x over previous
#include <cuda_runtime.h>
#include <cuda_bf16.h>
#include <cuda.h>
#include <cstdint>

#define BATCH 32
#define WDIM  168
#define MDIM  2048
#define HIDD  128
#define NHOPS 6
#define BWCOL (BATCH * WDIM)   // 5376
#define KWPAD 192

#if defined(__CUDA_ARCH__) && defined(__CUDA_ARCH_FEAT_SM103_ALL)
#define HAS_TC 1
#else
#define HAS_TC 0
#endif

// t stored TRANSPOSED: T[n][m], m contiguous (GEMM B operand). Split bf16 hi/lo.
__device__ __align__(1024) __nv_bfloat16 g_hi[2][(size_t)BWCOL * MDIM];
__device__ __align__(1024) __nv_bfloat16 g_lo[2][(size_t)BWCOL * MDIM];
__device__ __align__(1024) __nv_bfloat16 g_Lhi[(size_t)MDIM * MDIM];
__device__ __align__(1024) __nv_bfloat16 g_Llo[(size_t)MDIM * MDIM];
// m-major copy for MLP A operand: tmT[slot][b][m][wpad], double-buffered for hop overlap
__device__ __align__(1024) __nv_bfloat16 g_tmThi[2][(size_t)BATCH * MDIM * KWPAD];
__device__ __align__(1024) __nv_bfloat16 g_tmTlo[2][(size_t)BATCH * MDIM * KWPAD];
// W1 split, zero-padded K: [hop][128][192]
__device__ __align__(1024) __nv_bfloat16 g_W1hi[(NHOPS + 1) * HIDD * KWPAD];
__device__ __align__(1024) __nv_bfloat16 g_W1lo[(NHOPS + 1) * HIDD * KWPAD];

// ======================= common helpers =======================
__device__ __forceinline__ uint32_t smem_u32(const void* p) {
    uint32_t a;
    asm("{ .reg .u64 t; cvta.to.shared.u64 t, %1; cvt.u32.u64 %0, t; }" : "=r"(a) : "l"(p));
    return a;
}

// ======================= splits =======================
__global__ void split_kernel(const float* __restrict__ in, __nv_bfloat16* __restrict__ hi,
                             __nv_bfloat16* __restrict__ lo, int n4) {
    int i = blockIdx.x * blockDim.x + threadIdx.x;
    if (i >= n4) return;
    float4 v = ((const float4*)in)[i];
    __nv_bfloat16 h[4], l[4];
    float vv[4] = {v.x, v.y, v.z, v.w};
    #pragma unroll
    for (int j = 0; j < 4; j++) {
        h[j] = __float2bfloat16(vv[j]);
        l[j] = __float2bfloat16(vv[j] - __bfloat162float(h[j]));
    }
    ((ushort4*)hi)[i] = make_ushort4(*(unsigned short*)&h[0], *(unsigned short*)&h[1],
                                     *(unsigned short*)&h[2], *(unsigned short*)&h[3]);
    ((ushort4*)lo)[i] = make_ushort4(*(unsigned short*)&l[0], *(unsigned short*)&l[1],
                                     *(unsigned short*)&l[2], *(unsigned short*)&l[3]);
}

__global__ void splitW1_kernel(const float* __restrict__ W1, __nv_bfloat16* __restrict__ hi,
                               __nv_bfloat16* __restrict__ lo) {
    int i = blockIdx.x * blockDim.x + threadIdx.x;
    if (i >= (NHOPS + 1) * HIDD * KWPAD) return;
    int w = i % KWPAD;
    int hh = i / KWPAD;
    float v = (w < WDIM) ? W1[hh * WDIM + w] : 0.f;
    __nv_bfloat16 h = __float2bfloat16(v);
    hi[i] = h;
    lo[i] = __float2bfloat16(v - __bfloat162float(h));
}

// fused prologue: x[b][w][m] -> hi0/lo0 [n=b*W+w][m] AND tmT[b][m][wpad] (w>=168 zero)
__global__ void prep_kernel(const float* __restrict__ x,
                            __nv_bfloat16* __restrict__ hi0,
                            __nv_bfloat16* __restrict__ lo0,
                            __nv_bfloat16* __restrict__ thi,
                            __nv_bfloat16* __restrict__ tlo) {
    __shared__ __nv_bfloat16 th[32][33], tl[32][33];
    int m0 = blockIdx.x * 32, w0 = blockIdx.y * 32, b = blockIdx.z;
    int tx = threadIdx.x, ty = threadIdx.y;
    #pragma unroll
    for (int i = ty; i < 32; i += 8) {
        int w = w0 + i;
        float v = (w < WDIM) ? x[((size_t)b * WDIM + w) * MDIM + m0 + tx] : 0.f;
        __nv_bfloat16 h = __float2bfloat16(v);
        __nv_bfloat16 l = __float2bfloat16(v - __bfloat162float(h));
        th[i][tx] = h;
        tl[i][tx] = l;
        if (w < WDIM) {
            size_t gi = ((size_t)b * WDIM + w) * MDIM + m0 + tx;
            hi0[gi] = h;
            lo0[gi] = l;
        }
    }
    __syncthreads();
    #pragma unroll
    for (int i = ty; i < 32; i += 8) {
        size_t idx = ((size_t)b * MDIM + m0 + i) * KWPAD + w0 + tx;
        thi[idx] = th[tx][i];
        tlo[idx] = tl[tx][i];
    }
}

// ======================= tcgen05 macros ('a' targets only) =======================
#if HAS_TC
__device__ __forceinline__ uint32_t elect_one() {
    uint32_t p;
    asm volatile("{ .reg .pred p; elect.sync _|p, 0xFFFFFFFF; selp.b32 %0, 1, 0, p; }" : "=r"(p));
    return p;
}
#define MBAR_INIT(a, c) asm volatile("mbarrier.init.shared.b64 [%0], %1;" :: "r"(a), "r"(c) : "memory")
#define MBAR_EXPECT_TX(a, b) asm volatile("mbarrier.arrive.expect_tx.shared.b64 _, [%0], %1;" :: "r"(a), "r"(b) : "memory")
#define MBAR_ARRIVE(a) asm volatile("mbarrier.arrive.shared.b64 _, [%0];" :: "r"(a) : "memory")
#define MBAR_WAIT(a, ph) do { \
    uint32_t _m = (a), _p = (ph), _d; \
    asm volatile("{ .reg .pred p; mbarrier.try_wait.parity.acquire.cta.shared::cta.b64 p, [%1], %2; selp.b32 %0,1,0,p; }" \
        : "=r"(_d) : "r"(_m), "r"(_p) : "memory"); \
    if (!_d) { asm volatile("{ .reg .pred P1; WL%=: mbarrier.try_wait.parity.acquire.cta.shared::cta.b64 P1, [%0], %1, 0x989680; @P1 bra.uni WD%=; bra.uni WL%=; WD%=: }" \
        :: "r"(_m), "r"(_p) : "memory"); } \
} while (0)
#define MBAR_ARRIVE_RANK0(a) \
    asm volatile("{ .reg .b32 ra; mapa.shared::cluster.u32 ra, %0, 0; mbarrier.arrive.shared::cluster.b64 _, [ra]; }" \
        :: "r"(a) : "memory")
#define TMA_2D(sm, map, cx, cy, mb) \
    asm volatile("cp.async.bulk.tensor.2d.shared::cta.global.tile.mbarrier::complete_tx::bytes [%0], [%1, {%2, %3}], [%4];" \
        :: "r"(sm), "l"(map), "r"(cx), "r"(cy), "r"(mb) : "memory")
#define TMA_2D_CG2(sm, map, cx, cy, mb) \
    asm volatile("{ .reg .b32 lb; and.b32 lb, %4, 0xFEFFFFFF;\n\t" \
        "cp.async.bulk.tensor.2d.cta_group::2.shared::cluster.global.tile.mbarrier::complete_tx::bytes " \
        "[%0], [%1, {%2, %3}], [lb]; }" \
        :: "r"(sm), "l"(map), "r"(cx), "r"(cy), "r"(mb) : "memory")
#define TC_ALLOC(smaddr, n)      asm volatile("tcgen05.alloc.cta_group::1.sync.aligned.shared::cta.b32 [%0], %1;" :: "r"(smaddr), "r"(n) : "memory")
#define TC_RELINQ()              asm volatile("tcgen05.relinquish_alloc_permit.cta_group::1.sync.aligned;")
#define TC_DEALLOC(t, n)         asm volatile("tcgen05.dealloc.cta_group::1.sync.aligned.b32 %0, %1;" :: "r"(t), "r"(n))
#define TC_COMMIT(mb)            asm volatile("tcgen05.commit.cta_group::1.mbarrier::arrive::one.shared::cluster.b64 [%0];" :: "r"(mb) : "memory")
#define TC_ALLOC_CG2(smaddr, n)  asm volatile("tcgen05.alloc.cta_group::2.sync.aligned.shared::cta.b32 [%0], %1;" :: "r"(smaddr), "r"(n) : "memory")
#define TC_RELINQ_CG2()          asm volatile("tcgen05.relinquish_alloc_permit.cta_group::2.sync.aligned;")
#define TC_DEALLOC_CG2(t, n)     asm volatile("tcgen05.dealloc.cta_group::2.sync.aligned.b32 %0, %1;" :: "r"(t), "r"(n))
#define TC_COMMIT_MC2(mb) \
    asm volatile("tcgen05.commit.cta_group::2.mbarrier::arrive::one.shared::cluster.multicast::cluster.b64 [%0], %1;" \
        :: "r"(mb), "h"((unsigned short)0x3) : "memory")
#define TC_FENCE_AFTER()      asm volatile("tcgen05.fence::after_thread_sync;" ::: "memory")
#define TC_FENCE_BEFORE()     asm volatile("tcgen05.fence::before_thread_sync;" ::: "memory")
#define TC_WAIT_LD()          asm volatile("tcgen05.wait::ld.sync.aligned;" ::: "memory")
#define TC_LD_X32(r, addr) \
    asm volatile("tcgen05.ld.sync.aligned.32x32b.x32.b32 " \
        "{%0,%1,%2,%3,%4,%5,%6,%7,%8,%9,%10,%11,%12,%13,%14,%15," \
        "%16,%17,%18,%19,%20,%21,%22,%23,%24,%25,%26,%27,%28,%29,%30,%31}, [%32];" \
        : "=r"((r)[0]),"=r"((r)[1]),"=r"((r)[2]),"=r"((r)[3]),"=r"((r)[4]),"=r"((r)[5]),"=r"((r)[6]),"=r"((r)[7]), \
          "=r"((r)[8]),"=r"((r)[9]),"=r"((r)[10]),"=r"((r)[11]),"=r"((r)[12]),"=r"((r)[13]),"=r"((r)[14]),"=r"((r)[15]), \
          "=r"((r)[16]),"=r"((r)[17]),"=r"((r)[18]),"=r"((r)[19]),"=r"((r)[20]),"=r"((r)[21]),"=r"((r)[22]),"=r"((r)[23]), \
          "=r"((r)[24]),"=r"((r)[25]),"=r"((r)[26]),"=r"((r)[27]),"=r"((r)[28]),"=r"((r)[29]),"=r"((r)[30]),"=r"((r)[31]) \
        : "r"(addr))
#define CLUSTER_SYNC() do { \
    asm volatile("barrier.cluster.arrive.aligned;" ::: "memory"); \
    asm volatile("barrier.cluster.wait.aligned;" ::: "memory"); \
} while (0)

static constexpr uint64_t DESC_SW128 =
    (uint64_t(2) << 61) | (uint64_t(1) << 46) | (uint64_t(64) << 32) | (uint64_t(1) << 16);
__device__ __forceinline__ uint64_t mk_desc(uint32_t sm) {
    return DESC_SW128 | ((uint64_t)(sm >> 4) & 0x3FFF);
}
// kind::f16, D=F32, A=BF16, B=BF16, M=256 (cg2): N=256 / N=128 variants
#define IDESC_CG2_N256 0x10400490u
#define IDESC_CG2_N128 0x10200490u
__device__ __forceinline__ void mma_cg2(uint32_t d, uint64_t a, uint64_t b,
                                        uint32_t idesc, uint32_t en) {
    asm volatile("{ .reg .pred p; setp.ne.u32 p, %5, 0;\n\t"
        "tcgen05.mma.cta_group::2.kind::f16 [%0], %1, %2, %3, {%4,%4,%4,%4,%4,%4,%4,%4}, p; }"
        :: "r"(d), "l"(a), "l"(b), "r"(idesc), "r"(0u), "r"(en) : "memory");
}
// kind::f16, D=F32, A=BF16 K-major, B=BF16 K-major, M=128, N=128 (cg1)
#define IDESC_M128N128 0x8200490u
__device__ __forceinline__ void mma_128(uint32_t d, uint64_t a, uint64_t b, uint32_t en) {
    asm volatile("{ .reg .pred p; setp.ne.u32 p, %5, 0;\n\t"
        "tcgen05.mma.cta_group::1.kind::f16 [%0], %1, %2, %3, {%4,%4,%4,%4}, p; }"
        :: "r"(d), "l"(a), "l"(b), "r"(IDESC_M128N128), "r"(0u), "r"(en) : "memory");
}
#endif // HAS_TC

// ======================= persistent cg2 propagation GEMM (68 pairs = 136 SMs) ==========
#define KCHUNK 64
#define NCHUNK 32
#define NSTAGE 3
#define NPAIRS 68
#define SM_TMEMPTR 0
#define SM_FULL(s)  (16 + (s) * 8)
#define SM_EMPTY(s) (48 + (s) * 8)
#define SM_MDONE(t) (80 + (t) * 8)
#define SM_EPID(t)  (96 + (t) * 8)
#define STAGE_CTA 65536
#define SM_STAGE(s) (1024 + (s) * STAGE_CTA)
#define A_HI(s) (SM_STAGE(s))
#define A_LO(s) (SM_STAGE(s) + 16384)
#define B_HI(s) (SM_STAGE(s) + 32768)
#define B_LO(s) (SM_STAGE(s) + 49152)
#define EPI_PITCH 136
#define EPI_BYTES (32 * EPI_PITCH * 2)
#define EPI_HI (1024 + NSTAGE * STAGE_CTA)
#define EPI_LO (EPI_HI + EPI_BYTES)
#define TC_SMEM (EPI_LO + EPI_BYTES)

// balanced: units 0,1 = full tiles (pair, pair+68); unit 2 (pairs<64) = half of
// tile 136+(pair>>1), n-offset (pair&1)*128, N=128.
#if HAS_TC
__device__ __forceinline__ void unit_params(int pair, int u, int& mt, int& nt,
                                            int& noff, int& nlen) {
    int t = (u == 0) ? pair : ((u == 1) ? pair + NPAIRS : 136 + (pair >> 1));
    mt = t & 7;
    nt = t >> 3;
    noff = (u < 2) ? 0 : ((pair & 1) * 128);
    nlen = (u < 2) ? 256 : 128;
}
#endif

__global__ __launch_bounds__(192, 1) __cluster_dims__(2, 1, 1) void gemm_tc(
    const __grid_constant__ CUtensorMap mapAhi,
    const __grid_constant__ CUtensorMap mapAlo,
    const __grid_constant__ CUtensorMap mapBhi,     // box 64 x 128 rows
    const __grid_constant__ CUtensorMap mapBlo,
    const __grid_constant__ CUtensorMap mapBhi64,   // box 64 x 64 rows
    const __grid_constant__ CUtensorMap mapBlo64,
    __nv_bfloat16* __restrict__ dst_hi,
    __nv_bfloat16* __restrict__ dst_lo,
    __nv_bfloat16* __restrict__ tmT_hi,
    __nv_bfloat16* __restrict__ tmT_lo,
    int write_nm)
{
#if HAS_TC
    extern __shared__ char smem[];
    uint32_t smb = smem_u32(smem);
    int tid = threadIdx.x, wid = tid >> 5, lane = tid & 31;
    uint32_t rank;
    asm("mov.u32 %0, %%cluster_ctarank;" : "=r"(rank));
    int pair = blockIdx.x >> 1;
    int my_units = 2 + (pair < 64 ? 1 : 0);
    int total = my_units * NCHUNK;

    if (wid == 4) { TC_ALLOC_CG2(smb + SM_TMEMPTR, 512); TC_RELINQ_CG2(); }
    if (tid == 0) {
        #pragma unroll
        for (int s = 0; s < NSTAGE; s++) {
            MBAR_INIT(smb + SM_FULL(s), 1);
            MBAR_INIT(smb + SM_EMPTY(s), 1);
        }
        MBAR_INIT(smb + SM_MDONE(0), 1);
        MBAR_INIT(smb + SM_MDONE(1), 1);
        MBAR_INIT(smb + SM_EPID(0), 2);
        MBAR_INIT(smb + SM_EPID(1), 2);
    }
    __syncthreads();
    CLUSTER_SYNC();

    uint32_t tmem;
    asm volatile("ld.shared.b32 %0, [%1];" : "=r"(tmem) : "r"(smb + SM_TMEMPTR));

    if (wid == 4) {
        // ---------------- TMA producer warp (both ranks) ----------------
        uint32_t e1 = elect_one();
        uint32_t pe[NSTAGE] = {0, 0, 0};
        if (e1) {
            int s = 0;
            for (int g = 0; g < total; g++) {
                if (g >= NSTAGE) { MBAR_WAIT(smb + SM_EMPTY(s), pe[s]); pe[s] ^= 1; }
                int u = g >> 5, c = g & 31;
                int mt, nt, noff, nlen;
                unit_params(pair, u, mt, nt, noff, nlen);
                int k0 = c * KCHUNK;
                int ma = mt * 256 + (int)rank * 128;
                int nb = nt * 256 + noff + (int)rank * (nlen >> 1);
                if (rank == 0) {
                    uint32_t tx = 65536u + (uint32_t)nlen * 256u;
                    MBAR_EXPECT_TX(smb + SM_FULL(s), tx);
                }
                TMA_2D_CG2(smb + A_HI(s), &mapAhi, k0, ma, smb + SM_FULL(s));
                TMA_2D_CG2(smb + A_LO(s), &mapAlo, k0, ma, smb + SM_FULL(s));
                if (nlen == 256) {
                    TMA_2D_CG2(smb + B_HI(s), &mapBhi, k0, nb, smb + SM_FULL(s));
                    TMA_2D_CG2(smb + B_LO(s), &mapBlo, k0, nb, smb + SM_FULL(s));
                } else {
                    TMA_2D_CG2(smb + B_HI(s), &mapBhi64, k0, nb, smb + SM_FULL(s));
                    TMA_2D_CG2(smb + B_LO(s), &mapBlo64, k0, nb, smb + SM_FULL(s));
                }
                if (++s == NSTAGE) s = 0;
            }
        }
    } else if (wid == 5) {
        // ---------------- MMA consumer warp (rank 0 only) ----------------
        if (rank == 0) {
            uint32_t e1 = elect_one();
            uint32_t pf[NSTAGE] = {0, 0, 0}, ped[2] = {0, 0};
            int s = 0;
            for (int g = 0; g < total; g++) {
                int c = g & 31, u = g >> 5, slot = u & 1;
                int mt, nt, noff, nlen;
                unit_params(pair, u, mt, nt, noff, nlen);
                uint32_t idesc = (nlen == 256) ? IDESC_CG2_N256 : IDESC_CG2_N128;
                if (c == 0 && u >= 2) {
                    MBAR_WAIT(smb + SM_EPID(slot), ped[slot]); ped[slot] ^= 1;
                }
                MBAR_WAIT(smb + SM_FULL(s), pf[s]); pf[s] ^= 1;
                if (e1) {
                    uint64_t ah = mk_desc(smb + A_HI(s));
                    uint64_t al = mk_desc(smb + A_LO(s));
                    uint64_t bh = mk_desc(smb + B_HI(s));
                    uint64_t bl = mk_desc(smb + B_LO(s));
                    uint32_t dt = tmem + slot * 256;
                    #pragma unroll
                    for (int ks = 0; ks < 4; ks++)
                        mma_cg2(dt, ah + ks * 2, bh + ks * 2, idesc, (c == 0 && ks == 0) ? 0u : 1u);
                    #pragma unroll
                    for (int ks = 0; ks < 4; ks++)
                        mma_cg2(dt, ah + ks * 2, bl + ks * 2, idesc, 1u);
                    #pragma unroll
                    for (int ks = 0; ks < 4; ks++)
                        mma_cg2(dt, al + ks * 2, bh + ks * 2, idesc, 1u);
                    TC_COMMIT_MC2(smb + SM_EMPTY(s));
                    if (c == NCHUNK - 1) TC_COMMIT_MC2(smb + SM_MDONE(slot));
                }
                if (++s == NSTAGE) s = 0;
            }
        }
    } else {
        // ---------------- epilogue warps 0..3 (128 threads) ----------------
        uint32_t pm[2] = {0, 0};
        __nv_bfloat16* shi = (__nv_bfloat16*)(smem + EPI_HI);
        __nv_bfloat16* slo = (__nv_bfloat16*)(smem + EPI_LO);
        int mloc = wid * 32 + lane;
        for (int u = 0; u < my_units; u++) {
            int slot = u & 1;
            int mt, nt, noff, nlen;
            unit_params(pair, u, mt, nt, noff, nlen);
            int mg = mt * 256 + (int)rank * 128;
            int ng = nt * 256 + noff;
            int blkcnt = nlen >> 5;
            MBAR_WAIT(smb + SM_MDONE(slot), pm[slot]); pm[slot] ^= 1;
            TC_FENCE_AFTER();
            #pragma unroll 1
            for (int blk = 0; blk < blkcnt; blk++) {
                uint32_t r[32];
                TC_LD_X32(r, tmem + slot * 256 + blk * 32);
                TC_WAIT_LD();
                #pragma unroll
                for (int j = 0; j < 32; j++) {
                    float v = __uint_as_float(r[j]);
                    __nv_bfloat16 h = __float2bfloat16(v);
                    __nv_bfloat16 l = __float2bfloat16(v - __bfloat162float(h));
                    shi[j * EPI_PITCH + mloc] = h;
                    slo[j * EPI_PITCH + mloc] = l;
                }
                asm volatile("bar.sync 1, 128;" ::: "memory");
                if (write_nm) {
                    #pragma unroll
                    for (int idx = tid; idx < 512; idx += 128) {
                        int nl = idx >> 4;
                        int m8 = (idx & 15) * 8;
                        size_t ga = (size_t)(ng + blk * 32 + nl) * MDIM + mg + m8;
                        *(uint4*)(dst_hi + ga) = *(uint4*)(shi + nl * EPI_PITCH + m8);
                        *(uint4*)(dst_lo + ga) = *(uint4*)(slo + nl * EPI_PITCH + m8);
                    }
                }
                {
                    int mrow = mg + tid;
                    #pragma unroll
                    for (int j8 = 0; j8 < 32; j8 += 8) {
                        int n0 = ng + blk * 32 + j8;
                        int bb = n0 / WDIM;
                        int w = n0 - bb * WDIM;
                        uint4 uh, ul;
                        unsigned short* ph = (unsigned short*)&uh;
                        unsigned short* pl = (unsigned short*)&ul;
                        #pragma unroll
                        for (int q = 0; q < 8; q++) {
                            ph[q] = *(unsigned short*)&shi[(j8 + q) * EPI_PITCH + tid];
                            pl[q] = *(unsigned short*)&slo[(j8 + q) * EPI_PITCH + tid];
                        }
                        size_t base = ((size_t)bb * MDIM + mrow) * KWPAD + w;
                        *(uint4*)(tmT_hi + base) = uh;
                        *(uint4*)(tmT_lo + base) = ul;
                    }
                }
                asm volatile("bar.sync 1, 128;" ::: "memory");
            }
            TC_FENCE_BEFORE();
            if (tid == 0) MBAR_ARRIVE_RANK0(smb + SM_EPID(slot));
        }
    }
    __syncthreads();
    if (wid == 4) TC_DEALLOC_CG2(tmem, 512);
    CLUSTER_SYNC();
#endif
}

// ======================= persistent tensor-core fused MLP (dynamic grid) =======
// tiles t = cta, cta+G, ... < 512. W1 resident; A streamed 3-stage; TMEM 2x128 D.
#define MLF(s)    (16 + (s) * 8)
#define MLE(s)    (48 + (s) * 8)
#define MLW1F     80
#define MLMD(t)   (88 + (t) * 8)
#define MLEP(t)   (104 + (t) * 8)
#define MLA_HI(s) (1024 + (s) * 32768)
#define MLA_LO(s) (MLA_HI(s) + 16384)
#define MLW1H(c)  (1024 + 98304 + (c) * 16384)
#define MLW1L(c)  (1024 + 98304 + 49152 + (c) * 16384)
#define MLP_SMEM  (1024 + 98304 + 98304)   // 197632

__global__ __launch_bounds__(192, 1) void mlp_tc(
    const __grid_constant__ CUtensorMap mapAhi,
    const __grid_constant__ CUtensorMap mapAlo,
    const __grid_constant__ CUtensorMap mapBhi,
    const __grid_constant__ CUtensorMap mapBlo,
    const float* __restrict__ b1,
    const float* __restrict__ W2,
    const float* __restrict__ b2,
    int hop, int accum,
    float* __restrict__ out)
{
#if HAS_TC
    extern __shared__ char smem[];
    uint32_t smb = smem_u32(smem);
    int tid = threadIdx.x, wid = tid >> 5;
    int cta = blockIdx.x;
    int G = gridDim.x;
    int ntiles = (511 - cta) / G + 1;

    if (wid == 4) { TC_ALLOC(smb + SM_TMEMPTR, 256); TC_RELINQ(); }
    if (tid == 0) {
        #pragma unroll
        for (int s = 0; s < 3; s++) {
            MBAR_INIT(smb + MLF(s), 1);
            MBAR_INIT(smb + MLE(s), 1);
        }
        MBAR_INIT(smb + MLW1F, 1);
        MBAR_INIT(smb + MLMD(0), 1);
        MBAR_INIT(smb + MLMD(1), 1);
        MBAR_INIT(smb + MLEP(0), 1);
        MBAR_INIT(smb + MLEP(1), 1);
    }
    __syncthreads();
    uint32_t tmem;
    asm volatile("ld.shared.b32 %0, [%1];" : "=r"(tmem) : "r"(smb + SM_TMEMPTR));

    int total = ntiles * 3;
    if (wid == 4) {
        // ---------------- TMA producer warp ----------------
        uint32_t e1 = elect_one();
        uint32_t pe[3] = {0, 0, 0};
        if (e1) {
            MBAR_EXPECT_TX(smb + MLW1F, 98304);
            #pragma unroll
            for (int c = 0; c < 3; c++) {
                TMA_2D(smb + MLW1H(c), &mapBhi, c * 64, hop * HIDD, smb + MLW1F);
                TMA_2D(smb + MLW1L(c), &mapBlo, c * 64, hop * HIDD, smb + MLW1F);
            }
            int s = 0;
            for (int g = 0; g < total; g++) {
                if (g >= 3) { MBAR_WAIT(smb + MLE(s), pe[s]); pe[s] ^= 1; }
                int u = g / 3, c = g - u * 3;
                int t = cta + G * u;
                int arow = (t >> 4) * MDIM + (t & 15) * 128;
                MBAR_EXPECT_TX(smb + MLF(s), 32768);
                TMA_2D(smb + MLA_HI(s), &mapAhi, c * 64, arow, smb + MLF(s));
                TMA_2D(smb + MLA_LO(s), &mapAlo, c * 64, arow, smb + MLF(s));
                if (++s == 3) s = 0;
            }
        }
    } else if (wid == 5) {
        // ---------------- MMA consumer warp ----------------
        uint32_t e1 = elect_one();
        uint32_t pf[3] = {0, 0, 0}, ped[2] = {0, 0};
        MBAR_WAIT(smb + MLW1F, 0);
        int s = 0;
        for (int g = 0; g < total; g++) {
            int u = g / 3, c = g - u * 3, slot = u & 1;
            if (c == 0 && u >= 2) {
                MBAR_WAIT(smb + MLEP(slot), ped[slot]); ped[slot] ^= 1;
            }
            MBAR_WAIT(smb + MLF(s), pf[s]); pf[s] ^= 1;
            if (e1) {
                uint64_t ah = mk_desc(smb + MLA_HI(s));
                uint64_t al = mk_desc(smb + MLA_LO(s));
                uint64_t bh = mk_desc(smb + MLW1H(c));
                uint64_t bl = mk_desc(smb + MLW1L(c));
                uint32_t dt = tmem + slot * 128;
                #pragma unroll
                for (int ks = 0; ks < 4; ks++)
                    mma_128(dt, ah + ks * 2, bh + ks * 2, (c == 0 && ks == 0) ? 0u : 1u);
                #pragma unroll
                for (int ks = 0; ks < 4; ks++)
                    mma_128(dt, ah + ks * 2, bl + ks * 2, 1u);
                #pragma unroll
                for (int ks = 0; ks < 4; ks++)
                    mma_128(dt, al + ks * 2, bh + ks * 2, 1u);
                TC_COMMIT(smb + MLE(s));
                if (c == 2) TC_COMMIT(smb + MLMD(slot));
            }
            if (++s == 3) s = 0;
        }
    } else {
        // ---------------- epilogue warps 0..3 (128 threads), lane = m ----------------
        uint32_t pm[2] = {0, 0};
        const float* b1h = b1 + hop * HIDD;
        const float* W2h = W2 + hop * HIDD;
        float b2v = b2[hop];
        for (int u = 0; u < ntiles; u++) {
            int slot = u & 1;
            int t = cta + G * u;
            int gi = (t >> 4) * MDIM + (t & 15) * 128 + tid;
            MBAR_WAIT(smb + MLMD(slot), pm[slot]); pm[slot] ^= 1;
            TC_FENCE_AFTER();
            float s = 0.f;
            #pragma unroll 1
            for (int cb = 0; cb < 4; cb++) {
                uint32_t r[32];
                TC_LD_X32(r, tmem + slot * 128 + cb * 32);
                TC_WAIT_LD();
                #pragma unroll
                for (int j = 0; j < 32; j++) {
                    int h = cb * 32 + j;
                    s += W2h[h] * fmaxf(__uint_as_float(r[j]) + b1h[h], 0.f);
                }
            }
            TC_FENCE_BEFORE();
            s += b2v;
            if (accum) s += out[gi];
            out[gi] = s;
            asm volatile("bar.sync 1, 128;" ::: "memory");
            if (tid == 0) MBAR_ARRIVE(smb + MLEP(slot));
        }
    }
    __syncthreads();
    if (wid == 4) TC_DEALLOC(tmem, 256);
#endif
}

// ======================= host =======================
typedef CUresult (*PFN_tmEncode)(CUtensorMap*, CUtensorMapDataType, cuuint32_t, void*,
                                 const cuuint64_t*, const cuuint64_t*, const cuuint32_t*,
                                 const cuuint32_t*, CUtensorMapInterleave, CUtensorMapSwizzle,
                                 CUtensorMapL2promotion, CUtensorMapFloatOOBfill);

static void make_map(PFN_tmEncode enc, CUtensorMap* m, void* ptr,
                     unsigned long long d0, unsigned long long d1,
                     unsigned box0, unsigned box1) {
    cuuint64_t dims[2] = {d0, d1};
    cuuint64_t strides[1] = {d0 * 2};
    cuuint32_t box[2] = {box0, box1};
    cuuint32_t es[2] = {1, 1};
    enc(m, CU_TENSOR_MAP_DATA_TYPE_BFLOAT16, 2, ptr, dims, strides, box, es,
        CU_TENSOR_MAP_INTERLEAVE_NONE, CU_TENSOR_MAP_SWIZZLE_128B,
        CU_TENSOR_MAP_L2_PROMOTION_L2_128B, CU_TENSOR_MAP_FLOAT_OOB_FILL_NONE);
}

extern "C" void kernel_launch(void* const* d_in, const int* in_sizes, int n_in,
                              void* d_out, int out_size) {
    const float* x  = (const float*)d_in[0];
    const float* L  = (const float*)d_in[1];
    const float* W1 = (const float*)d_in[2];
    const float* b1 = (const float*)d_in[3];
    const float* W2 = (const float*)d_in[4];
    const float* b2 = (const float*)d_in[5];
    float* out = (float*)d_out;

    __nv_bfloat16 *hi0, *hi1, *lo0, *lo1, *Lhi, *Llo, *W1hi, *W1lo;
    __nv_bfloat16 *tmThi0, *tmTlo0, *tmThi1, *tmTlo1;
    cudaGetSymbolAddress((void**)&hi0, g_hi);
    hi1 = hi0 + (size_t)BWCOL * MDIM;
    cudaGetSymbolAddress((void**)&lo0, g_lo);
    lo1 = lo0 + (size_t)BWCOL * MDIM;
    cudaGetSymbolAddress((void**)&Lhi, g_Lhi);
    cudaGetSymbolAddress((void**)&Llo, g_Llo);
    cudaGetSymbolAddress((void**)&W1hi, g_W1hi);
    cudaGetSymbolAddress((void**)&W1lo, g_W1lo);
    cudaGetSymbolAddress((void**)&tmThi0, g_tmThi);
    tmThi1 = tmThi0 + (size_t)BATCH * MDIM * KWPAD;
    cudaGetSymbolAddress((void**)&tmTlo0, g_tmTlo);
    tmTlo1 = tmTlo0 + (size_t)BATCH * MDIM * KWPAD;

    PFN_tmEncode enc = nullptr;
    cudaDriverEntryPointQueryResult qr;
    cudaGetDriverEntryPointByVersion("cuTensorMapEncodeTiled", (void**)&enc, 12000,
                                     cudaEnableDefault, &qr);

    CUtensorMap mAhi, mAlo, mBhi[2], mBlo[2], mBhi64[2], mBlo64[2];
    CUtensorMap mW1hi, mW1lo, mTmhi[2], mTmlo[2];
    make_map(enc, &mAhi, Lhi, MDIM, MDIM, 64, 128);
    make_map(enc, &mAlo, Llo, MDIM, MDIM, 64, 128);
    make_map(enc, &mBhi[0], hi0, MDIM, BWCOL, 64, 128);
    make_map(enc, &mBhi[1], hi1, MDIM, BWCOL, 64, 128);
    make_map(enc, &mBlo[0], lo0, MDIM, BWCOL, 64, 128);
    make_map(enc, &mBlo[1], lo1, MDIM, BWCOL, 64, 128);
    make_map(enc, &mBhi64[0], hi0, MDIM, BWCOL, 64, 64);
    make_map(enc, &mBhi64[1], hi1, MDIM, BWCOL, 64, 64);
    make_map(enc, &mBlo64[0], lo0, MDIM, BWCOL, 64, 64);
    make_map(enc, &mBlo64[1], lo1, MDIM, BWCOL, 64, 64);
    make_map(enc, &mW1hi, W1hi, KWPAD, (NHOPS + 1) * HIDD, 64, 128);
    make_map(enc, &mW1lo, W1lo, KWPAD, (NHOPS + 1) * HIDD, 64, 128);
    make_map(enc, &mTmhi[0], tmThi0, KWPAD, (unsigned long long)BATCH * MDIM, 64, 128);
    make_map(enc, &mTmhi[1], tmThi1, KWPAD, (unsigned long long)BATCH * MDIM, 64, 128);
    make_map(enc, &mTmlo[0], tmTlo0, KWPAD, (unsigned long long)BATCH * MDIM, 64, 128);
    make_map(enc, &mTmlo[1], tmTlo1, KWPAD, (unsigned long long)BATCH * MDIM, 64, 128);

    cudaFuncSetAttribute(gemm_tc, cudaFuncAttributeMaxDynamicSharedMemorySize, TC_SMEM);
    cudaFuncSetAttribute(mlp_tc, cudaFuncAttributeMaxDynamicSharedMemorySize, MLP_SMEM);

    __nv_bfloat16* tmThiS[2] = {tmThi0, tmThi1};
    __nv_bfloat16* tmTloS[2] = {tmTlo0, tmTlo1};

    cudaStream_t s1;
    cudaStreamCreateWithFlags(&s1, cudaStreamNonBlocking);
    cudaEvent_t eG[NHOPS + 1], eM[NHOPS + 1];
    for (int i = 0; i <= NHOPS; i++) {
        cudaEventCreateWithFlags(&eG[i], cudaEventDisableTiming);
        cudaEventCreateWithFlags(&eM[i], cudaEventDisableTiming);
    }

    {
        dim3 tg(MDIM / 32, KWPAD / 32, BATCH), tb(32, 8);
        prep_kernel<<<tg, tb>>>(x, hi0, lo0, tmThi0, tmTlo0);   // tmT slot 0
        int n4 = (MDIM * MDIM) / 4;
        split_kernel<<<(n4 + 255) / 256, 256>>>(L, Lhi, Llo, n4);
        int nw = (NHOPS + 1) * HIDD * KWPAD;
        splitW1_kernel<<<(nw + 255) / 256, 256>>>(W1, W1hi, W1lo);
    }

    // hop 0 MLP on side stream, 12 CTAs (co-resident with gemm(1)'s 136 CTAs)
    cudaEventRecord(eG[0], 0);
    cudaStreamWaitEvent(s1, eG[0], 0);
    mlp_tc<<<12, 192, MLP_SMEM, s1>>>(mTmhi[0], mTmlo[0], mW1hi, mW1lo,
                                      b1, W2, b2, 0, 0, out);
    cudaEventRecord(eM[0], s1);

    for (int hop = 1; hop <= NHOPS; hop++) {
        int src = (hop + 1) & 1;
        int dst = hop & 1;
        int slot = hop & 1;
        if (hop >= 2) cudaStreamWaitEvent(0, eM[hop - 2], 0);
        gemm_tc<<<2 * NPAIRS, 192, TC_SMEM>>>(mAhi, mAlo, mBhi[src], mBlo[src],
                                              mBhi64[src], mBlo64[src],
                                              dst ? hi1 : hi0, dst ? lo1 : lo0,
                                              tmThiS[slot], tmTloS[slot],
                                              hop < NHOPS ? 1 : 0);
        cudaEventRecord(eG[hop], 0);
        cudaStreamWaitEvent(s1, eG[hop], 0);
        // hops 1..5: 12-CTA persistent mlp hidden under next gemm; last hop full width
        int mgrid = (hop < NHOPS) ? 12 : 128;
        mlp_tc<<<mgrid, 192, MLP_SMEM, s1>>>(mTmhi[slot], mTmlo[slot], mW1hi, mW1lo,
                                             b1, W2, b2, hop, 1, out);
        cudaEventRecord(eM[hop], s1);
    }
    cudaStreamWaitEvent(0, eM[NHOPS], 0);
}

// round 15
// speedup vs baseline: 10.0864x; 1.0127x over previous
#include <cuda_runtime.h>
#include <cuda_bf16.h>
#include <cuda.h>
#include <cstdint>

#define BATCH 32
#define WDIM  168
#define MDIM  2048
#define HIDD  128
#define NHOPS 6
#define BWCOL (BATCH * WDIM)   // 5376
#define KWPAD 192

#if defined(__CUDA_ARCH__) && defined(__CUDA_ARCH_FEAT_SM103_ALL)
#define HAS_TC 1
#else
#define HAS_TC 0
#endif

// t stored TRANSPOSED: T[n][m], m contiguous (GEMM B operand). Split bf16 hi/lo.
__device__ __align__(1024) __nv_bfloat16 g_hi[2][(size_t)BWCOL * MDIM];
__device__ __align__(1024) __nv_bfloat16 g_lo[2][(size_t)BWCOL * MDIM];
__device__ __align__(1024) __nv_bfloat16 g_Lhi[(size_t)MDIM * MDIM];
__device__ __align__(1024) __nv_bfloat16 g_Llo[(size_t)MDIM * MDIM];
// m-major copy for MLP A operand: tmT[slot][b][m][wpad], double-buffered for hop overlap
__device__ __align__(1024) __nv_bfloat16 g_tmThi[2][(size_t)BATCH * MDIM * KWPAD];
__device__ __align__(1024) __nv_bfloat16 g_tmTlo[2][(size_t)BATCH * MDIM * KWPAD];
// W1 split, zero-padded K: [hop][128][192]
__device__ __align__(1024) __nv_bfloat16 g_W1hi[(NHOPS + 1) * HIDD * KWPAD];
__device__ __align__(1024) __nv_bfloat16 g_W1lo[(NHOPS + 1) * HIDD * KWPAD];

// ======================= common helpers =======================
__device__ __forceinline__ uint32_t smem_u32(const void* p) {
    uint32_t a;
    asm("{ .reg .u64 t; cvta.to.shared.u64 t, %1; cvt.u32.u64 %0, t; }" : "=r"(a) : "l"(p));
    return a;
}

// ======================= splits =======================
__global__ void split_kernel(const float* __restrict__ in, __nv_bfloat16* __restrict__ hi,
                             __nv_bfloat16* __restrict__ lo, int n4) {
    int i = blockIdx.x * blockDim.x + threadIdx.x;
    if (i >= n4) return;
    float4 v = ((const float4*)in)[i];
    __nv_bfloat16 h[4], l[4];
    float vv[4] = {v.x, v.y, v.z, v.w};
    #pragma unroll
    for (int j = 0; j < 4; j++) {
        h[j] = __float2bfloat16(vv[j]);
        l[j] = __float2bfloat16(vv[j] - __bfloat162float(h[j]));
    }
    ((ushort4*)hi)[i] = make_ushort4(*(unsigned short*)&h[0], *(unsigned short*)&h[1],
                                     *(unsigned short*)&h[2], *(unsigned short*)&h[3]);
    ((ushort4*)lo)[i] = make_ushort4(*(unsigned short*)&l[0], *(unsigned short*)&l[1],
                                     *(unsigned short*)&l[2], *(unsigned short*)&l[3]);
}

__global__ void splitW1_kernel(const float* __restrict__ W1, __nv_bfloat16* __restrict__ hi,
                               __nv_bfloat16* __restrict__ lo) {
    int i = blockIdx.x * blockDim.x + threadIdx.x;
    if (i >= (NHOPS + 1) * HIDD * KWPAD) return;
    int w = i % KWPAD;
    int hh = i / KWPAD;
    float v = (w < WDIM) ? W1[hh * WDIM + w] : 0.f;
    __nv_bfloat16 h = __float2bfloat16(v);
    hi[i] = h;
    lo[i] = __float2bfloat16(v - __bfloat162float(h));
}

// fused prologue: x[b][w][m] -> hi0/lo0 [n=b*W+w][m] AND tmT[b][m][wpad] (w>=168 zero)
__global__ void prep_kernel(const float* __restrict__ x,
                            __nv_bfloat16* __restrict__ hi0,
                            __nv_bfloat16* __restrict__ lo0,
                            __nv_bfloat16* __restrict__ thi,
                            __nv_bfloat16* __restrict__ tlo) {
    __shared__ __nv_bfloat16 th[32][33], tl[32][33];
    int m0 = blockIdx.x * 32, w0 = blockIdx.y * 32, b = blockIdx.z;
    int tx = threadIdx.x, ty = threadIdx.y;
    #pragma unroll
    for (int i = ty; i < 32; i += 8) {
        int w = w0 + i;
        float v = (w < WDIM) ? x[((size_t)b * WDIM + w) * MDIM + m0 + tx] : 0.f;
        __nv_bfloat16 h = __float2bfloat16(v);
        __nv_bfloat16 l = __float2bfloat16(v - __bfloat162float(h));
        th[i][tx] = h;
        tl[i][tx] = l;
        if (w < WDIM) {
            size_t gi = ((size_t)b * WDIM + w) * MDIM + m0 + tx;
            hi0[gi] = h;
            lo0[gi] = l;
        }
    }
    __syncthreads();
    // vectorized tmT: 128 items of (m-row, 8 consecutive w) -> uint4 stores
    int t = ty * 32 + tx;
    if (t < 128) {
        int row = t >> 2;
        int wg = (t & 3) * 8;
        uint4 uh, ul;
        unsigned short* ph = (unsigned short*)&uh;
        unsigned short* pl = (unsigned short*)&ul;
        #pragma unroll
        for (int q = 0; q < 8; q++) {
            ph[q] = *(unsigned short*)&th[wg + q][row];
            pl[q] = *(unsigned short*)&tl[wg + q][row];
        }
        size_t base = ((size_t)b * MDIM + m0 + row) * KWPAD + w0 + wg;
        *(uint4*)(thi + base) = uh;
        *(uint4*)(tlo + base) = ul;
    }
}

// ======================= tcgen05 macros ('a' targets only) =======================
#if HAS_TC
__device__ __forceinline__ uint32_t elect_one() {
    uint32_t p;
    asm volatile("{ .reg .pred p; elect.sync _|p, 0xFFFFFFFF; selp.b32 %0, 1, 0, p; }" : "=r"(p));
    return p;
}
#define MBAR_INIT(a, c) asm volatile("mbarrier.init.shared.b64 [%0], %1;" :: "r"(a), "r"(c) : "memory")
#define MBAR_EXPECT_TX(a, b) asm volatile("mbarrier.arrive.expect_tx.shared.b64 _, [%0], %1;" :: "r"(a), "r"(b) : "memory")
#define MBAR_ARRIVE(a) asm volatile("mbarrier.arrive.shared.b64 _, [%0];" :: "r"(a) : "memory")
#define MBAR_WAIT(a, ph) do { \
    uint32_t _m = (a), _p = (ph), _d; \
    asm volatile("{ .reg .pred p; mbarrier.try_wait.parity.acquire.cta.shared::cta.b64 p, [%1], %2; selp.b32 %0,1,0,p; }" \
        : "=r"(_d) : "r"(_m), "r"(_p) : "memory"); \
    if (!_d) { asm volatile("{ .reg .pred P1; WL%=: mbarrier.try_wait.parity.acquire.cta.shared::cta.b64 P1, [%0], %1, 0x989680; @P1 bra.uni WD%=; bra.uni WL%=; WD%=: }" \
        :: "r"(_m), "r"(_p) : "memory"); } \
} while (0)
#define MBAR_ARRIVE_RANK0(a) \
    asm volatile("{ .reg .b32 ra; mapa.shared::cluster.u32 ra, %0, 0; mbarrier.arrive.shared::cluster.b64 _, [ra]; }" \
        :: "r"(a) : "memory")
#define TMA_2D(sm, map, cx, cy, mb) \
    asm volatile("cp.async.bulk.tensor.2d.shared::cta.global.tile.mbarrier::complete_tx::bytes [%0], [%1, {%2, %3}], [%4];" \
        :: "r"(sm), "l"(map), "r"(cx), "r"(cy), "r"(mb) : "memory")
#define TMA_2D_CG2(sm, map, cx, cy, mb) \
    asm volatile("{ .reg .b32 lb; and.b32 lb, %4, 0xFEFFFFFF;\n\t" \
        "cp.async.bulk.tensor.2d.cta_group::2.shared::cluster.global.tile.mbarrier::complete_tx::bytes " \
        "[%0], [%1, {%2, %3}], [lb]; }" \
        :: "r"(sm), "l"(map), "r"(cx), "r"(cy), "r"(mb) : "memory")
#define TC_ALLOC(smaddr, n)      asm volatile("tcgen05.alloc.cta_group::1.sync.aligned.shared::cta.b32 [%0], %1;" :: "r"(smaddr), "r"(n) : "memory")
#define TC_RELINQ()              asm volatile("tcgen05.relinquish_alloc_permit.cta_group::1.sync.aligned;")
#define TC_DEALLOC(t, n)         asm volatile("tcgen05.dealloc.cta_group::1.sync.aligned.b32 %0, %1;" :: "r"(t), "r"(n))
#define TC_COMMIT(mb)            asm volatile("tcgen05.commit.cta_group::1.mbarrier::arrive::one.shared::cluster.b64 [%0];" :: "r"(mb) : "memory")
#define TC_ALLOC_CG2(smaddr, n)  asm volatile("tcgen05.alloc.cta_group::2.sync.aligned.shared::cta.b32 [%0], %1;" :: "r"(smaddr), "r"(n) : "memory")
#define TC_RELINQ_CG2()          asm volatile("tcgen05.relinquish_alloc_permit.cta_group::2.sync.aligned;")
#define TC_DEALLOC_CG2(t, n)     asm volatile("tcgen05.dealloc.cta_group::2.sync.aligned.b32 %0, %1;" :: "r"(t), "r"(n))
#define TC_COMMIT_MC2(mb) \
    asm volatile("tcgen05.commit.cta_group::2.mbarrier::arrive::one.shared::cluster.multicast::cluster.b64 [%0], %1;" \
        :: "r"(mb), "h"((unsigned short)0x3) : "memory")
#define TC_FENCE_AFTER()      asm volatile("tcgen05.fence::after_thread_sync;" ::: "memory")
#define TC_FENCE_BEFORE()     asm volatile("tcgen05.fence::before_thread_sync;" ::: "memory")
#define TC_WAIT_LD()          asm volatile("tcgen05.wait::ld.sync.aligned;" ::: "memory")
#define TC_LD_X32(r, addr) \
    asm volatile("tcgen05.ld.sync.aligned.32x32b.x32.b32 " \
        "{%0,%1,%2,%3,%4,%5,%6,%7,%8,%9,%10,%11,%12,%13,%14,%15," \
        "%16,%17,%18,%19,%20,%21,%22,%23,%24,%25,%26,%27,%28,%29,%30,%31}, [%32];" \
        : "=r"((r)[0]),"=r"((r)[1]),"=r"((r)[2]),"=r"((r)[3]),"=r"((r)[4]),"=r"((r)[5]),"=r"((r)[6]),"=r"((r)[7]), \
          "=r"((r)[8]),"=r"((r)[9]),"=r"((r)[10]),"=r"((r)[11]),"=r"((r)[12]),"=r"((r)[13]),"=r"((r)[14]),"=r"((r)[15]), \
          "=r"((r)[16]),"=r"((r)[17]),"=r"((r)[18]),"=r"((r)[19]),"=r"((r)[20]),"=r"((r)[21]),"=r"((r)[22]),"=r"((r)[23]), \
          "=r"((r)[24]),"=r"((r)[25]),"=r"((r)[26]),"=r"((r)[27]),"=r"((r)[28]),"=r"((r)[29]),"=r"((r)[30]),"=r"((r)[31]) \
        : "r"(addr))
#define CLUSTER_SYNC() do { \
    asm volatile("barrier.cluster.arrive.aligned;" ::: "memory"); \
    asm volatile("barrier.cluster.wait.aligned;" ::: "memory"); \
} while (0)

static constexpr uint64_t DESC_SW128 =
    (uint64_t(2) << 61) | (uint64_t(1) << 46) | (uint64_t(64) << 32) | (uint64_t(1) << 16);
__device__ __forceinline__ uint64_t mk_desc(uint32_t sm) {
    return DESC_SW128 | ((uint64_t)(sm >> 4) & 0x3FFF);
}
// kind::f16, D=F32, A=BF16, B=BF16, M=256 (cg2): N=256 / N=128 variants
#define IDESC_CG2_N256 0x10400490u
#define IDESC_CG2_N128 0x10200490u
__device__ __forceinline__ void mma_cg2(uint32_t d, uint64_t a, uint64_t b,
                                        uint32_t idesc, uint32_t en) {
    asm volatile("{ .reg .pred p; setp.ne.u32 p, %5, 0;\n\t"
        "tcgen05.mma.cta_group::2.kind::f16 [%0], %1, %2, %3, {%4,%4,%4,%4,%4,%4,%4,%4}, p; }"
        :: "r"(d), "l"(a), "l"(b), "r"(idesc), "r"(0u), "r"(en) : "memory");
}
// kind::f16, D=F32, A=BF16 K-major, B=BF16 K-major, M=128, N=128 (cg1)
#define IDESC_M128N128 0x8200490u
__device__ __forceinline__ void mma_128(uint32_t d, uint64_t a, uint64_t b, uint32_t en) {
    asm volatile("{ .reg .pred p; setp.ne.u32 p, %5, 0;\n\t"
        "tcgen05.mma.cta_group::1.kind::f16 [%0], %1, %2, %3, {%4,%4,%4,%4}, p; }"
        :: "r"(d), "l"(a), "l"(b), "r"(IDESC_M128N128), "r"(0u), "r"(en) : "memory");
}
#endif // HAS_TC

// ======================= persistent cg2 propagation GEMM (68 pairs = 136 SMs) ==========
#define KCHUNK 64
#define NCHUNK 32
#define NSTAGE 3
#define NPAIRS 68
#define SM_TMEMPTR 0
#define SM_FULL(s)  (16 + (s) * 8)
#define SM_EMPTY(s) (48 + (s) * 8)
#define SM_MDONE(t) (80 + (t) * 8)
#define SM_EPID(t)  (96 + (t) * 8)
#define STAGE_CTA 65536
#define SM_STAGE(s) (1024 + (s) * STAGE_CTA)
#define A_HI(s) (SM_STAGE(s))
#define A_LO(s) (SM_STAGE(s) + 16384)
#define B_HI(s) (SM_STAGE(s) + 32768)
#define B_LO(s) (SM_STAGE(s) + 49152)
#define EPI_PITCH 136
#define EPI_BYTES (32 * EPI_PITCH * 2)
#define EPI_HI (1024 + NSTAGE * STAGE_CTA)
#define EPI_LO (EPI_HI + EPI_BYTES)
#define TC_SMEM (EPI_LO + EPI_BYTES)

// balanced: units 0,1 = full tiles (pair, pair+68); unit 2 (pairs<64) = half of
// tile 136+(pair>>1), n-offset (pair&1)*128, N=128.
#if HAS_TC
__device__ __forceinline__ void unit_params(int pair, int u, int& mt, int& nt,
                                            int& noff, int& nlen) {
    int t = (u == 0) ? pair : ((u == 1) ? pair + NPAIRS : 136 + (pair >> 1));
    mt = t & 7;
    nt = t >> 3;
    noff = (u < 2) ? 0 : ((pair & 1) * 128);
    nlen = (u < 2) ? 256 : 128;
}
#endif

__global__ __launch_bounds__(192, 1) __cluster_dims__(2, 1, 1) void gemm_tc(
    const __grid_constant__ CUtensorMap mapAhi,
    const __grid_constant__ CUtensorMap mapAlo,
    const __grid_constant__ CUtensorMap mapBhi,     // box 64 x 128 rows
    const __grid_constant__ CUtensorMap mapBlo,
    const __grid_constant__ CUtensorMap mapBhi64,   // box 64 x 64 rows
    const __grid_constant__ CUtensorMap mapBlo64,
    __nv_bfloat16* __restrict__ dst_hi,
    __nv_bfloat16* __restrict__ dst_lo,
    __nv_bfloat16* __restrict__ tmT_hi,
    __nv_bfloat16* __restrict__ tmT_lo,
    int write_nm)
{
#if HAS_TC
    extern __shared__ char smem[];
    uint32_t smb = smem_u32(smem);
    int tid = threadIdx.x, wid = tid >> 5, lane = tid & 31;
    uint32_t rank;
    asm("mov.u32 %0, %%cluster_ctarank;" : "=r"(rank));
    int pair = blockIdx.x >> 1;
    int my_units = 2 + (pair < 64 ? 1 : 0);
    int total = my_units * NCHUNK;

    if (wid == 4) { TC_ALLOC_CG2(smb + SM_TMEMPTR, 512); TC_RELINQ_CG2(); }
    if (tid == 0) {
        #pragma unroll
        for (int s = 0; s < NSTAGE; s++) {
            MBAR_INIT(smb + SM_FULL(s), 1);
            MBAR_INIT(smb + SM_EMPTY(s), 1);
        }
        MBAR_INIT(smb + SM_MDONE(0), 1);
        MBAR_INIT(smb + SM_MDONE(1), 1);
        MBAR_INIT(smb + SM_EPID(0), 2);
        MBAR_INIT(smb + SM_EPID(1), 2);
    }
    __syncthreads();
    CLUSTER_SYNC();

    uint32_t tmem;
    asm volatile("ld.shared.b32 %0, [%1];" : "=r"(tmem) : "r"(smb + SM_TMEMPTR));

    if (wid == 4) {
        // ---------------- TMA producer warp (both ranks) ----------------
        uint32_t e1 = elect_one();
        uint32_t pe[NSTAGE] = {0, 0, 0};
        if (e1) {
            int s = 0;
            for (int g = 0; g < total; g++) {
                if (g >= NSTAGE) { MBAR_WAIT(smb + SM_EMPTY(s), pe[s]); pe[s] ^= 1; }
                int u = g >> 5, c = g & 31;
                int mt, nt, noff, nlen;
                unit_params(pair, u, mt, nt, noff, nlen);
                int k0 = c * KCHUNK;
                int ma = mt * 256 + (int)rank * 128;
                int nb = nt * 256 + noff + (int)rank * (nlen >> 1);
                if (rank == 0) {
                    uint32_t tx = 65536u + (uint32_t)nlen * 256u;
                    MBAR_EXPECT_TX(smb + SM_FULL(s), tx);
                }
                TMA_2D_CG2(smb + A_HI(s), &mapAhi, k0, ma, smb + SM_FULL(s));
                TMA_2D_CG2(smb + A_LO(s), &mapAlo, k0, ma, smb + SM_FULL(s));
                if (nlen == 256) {
                    TMA_2D_CG2(smb + B_HI(s), &mapBhi, k0, nb, smb + SM_FULL(s));
                    TMA_2D_CG2(smb + B_LO(s), &mapBlo, k0, nb, smb + SM_FULL(s));
                } else {
                    TMA_2D_CG2(smb + B_HI(s), &mapBhi64, k0, nb, smb + SM_FULL(s));
                    TMA_2D_CG2(smb + B_LO(s), &mapBlo64, k0, nb, smb + SM_FULL(s));
                }
                if (++s == NSTAGE) s = 0;
            }
        }
    } else if (wid == 5) {
        // ---------------- MMA consumer warp (rank 0 only) ----------------
        if (rank == 0) {
            uint32_t e1 = elect_one();
            uint32_t pf[NSTAGE] = {0, 0, 0}, ped[2] = {0, 0};
            int s = 0;
            for (int g = 0; g < total; g++) {
                int c = g & 31, u = g >> 5, slot = u & 1;
                int mt, nt, noff, nlen;
                unit_params(pair, u, mt, nt, noff, nlen);
                uint32_t idesc = (nlen == 256) ? IDESC_CG2_N256 : IDESC_CG2_N128;
                if (c == 0 && u >= 2) {
                    MBAR_WAIT(smb + SM_EPID(slot), ped[slot]); ped[slot] ^= 1;
                }
                MBAR_WAIT(smb + SM_FULL(s), pf[s]); pf[s] ^= 1;
                if (e1) {
                    uint64_t ah = mk_desc(smb + A_HI(s));
                    uint64_t al = mk_desc(smb + A_LO(s));
                    uint64_t bh = mk_desc(smb + B_HI(s));
                    uint64_t bl = mk_desc(smb + B_LO(s));
                    uint32_t dt = tmem + slot * 256;
                    #pragma unroll
                    for (int ks = 0; ks < 4; ks++)
                        mma_cg2(dt, ah + ks * 2, bh + ks * 2, idesc, (c == 0 && ks == 0) ? 0u : 1u);
                    #pragma unroll
                    for (int ks = 0; ks < 4; ks++)
                        mma_cg2(dt, ah + ks * 2, bl + ks * 2, idesc, 1u);
                    #pragma unroll
                    for (int ks = 0; ks < 4; ks++)
                        mma_cg2(dt, al + ks * 2, bh + ks * 2, idesc, 1u);
                    TC_COMMIT_MC2(smb + SM_EMPTY(s));
                    if (c == NCHUNK - 1) TC_COMMIT_MC2(smb + SM_MDONE(slot));
                }
                if (++s == NSTAGE) s = 0;
            }
        }
    } else {
        // ---------------- epilogue warps 0..3 (128 threads) ----------------
        uint32_t pm[2] = {0, 0};
        __nv_bfloat16* shi = (__nv_bfloat16*)(smem + EPI_HI);
        __nv_bfloat16* slo = (__nv_bfloat16*)(smem + EPI_LO);
        int mloc = wid * 32 + lane;
        for (int u = 0; u < my_units; u++) {
            int slot = u & 1;
            int mt, nt, noff, nlen;
            unit_params(pair, u, mt, nt, noff, nlen);
            int mg = mt * 256 + (int)rank * 128;
            int ng = nt * 256 + noff;
            int blkcnt = nlen >> 5;
            MBAR_WAIT(smb + SM_MDONE(slot), pm[slot]); pm[slot] ^= 1;
            TC_FENCE_AFTER();
            #pragma unroll 1
            for (int blk = 0; blk < blkcnt; blk++) {
                uint32_t r[32];
                TC_LD_X32(r, tmem + slot * 256 + blk * 32);
                TC_WAIT_LD();
                #pragma unroll
                for (int j = 0; j < 32; j++) {
                    float v = __uint_as_float(r[j]);
                    __nv_bfloat16 h = __float2bfloat16(v);
                    __nv_bfloat16 l = __float2bfloat16(v - __bfloat162float(h));
                    shi[j * EPI_PITCH + mloc] = h;
                    slo[j * EPI_PITCH + mloc] = l;
                }
                asm volatile("bar.sync 1, 128;" ::: "memory");
                if (write_nm) {
                    #pragma unroll
                    for (int idx = tid; idx < 512; idx += 128) {
                        int nl = idx >> 4;
                        int m8 = (idx & 15) * 8;
                        size_t ga = (size_t)(ng + blk * 32 + nl) * MDIM + mg + m8;
                        *(uint4*)(dst_hi + ga) = *(uint4*)(shi + nl * EPI_PITCH + m8);
                        *(uint4*)(dst_lo + ga) = *(uint4*)(slo + nl * EPI_PITCH + m8);
                    }
                }
                {
                    int mrow = mg + tid;
                    #pragma unroll
                    for (int j8 = 0; j8 < 32; j8 += 8) {
                        int n0 = ng + blk * 32 + j8;
                        int bb = n0 / WDIM;
                        int w = n0 - bb * WDIM;
                        uint4 uh, ul;
                        unsigned short* ph = (unsigned short*)&uh;
                        unsigned short* pl = (unsigned short*)&ul;
                        #pragma unroll
                        for (int q = 0; q < 8; q++) {
                            ph[q] = *(unsigned short*)&shi[(j8 + q) * EPI_PITCH + tid];
                            pl[q] = *(unsigned short*)&slo[(j8 + q) * EPI_PITCH + tid];
                        }
                        size_t base = ((size_t)bb * MDIM + mrow) * KWPAD + w;
                        *(uint4*)(tmT_hi + base) = uh;
                        *(uint4*)(tmT_lo + base) = ul;
                    }
                }
                asm volatile("bar.sync 1, 128;" ::: "memory");
            }
            TC_FENCE_BEFORE();
            if (tid == 0) MBAR_ARRIVE_RANK0(smb + SM_EPID(slot));
        }
    }
    __syncthreads();
    if (wid == 4) TC_DEALLOC_CG2(tmem, 512);
    CLUSTER_SYNC();
#endif
}

// ======================= persistent tensor-core fused MLP (dynamic grid) =======
// tiles t = cta, cta+G, ... < 512. W1 resident; A streamed 3-stage; TMEM 2x128 D.
// K = 168 <= 176: chunk 2 only needs 3 K16 MMAs per term (zero-padded operands).
#define MLF(s)    (16 + (s) * 8)
#define MLE(s)    (48 + (s) * 8)
#define MLW1F     80
#define MLMD(t)   (88 + (t) * 8)
#define MLEP(t)   (104 + (t) * 8)
#define MLA_HI(s) (1024 + (s) * 32768)
#define MLA_LO(s) (MLA_HI(s) + 16384)
#define MLW1H(c)  (1024 + 98304 + (c) * 16384)
#define MLW1L(c)  (1024 + 98304 + 49152 + (c) * 16384)
#define MLP_SMEM  (1024 + 98304 + 98304)   // 197632

__global__ __launch_bounds__(192, 1) void mlp_tc(
    const __grid_constant__ CUtensorMap mapAhi,
    const __grid_constant__ CUtensorMap mapAlo,
    const __grid_constant__ CUtensorMap mapBhi,
    const __grid_constant__ CUtensorMap mapBlo,
    const float* __restrict__ b1,
    const float* __restrict__ W2,
    const float* __restrict__ b2,
    int hop, int accum,
    float* __restrict__ out)
{
#if HAS_TC
    extern __shared__ char smem[];
    uint32_t smb = smem_u32(smem);
    int tid = threadIdx.x, wid = tid >> 5;
    int cta = blockIdx.x;
    int G = gridDim.x;
    int ntiles = (511 - cta) / G + 1;

    if (wid == 4) { TC_ALLOC(smb + SM_TMEMPTR, 256); TC_RELINQ(); }
    if (tid == 0) {
        #pragma unroll
        for (int s = 0; s < 3; s++) {
            MBAR_INIT(smb + MLF(s), 1);
            MBAR_INIT(smb + MLE(s), 1);
        }
        MBAR_INIT(smb + MLW1F, 1);
        MBAR_INIT(smb + MLMD(0), 1);
        MBAR_INIT(smb + MLMD(1), 1);
        MBAR_INIT(smb + MLEP(0), 1);
        MBAR_INIT(smb + MLEP(1), 1);
    }
    __syncthreads();
    uint32_t tmem;
    asm volatile("ld.shared.b32 %0, [%1];" : "=r"(tmem) : "r"(smb + SM_TMEMPTR));

    int total = ntiles * 3;
    if (wid == 4) {
        // ---------------- TMA producer warp ----------------
        uint32_t e1 = elect_one();
        uint32_t pe[3] = {0, 0, 0};
        if (e1) {
            MBAR_EXPECT_TX(smb + MLW1F, 98304);
            #pragma unroll
            for (int c = 0; c < 3; c++) {
                TMA_2D(smb + MLW1H(c), &mapBhi, c * 64, hop * HIDD, smb + MLW1F);
                TMA_2D(smb + MLW1L(c), &mapBlo, c * 64, hop * HIDD, smb + MLW1F);
            }
            int s = 0;
            for (int g = 0; g < total; g++) {
                if (g >= 3) { MBAR_WAIT(smb + MLE(s), pe[s]); pe[s] ^= 1; }
                int u = g / 3, c = g - u * 3;
                int t = cta + G * u;
                int arow = (t >> 4) * MDIM + (t & 15) * 128;
                MBAR_EXPECT_TX(smb + MLF(s), 32768);
                TMA_2D(smb + MLA_HI(s), &mapAhi, c * 64, arow, smb + MLF(s));
                TMA_2D(smb + MLA_LO(s), &mapAlo, c * 64, arow, smb + MLF(s));
                if (++s == 3) s = 0;
            }
        }
    } else if (wid == 5) {
        // ---------------- MMA consumer warp ----------------
        uint32_t e1 = elect_one();
        uint32_t pf[3] = {0, 0, 0}, ped[2] = {0, 0};
        MBAR_WAIT(smb + MLW1F, 0);
        int s = 0;
        for (int g = 0; g < total; g++) {
            int u = g / 3, c = g - u * 3, slot = u & 1;
            if (c == 0 && u >= 2) {
                MBAR_WAIT(smb + MLEP(slot), ped[slot]); ped[slot] ^= 1;
            }
            MBAR_WAIT(smb + MLF(s), pf[s]); pf[s] ^= 1;
            if (e1) {
                uint64_t ah = mk_desc(smb + MLA_HI(s));
                uint64_t al = mk_desc(smb + MLA_LO(s));
                uint64_t bh = mk_desc(smb + MLW1H(c));
                uint64_t bl = mk_desc(smb + MLW1L(c));
                uint32_t dt = tmem + slot * 128;
                int nks = (c == 2) ? 3 : 4;   // K=168 fits in 176
                for (int ks = 0; ks < nks; ks++)
                    mma_128(dt, ah + ks * 2, bh + ks * 2, (c == 0 && ks == 0) ? 0u : 1u);
                for (int ks = 0; ks < nks; ks++)
                    mma_128(dt, ah + ks * 2, bl + ks * 2, 1u);
                for (int ks = 0; ks < nks; ks++)
                    mma_128(dt, al + ks * 2, bh + ks * 2, 1u);
                TC_COMMIT(smb + MLE(s));
                if (c == 2) TC_COMMIT(smb + MLMD(slot));
            }
            if (++s == 3) s = 0;
        }
    } else {
        // ---------------- epilogue warps 0..3 (128 threads), lane = m ----------------
        uint32_t pm[2] = {0, 0};
        const float* b1h = b1 + hop * HIDD;
        const float* W2h = W2 + hop * HIDD;
        float b2v = b2[hop];
        for (int u = 0; u < ntiles; u++) {
            int slot = u & 1;
            int t = cta + G * u;
            int gi = (t >> 4) * MDIM + (t & 15) * 128 + tid;
            MBAR_WAIT(smb + MLMD(slot), pm[slot]); pm[slot] ^= 1;
            TC_FENCE_AFTER();
            float s = 0.f;
            #pragma unroll 1
            for (int cb = 0; cb < 4; cb++) {
                uint32_t r[32];
                TC_LD_X32(r, tmem + slot * 128 + cb * 32);
                TC_WAIT_LD();
                #pragma unroll
                for (int j = 0; j < 32; j++) {
                    int h = cb * 32 + j;
                    s += W2h[h] * fmaxf(__uint_as_float(r[j]) + b1h[h], 0.f);
                }
            }
            TC_FENCE_BEFORE();
            s += b2v;
            if (accum) s += out[gi];
            out[gi] = s;
            asm volatile("bar.sync 1, 128;" ::: "memory");
            if (tid == 0) MBAR_ARRIVE(smb + MLEP(slot));
        }
    }
    __syncthreads();
    if (wid == 4) TC_DEALLOC(tmem, 256);
#endif
}

// ======================= host =======================
typedef CUresult (*PFN_tmEncode)(CUtensorMap*, CUtensorMapDataType, cuuint32_t, void*,
                                 const cuuint64_t*, const cuuint64_t*, const cuuint32_t*,
                                 const cuuint32_t*, CUtensorMapInterleave, CUtensorMapSwizzle,
                                 CUtensorMapL2promotion, CUtensorMapFloatOOBfill);

static void make_map(PFN_tmEncode enc, CUtensorMap* m, void* ptr,
                     unsigned long long d0, unsigned long long d1,
                     unsigned box0, unsigned box1) {
    cuuint64_t dims[2] = {d0, d1};
    cuuint64_t strides[1] = {d0 * 2};
    cuuint32_t box[2] = {box0, box1};
    cuuint32_t es[2] = {1, 1};
    enc(m, CU_TENSOR_MAP_DATA_TYPE_BFLOAT16, 2, ptr, dims, strides, box, es,
        CU_TENSOR_MAP_INTERLEAVE_NONE, CU_TENSOR_MAP_SWIZZLE_128B,
        CU_TENSOR_MAP_L2_PROMOTION_L2_128B, CU_TENSOR_MAP_FLOAT_OOB_FILL_NONE);
}

extern "C" void kernel_launch(void* const* d_in, const int* in_sizes, int n_in,
                              void* d_out, int out_size) {
    const float* x  = (const float*)d_in[0];
    const float* L  = (const float*)d_in[1];
    const float* W1 = (const float*)d_in[2];
    const float* b1 = (const float*)d_in[3];
    const float* W2 = (const float*)d_in[4];
    const float* b2 = (const float*)d_in[5];
    float* out = (float*)d_out;

    __nv_bfloat16 *hi0, *hi1, *lo0, *lo1, *Lhi, *Llo, *W1hi, *W1lo;
    __nv_bfloat16 *tmThi0, *tmTlo0, *tmThi1, *tmTlo1;
    cudaGetSymbolAddress((void**)&hi0, g_hi);
    hi1 = hi0 + (size_t)BWCOL * MDIM;
    cudaGetSymbolAddress((void**)&lo0, g_lo);
    lo1 = lo0 + (size_t)BWCOL * MDIM;
    cudaGetSymbolAddress((void**)&Lhi, g_Lhi);
    cudaGetSymbolAddress((void**)&Llo, g_Llo);
    cudaGetSymbolAddress((void**)&W1hi, g_W1hi);
    cudaGetSymbolAddress((void**)&W1lo, g_W1lo);
    cudaGetSymbolAddress((void**)&tmThi0, g_tmThi);
    tmThi1 = tmThi0 + (size_t)BATCH * MDIM * KWPAD;
    cudaGetSymbolAddress((void**)&tmTlo0, g_tmTlo);
    tmTlo1 = tmTlo0 + (size_t)BATCH * MDIM * KWPAD;

    PFN_tmEncode enc = nullptr;
    cudaDriverEntryPointQueryResult qr;
    cudaGetDriverEntryPointByVersion("cuTensorMapEncodeTiled", (void**)&enc, 12000,
                                     cudaEnableDefault, &qr);

    CUtensorMap mAhi, mAlo, mBhi[2], mBlo[2], mBhi64[2], mBlo64[2];
    CUtensorMap mW1hi, mW1lo, mTmhi[2], mTmlo[2];
    make_map(enc, &mAhi, Lhi, MDIM, MDIM, 64, 128);
    make_map(enc, &mAlo, Llo, MDIM, MDIM, 64, 128);
    make_map(enc, &mBhi[0], hi0, MDIM, BWCOL, 64, 128);
    make_map(enc, &mBhi[1], hi1, MDIM, BWCOL, 64, 128);
    make_map(enc, &mBlo[0], lo0, MDIM, BWCOL, 64, 128);
    make_map(enc, &mBlo[1], lo1, MDIM, BWCOL, 64, 128);
    make_map(enc, &mBhi64[0], hi0, MDIM, BWCOL, 64, 64);
    make_map(enc, &mBhi64[1], hi1, MDIM, BWCOL, 64, 64);
    make_map(enc, &mBlo64[0], lo0, MDIM, BWCOL, 64, 64);
    make_map(enc, &mBlo64[1], lo1, MDIM, BWCOL, 64, 64);
    make_map(enc, &mW1hi, W1hi, KWPAD, (NHOPS + 1) * HIDD, 64, 128);
    make_map(enc, &mW1lo, W1lo, KWPAD, (NHOPS + 1) * HIDD, 64, 128);
    make_map(enc, &mTmhi[0], tmThi0, KWPAD, (unsigned long long)BATCH * MDIM, 64, 128);
    make_map(enc, &mTmhi[1], tmThi1, KWPAD, (unsigned long long)BATCH * MDIM, 64, 128);
    make_map(enc, &mTmlo[0], tmTlo0, KWPAD, (unsigned long long)BATCH * MDIM, 64, 128);
    make_map(enc, &mTmlo[1], tmTlo1, KWPAD, (unsigned long long)BATCH * MDIM, 64, 128);

    cudaFuncSetAttribute(gemm_tc, cudaFuncAttributeMaxDynamicSharedMemorySize, TC_SMEM);
    cudaFuncSetAttribute(mlp_tc, cudaFuncAttributeMaxDynamicSharedMemorySize, MLP_SMEM);

    __nv_bfloat16* tmThiS[2] = {tmThi0, tmThi1};
    __nv_bfloat16* tmTloS[2] = {tmTlo0, tmTlo1};

    cudaStream_t s1;
    cudaStreamCreateWithFlags(&s1, cudaStreamNonBlocking);
    cudaEvent_t eG[NHOPS + 1], eM[NHOPS + 1], eP, eL, eS;
    for (int i = 0; i <= NHOPS; i++) {
        cudaEventCreateWithFlags(&eG[i], cudaEventDisableTiming);
        cudaEventCreateWithFlags(&eM[i], cudaEventDisableTiming);
    }
    cudaEventCreateWithFlags(&eP, cudaEventDisableTiming);
    cudaEventCreateWithFlags(&eL, cudaEventDisableTiming);
    cudaEventCreateWithFlags(&eS, cudaEventDisableTiming);

    // prologue fork: s1 must be forked FROM the capture-origin stream first
    {
        cudaEventRecord(eS, 0);
        cudaStreamWaitEvent(s1, eS, 0);   // legal fork into capture

        int n4 = (MDIM * MDIM) / 4;
        split_kernel<<<(n4 + 255) / 256, 256, 0, s1>>>(L, Lhi, Llo, n4);
        int nw = (NHOPS + 1) * HIDD * KWPAD;
        splitW1_kernel<<<(nw + 255) / 256, 256, 0, s1>>>(W1, W1hi, W1lo);
        cudaEventRecord(eL, s1);

        dim3 tg(MDIM / 32, KWPAD / 32, BATCH), tb(32, 8);
        prep_kernel<<<tg, tb>>>(x, hi0, lo0, tmThi0, tmTlo0);   // stream 0
        cudaEventRecord(eP, 0);
        cudaStreamWaitEvent(0, eL, 0);    // gemm(1) needs Lhi/Llo
    }

    // hop 0 MLP on side stream, 12 CTAs (co-resident with gemm(1)'s 136 CTAs)
    cudaStreamWaitEvent(s1, eP, 0);       // needs tmT slot 0 (W1 split already on s1)
    mlp_tc<<<12, 192, MLP_SMEM, s1>>>(mTmhi[0], mTmlo[0], mW1hi, mW1lo,
                                      b1, W2, b2, 0, 0, out);
    cudaEventRecord(eM[0], s1);

    for (int hop = 1; hop <= NHOPS; hop++) {
        int src = (hop + 1) & 1;
        int dst = hop & 1;
        int slot = hop & 1;
        if (hop >= 2) cudaStreamWaitEvent(0, eM[hop - 2], 0);
        gemm_tc<<<2 * NPAIRS, 192, TC_SMEM>>>(mAhi, mAlo, mBhi[src], mBlo[src],
                                              mBhi64[src], mBlo64[src],
                                              dst ? hi1 : hi0, dst ? lo1 : lo0,
                                              tmThiS[slot], tmTloS[slot],
                                              hop < NHOPS ? 1 : 0);
        cudaEventRecord(eG[hop], 0);
        cudaStreamWaitEvent(s1, eG[hop], 0);
        int mgrid = (hop < NHOPS) ? 12 : 128;
        mlp_tc<<<mgrid, 192, MLP_SMEM, s1>>>(mTmhi[slot], mTmlo[slot], mW1hi, mW1lo,
                                             b1, W2, b2, hop, 1, out);
        cudaEventRecord(eM[hop], s1);
    }
    cudaStreamWaitEvent(0, eM[NHOPS], 0);
}

// round 16
// speedup vs baseline: 10.1333x; 1.0047x over previous
#include <cuda_runtime.h>
#include <cuda_bf16.h>
#include <cuda.h>
#include <cstdint>

#define BATCH 32
#define WDIM  168
#define MDIM  2048
#define HIDD  128
#define NHOPS 6
#define BWCOL (BATCH * WDIM)   // 5376
#define KWPAD 192

#if defined(__CUDA_ARCH__) && defined(__CUDA_ARCH_FEAT_SM103_ALL)
#define HAS_TC 1
#else
#define HAS_TC 0
#endif

// t stored TRANSPOSED: T[n][m], m contiguous (GEMM B operand). Split bf16 hi/lo.
__device__ __align__(1024) __nv_bfloat16 g_hi[2][(size_t)BWCOL * MDIM];
__device__ __align__(1024) __nv_bfloat16 g_lo[2][(size_t)BWCOL * MDIM];
__device__ __align__(1024) __nv_bfloat16 g_Lhi[(size_t)MDIM * MDIM];
__device__ __align__(1024) __nv_bfloat16 g_Llo[(size_t)MDIM * MDIM];
// m-major copy for MLP A operand: tmT[slot][b][m][wpad], double-buffered for hop overlap
__device__ __align__(1024) __nv_bfloat16 g_tmThi[2][(size_t)BATCH * MDIM * KWPAD];
__device__ __align__(1024) __nv_bfloat16 g_tmTlo[2][(size_t)BATCH * MDIM * KWPAD];
// W1 split, zero-padded K: [hop][128][192]
__device__ __align__(1024) __nv_bfloat16 g_W1hi[(NHOPS + 1) * HIDD * KWPAD];
__device__ __align__(1024) __nv_bfloat16 g_W1lo[(NHOPS + 1) * HIDD * KWPAD];
// device-side sync flags (reset every kernel_launch call)
__device__ unsigned g_bar;
__device__ unsigned g_mflag[8];

// ======================= common helpers =======================
__device__ __forceinline__ uint32_t smem_u32(const void* p) {
    uint32_t a;
    asm("{ .reg .u64 t; cvta.to.shared.u64 t, %1; cvt.u32.u64 %0, t; }" : "=r"(a) : "l"(p));
    return a;
}
__device__ __forceinline__ void spin_ge(unsigned* p, unsigned target) {
    for (int i = 0; i < 2000000; i++) {           // ~200ms bound: never trips live
        if (atomicAdd(p, 0u) >= target) return;
        __nanosleep(100);
    }
}

__global__ void reset_kernel() {
    g_bar = 0;
    #pragma unroll
    for (int i = 0; i < 8; i++) g_mflag[i] = 0;
}

// ======================= splits =======================
__global__ void split_kernel(const float* __restrict__ in, __nv_bfloat16* __restrict__ hi,
                             __nv_bfloat16* __restrict__ lo, int n4) {
    int i = blockIdx.x * blockDim.x + threadIdx.x;
    if (i >= n4) return;
    float4 v = ((const float4*)in)[i];
    __nv_bfloat16 h[4], l[4];
    float vv[4] = {v.x, v.y, v.z, v.w};
    #pragma unroll
    for (int j = 0; j < 4; j++) {
        h[j] = __float2bfloat16(vv[j]);
        l[j] = __float2bfloat16(vv[j] - __bfloat162float(h[j]));
    }
    ((ushort4*)hi)[i] = make_ushort4(*(unsigned short*)&h[0], *(unsigned short*)&h[1],
                                     *(unsigned short*)&h[2], *(unsigned short*)&h[3]);
    ((ushort4*)lo)[i] = make_ushort4(*(unsigned short*)&l[0], *(unsigned short*)&l[1],
                                     *(unsigned short*)&l[2], *(unsigned short*)&l[3]);
}

__global__ void splitW1_kernel(const float* __restrict__ W1, __nv_bfloat16* __restrict__ hi,
                               __nv_bfloat16* __restrict__ lo) {
    int i = blockIdx.x * blockDim.x + threadIdx.x;
    if (i >= (NHOPS + 1) * HIDD * KWPAD) return;
    int w = i % KWPAD;
    int hh = i / KWPAD;
    float v = (w < WDIM) ? W1[hh * WDIM + w] : 0.f;
    __nv_bfloat16 h = __float2bfloat16(v);
    hi[i] = h;
    lo[i] = __float2bfloat16(v - __bfloat162float(h));
}

// fused prologue: x[b][w][m] -> hi0/lo0 [n=b*W+w][m] AND tmT[b][m][wpad] (w>=168 zero)
__global__ void prep_kernel(const float* __restrict__ x,
                            __nv_bfloat16* __restrict__ hi0,
                            __nv_bfloat16* __restrict__ lo0,
                            __nv_bfloat16* __restrict__ thi,
                            __nv_bfloat16* __restrict__ tlo) {
    __shared__ __nv_bfloat16 th[32][33], tl[32][33];
    int m0 = blockIdx.x * 32, w0 = blockIdx.y * 32, b = blockIdx.z;
    int tx = threadIdx.x, ty = threadIdx.y;
    #pragma unroll
    for (int i = ty; i < 32; i += 8) {
        int w = w0 + i;
        float v = (w < WDIM) ? x[((size_t)b * WDIM + w) * MDIM + m0 + tx] : 0.f;
        __nv_bfloat16 h = __float2bfloat16(v);
        __nv_bfloat16 l = __float2bfloat16(v - __bfloat162float(h));
        th[i][tx] = h;
        tl[i][tx] = l;
        if (w < WDIM) {
            size_t gi = ((size_t)b * WDIM + w) * MDIM + m0 + tx;
            hi0[gi] = h;
            lo0[gi] = l;
        }
    }
    __syncthreads();
    int t = ty * 32 + tx;
    if (t < 128) {
        int row = t >> 2;
        int wg = (t & 3) * 8;
        uint4 uh, ul;
        unsigned short* ph = (unsigned short*)&uh;
        unsigned short* pl = (unsigned short*)&ul;
        #pragma unroll
        for (int q = 0; q < 8; q++) {
            ph[q] = *(unsigned short*)&th[wg + q][row];
            pl[q] = *(unsigned short*)&tl[wg + q][row];
        }
        size_t base = ((size_t)b * MDIM + m0 + row) * KWPAD + w0 + wg;
        *(uint4*)(thi + base) = uh;
        *(uint4*)(tlo + base) = ul;
    }
}

// ======================= tcgen05 macros ('a' targets only) =======================
#if HAS_TC
__device__ __forceinline__ uint32_t elect_one() {
    uint32_t p;
    asm volatile("{ .reg .pred p; elect.sync _|p, 0xFFFFFFFF; selp.b32 %0, 1, 0, p; }" : "=r"(p));
    return p;
}
#define MBAR_INIT(a, c) asm volatile("mbarrier.init.shared.b64 [%0], %1;" :: "r"(a), "r"(c) : "memory")
#define MBAR_EXPECT_TX(a, b) asm volatile("mbarrier.arrive.expect_tx.shared.b64 _, [%0], %1;" :: "r"(a), "r"(b) : "memory")
#define MBAR_ARRIVE(a) asm volatile("mbarrier.arrive.shared.b64 _, [%0];" :: "r"(a) : "memory")
#define MBAR_WAIT(a, ph) do { \
    uint32_t _m = (a), _p = (ph), _d; \
    asm volatile("{ .reg .pred p; mbarrier.try_wait.parity.acquire.cta.shared::cta.b64 p, [%1], %2; selp.b32 %0,1,0,p; }" \
        : "=r"(_d) : "r"(_m), "r"(_p) : "memory"); \
    if (!_d) { asm volatile("{ .reg .pred P1; WL%=: mbarrier.try_wait.parity.acquire.cta.shared::cta.b64 P1, [%0], %1, 0x989680; @P1 bra.uni WD%=; bra.uni WL%=; WD%=: }" \
        :: "r"(_m), "r"(_p) : "memory"); } \
} while (0)
#define MBAR_ARRIVE_RANK0(a) \
    asm volatile("{ .reg .b32 ra; mapa.shared::cluster.u32 ra, %0, 0; mbarrier.arrive.shared::cluster.b64 _, [ra]; }" \
        :: "r"(a) : "memory")
#define TMA_2D(sm, map, cx, cy, mb) \
    asm volatile("cp.async.bulk.tensor.2d.shared::cta.global.tile.mbarrier::complete_tx::bytes [%0], [%1, {%2, %3}], [%4];" \
        :: "r"(sm), "l"(map), "r"(cx), "r"(cy), "r"(mb) : "memory")
#define TMA_2D_CG2(sm, map, cx, cy, mb) \
    asm volatile("{ .reg .b32 lb; and.b32 lb, %4, 0xFEFFFFFF;\n\t" \
        "cp.async.bulk.tensor.2d.cta_group::2.shared::cluster.global.tile.mbarrier::complete_tx::bytes " \
        "[%0], [%1, {%2, %3}], [lb]; }" \
        :: "r"(sm), "l"(map), "r"(cx), "r"(cy), "r"(mb) : "memory")
#define TC_ALLOC(smaddr, n)      asm volatile("tcgen05.alloc.cta_group::1.sync.aligned.shared::cta.b32 [%0], %1;" :: "r"(smaddr), "r"(n) : "memory")
#define TC_RELINQ()              asm volatile("tcgen05.relinquish_alloc_permit.cta_group::1.sync.aligned;")
#define TC_DEALLOC(t, n)         asm volatile("tcgen05.dealloc.cta_group::1.sync.aligned.b32 %0, %1;" :: "r"(t), "r"(n))
#define TC_COMMIT(mb)            asm volatile("tcgen05.commit.cta_group::1.mbarrier::arrive::one.shared::cluster.b64 [%0];" :: "r"(mb) : "memory")
#define TC_ALLOC_CG2(smaddr, n)  asm volatile("tcgen05.alloc.cta_group::2.sync.aligned.shared::cta.b32 [%0], %1;" :: "r"(smaddr), "r"(n) : "memory")
#define TC_RELINQ_CG2()          asm volatile("tcgen05.relinquish_alloc_permit.cta_group::2.sync.aligned;")
#define TC_DEALLOC_CG2(t, n)     asm volatile("tcgen05.dealloc.cta_group::2.sync.aligned.b32 %0, %1;" :: "r"(t), "r"(n))
#define TC_COMMIT_MC2(mb) \
    asm volatile("tcgen05.commit.cta_group::2.mbarrier::arrive::one.shared::cluster.multicast::cluster.b64 [%0], %1;" \
        :: "r"(mb), "h"((unsigned short)0x3) : "memory")
#define TC_FENCE_AFTER()      asm volatile("tcgen05.fence::after_thread_sync;" ::: "memory")
#define TC_FENCE_BEFORE()     asm volatile("tcgen05.fence::before_thread_sync;" ::: "memory")
#define TC_WAIT_LD()          asm volatile("tcgen05.wait::ld.sync.aligned;" ::: "memory")
#define TC_LD_X32(r, addr) \
    asm volatile("tcgen05.ld.sync.aligned.32x32b.x32.b32 " \
        "{%0,%1,%2,%3,%4,%5,%6,%7,%8,%9,%10,%11,%12,%13,%14,%15," \
        "%16,%17,%18,%19,%20,%21,%22,%23,%24,%25,%26,%27,%28,%29,%30,%31}, [%32];" \
        : "=r"((r)[0]),"=r"((r)[1]),"=r"((r)[2]),"=r"((r)[3]),"=r"((r)[4]),"=r"((r)[5]),"=r"((r)[6]),"=r"((r)[7]), \
          "=r"((r)[8]),"=r"((r)[9]),"=r"((r)[10]),"=r"((r)[11]),"=r"((r)[12]),"=r"((r)[13]),"=r"((r)[14]),"=r"((r)[15]), \
          "=r"((r)[16]),"=r"((r)[17]),"=r"((r)[18]),"=r"((r)[19]),"=r"((r)[20]),"=r"((r)[21]),"=r"((r)[22]),"=r"((r)[23]), \
          "=r"((r)[24]),"=r"((r)[25]),"=r"((r)[26]),"=r"((r)[27]),"=r"((r)[28]),"=r"((r)[29]),"=r"((r)[30]),"=r"((r)[31]) \
        : "r"(addr))
#define CLUSTER_SYNC() do { \
    asm volatile("barrier.cluster.arrive.aligned;" ::: "memory"); \
    asm volatile("barrier.cluster.wait.aligned;" ::: "memory"); \
} while (0)

static constexpr uint64_t DESC_SW128 =
    (uint64_t(2) << 61) | (uint64_t(1) << 46) | (uint64_t(64) << 32) | (uint64_t(1) << 16);
__device__ __forceinline__ uint64_t mk_desc(uint32_t sm) {
    return DESC_SW128 | ((uint64_t)(sm >> 4) & 0x3FFF);
}
#define IDESC_CG2_N256 0x10400490u
#define IDESC_CG2_N128 0x10200490u
__device__ __forceinline__ void mma_cg2(uint32_t d, uint64_t a, uint64_t b,
                                        uint32_t idesc, uint32_t en) {
    asm volatile("{ .reg .pred p; setp.ne.u32 p, %5, 0;\n\t"
        "tcgen05.mma.cta_group::2.kind::f16 [%0], %1, %2, %3, {%4,%4,%4,%4,%4,%4,%4,%4}, p; }"
        :: "r"(d), "l"(a), "l"(b), "r"(idesc), "r"(0u), "r"(en) : "memory");
}
#define IDESC_M128N128 0x8200490u
__device__ __forceinline__ void mma_128(uint32_t d, uint64_t a, uint64_t b, uint32_t en) {
    asm volatile("{ .reg .pred p; setp.ne.u32 p, %5, 0;\n\t"
        "tcgen05.mma.cta_group::1.kind::f16 [%0], %1, %2, %3, {%4,%4,%4,%4}, p; }"
        :: "r"(d), "l"(a), "l"(b), "r"(IDESC_M128N128), "r"(0u), "r"(en) : "memory");
}

// grid-wide hop barrier: all 192 threads of every gemm CTA participate
__device__ __forceinline__ void hop_barrier(int h) {
    __threadfence();
    asm volatile("bar.sync 0, 192;" ::: "memory");
    if (threadIdx.x == 0) {
        atomicAdd(&g_bar, 1u);
        spin_ge(&g_bar, 136u * (unsigned)h);
    }
    asm volatile("bar.sync 0, 192;" ::: "memory");
    __threadfence();
    asm volatile("fence.proxy.async;" ::: "memory");
}
#endif // HAS_TC

// ======================= persistent cg2 propagation GEMM: 6 hops in ONE launch =========
#define KCHUNK 64
#define NCHUNK 32
#define NSTAGE 3
#define NPAIRS 68
#define SM_TMEMPTR 0
#define SM_FULL(s)  (16 + (s) * 8)
#define SM_EMPTY(s) (48 + (s) * 8)
#define SM_MDONE(t) (80 + (t) * 8)
#define SM_EPID(t)  (96 + (t) * 8)
#define STAGE_CTA 65536
#define SM_STAGE(s) (1024 + (s) * STAGE_CTA)
#define A_HI(s) (SM_STAGE(s))
#define A_LO(s) (SM_STAGE(s) + 16384)
#define B_HI(s) (SM_STAGE(s) + 32768)
#define B_LO(s) (SM_STAGE(s) + 49152)
#define EPI_PITCH 136
#define EPI_BYTES (32 * EPI_PITCH * 2)
#define EPI_HI (1024 + NSTAGE * STAGE_CTA)
#define EPI_LO (EPI_HI + EPI_BYTES)
#define TC_SMEM (EPI_LO + EPI_BYTES)

#if HAS_TC
__device__ __forceinline__ void unit_params(int pair, int u, int& mt, int& nt,
                                            int& noff, int& nlen) {
    int t = (u == 0) ? pair : ((u == 1) ? pair + NPAIRS : 136 + (pair >> 1));
    mt = t & 7;
    nt = t >> 3;
    noff = (u < 2) ? 0 : ((pair & 1) * 128);
    nlen = (u < 2) ? 256 : 128;
}
#endif

__global__ __launch_bounds__(192, 1) __cluster_dims__(2, 1, 1) void gemm_tc(
    const __grid_constant__ CUtensorMap mapAhi,
    const __grid_constant__ CUtensorMap mapAlo,
    const __grid_constant__ CUtensorMap mapBhi0,    // buffer0 as src, box 64x128
    const __grid_constant__ CUtensorMap mapBlo0,
    const __grid_constant__ CUtensorMap mapBhi0q,   // buffer0, box 64x64
    const __grid_constant__ CUtensorMap mapBlo0q,
    const __grid_constant__ CUtensorMap mapBhi1,    // buffer1 as src
    const __grid_constant__ CUtensorMap mapBlo1,
    const __grid_constant__ CUtensorMap mapBhi1q,
    const __grid_constant__ CUtensorMap mapBlo1q,
    __nv_bfloat16* __restrict__ hi0, __nv_bfloat16* __restrict__ lo0,
    __nv_bfloat16* __restrict__ hi1, __nv_bfloat16* __restrict__ lo1,
    __nv_bfloat16* __restrict__ tmThi0, __nv_bfloat16* __restrict__ tmTlo0,
    __nv_bfloat16* __restrict__ tmThi1, __nv_bfloat16* __restrict__ tmTlo1)
{
#if HAS_TC
    extern __shared__ char smem[];
    uint32_t smb = smem_u32(smem);
    int tid = threadIdx.x, wid = tid >> 5, lane = tid & 31;
    uint32_t rank;
    asm("mov.u32 %0, %%cluster_ctarank;" : "=r"(rank));
    int pair = blockIdx.x >> 1;
    int my_units = 2 + (pair < 64 ? 1 : 0);
    int total = my_units * NCHUNK;

    if (wid == 4) { TC_ALLOC_CG2(smb + SM_TMEMPTR, 512); TC_RELINQ_CG2(); }
    if (tid == 0) {
        #pragma unroll
        for (int s = 0; s < NSTAGE; s++) {
            MBAR_INIT(smb + SM_FULL(s), 1);
            MBAR_INIT(smb + SM_EMPTY(s), 1);
        }
        MBAR_INIT(smb + SM_MDONE(0), 1);
        MBAR_INIT(smb + SM_MDONE(1), 1);
        MBAR_INIT(smb + SM_EPID(0), 2);
        MBAR_INIT(smb + SM_EPID(1), 2);
    }
    __syncthreads();
    CLUSTER_SYNC();

    uint32_t tmem;
    asm volatile("ld.shared.b32 %0, [%1];" : "=r"(tmem) : "r"(smb + SM_TMEMPTR));

    if (wid == 4) {
        // ---------------- TMA producer warp (both ranks), persistent over hops --------
        uint32_t e1 = elect_one();
        uint32_t pe[NSTAGE] = {0, 0, 0};
        int s = 0, gg = 0;
        for (int h = 1; h <= NHOPS; h++) {
            const CUtensorMap* bh  = (h & 1) ? &mapBhi0  : &mapBhi1;
            const CUtensorMap* bl  = (h & 1) ? &mapBlo0  : &mapBlo1;
            const CUtensorMap* bhq = (h & 1) ? &mapBhi0q : &mapBhi1q;
            const CUtensorMap* blq = (h & 1) ? &mapBlo0q : &mapBlo1q;
            if (e1) {
                for (int g = 0; g < total; g++, gg++) {
                    if (gg >= NSTAGE) { MBAR_WAIT(smb + SM_EMPTY(s), pe[s]); pe[s] ^= 1; }
                    int u = g >> 5, c = g & 31;
                    int mt, nt, noff, nlen;
                    unit_params(pair, u, mt, nt, noff, nlen);
                    int k0 = c * KCHUNK;
                    int ma = mt * 256 + (int)rank * 128;
                    int nb = nt * 256 + noff + (int)rank * (nlen >> 1);
                    if (rank == 0) {
                        uint32_t tx = 65536u + (uint32_t)nlen * 256u;
                        MBAR_EXPECT_TX(smb + SM_FULL(s), tx);
                    }
                    TMA_2D_CG2(smb + A_HI(s), &mapAhi, k0, ma, smb + SM_FULL(s));
                    TMA_2D_CG2(smb + A_LO(s), &mapAlo, k0, ma, smb + SM_FULL(s));
                    if (nlen == 256) {
                        TMA_2D_CG2(smb + B_HI(s), bh, k0, nb, smb + SM_FULL(s));
                        TMA_2D_CG2(smb + B_LO(s), bl, k0, nb, smb + SM_FULL(s));
                    } else {
                        TMA_2D_CG2(smb + B_HI(s), bhq, k0, nb, smb + SM_FULL(s));
                        TMA_2D_CG2(smb + B_LO(s), blq, k0, nb, smb + SM_FULL(s));
                    }
                    if (++s == NSTAGE) s = 0;
                }
            }
            hop_barrier(h);
        }
    } else if (wid == 5) {
        // ---------------- MMA consumer warp (rank 0 only), persistent -----------------
        uint32_t e1 = elect_one();
        uint32_t pf[NSTAGE] = {0, 0, 0}, ped0 = 0;
        int s = 0;
        for (int h = 1; h <= NHOPS; h++) {
            if (rank == 0) {
                for (int g = 0; g < total; g++) {
                    int c = g & 31, u = g >> 5, slot = u & 1;
                    int mt, nt, noff, nlen;
                    unit_params(pair, u, mt, nt, noff, nlen);
                    uint32_t idesc = (nlen == 256) ? IDESC_CG2_N256 : IDESC_CG2_N128;
                    if (c == 0 && u == 2) {   // within-hop D-slot-0 reuse
                        MBAR_WAIT(smb + SM_EPID(0), ped0); ped0 ^= 1;
                    }
                    MBAR_WAIT(smb + SM_FULL(s), pf[s]); pf[s] ^= 1;
                    if (e1) {
                        uint64_t ah = mk_desc(smb + A_HI(s));
                        uint64_t al = mk_desc(smb + A_LO(s));
                        uint64_t bh = mk_desc(smb + B_HI(s));
                        uint64_t bl = mk_desc(smb + B_LO(s));
                        uint32_t dt = tmem + slot * 256;
                        #pragma unroll
                        for (int ks = 0; ks < 4; ks++)
                            mma_cg2(dt, ah + ks * 2, bh + ks * 2, idesc, (c == 0 && ks == 0) ? 0u : 1u);
                        #pragma unroll
                        for (int ks = 0; ks < 4; ks++)
                            mma_cg2(dt, ah + ks * 2, bl + ks * 2, idesc, 1u);
                        #pragma unroll
                        for (int ks = 0; ks < 4; ks++)
                            mma_cg2(dt, al + ks * 2, bh + ks * 2, idesc, 1u);
                        TC_COMMIT_MC2(smb + SM_EMPTY(s));
                        if (c == NCHUNK - 1) TC_COMMIT_MC2(smb + SM_MDONE(slot));
                    }
                    if (++s == NSTAGE) s = 0;
                }
            }
            hop_barrier(h);
        }
    } else {
        // ---------------- epilogue warps 0..3 (128 threads), persistent ---------------
        uint32_t pm[2] = {0, 0};
        __nv_bfloat16* shi = (__nv_bfloat16*)(smem + EPI_HI);
        __nv_bfloat16* slo = (__nv_bfloat16*)(smem + EPI_LO);
        int mloc = wid * 32 + lane;
        for (int h = 1; h <= NHOPS; h++) {
            int write_nm = (h < NHOPS);
            __nv_bfloat16* dst_hi = (h & 1) ? hi1 : hi0;
            __nv_bfloat16* dst_lo = (h & 1) ? lo1 : lo0;
            __nv_bfloat16* tmT_hi = (h & 1) ? tmThi1 : tmThi0;
            __nv_bfloat16* tmT_lo = (h & 1) ? tmTlo1 : tmTlo0;
            // tmT slot is read by mlp(h-2): wait its 12 CTAs before overwriting
            if (h >= 2) {
                if (tid == 0) spin_ge(&g_mflag[h - 2], 12u);
                asm volatile("bar.sync 1, 128;" ::: "memory");
                __threadfence();
            }
            for (int u = 0; u < my_units; u++) {
                int slot = u & 1;
                int mt, nt, noff, nlen;
                unit_params(pair, u, mt, nt, noff, nlen);
                int mg = mt * 256 + (int)rank * 128;
                int ng = nt * 256 + noff;
                int blkcnt = nlen >> 5;
                MBAR_WAIT(smb + SM_MDONE(slot), pm[slot]); pm[slot] ^= 1;
                TC_FENCE_AFTER();
                #pragma unroll 1
                for (int blk = 0; blk < blkcnt; blk++) {
                    uint32_t r[32];
                    TC_LD_X32(r, tmem + slot * 256 + blk * 32);
                    TC_WAIT_LD();
                    #pragma unroll
                    for (int j = 0; j < 32; j++) {
                        float v = __uint_as_float(r[j]);
                        __nv_bfloat16 hh = __float2bfloat16(v);
                        __nv_bfloat16 ll = __float2bfloat16(v - __bfloat162float(hh));
                        shi[j * EPI_PITCH + mloc] = hh;
                        slo[j * EPI_PITCH + mloc] = ll;
                    }
                    asm volatile("bar.sync 1, 128;" ::: "memory");
                    if (write_nm) {
                        #pragma unroll
                        for (int idx = tid; idx < 512; idx += 128) {
                            int nl = idx >> 4;
                            int m8 = (idx & 15) * 8;
                            size_t ga = (size_t)(ng + blk * 32 + nl) * MDIM + mg + m8;
                            *(uint4*)(dst_hi + ga) = *(uint4*)(shi + nl * EPI_PITCH + m8);
                            *(uint4*)(dst_lo + ga) = *(uint4*)(slo + nl * EPI_PITCH + m8);
                        }
                    }
                    {
                        int mrow = mg + tid;
                        #pragma unroll
                        for (int j8 = 0; j8 < 32; j8 += 8) {
                            int n0 = ng + blk * 32 + j8;
                            int bb = n0 / WDIM;
                            int w = n0 - bb * WDIM;
                            uint4 uh, ul;
                            unsigned short* ph = (unsigned short*)&uh;
                            unsigned short* pl = (unsigned short*)&ul;
                            #pragma unroll
                            for (int q = 0; q < 8; q++) {
                                ph[q] = *(unsigned short*)&shi[(j8 + q) * EPI_PITCH + tid];
                                pl[q] = *(unsigned short*)&slo[(j8 + q) * EPI_PITCH + tid];
                            }
                            size_t base = ((size_t)bb * MDIM + mrow) * KWPAD + w;
                            *(uint4*)(tmT_hi + base) = uh;
                            *(uint4*)(tmT_lo + base) = ul;
                        }
                    }
                    asm volatile("bar.sync 1, 128;" ::: "memory");
                }
                TC_FENCE_BEFORE();
                // balanced EPID: one arrival pair per hop (only when u2 will reuse slot0)
                if (tid == 0 && u == 0 && my_units == 3)
                    MBAR_ARRIVE_RANK0(smb + SM_EPID(0));
            }
            hop_barrier(h);
        }
    }
    __syncthreads();
    if (wid == 4) TC_DEALLOC_CG2(tmem, 512);
    CLUSTER_SYNC();
#endif
}

// ======================= persistent tensor-core fused MLP (dynamic grid) =======
#define MLF(s)    (16 + (s) * 8)
#define MLE(s)    (48 + (s) * 8)
#define MLW1F     80
#define MLMD(t)   (88 + (t) * 8)
#define MLEP(t)   (104 + (t) * 8)
#define MLA_HI(s) (1024 + (s) * 32768)
#define MLA_LO(s) (MLA_HI(s) + 16384)
#define MLW1H(c)  (1024 + 98304 + (c) * 16384)
#define MLW1L(c)  (1024 + 98304 + 49152 + (c) * 16384)
#define MLP_SMEM  (1024 + 98304 + 98304)   // 197632

__global__ __launch_bounds__(192, 1) void mlp_tc(
    const __grid_constant__ CUtensorMap mapAhi,
    const __grid_constant__ CUtensorMap mapAlo,
    const __grid_constant__ CUtensorMap mapBhi,
    const __grid_constant__ CUtensorMap mapBlo,
    const float* __restrict__ b1,
    const float* __restrict__ W2,
    const float* __restrict__ b2,
    int hop, int accum,
    float* __restrict__ out)
{
#if HAS_TC
    extern __shared__ char smem[];
    uint32_t smb = smem_u32(smem);
    int tid = threadIdx.x, wid = tid >> 5;
    int cta = blockIdx.x;
    int G = gridDim.x;
    int ntiles = (511 - cta) / G + 1;

    // wait until gemm finished hop `hop` (device flag; hop 0 gated by event on host)
    if (hop >= 1) {
        if (tid == 0) spin_ge(&g_bar, 136u * (unsigned)hop);
        __syncthreads();
        __threadfence();
        asm volatile("fence.proxy.async;" ::: "memory");
    }

    if (wid == 4) { TC_ALLOC(smb + SM_TMEMPTR, 256); TC_RELINQ(); }
    if (tid == 0) {
        #pragma unroll
        for (int s = 0; s < 3; s++) {
            MBAR_INIT(smb + MLF(s), 1);
            MBAR_INIT(smb + MLE(s), 1);
        }
        MBAR_INIT(smb + MLW1F, 1);
        MBAR_INIT(smb + MLMD(0), 1);
        MBAR_INIT(smb + MLMD(1), 1);
        MBAR_INIT(smb + MLEP(0), 1);
        MBAR_INIT(smb + MLEP(1), 1);
    }
    __syncthreads();
    uint32_t tmem;
    asm volatile("ld.shared.b32 %0, [%1];" : "=r"(tmem) : "r"(smb + SM_TMEMPTR));

    int total = ntiles * 3;
    if (wid == 4) {
        uint32_t e1 = elect_one();
        uint32_t pe[3] = {0, 0, 0};
        if (e1) {
            MBAR_EXPECT_TX(smb + MLW1F, 98304);
            #pragma unroll
            for (int c = 0; c < 3; c++) {
                TMA_2D(smb + MLW1H(c), &mapBhi, c * 64, hop * HIDD, smb + MLW1F);
                TMA_2D(smb + MLW1L(c), &mapBlo, c * 64, hop * HIDD, smb + MLW1F);
            }
            int s = 0;
            for (int g = 0; g < total; g++) {
                if (g >= 3) { MBAR_WAIT(smb + MLE(s), pe[s]); pe[s] ^= 1; }
                int u = g / 3, c = g - u * 3;
                int t = cta + G * u;
                int arow = (t >> 4) * MDIM + (t & 15) * 128;
                MBAR_EXPECT_TX(smb + MLF(s), 32768);
                TMA_2D(smb + MLA_HI(s), &mapAhi, c * 64, arow, smb + MLF(s));
                TMA_2D(smb + MLA_LO(s), &mapAlo, c * 64, arow, smb + MLF(s));
                if (++s == 3) s = 0;
            }
        }
    } else if (wid == 5) {
        uint32_t e1 = elect_one();
        uint32_t pf[3] = {0, 0, 0}, ped[2] = {0, 0};
        MBAR_WAIT(smb + MLW1F, 0);
        int s = 0;
        for (int g = 0; g < total; g++) {
            int u = g / 3, c = g - u * 3, slot = u & 1;
            if (c == 0 && u >= 2) {
                MBAR_WAIT(smb + MLEP(slot), ped[slot]); ped[slot] ^= 1;
            }
            MBAR_WAIT(smb + MLF(s), pf[s]); pf[s] ^= 1;
            if (e1) {
                uint64_t ah = mk_desc(smb + MLA_HI(s));
                uint64_t al = mk_desc(smb + MLA_LO(s));
                uint64_t bh = mk_desc(smb + MLW1H(c));
                uint64_t bl = mk_desc(smb + MLW1L(c));
                uint32_t dt = tmem + slot * 128;
                int nks = (c == 2) ? 3 : 4;   // K=168 fits in 176
                for (int ks = 0; ks < nks; ks++)
                    mma_128(dt, ah + ks * 2, bh + ks * 2, (c == 0 && ks == 0) ? 0u : 1u);
                for (int ks = 0; ks < nks; ks++)
                    mma_128(dt, ah + ks * 2, bl + ks * 2, 1u);
                for (int ks = 0; ks < nks; ks++)
                    mma_128(dt, al + ks * 2, bh + ks * 2, 1u);
                TC_COMMIT(smb + MLE(s));
                if (c == 2) TC_COMMIT(smb + MLMD(slot));
            }
            if (++s == 3) s = 0;
        }
    } else {
        uint32_t pm[2] = {0, 0};
        const float* b1h = b1 + hop * HIDD;
        const float* W2h = W2 + hop * HIDD;
        float b2v = b2[hop];
        for (int u = 0; u < ntiles; u++) {
            int slot = u & 1;
            int t = cta + G * u;
            int gi = (t >> 4) * MDIM + (t & 15) * 128 + tid;
            MBAR_WAIT(smb + MLMD(slot), pm[slot]); pm[slot] ^= 1;
            TC_FENCE_AFTER();
            float s = 0.f;
            #pragma unroll 1
            for (int cb = 0; cb < 4; cb++) {
                uint32_t r[32];
                TC_LD_X32(r, tmem + slot * 128 + cb * 32);
                TC_WAIT_LD();
                #pragma unroll
                for (int j = 0; j < 32; j++) {
                    int h = cb * 32 + j;
                    s += W2h[h] * fmaxf(__uint_as_float(r[j]) + b1h[h], 0.f);
                }
            }
            TC_FENCE_BEFORE();
            s += b2v;
            if (accum) s += out[gi];
            out[gi] = s;
            asm volatile("bar.sync 1, 128;" ::: "memory");
            if (tid == 0) MBAR_ARRIVE(smb + MLEP(slot));
        }
    }
    __syncthreads();
    if (wid == 4) TC_DEALLOC(tmem, 256);
    __syncthreads();
    if (tid == 0) {           // signal: this CTA's tmT reads complete
        __threadfence();
        atomicAdd(&g_mflag[hop], 1u);
    }
#endif
}

// ======================= host =======================
typedef CUresult (*PFN_tmEncode)(CUtensorMap*, CUtensorMapDataType, cuuint32_t, void*,
                                 const cuuint64_t*, const cuuint64_t*, const cuuint32_t*,
                                 const cuuint32_t*, CUtensorMapInterleave, CUtensorMapSwizzle,
                                 CUtensorMapL2promotion, CUtensorMapFloatOOBfill);

static void make_map(PFN_tmEncode enc, CUtensorMap* m, void* ptr,
                     unsigned long long d0, unsigned long long d1,
                     unsigned box0, unsigned box1) {
    cuuint64_t dims[2] = {d0, d1};
    cuuint64_t strides[1] = {d0 * 2};
    cuuint32_t box[2] = {box0, box1};
    cuuint32_t es[2] = {1, 1};
    enc(m, CU_TENSOR_MAP_DATA_TYPE_BFLOAT16, 2, ptr, dims, strides, box, es,
        CU_TENSOR_MAP_INTERLEAVE_NONE, CU_TENSOR_MAP_SWIZZLE_128B,
        CU_TENSOR_MAP_L2_PROMOTION_L2_128B, CU_TENSOR_MAP_FLOAT_OOB_FILL_NONE);
}

extern "C" void kernel_launch(void* const* d_in, const int* in_sizes, int n_in,
                              void* d_out, int out_size) {
    const float* x  = (const float*)d_in[0];
    const float* L  = (const float*)d_in[1];
    const float* W1 = (const float*)d_in[2];
    const float* b1 = (const float*)d_in[3];
    const float* W2 = (const float*)d_in[4];
    const float* b2 = (const float*)d_in[5];
    float* out = (float*)d_out;

    __nv_bfloat16 *hi0, *hi1, *lo0, *lo1, *Lhi, *Llo, *W1hi, *W1lo;
    __nv_bfloat16 *tmThi0, *tmTlo0, *tmThi1, *tmTlo1;
    cudaGetSymbolAddress((void**)&hi0, g_hi);
    hi1 = hi0 + (size_t)BWCOL * MDIM;
    cudaGetSymbolAddress((void**)&lo0, g_lo);
    lo1 = lo0 + (size_t)BWCOL * MDIM;
    cudaGetSymbolAddress((void**)&Lhi, g_Lhi);
    cudaGetSymbolAddress((void**)&Llo, g_Llo);
    cudaGetSymbolAddress((void**)&W1hi, g_W1hi);
    cudaGetSymbolAddress((void**)&W1lo, g_W1lo);
    cudaGetSymbolAddress((void**)&tmThi0, g_tmThi);
    tmThi1 = tmThi0 + (size_t)BATCH * MDIM * KWPAD;
    cudaGetSymbolAddress((void**)&tmTlo0, g_tmTlo);
    tmTlo1 = tmTlo0 + (size_t)BATCH * MDIM * KWPAD;

    PFN_tmEncode enc = nullptr;
    cudaDriverEntryPointQueryResult qr;
    cudaGetDriverEntryPointByVersion("cuTensorMapEncodeTiled", (void**)&enc, 12000,
                                     cudaEnableDefault, &qr);

    CUtensorMap mAhi, mAlo, mBhi[2], mBlo[2], mBhiq[2], mBloq[2];
    CUtensorMap mW1hi, mW1lo, mTmhi[2], mTmlo[2];
    make_map(enc, &mAhi, Lhi, MDIM, MDIM, 64, 128);
    make_map(enc, &mAlo, Llo, MDIM, MDIM, 64, 128);
    make_map(enc, &mBhi[0], hi0, MDIM, BWCOL, 64, 128);
    make_map(enc, &mBhi[1], hi1, MDIM, BWCOL, 64, 128);
    make_map(enc, &mBlo[0], lo0, MDIM, BWCOL, 64, 128);
    make_map(enc, &mBlo[1], lo1, MDIM, BWCOL, 64, 128);
    make_map(enc, &mBhiq[0], hi0, MDIM, BWCOL, 64, 64);
    make_map(enc, &mBhiq[1], hi1, MDIM, BWCOL, 64, 64);
    make_map(enc, &mBloq[0], lo0, MDIM, BWCOL, 64, 64);
    make_map(enc, &mBloq[1], lo1, MDIM, BWCOL, 64, 64);
    make_map(enc, &mW1hi, W1hi, KWPAD, (NHOPS + 1) * HIDD, 64, 128);
    make_map(enc, &mW1lo, W1lo, KWPAD, (NHOPS + 1) * HIDD, 64, 128);
    make_map(enc, &mTmhi[0], tmThi0, KWPAD, (unsigned long long)BATCH * MDIM, 64, 128);
    make_map(enc, &mTmhi[1], tmThi1, KWPAD, (unsigned long long)BATCH * MDIM, 64, 128);
    make_map(enc, &mTmlo[0], tmTlo0, KWPAD, (unsigned long long)BATCH * MDIM, 64, 128);
    make_map(enc, &mTmlo[1], tmTlo1, KWPAD, (unsigned long long)BATCH * MDIM, 64, 128);

    cudaFuncSetAttribute(gemm_tc, cudaFuncAttributeMaxDynamicSharedMemorySize, TC_SMEM);
    cudaFuncSetAttribute(mlp_tc, cudaFuncAttributeMaxDynamicSharedMemorySize, MLP_SMEM);

    cudaStream_t s1;
    cudaStreamCreateWithFlags(&s1, cudaStreamNonBlocking);
    cudaEvent_t eP, eL, eS, eM6;
    cudaEventCreateWithFlags(&eP, cudaEventDisableTiming);
    cudaEventCreateWithFlags(&eL, cudaEventDisableTiming);
    cudaEventCreateWithFlags(&eS, cudaEventDisableTiming);
    cudaEventCreateWithFlags(&eM6, cudaEventDisableTiming);

    // stream 0: reset flags first (determinism across graph replays)
    reset_kernel<<<1, 1>>>();
    cudaEventRecord(eS, 0);
    cudaStreamWaitEvent(s1, eS, 0);   // legal fork into capture, after reset

    // s1: L and W1 splits, concurrent with prep
    {
        int n4 = (MDIM * MDIM) / 4;
        split_kernel<<<(n4 + 255) / 256, 256, 0, s1>>>(L, Lhi, Llo, n4);
        int nw = (NHOPS + 1) * HIDD * KWPAD;
        splitW1_kernel<<<(nw + 255) / 256, 256, 0, s1>>>(W1, W1hi, W1lo);
        cudaEventRecord(eL, s1);
    }
    // stream 0: prep (x -> hi0/lo0 + tmT slot 0)
    {
        dim3 tg(MDIM / 32, KWPAD / 32, BATCH), tb(32, 8);
        prep_kernel<<<tg, tb>>>(x, hi0, lo0, tmThi0, tmTlo0);
        cudaEventRecord(eP, 0);
        cudaStreamWaitEvent(0, eL, 0);    // gemm needs Lhi/Llo
    }

    // ONE persistent gemm launch covering hops 1..6 (136 CTAs; 12 SMs left for mlp)
    gemm_tc<<<2 * NPAIRS, 192, TC_SMEM>>>(
        mAhi, mAlo,
        mBhi[0], mBlo[0], mBhiq[0], mBloq[0],
        mBhi[1], mBlo[1], mBhiq[1], mBloq[1],
        hi0, lo0, hi1, lo1,
        tmThi0, tmTlo0, tmThi1, tmTlo1);

    // mlp chain on s1: hop 0 gated by prep event; hops 1..6 self-gate on g_bar
    cudaStreamWaitEvent(s1, eP, 0);
    mlp_tc<<<12, 192, MLP_SMEM, s1>>>(mTmhi[0], mTmlo[0], mW1hi, mW1lo,
                                      b1, W2, b2, 0, 0, out);
    for (int hop = 1; hop <= NHOPS; hop++) {
        int slot = hop & 1;
        int mgrid = (hop < NHOPS) ? 12 : 128;
        mlp_tc<<<mgrid, 192, MLP_SMEM, s1>>>(mTmhi[slot], mTmlo[slot], mW1hi, mW1lo,
                                             b1, W2, b2, hop, 1, out);
    }
    cudaEventRecord(eM6, s1);
    cudaStreamWaitEvent(0, eM6, 0);   // join: out complete after final MLP
}

// round 17
// speedup vs baseline: 10.3651x; 1.0229x over previous
#include <cuda_runtime.h>
#include <cuda_bf16.h>
#include <cuda.h>
#include <cstdint>

#define BATCH 32
#define WDIM  168
#define MDIM  2048
#define HIDD  128
#define NHOPS 6
#define BWCOL (BATCH * WDIM)   // 5376
#define KWPAD 192

#if defined(__CUDA_ARCH__) && defined(__CUDA_ARCH_FEAT_SM103_ALL)
#define HAS_TC 1
#else
#define HAS_TC 0
#endif

// t stored TRANSPOSED: T[n][m], m contiguous (GEMM B operand). Split bf16 hi/lo.
__device__ __align__(1024) __nv_bfloat16 g_hi[2][(size_t)BWCOL * MDIM];
__device__ __align__(1024) __nv_bfloat16 g_lo[2][(size_t)BWCOL * MDIM];
__device__ __align__(1024) __nv_bfloat16 g_Lhi[(size_t)MDIM * MDIM];
__device__ __align__(1024) __nv_bfloat16 g_Llo[(size_t)MDIM * MDIM];
// m-major copy for MLP A operand: tmT[slot][b][m][wpad], double-buffered for hop overlap
__device__ __align__(1024) __nv_bfloat16 g_tmThi[2][(size_t)BATCH * MDIM * KWPAD];
__device__ __align__(1024) __nv_bfloat16 g_tmTlo[2][(size_t)BATCH * MDIM * KWPAD];
// W1 split, zero-padded K: [hop][128][192]
__device__ __align__(1024) __nv_bfloat16 g_W1hi[(NHOPS + 1) * HIDD * KWPAD];
__device__ __align__(1024) __nv_bfloat16 g_W1lo[(NHOPS + 1) * HIDD * KWPAD];
// device-side sync flags (reset every kernel_launch call)
__device__ unsigned g_bar;
__device__ unsigned g_mflag[8];

// ======================= common helpers =======================
__device__ __forceinline__ uint32_t smem_u32(const void* p) {
    uint32_t a;
    asm("{ .reg .u64 t; cvta.to.shared.u64 t, %1; cvt.u32.u64 %0, t; }" : "=r"(a) : "l"(p));
    return a;
}
__device__ __forceinline__ void spin_ge(unsigned* p, unsigned target) {
    for (int i = 0; i < 2000000; i++) {           // ~200ms bound: never trips live
        if (atomicAdd(p, 0u) >= target) return;
        __nanosleep(100);
    }
}

__global__ void reset_kernel() {
    g_bar = 0;
    #pragma unroll
    for (int i = 0; i < 8; i++) g_mflag[i] = 0;
}

// ======================= splits =======================
__global__ void split_kernel(const float* __restrict__ in, __nv_bfloat16* __restrict__ hi,
                             __nv_bfloat16* __restrict__ lo, int n4) {
    int i = blockIdx.x * blockDim.x + threadIdx.x;
    if (i >= n4) return;
    float4 v = ((const float4*)in)[i];
    __nv_bfloat16 h[4], l[4];
    float vv[4] = {v.x, v.y, v.z, v.w};
    #pragma unroll
    for (int j = 0; j < 4; j++) {
        h[j] = __float2bfloat16(vv[j]);
        l[j] = __float2bfloat16(vv[j] - __bfloat162float(h[j]));
    }
    ((ushort4*)hi)[i] = make_ushort4(*(unsigned short*)&h[0], *(unsigned short*)&h[1],
                                     *(unsigned short*)&h[2], *(unsigned short*)&h[3]);
    ((ushort4*)lo)[i] = make_ushort4(*(unsigned short*)&l[0], *(unsigned short*)&l[1],
                                     *(unsigned short*)&l[2], *(unsigned short*)&l[3]);
}

__global__ void splitW1_kernel(const float* __restrict__ W1, __nv_bfloat16* __restrict__ hi,
                               __nv_bfloat16* __restrict__ lo) {
    int i = blockIdx.x * blockDim.x + threadIdx.x;
    if (i >= (NHOPS + 1) * HIDD * KWPAD) return;
    int w = i % KWPAD;
    int hh = i / KWPAD;
    float v = (w < WDIM) ? W1[hh * WDIM + w] : 0.f;
    __nv_bfloat16 h = __float2bfloat16(v);
    hi[i] = h;
    lo[i] = __float2bfloat16(v - __bfloat162float(h));
}

// fused prologue (vectorized): x[b][w][m] -> hi0/lo0 [n][m] AND tmT[b][m][wpad].
// Tile: 32 w x 64 m per block, 256 threads, float4 loads / uint4 stores.
__global__ void prep_kernel(const float* __restrict__ x,
                            __nv_bfloat16* __restrict__ hi0,
                            __nv_bfloat16* __restrict__ lo0,
                            __nv_bfloat16* __restrict__ thi,
                            __nv_bfloat16* __restrict__ tlo) {
    __shared__ __align__(16) __nv_bfloat16 th[32 * 72], tl[32 * 72];
    int m0 = blockIdx.x * 64, w0 = blockIdx.y * 32, b = blockIdx.z;
    int t = threadIdx.x;
    // pass 1: w = t>>3 (0..31), mg = (t&7)*8
    int w = t >> 3;
    int mg = (t & 7) * 8;
    int gw = w0 + w;
    float4 v0 = make_float4(0.f, 0.f, 0.f, 0.f), v1 = v0;
    if (gw < WDIM) {
        const float4* src = (const float4*)(x + ((size_t)b * WDIM + gw) * MDIM + m0 + mg);
        v0 = src[0];
        v1 = src[1];
    }
    float vv[8] = {v0.x, v0.y, v0.z, v0.w, v1.x, v1.y, v1.z, v1.w};
    uint4 uh, ul;
    unsigned short* ph = (unsigned short*)&uh;
    unsigned short* pl = (unsigned short*)&ul;
    #pragma unroll
    for (int q = 0; q < 8; q++) {
        __nv_bfloat16 h = __float2bfloat16(vv[q]);
        __nv_bfloat16 l = __float2bfloat16(vv[q] - __bfloat162float(h));
        ph[q] = *(unsigned short*)&h;
        pl[q] = *(unsigned short*)&l;
    }
    if (gw < WDIM) {
        size_t gi = ((size_t)b * WDIM + gw) * MDIM + m0 + mg;
        *(uint4*)(hi0 + gi) = uh;
        *(uint4*)(lo0 + gi) = ul;
    }
    *(uint4*)(th + w * 72 + mg) = uh;
    *(uint4*)(tl + w * 72 + mg) = ul;
    __syncthreads();
    // pass 2: row = t>>2 (0..63 m), wg = (t&3)*8; gather 8 w per m -> uint4
    int row = t >> 2;
    int wg = (t & 3) * 8;
    uint4 oh, ol;
    unsigned short* qh = (unsigned short*)&oh;
    unsigned short* ql = (unsigned short*)&ol;
    #pragma unroll
    for (int q = 0; q < 8; q++) {
        qh[q] = *(unsigned short*)&th[(wg + q) * 72 + row];
        ql[q] = *(unsigned short*)&tl[(wg + q) * 72 + row];
    }
    size_t base = ((size_t)b * MDIM + m0 + row) * KWPAD + w0 + wg;
    *(uint4*)(thi + base) = oh;
    *(uint4*)(tlo + base) = ol;
}

// ======================= tcgen05 macros ('a' targets only) =======================
#if HAS_TC
__device__ __forceinline__ uint32_t elect_one() {
    uint32_t p;
    asm volatile("{ .reg .pred p; elect.sync _|p, 0xFFFFFFFF; selp.b32 %0, 1, 0, p; }" : "=r"(p));
    return p;
}
#define MBAR_INIT(a, c) asm volatile("mbarrier.init.shared.b64 [%0], %1;" :: "r"(a), "r"(c) : "memory")
#define MBAR_EXPECT_TX(a, b) asm volatile("mbarrier.arrive.expect_tx.shared.b64 _, [%0], %1;" :: "r"(a), "r"(b) : "memory")
#define MBAR_ARRIVE(a) asm volatile("mbarrier.arrive.shared.b64 _, [%0];" :: "r"(a) : "memory")
#define MBAR_WAIT(a, ph) do { \
    uint32_t _m = (a), _p = (ph), _d; \
    asm volatile("{ .reg .pred p; mbarrier.try_wait.parity.acquire.cta.shared::cta.b64 p, [%1], %2; selp.b32 %0,1,0,p; }" \
        : "=r"(_d) : "r"(_m), "r"(_p) : "memory"); \
    if (!_d) { asm volatile("{ .reg .pred P1; WL%=: mbarrier.try_wait.parity.acquire.cta.shared::cta.b64 P1, [%0], %1, 0x989680; @P1 bra.uni WD%=; bra.uni WL%=; WD%=: }" \
        :: "r"(_m), "r"(_p) : "memory"); } \
} while (0)
#define MBAR_ARRIVE_RANK0(a) \
    asm volatile("{ .reg .b32 ra; mapa.shared::cluster.u32 ra, %0, 0; mbarrier.arrive.shared::cluster.b64 _, [ra]; }" \
        :: "r"(a) : "memory")
#define TMA_2D(sm, map, cx, cy, mb) \
    asm volatile("cp.async.bulk.tensor.2d.shared::cta.global.tile.mbarrier::complete_tx::bytes [%0], [%1, {%2, %3}], [%4];" \
        :: "r"(sm), "l"(map), "r"(cx), "r"(cy), "r"(mb) : "memory")
#define TMA_2D_CG2(sm, map, cx, cy, mb) \
    asm volatile("{ .reg .b32 lb; and.b32 lb, %4, 0xFEFFFFFF;\n\t" \
        "cp.async.bulk.tensor.2d.cta_group::2.shared::cluster.global.tile.mbarrier::complete_tx::bytes " \
        "[%0], [%1, {%2, %3}], [lb]; }" \
        :: "r"(sm), "l"(map), "r"(cx), "r"(cy), "r"(mb) : "memory")
#define TC_ALLOC(smaddr, n)      asm volatile("tcgen05.alloc.cta_group::1.sync.aligned.shared::cta.b32 [%0], %1;" :: "r"(smaddr), "r"(n) : "memory")
#define TC_RELINQ()              asm volatile("tcgen05.relinquish_alloc_permit.cta_group::1.sync.aligned;")
#define TC_DEALLOC(t, n)         asm volatile("tcgen05.dealloc.cta_group::1.sync.aligned.b32 %0, %1;" :: "r"(t), "r"(n))
#define TC_COMMIT(mb)            asm volatile("tcgen05.commit.cta_group::1.mbarrier::arrive::one.shared::cluster.b64 [%0];" :: "r"(mb) : "memory")
#define TC_ALLOC_CG2(smaddr, n)  asm volatile("tcgen05.alloc.cta_group::2.sync.aligned.shared::cta.b32 [%0], %1;" :: "r"(smaddr), "r"(n) : "memory")
#define TC_RELINQ_CG2()          asm volatile("tcgen05.relinquish_alloc_permit.cta_group::2.sync.aligned;")
#define TC_DEALLOC_CG2(t, n)     asm volatile("tcgen05.dealloc.cta_group::2.sync.aligned.b32 %0, %1;" :: "r"(t), "r"(n))
#define TC_COMMIT_MC2(mb) \
    asm volatile("tcgen05.commit.cta_group::2.mbarrier::arrive::one.shared::cluster.multicast::cluster.b64 [%0], %1;" \
        :: "r"(mb), "h"((unsigned short)0x3) : "memory")
#define TC_FENCE_AFTER()      asm volatile("tcgen05.fence::after_thread_sync;" ::: "memory")
#define TC_FENCE_BEFORE()     asm volatile("tcgen05.fence::before_thread_sync;" ::: "memory")
#define TC_WAIT_LD()          asm volatile("tcgen05.wait::ld.sync.aligned;" ::: "memory")
#define TC_LD_X32(r, addr) \
    asm volatile("tcgen05.ld.sync.aligned.32x32b.x32.b32 " \
        "{%0,%1,%2,%3,%4,%5,%6,%7,%8,%9,%10,%11,%12,%13,%14,%15," \
        "%16,%17,%18,%19,%20,%21,%22,%23,%24,%25,%26,%27,%28,%29,%30,%31}, [%32];" \
        : "=r"((r)[0]),"=r"((r)[1]),"=r"((r)[2]),"=r"((r)[3]),"=r"((r)[4]),"=r"((r)[5]),"=r"((r)[6]),"=r"((r)[7]), \
          "=r"((r)[8]),"=r"((r)[9]),"=r"((r)[10]),"=r"((r)[11]),"=r"((r)[12]),"=r"((r)[13]),"=r"((r)[14]),"=r"((r)[15]), \
          "=r"((r)[16]),"=r"((r)[17]),"=r"((r)[18]),"=r"((r)[19]),"=r"((r)[20]),"=r"((r)[21]),"=r"((r)[22]),"=r"((r)[23]), \
          "=r"((r)[24]),"=r"((r)[25]),"=r"((r)[26]),"=r"((r)[27]),"=r"((r)[28]),"=r"((r)[29]),"=r"((r)[30]),"=r"((r)[31]) \
        : "r"(addr))
#define CLUSTER_SYNC() do { \
    asm volatile("barrier.cluster.arrive.aligned;" ::: "memory"); \
    asm volatile("barrier.cluster.wait.aligned;" ::: "memory"); \
} while (0)

static constexpr uint64_t DESC_SW128 =
    (uint64_t(2) << 61) | (uint64_t(1) << 46) | (uint64_t(64) << 32) | (uint64_t(1) << 16);
__device__ __forceinline__ uint64_t mk_desc(uint32_t sm) {
    return DESC_SW128 | ((uint64_t)(sm >> 4) & 0x3FFF);
}
#define IDESC_CG2_N256 0x10400490u
#define IDESC_CG2_N128 0x10200490u
__device__ __forceinline__ void mma_cg2(uint32_t d, uint64_t a, uint64_t b,
                                        uint32_t idesc, uint32_t en) {
    asm volatile("{ .reg .pred p; setp.ne.u32 p, %5, 0;\n\t"
        "tcgen05.mma.cta_group::2.kind::f16 [%0], %1, %2, %3, {%4,%4,%4,%4,%4,%4,%4,%4}, p; }"
        :: "r"(d), "l"(a), "l"(b), "r"(idesc), "r"(0u), "r"(en) : "memory");
}
#define IDESC_M128N128 0x8200490u
__device__ __forceinline__ void mma_128(uint32_t d, uint64_t a, uint64_t b, uint32_t en) {
    asm volatile("{ .reg .pred p; setp.ne.u32 p, %5, 0;\n\t"
        "tcgen05.mma.cta_group::1.kind::f16 [%0], %1, %2, %3, {%4,%4,%4,%4}, p; }"
        :: "r"(d), "l"(a), "l"(b), "r"(IDESC_M128N128), "r"(0u), "r"(en) : "memory");
}

// grid-wide hop barrier: all 192 threads of every gemm CTA participate
__device__ __forceinline__ void hop_barrier(int h) {
    __threadfence();
    asm volatile("bar.sync 0, 192;" ::: "memory");
    if (threadIdx.x == 0) {
        atomicAdd(&g_bar, 1u);
        spin_ge(&g_bar, 136u * (unsigned)h);
    }
    asm volatile("bar.sync 0, 192;" ::: "memory");
    __threadfence();
    asm volatile("fence.proxy.async;" ::: "memory");
}
#endif // HAS_TC

// ======================= persistent cg2 propagation GEMM: 6 hops in ONE launch =========
#define KCHUNK 64
#define NCHUNK 32
#define NSTAGE 3
#define NPAIRS 68
#define SM_TMEMPTR 0
#define SM_FULL(s)  (16 + (s) * 8)
#define SM_EMPTY(s) (48 + (s) * 8)
#define SM_MDONE(t) (80 + (t) * 8)
#define SM_EPID(t)  (96 + (t) * 8)
#define STAGE_CTA 65536
#define SM_STAGE(s) (1024 + (s) * STAGE_CTA)
#define A_HI(s) (SM_STAGE(s))
#define A_LO(s) (SM_STAGE(s) + 16384)
#define B_HI(s) (SM_STAGE(s) + 32768)
#define B_LO(s) (SM_STAGE(s) + 49152)
#define EPI_PITCH 136
#define EPI_BYTES (32 * EPI_PITCH * 2)
#define EPI_HI (1024 + NSTAGE * STAGE_CTA)
#define EPI_LO (EPI_HI + EPI_BYTES)
#define TC_SMEM (EPI_LO + EPI_BYTES)

#if HAS_TC
__device__ __forceinline__ void unit_params(int pair, int u, int& mt, int& nt,
                                            int& noff, int& nlen) {
    int t = (u == 0) ? pair : ((u == 1) ? pair + NPAIRS : 136 + (pair >> 1));
    mt = t & 7;
    nt = t >> 3;
    noff = (u < 2) ? 0 : ((pair & 1) * 128);
    nlen = (u < 2) ? 256 : 128;
}
#endif

__global__ __launch_bounds__(192, 1) __cluster_dims__(2, 1, 1) void gemm_tc(
    const __grid_constant__ CUtensorMap mapAhi,
    const __grid_constant__ CUtensorMap mapAlo,
    const __grid_constant__ CUtensorMap mapBhi0,    // buffer0 as src, box 64x128
    const __grid_constant__ CUtensorMap mapBlo0,
    const __grid_constant__ CUtensorMap mapBhi0q,   // buffer0, box 64x64
    const __grid_constant__ CUtensorMap mapBlo0q,
    const __grid_constant__ CUtensorMap mapBhi1,    // buffer1 as src
    const __grid_constant__ CUtensorMap mapBlo1,
    const __grid_constant__ CUtensorMap mapBhi1q,
    const __grid_constant__ CUtensorMap mapBlo1q,
    __nv_bfloat16* __restrict__ hi0, __nv_bfloat16* __restrict__ lo0,
    __nv_bfloat16* __restrict__ hi1, __nv_bfloat16* __restrict__ lo1,
    __nv_bfloat16* __restrict__ tmThi0, __nv_bfloat16* __restrict__ tmTlo0,
    __nv_bfloat16* __restrict__ tmThi1, __nv_bfloat16* __restrict__ tmTlo1)
{
#if HAS_TC
    extern __shared__ char smem[];
    uint32_t smb = smem_u32(smem);
    int tid = threadIdx.x, wid = tid >> 5, lane = tid & 31;
    uint32_t rank;
    asm("mov.u32 %0, %%cluster_ctarank;" : "=r"(rank));
    int pair = blockIdx.x >> 1;
    int my_units = 2 + (pair < 64 ? 1 : 0);
    int total = my_units * NCHUNK;

    if (wid == 4) { TC_ALLOC_CG2(smb + SM_TMEMPTR, 512); TC_RELINQ_CG2(); }
    if (tid == 0) {
        #pragma unroll
        for (int s = 0; s < NSTAGE; s++) {
            MBAR_INIT(smb + SM_FULL(s), 1);
            MBAR_INIT(smb + SM_EMPTY(s), 1);
        }
        MBAR_INIT(smb + SM_MDONE(0), 1);
        MBAR_INIT(smb + SM_MDONE(1), 1);
        MBAR_INIT(smb + SM_EPID(0), 2);
        MBAR_INIT(smb + SM_EPID(1), 2);
    }
    __syncthreads();
    CLUSTER_SYNC();

    uint32_t tmem;
    asm volatile("ld.shared.b32 %0, [%1];" : "=r"(tmem) : "r"(smb + SM_TMEMPTR));

    if (wid == 4) {
        // ---------------- TMA producer warp (both ranks), persistent over hops --------
        uint32_t e1 = elect_one();
        uint32_t pe[NSTAGE] = {0, 0, 0};
        int s = 0, gg = 0;
        for (int h = 1; h <= NHOPS; h++) {
            const CUtensorMap* bh  = (h & 1) ? &mapBhi0  : &mapBhi1;
            const CUtensorMap* bl  = (h & 1) ? &mapBlo0  : &mapBlo1;
            const CUtensorMap* bhq = (h & 1) ? &mapBhi0q : &mapBhi1q;
            const CUtensorMap* blq = (h & 1) ? &mapBlo0q : &mapBlo1q;
            if (e1) {
                for (int g = 0; g < total; g++, gg++) {
                    if (gg >= NSTAGE) { MBAR_WAIT(smb + SM_EMPTY(s), pe[s]); pe[s] ^= 1; }
                    int u = g >> 5, c = g & 31;
                    int mt, nt, noff, nlen;
                    unit_params(pair, u, mt, nt, noff, nlen);
                    int k0 = c * KCHUNK;
                    int ma = mt * 256 + (int)rank * 128;
                    int nb = nt * 256 + noff + (int)rank * (nlen >> 1);
                    if (rank == 0) {
                        uint32_t tx = 65536u + (uint32_t)nlen * 256u;
                        MBAR_EXPECT_TX(smb + SM_FULL(s), tx);
                    }
                    TMA_2D_CG2(smb + A_HI(s), &mapAhi, k0, ma, smb + SM_FULL(s));
                    TMA_2D_CG2(smb + A_LO(s), &mapAlo, k0, ma, smb + SM_FULL(s));
                    if (nlen == 256) {
                        TMA_2D_CG2(smb + B_HI(s), bh, k0, nb, smb + SM_FULL(s));
                        TMA_2D_CG2(smb + B_LO(s), bl, k0, nb, smb + SM_FULL(s));
                    } else {
                        TMA_2D_CG2(smb + B_HI(s), bhq, k0, nb, smb + SM_FULL(s));
                        TMA_2D_CG2(smb + B_LO(s), blq, k0, nb, smb + SM_FULL(s));
                    }
                    if (++s == NSTAGE) s = 0;
                }
            }
            hop_barrier(h);
        }
    } else if (wid == 5) {
        // ---------------- MMA consumer warp (rank 0 only), persistent -----------------
        uint32_t e1 = elect_one();
        uint32_t pf[NSTAGE] = {0, 0, 0}, ped0 = 0;
        int s = 0;
        for (int h = 1; h <= NHOPS; h++) {
            if (rank == 0) {
                for (int g = 0; g < total; g++) {
                    int c = g & 31, u = g >> 5, slot = u & 1;
                    int mt, nt, noff, nlen;
                    unit_params(pair, u, mt, nt, noff, nlen);
                    uint32_t idesc = (nlen == 256) ? IDESC_CG2_N256 : IDESC_CG2_N128;
                    if (c == 0 && u == 2) {   // within-hop D-slot-0 reuse
                        MBAR_WAIT(smb + SM_EPID(0), ped0); ped0 ^= 1;
                    }
                    MBAR_WAIT(smb + SM_FULL(s), pf[s]); pf[s] ^= 1;
                    if (e1) {
                        uint64_t ah = mk_desc(smb + A_HI(s));
                        uint64_t al = mk_desc(smb + A_LO(s));
                        uint64_t bh = mk_desc(smb + B_HI(s));
                        uint64_t bl = mk_desc(smb + B_LO(s));
                        uint32_t dt = tmem + slot * 256;
                        #pragma unroll
                        for (int ks = 0; ks < 4; ks++)
                            mma_cg2(dt, ah + ks * 2, bh + ks * 2, idesc, (c == 0 && ks == 0) ? 0u : 1u);
                        #pragma unroll
                        for (int ks = 0; ks < 4; ks++)
                            mma_cg2(dt, ah + ks * 2, bl + ks * 2, idesc, 1u);
                        #pragma unroll
                        for (int ks = 0; ks < 4; ks++)
                            mma_cg2(dt, al + ks * 2, bh + ks * 2, idesc, 1u);
                        TC_COMMIT_MC2(smb + SM_EMPTY(s));
                        if (c == NCHUNK - 1) TC_COMMIT_MC2(smb + SM_MDONE(slot));
                    }
                    if (++s == NSTAGE) s = 0;
                }
            }
            hop_barrier(h);
        }
    } else {
        // ---------------- epilogue warps 0..3 (128 threads), persistent ---------------
        uint32_t pm[2] = {0, 0};
        __nv_bfloat16* shi = (__nv_bfloat16*)(smem + EPI_HI);
        __nv_bfloat16* slo = (__nv_bfloat16*)(smem + EPI_LO);
        int mloc = wid * 32 + lane;
        for (int h = 1; h <= NHOPS; h++) {
            int write_nm = (h < NHOPS);
            __nv_bfloat16* dst_hi = (h & 1) ? hi1 : hi0;
            __nv_bfloat16* dst_lo = (h & 1) ? lo1 : lo0;
            __nv_bfloat16* tmT_hi = (h & 1) ? tmThi1 : tmThi0;
            __nv_bfloat16* tmT_lo = (h & 1) ? tmTlo1 : tmTlo0;
            // tmT slot is read by mlp(h-2): wait its 12 CTAs before overwriting
            if (h >= 2) {
                if (tid == 0) spin_ge(&g_mflag[h - 2], 12u);
                asm volatile("bar.sync 1, 128;" ::: "memory");
                __threadfence();
            }
            for (int u = 0; u < my_units; u++) {
                int slot = u & 1;
                int mt, nt, noff, nlen;
                unit_params(pair, u, mt, nt, noff, nlen);
                int mg = mt * 256 + (int)rank * 128;
                int ng = nt * 256 + noff;
                int blkcnt = nlen >> 5;
                MBAR_WAIT(smb + SM_MDONE(slot), pm[slot]); pm[slot] ^= 1;
                TC_FENCE_AFTER();
                #pragma unroll 1
                for (int blk = 0; blk < blkcnt; blk++) {
                    uint32_t r[32];
                    TC_LD_X32(r, tmem + slot * 256 + blk * 32);
                    TC_WAIT_LD();
                    #pragma unroll
                    for (int j = 0; j < 32; j++) {
                        float v = __uint_as_float(r[j]);
                        __nv_bfloat16 hh = __float2bfloat16(v);
                        __nv_bfloat16 ll = __float2bfloat16(v - __bfloat162float(hh));
                        shi[j * EPI_PITCH + mloc] = hh;
                        slo[j * EPI_PITCH + mloc] = ll;
                    }
                    asm volatile("bar.sync 1, 128;" ::: "memory");
                    if (write_nm) {
                        #pragma unroll
                        for (int idx = tid; idx < 512; idx += 128) {
                            int nl = idx >> 4;
                            int m8 = (idx & 15) * 8;
                            size_t ga = (size_t)(ng + blk * 32 + nl) * MDIM + mg + m8;
                            *(uint4*)(dst_hi + ga) = *(uint4*)(shi + nl * EPI_PITCH + m8);
                            *(uint4*)(dst_lo + ga) = *(uint4*)(slo + nl * EPI_PITCH + m8);
                        }
                    }
                    {
                        int mrow = mg + tid;
                        #pragma unroll
                        for (int j8 = 0; j8 < 32; j8 += 8) {
                            int n0 = ng + blk * 32 + j8;
                            int bb = n0 / WDIM;
                            int w = n0 - bb * WDIM;
                            uint4 uh, ul;
                            unsigned short* ph = (unsigned short*)&uh;
                            unsigned short* pl = (unsigned short*)&ul;
                            #pragma unroll
                            for (int q = 0; q < 8; q++) {
                                ph[q] = *(unsigned short*)&shi[(j8 + q) * EPI_PITCH + tid];
                                pl[q] = *(unsigned short*)&slo[(j8 + q) * EPI_PITCH + tid];
                            }
                            size_t base = ((size_t)bb * MDIM + mrow) * KWPAD + w;
                            *(uint4*)(tmT_hi + base) = uh;
                            *(uint4*)(tmT_lo + base) = ul;
                        }
                    }
                    asm volatile("bar.sync 1, 128;" ::: "memory");
                }
                TC_FENCE_BEFORE();
                // balanced EPID: one arrival pair per hop (only when u2 will reuse slot0)
                if (tid == 0 && u == 0 && my_units == 3)
                    MBAR_ARRIVE_RANK0(smb + SM_EPID(0));
            }
            hop_barrier(h);
        }
    }
    __syncthreads();
    if (wid == 4) TC_DEALLOC_CG2(tmem, 512);
    CLUSTER_SYNC();
#endif
}

// ======================= persistent tensor-core fused MLP (dynamic grid) =======
#define MLF(s)    (16 + (s) * 8)
#define MLE(s)    (48 + (s) * 8)
#define MLW1F     80
#define MLMD(t)   (88 + (t) * 8)
#define MLEP(t)   (104 + (t) * 8)
#define MLA_HI(s) (1024 + (s) * 32768)
#define MLA_LO(s) (MLA_HI(s) + 16384)
#define MLW1H(c)  (1024 + 98304 + (c) * 16384)
#define MLW1L(c)  (1024 + 98304 + 49152 + (c) * 16384)
#define MLP_SMEM  (1024 + 98304 + 98304)   // 197632

__global__ __launch_bounds__(192, 1) void mlp_tc(
    const __grid_constant__ CUtensorMap mapAhi,
    const __grid_constant__ CUtensorMap mapAlo,
    const __grid_constant__ CUtensorMap mapBhi,
    const __grid_constant__ CUtensorMap mapBlo,
    const float* __restrict__ b1,
    const float* __restrict__ W2,
    const float* __restrict__ b2,
    int hop, int accum,
    float* __restrict__ out)
{
#if HAS_TC
    extern __shared__ char smem[];
    uint32_t smb = smem_u32(smem);
    int tid = threadIdx.x, wid = tid >> 5;
    int cta = blockIdx.x;
    int G = gridDim.x;
    int ntiles = (511 - cta) / G + 1;

    // wait until gemm finished hop `hop` (device flag; hop 0 gated by event on host)
    if (hop >= 1) {
        if (tid == 0) spin_ge(&g_bar, 136u * (unsigned)hop);
        __syncthreads();
        __threadfence();
        asm volatile("fence.proxy.async;" ::: "memory");
    }

    if (wid == 4) { TC_ALLOC(smb + SM_TMEMPTR, 256); TC_RELINQ(); }
    if (tid == 0) {
        #pragma unroll
        for (int s = 0; s < 3; s++) {
            MBAR_INIT(smb + MLF(s), 1);
            MBAR_INIT(smb + MLE(s), 1);
        }
        MBAR_INIT(smb + MLW1F, 1);
        MBAR_INIT(smb + MLMD(0), 1);
        MBAR_INIT(smb + MLMD(1), 1);
        MBAR_INIT(smb + MLEP(0), 1);
        MBAR_INIT(smb + MLEP(1), 1);
    }
    __syncthreads();
    uint32_t tmem;
    asm volatile("ld.shared.b32 %0, [%1];" : "=r"(tmem) : "r"(smb + SM_TMEMPTR));

    int total = ntiles * 3;
    if (wid == 4) {
        uint32_t e1 = elect_one();
        uint32_t pe[3] = {0, 0, 0};
        if (e1) {
            MBAR_EXPECT_TX(smb + MLW1F, 98304);
            #pragma unroll
            for (int c = 0; c < 3; c++) {
                TMA_2D(smb + MLW1H(c), &mapBhi, c * 64, hop * HIDD, smb + MLW1F);
                TMA_2D(smb + MLW1L(c), &mapBlo, c * 64, hop * HIDD, smb + MLW1F);
            }
            int s = 0;
            for (int g = 0; g < total; g++) {
                if (g >= 3) { MBAR_WAIT(smb + MLE(s), pe[s]); pe[s] ^= 1; }
                int u = g / 3, c = g - u * 3;
                int t = cta + G * u;
                int arow = (t >> 4) * MDIM + (t & 15) * 128;
                MBAR_EXPECT_TX(smb + MLF(s), 32768);
                TMA_2D(smb + MLA_HI(s), &mapAhi, c * 64, arow, smb + MLF(s));
                TMA_2D(smb + MLA_LO(s), &mapAlo, c * 64, arow, smb + MLF(s));
                if (++s == 3) s = 0;
            }
        }
    } else if (wid == 5) {
        uint32_t e1 = elect_one();
        uint32_t pf[3] = {0, 0, 0}, ped[2] = {0, 0};
        MBAR_WAIT(smb + MLW1F, 0);
        int s = 0;
        for (int g = 0; g < total; g++) {
            int u = g / 3, c = g - u * 3, slot = u & 1;
            if (c == 0 && u >= 2) {
                MBAR_WAIT(smb + MLEP(slot), ped[slot]); ped[slot] ^= 1;
            }
            MBAR_WAIT(smb + MLF(s), pf[s]); pf[s] ^= 1;
            if (e1) {
                uint64_t ah = mk_desc(smb + MLA_HI(s));
                uint64_t al = mk_desc(smb + MLA_LO(s));
                uint64_t bh = mk_desc(smb + MLW1H(c));
                uint64_t bl = mk_desc(smb + MLW1L(c));
                uint32_t dt = tmem + slot * 128;
                int nks = (c == 2) ? 3 : 4;   // K=168 fits in 176
                for (int ks = 0; ks < nks; ks++)
                    mma_128(dt, ah + ks * 2, bh + ks * 2, (c == 0 && ks == 0) ? 0u : 1u);
                for (int ks = 0; ks < nks; ks++)
                    mma_128(dt, ah + ks * 2, bl + ks * 2, 1u);
                for (int ks = 0; ks < nks; ks++)
                    mma_128(dt, al + ks * 2, bh + ks * 2, 1u);
                TC_COMMIT(smb + MLE(s));
                if (c == 2) TC_COMMIT(smb + MLMD(slot));
            }
            if (++s == 3) s = 0;
        }
    } else {
        uint32_t pm[2] = {0, 0};
        const float* b1h = b1 + hop * HIDD;
        const float* W2h = W2 + hop * HIDD;
        float b2v = b2[hop];
        for (int u = 0; u < ntiles; u++) {
            int slot = u & 1;
            int t = cta + G * u;
            int gi = (t >> 4) * MDIM + (t & 15) * 128 + tid;
            MBAR_WAIT(smb + MLMD(slot), pm[slot]); pm[slot] ^= 1;
            TC_FENCE_AFTER();
            float s = 0.f;
            #pragma unroll 1
            for (int cb = 0; cb < 4; cb++) {
                uint32_t r[32];
                TC_LD_X32(r, tmem + slot * 128 + cb * 32);
                TC_WAIT_LD();
                #pragma unroll
                for (int j = 0; j < 32; j++) {
                    int h = cb * 32 + j;
                    s += W2h[h] * fmaxf(__uint_as_float(r[j]) + b1h[h], 0.f);
                }
            }
            TC_FENCE_BEFORE();
            s += b2v;
            if (accum) s += out[gi];
            out[gi] = s;
            asm volatile("bar.sync 1, 128;" ::: "memory");
            if (tid == 0) MBAR_ARRIVE(smb + MLEP(slot));
        }
    }
    __syncthreads();
    if (wid == 4) TC_DEALLOC(tmem, 256);
    __syncthreads();
    if (tid == 0) {           // signal: this CTA's tmT reads complete
        __threadfence();
        atomicAdd(&g_mflag[hop], 1u);
    }
#endif
}

// ======================= host =======================
typedef CUresult (*PFN_tmEncode)(CUtensorMap*, CUtensorMapDataType, cuuint32_t, void*,
                                 const cuuint64_t*, const cuuint64_t*, const cuuint32_t*,
                                 const cuuint32_t*, CUtensorMapInterleave, CUtensorMapSwizzle,
                                 CUtensorMapL2promotion, CUtensorMapFloatOOBfill);

static void make_map(PFN_tmEncode enc, CUtensorMap* m, void* ptr,
                     unsigned long long d0, unsigned long long d1,
                     unsigned box0, unsigned box1) {
    cuuint64_t dims[2] = {d0, d1};
    cuuint64_t strides[1] = {d0 * 2};
    cuuint32_t box[2] = {box0, box1};
    cuuint32_t es[2] = {1, 1};
    enc(m, CU_TENSOR_MAP_DATA_TYPE_BFLOAT16, 2, ptr, dims, strides, box, es,
        CU_TENSOR_MAP_INTERLEAVE_NONE, CU_TENSOR_MAP_SWIZZLE_128B,
        CU_TENSOR_MAP_L2_PROMOTION_L2_128B, CU_TENSOR_MAP_FLOAT_OOB_FILL_NONE);
}

extern "C" void kernel_launch(void* const* d_in, const int* in_sizes, int n_in,
                              void* d_out, int out_size) {
    const float* x  = (const float*)d_in[0];
    const float* L  = (const float*)d_in[1];
    const float* W1 = (const float*)d_in[2];
    const float* b1 = (const float*)d_in[3];
    const float* W2 = (const float*)d_in[4];
    const float* b2 = (const float*)d_in[5];
    float* out = (float*)d_out;

    __nv_bfloat16 *hi0, *hi1, *lo0, *lo1, *Lhi, *Llo, *W1hi, *W1lo;
    __nv_bfloat16 *tmThi0, *tmTlo0, *tmThi1, *tmTlo1;
    cudaGetSymbolAddress((void**)&hi0, g_hi);
    hi1 = hi0 + (size_t)BWCOL * MDIM;
    cudaGetSymbolAddress((void**)&lo0, g_lo);
    lo1 = lo0 + (size_t)BWCOL * MDIM;
    cudaGetSymbolAddress((void**)&Lhi, g_Lhi);
    cudaGetSymbolAddress((void**)&Llo, g_Llo);
    cudaGetSymbolAddress((void**)&W1hi, g_W1hi);
    cudaGetSymbolAddress((void**)&W1lo, g_W1lo);
    cudaGetSymbolAddress((void**)&tmThi0, g_tmThi);
    tmThi1 = tmThi0 + (size_t)BATCH * MDIM * KWPAD;
    cudaGetSymbolAddress((void**)&tmTlo0, g_tmTlo);
    tmTlo1 = tmTlo0 + (size_t)BATCH * MDIM * KWPAD;

    PFN_tmEncode enc = nullptr;
    cudaDriverEntryPointQueryResult qr;
    cudaGetDriverEntryPointByVersion("cuTensorMapEncodeTiled", (void**)&enc, 12000,
                                     cudaEnableDefault, &qr);

    CUtensorMap mAhi, mAlo, mBhi[2], mBlo[2], mBhiq[2], mBloq[2];
    CUtensorMap mW1hi, mW1lo, mTmhi[2], mTmlo[2];
    make_map(enc, &mAhi, Lhi, MDIM, MDIM, 64, 128);
    make_map(enc, &mAlo, Llo, MDIM, MDIM, 64, 128);
    make_map(enc, &mBhi[0], hi0, MDIM, BWCOL, 64, 128);
    make_map(enc, &mBhi[1], hi1, MDIM, BWCOL, 64, 128);
    make_map(enc, &mBlo[0], lo0, MDIM, BWCOL, 64, 128);
    make_map(enc, &mBlo[1], lo1, MDIM, BWCOL, 64, 128);
    make_map(enc, &mBhiq[0], hi0, MDIM, BWCOL, 64, 64);
    make_map(enc, &mBhiq[1], hi1, MDIM, BWCOL, 64, 64);
    make_map(enc, &mBloq[0], lo0, MDIM, BWCOL, 64, 64);
    make_map(enc, &mBloq[1], lo1, MDIM, BWCOL, 64, 64);
    make_map(enc, &mW1hi, W1hi, KWPAD, (NHOPS + 1) * HIDD, 64, 128);
    make_map(enc, &mW1lo, W1lo, KWPAD, (NHOPS + 1) * HIDD, 64, 128);
    make_map(enc, &mTmhi[0], tmThi0, KWPAD, (unsigned long long)BATCH * MDIM, 64, 128);
    make_map(enc, &mTmhi[1], tmThi1, KWPAD, (unsigned long long)BATCH * MDIM, 64, 128);
    make_map(enc, &mTmlo[0], tmTlo0, KWPAD, (unsigned long long)BATCH * MDIM, 64, 128);
    make_map(enc, &mTmlo[1], tmTlo1, KWPAD, (unsigned long long)BATCH * MDIM, 64, 128);

    cudaFuncSetAttribute(gemm_tc, cudaFuncAttributeMaxDynamicSharedMemorySize, TC_SMEM);
    cudaFuncSetAttribute(mlp_tc, cudaFuncAttributeMaxDynamicSharedMemorySize, MLP_SMEM);

    cudaStream_t s1;
    cudaStreamCreateWithFlags(&s1, cudaStreamNonBlocking);
    cudaEvent_t eP, eL, eS, eM6;
    cudaEventCreateWithFlags(&eP, cudaEventDisableTiming);
    cudaEventCreateWithFlags(&eL, cudaEventDisableTiming);
    cudaEventCreateWithFlags(&eS, cudaEventDisableTiming);
    cudaEventCreateWithFlags(&eM6, cudaEventDisableTiming);

    // stream 0: reset flags first (determinism across graph replays)
    reset_kernel<<<1, 1>>>();
    cudaEventRecord(eS, 0);
    cudaStreamWaitEvent(s1, eS, 0);   // legal fork into capture, after reset

    // s1: L and W1 splits, concurrent with prep
    {
        int n4 = (MDIM * MDIM) / 4;
        split_kernel<<<(n4 + 255) / 256, 256, 0, s1>>>(L, Lhi, Llo, n4);
        int nw = (NHOPS + 1) * HIDD * KWPAD;
        splitW1_kernel<<<(nw + 255) / 256, 256, 0, s1>>>(W1, W1hi, W1lo);
        cudaEventRecord(eL, s1);
    }
    // stream 0: prep (x -> hi0/lo0 + tmT slot 0), vectorized
    {
        dim3 tg(MDIM / 64, KWPAD / 32, BATCH);
        prep_kernel<<<tg, 256>>>(x, hi0, lo0, tmThi0, tmTlo0);
        cudaEventRecord(eP, 0);
        cudaStreamWaitEvent(0, eL, 0);    // gemm needs Lhi/Llo
    }

    // ONE persistent gemm launch covering hops 1..6 (136 CTAs; 12 SMs left for mlp)
    gemm_tc<<<2 * NPAIRS, 192, TC_SMEM>>>(
        mAhi, mAlo,
        mBhi[0], mBlo[0], mBhiq[0], mBloq[0],
        mBhi[1], mBlo[1], mBhiq[1], mBloq[1],
        hi0, lo0, hi1, lo1,
        tmThi0, tmTlo0, tmThi1, tmTlo1);

    // mlp chain on s1: hop 0 gated by prep event; hops 1..6 self-gate on g_bar
    cudaStreamWaitEvent(s1, eP, 0);
    mlp_tc<<<12, 192, MLP_SMEM, s1>>>(mTmhi[0], mTmlo[0], mW1hi, mW1lo,
                                      b1, W2, b2, 0, 0, out);
    for (int hop = 1; hop <= NHOPS; hop++) {
        int slot = hop & 1;
        int mgrid = (hop < NHOPS) ? 12 : 128;
        mlp_tc<<<mgrid, 192, MLP_SMEM, s1>>>(mTmhi[slot], mTmlo[slot], mW1hi, mW1lo,
                                             b1, W2, b2, hop, 1, out);
    }
    cudaEventRecord(eM6, s1);
    cudaStreamWaitEvent(0, eM6, 0);   // join: out complete after final MLP
}